// round 7
// baseline (speedup 1.0000x reference)
#include <cuda_runtime.h>
#include <math.h>
#include <stdint.h>

// ---------------- problem constants ----------------
// B=8, C=512, HEADS=8, DH=64, tokens=4097 (cls+4096), pad=255 -> N=4352
// landmarks m=256, l=17, pinv iters=6, res kernel 33  (build r7: 64x64 warp tiles, frag-major smem)
#define LSUB 17

// ---------------- device scratch ----------------
__device__ float g_h   [8L*4097*512];
__device__ float g_h2  [8L*4097*512];
__device__ float g_xp  [8L*4352*512];
__device__ float g_qkv [8L*4352*1536];
__device__ float g_ql  [64L*256*64];
__device__ float g_kl  [64L*256*64];
__device__ float g_sim1[64L*4352*256];
__device__ float g_sim3[64L*256*4352];
__device__ float g_a2  [64L*256*256];
__device__ float g_zA  [64L*256*256];
__device__ float g_zB  [64L*256*256];
__device__ float g_xz  [64L*256*256];
__device__ float g_t1  [64L*256*256];
__device__ float g_t2  [64L*256*256];
__device__ float g_a3v [64L*256*64];
__device__ float g_tmp2[64L*256*64];
__device__ float g_ac  [8L*4097*512];
__device__ float g_cnn [8L*512*4096];
__device__ float g_yp  [8L*512*4096];
__device__ float g_scal[2];

__device__ __forceinline__ float4 ldg4(const float* p){ return *(const float4*)p; }

// ---------------- tf32 mma helpers ----------------
__device__ __forceinline__ uint32_t f2tf(float x){
    uint32_t u; asm("cvt.rna.tf32.f32 %0, %1;" : "=r"(u) : "f"(x)); return u;
}
__device__ __forceinline__ void mma8(float* d, const uint32_t* a, const uint32_t* b){
    asm("mma.sync.aligned.m16n8k8.row.col.f32.tf32.tf32.f32 "
        "{%0,%1,%2,%3}, {%4,%5,%6,%7}, {%8,%9}, {%0,%1,%2,%3};"
        : "+f"(d[0]),"+f"(d[1]),"+f"(d[2]),"+f"(d[3])
        : "r"(a[0]),"r"(a[1]),"r"(a[2]),"r"(a[3]), "r"(b[0]),"r"(b[1]));
}

// Fragment-major scatter: element (row,k) of a 128x16 A tile -> LDS.128-loadable layout
__device__ __forceinline__ void scatA(uint32_t* Af, int row, int k, uint32_t v){
    int ks=k>>3, kc=k&7;
    Af[(((ks<<3)+(row>>4))<<7) + ((((row&7)<<2)+(kc&3))<<2) + ((row>>3)&1) + ((kc>>2)<<1)] = v;
}
// B tile with 32 n-tiles (256 cols)
__device__ __forceinline__ void scatB32(uint32_t* Bf, int n, int k, uint32_t v){
    int ks=k>>3, kc=k&7;
    Bf[(((ks<<5)+(n>>3))<<6) + ((((n&7)<<2)+(kc&3))<<1) + (kc>>2)] = v;
}
// B tile with 8 n-tiles (64 cols)
__device__ __forceinline__ void scatB8(uint32_t* Bf, int n, int k, uint32_t v){
    int ks=k>>3, kc=k&7;
    Bf[(((ks<<3)+(n>>3))<<6) + ((((n&7)<<2)+(kc&3))<<1) + (kc>>2)] = v;
}

// ---------------- small kernels ----------------
__global__ void k_build_h(const float* __restrict__ feat, const float* __restrict__ cls){
    long idx = (long)blockIdx.x*256 + threadIdx.x;
    if(idx >= 8L*4097*512) return;
    int c = idx & 511; long r = idx >> 9; int t = (int)(r % 4097); int b = (int)(r / 4097);
    g_h[idx] = (t==0) ? cls[c] : feat[((long)b*4096 + (t-1))*512 + c];
}

__global__ void k_zero_pad(float* __restrict__ xp){
    long idx = (long)blockIdx.x*256 + threadIdx.x;
    if(idx >= 8L*255*512) return;
    int c = idx & 511; long r = idx >> 9; int t = (int)(r % 255); int b = (int)(r / 255);
    xp[((long)b*4352 + t)*512 + c] = 0.f;
}

__global__ void k_ln(const float* __restrict__ h, const float* __restrict__ g,
                     const float* __restrict__ be, float* __restrict__ xp){
    long r = blockIdx.x;
    int b = (int)(r / 4097); int t = (int)(r % 4097);
    const float* x = h + r*512;
    float* y = xp + ((long)b*4352 + 255 + t)*512;
    int tid = threadIdx.x;
    __shared__ float red[256];
    float s = 0.f;
    for(int i=tid;i<512;i+=256) s += x[i];
    red[tid]=s; __syncthreads();
    for(int k=128;k;k>>=1){ if(tid<k) red[tid]+=red[tid+k]; __syncthreads(); }
    float mean = red[0] * (1.f/512.f); __syncthreads();
    float v = 0.f;
    for(int i=tid;i<512;i+=256){ float d=x[i]-mean; v += d*d; }
    red[tid]=v; __syncthreads();
    for(int k=128;k;k>>=1){ if(tid<k) red[tid]+=red[tid+k]; __syncthreads(); }
    float rstd = rsqrtf(red[0]*(1.f/512.f) + 1e-5f);
    for(int i=tid;i<512;i+=256) y[i] = (x[i]-mean)*rstd*g[i] + be[i];
}

// =====================================================================
// TF32 MMA, 128x256 block, 8 warps of 64x64, frag-major smem, 2-stage
// =====================================================================

// C = alpha * A @ B^T (+bias)(+C)   A:(M,K), B:(N,K). N must be mult of 256, K of 16.
__global__ void __launch_bounds__(256) k_mma_nt256(
    const float* __restrict__ A, int lda, long sAb, long sAh,
    const float* __restrict__ B, int ldb, long sBb, long sBh,
    float* __restrict__ C, int ldc, long sCb, long sCh,
    int M, int K, float alpha, const float* __restrict__ bias, int acc_flag)
{
    int z = blockIdx.z; int hh = z & 7; int bb = z >> 3;
    A += (long)bb*sAb + (long)hh*sAh;
    B += (long)bb*sBb + (long)hh*sBh;
    C += (long)bb*sCb + (long)hh*sCh;
    __shared__ uint32_t Af[2][2048];
    __shared__ uint32_t Bf[2][4096];
    int t = threadIdx.x, lane = t & 31, warp = t >> 5;
    int wm = warp >> 2, wn = warp & 3;
    int r0 = blockIdx.x*128, c0 = blockIdx.y*256;
    int alr = t >> 1, alk = (t & 1)*8;
    const float* Ap = A + (long)(r0+alr)*lda + alk;
    bool mA = (r0+alr) < M;
    const float* Bp0 = B + (long)(c0+alr)*ldb + alk;
    const float* Bp1 = B + (long)(c0+alr+128)*ldb + alk;
    const float4 z4 = make_float4(0.f,0.f,0.f,0.f);
    float4 a0,a1,b00,b01,b10,b11;
    a0 = mA?ldg4(Ap):z4; a1 = mA?ldg4(Ap+4):z4;
    b00 = ldg4(Bp0); b01 = ldg4(Bp0+4);
    b10 = ldg4(Bp1); b11 = ldg4(Bp1+4);
    // store stage 0
    {
        scatA(Af[0], alr, alk+0, f2tf(a0.x)); scatA(Af[0], alr, alk+1, f2tf(a0.y));
        scatA(Af[0], alr, alk+2, f2tf(a0.z)); scatA(Af[0], alr, alk+3, f2tf(a0.w));
        scatA(Af[0], alr, alk+4, f2tf(a1.x)); scatA(Af[0], alr, alk+5, f2tf(a1.y));
        scatA(Af[0], alr, alk+6, f2tf(a1.z)); scatA(Af[0], alr, alk+7, f2tf(a1.w));
        scatB32(Bf[0], alr, alk+0, f2tf(b00.x)); scatB32(Bf[0], alr, alk+1, f2tf(b00.y));
        scatB32(Bf[0], alr, alk+2, f2tf(b00.z)); scatB32(Bf[0], alr, alk+3, f2tf(b00.w));
        scatB32(Bf[0], alr, alk+4, f2tf(b01.x)); scatB32(Bf[0], alr, alk+5, f2tf(b01.y));
        scatB32(Bf[0], alr, alk+6, f2tf(b01.z)); scatB32(Bf[0], alr, alk+7, f2tf(b01.w));
        scatB32(Bf[0], alr+128, alk+0, f2tf(b10.x)); scatB32(Bf[0], alr+128, alk+1, f2tf(b10.y));
        scatB32(Bf[0], alr+128, alk+2, f2tf(b10.z)); scatB32(Bf[0], alr+128, alk+3, f2tf(b10.w));
        scatB32(Bf[0], alr+128, alk+4, f2tf(b11.x)); scatB32(Bf[0], alr+128, alk+5, f2tf(b11.y));
        scatB32(Bf[0], alr+128, alk+6, f2tf(b11.z)); scatB32(Bf[0], alr+128, alk+7, f2tf(b11.w));
    }
    __syncthreads();
    float acc[4][8][4];
    #pragma unroll
    for(int i=0;i<4;i++)
        #pragma unroll
        for(int j=0;j<8;j++)
            #pragma unroll
            for(int q=0;q<4;q++) acc[i][j][q]=0.f;
    int nk = K >> 4;
    for(int kt=0; kt<nk; kt++){
        if(kt+1<nk){
            int o = (kt+1)*16;
            a0 = mA?ldg4(Ap+o):z4; a1 = mA?ldg4(Ap+o+4):z4;
            b00 = ldg4(Bp0+o); b01 = ldg4(Bp0+o+4);
            b10 = ldg4(Bp1+o); b11 = ldg4(Bp1+o+4);
        }
        int buf = kt & 1;
        #pragma unroll
        for(int ks=0;ks<2;ks++){
            uint32_t af[4][4], bfr[8][2];
            #pragma unroll
            for(int mt=0;mt<4;mt++)
                *(uint4*)af[mt] = *(const uint4*)&Af[buf][(((ks<<3)+(wm<<2)+mt)<<7) + (lane<<2)];
            #pragma unroll
            for(int nt=0;nt<8;nt++)
                *(uint2*)bfr[nt] = *(const uint2*)&Bf[buf][(((ks<<5)+(wn<<3)+nt)<<6) + (lane<<1)];
            #pragma unroll
            for(int mt=0;mt<4;mt++)
                #pragma unroll
                for(int nt=0;nt<8;nt++)
                    mma8(acc[mt][nt], af[mt], bfr[nt]);
        }
        if(kt+1<nk){
            int s = (kt+1) & 1;
            scatA(Af[s], alr, alk+0, f2tf(a0.x)); scatA(Af[s], alr, alk+1, f2tf(a0.y));
            scatA(Af[s], alr, alk+2, f2tf(a0.z)); scatA(Af[s], alr, alk+3, f2tf(a0.w));
            scatA(Af[s], alr, alk+4, f2tf(a1.x)); scatA(Af[s], alr, alk+5, f2tf(a1.y));
            scatA(Af[s], alr, alk+6, f2tf(a1.z)); scatA(Af[s], alr, alk+7, f2tf(a1.w));
            scatB32(Bf[s], alr, alk+0, f2tf(b00.x)); scatB32(Bf[s], alr, alk+1, f2tf(b00.y));
            scatB32(Bf[s], alr, alk+2, f2tf(b00.z)); scatB32(Bf[s], alr, alk+3, f2tf(b00.w));
            scatB32(Bf[s], alr, alk+4, f2tf(b01.x)); scatB32(Bf[s], alr, alk+5, f2tf(b01.y));
            scatB32(Bf[s], alr, alk+6, f2tf(b01.z)); scatB32(Bf[s], alr, alk+7, f2tf(b01.w));
            scatB32(Bf[s], alr+128, alk+0, f2tf(b10.x)); scatB32(Bf[s], alr+128, alk+1, f2tf(b10.y));
            scatB32(Bf[s], alr+128, alk+2, f2tf(b10.z)); scatB32(Bf[s], alr+128, alk+3, f2tf(b10.w));
            scatB32(Bf[s], alr+128, alk+4, f2tf(b11.x)); scatB32(Bf[s], alr+128, alk+5, f2tf(b11.y));
            scatB32(Bf[s], alr+128, alk+6, f2tf(b11.z)); scatB32(Bf[s], alr+128, alk+7, f2tf(b11.w));
            __syncthreads();
        }
    }
    int g = lane >> 2, tq = lane & 3;
    #pragma unroll
    for(int mt=0;mt<4;mt++)
    #pragma unroll
    for(int i=0;i<2;i++){
        int gm = r0 + wm*64 + mt*16 + i*8 + g;
        if(gm>=M) continue;
        #pragma unroll
        for(int nt=0;nt<8;nt++){
            int gn = c0 + wn*64 + nt*8 + 2*tq;
            float2 v;
            v.x = alpha*acc[mt][nt][2*i];
            v.y = alpha*acc[mt][nt][2*i+1];
            if(bias){ v.x += bias[gn]; v.y += bias[gn+1]; }
            float* cp = C + (long)gm*ldc + gn;
            if(acc_flag){ v.x += cp[0]; v.y += cp[1]; }
            *(float2*)cp = v;
        }
    }
}

// C = alpha * A @ B (NN), N mult of 256. pinv epilogues: cmode: C=dconst*I-v;  D: D=dconst*I-v.
__global__ void __launch_bounds__(256) k_mma_nn256(
    const float* __restrict__ A, int lda, long sAb, long sAh,
    const float* __restrict__ B, int ldb, long sBb, long sBh,
    float* __restrict__ C, int ldc, long sCb, long sCh,
    float* __restrict__ D, long sDb, long sDh,
    int M, int K, float alpha, float dconst, int cmode)
{
    int z = blockIdx.z; int hh = z & 7; int bb = z >> 3;
    A += (long)bb*sAb + (long)hh*sAh;
    B += (long)bb*sBb + (long)hh*sBh;
    C += (long)bb*sCb + (long)hh*sCh;
    if(D) D += (long)bb*sDb + (long)hh*sDh;
    __shared__ uint32_t Af[2][2048];
    __shared__ uint32_t Bf[2][4096];
    int t = threadIdx.x, lane = t & 31, warp = t >> 5;
    int wm = warp >> 2, wn = warp & 3;
    int r0 = blockIdx.x*128, c0 = blockIdx.y*256;
    int alr = t >> 1, alk = (t & 1)*8;
    const float* Ap = A + (long)(r0+alr)*lda + alk;
    bool mA = (r0+alr) < M;
    int bk = t >> 4, bn = (t & 15)*16;   // row bk (k), cols bn..bn+15
    const float* Bp = B + (long)bk*ldb + c0 + bn;
    const float4 z4 = make_float4(0.f,0.f,0.f,0.f);
    float4 a0,a1,b0,b1,b2,b3;
    a0 = mA?ldg4(Ap):z4; a1 = mA?ldg4(Ap+4):z4;
    b0 = ldg4(Bp); b1 = ldg4(Bp+4); b2 = ldg4(Bp+8); b3 = ldg4(Bp+12);
    {
        scatA(Af[0], alr, alk+0, f2tf(a0.x)); scatA(Af[0], alr, alk+1, f2tf(a0.y));
        scatA(Af[0], alr, alk+2, f2tf(a0.z)); scatA(Af[0], alr, alk+3, f2tf(a0.w));
        scatA(Af[0], alr, alk+4, f2tf(a1.x)); scatA(Af[0], alr, alk+5, f2tf(a1.y));
        scatA(Af[0], alr, alk+6, f2tf(a1.z)); scatA(Af[0], alr, alk+7, f2tf(a1.w));
        scatB32(Bf[0], bn+0, bk, f2tf(b0.x));  scatB32(Bf[0], bn+1, bk, f2tf(b0.y));
        scatB32(Bf[0], bn+2, bk, f2tf(b0.z));  scatB32(Bf[0], bn+3, bk, f2tf(b0.w));
        scatB32(Bf[0], bn+4, bk, f2tf(b1.x));  scatB32(Bf[0], bn+5, bk, f2tf(b1.y));
        scatB32(Bf[0], bn+6, bk, f2tf(b1.z));  scatB32(Bf[0], bn+7, bk, f2tf(b1.w));
        scatB32(Bf[0], bn+8, bk, f2tf(b2.x));  scatB32(Bf[0], bn+9, bk, f2tf(b2.y));
        scatB32(Bf[0], bn+10, bk, f2tf(b2.z)); scatB32(Bf[0], bn+11, bk, f2tf(b2.w));
        scatB32(Bf[0], bn+12, bk, f2tf(b3.x)); scatB32(Bf[0], bn+13, bk, f2tf(b3.y));
        scatB32(Bf[0], bn+14, bk, f2tf(b3.z)); scatB32(Bf[0], bn+15, bk, f2tf(b3.w));
    }
    __syncthreads();
    float acc[4][8][4];
    #pragma unroll
    for(int i=0;i<4;i++)
        #pragma unroll
        for(int j=0;j<8;j++)
            #pragma unroll
            for(int q=0;q<4;q++) acc[i][j][q]=0.f;
    int nk = K >> 4;
    for(int kt=0; kt<nk; kt++){
        if(kt+1<nk){
            long o = (long)(kt+1)*16;
            a0 = mA?ldg4(Ap+o):z4; a1 = mA?ldg4(Ap+o+4):z4;
            const float* Bq = Bp + o*ldb;
            b0 = ldg4(Bq); b1 = ldg4(Bq+4); b2 = ldg4(Bq+8); b3 = ldg4(Bq+12);
        }
        int buf = kt & 1;
        #pragma unroll
        for(int ks=0;ks<2;ks++){
            uint32_t af[4][4], bfr[8][2];
            #pragma unroll
            for(int mt=0;mt<4;mt++)
                *(uint4*)af[mt] = *(const uint4*)&Af[buf][(((ks<<3)+(wm<<2)+mt)<<7) + (lane<<2)];
            #pragma unroll
            for(int nt=0;nt<8;nt++)
                *(uint2*)bfr[nt] = *(const uint2*)&Bf[buf][(((ks<<5)+(wn<<3)+nt)<<6) + (lane<<1)];
            #pragma unroll
            for(int mt=0;mt<4;mt++)
                #pragma unroll
                for(int nt=0;nt<8;nt++)
                    mma8(acc[mt][nt], af[mt], bfr[nt]);
        }
        if(kt+1<nk){
            int s = (kt+1) & 1;
            scatA(Af[s], alr, alk+0, f2tf(a0.x)); scatA(Af[s], alr, alk+1, f2tf(a0.y));
            scatA(Af[s], alr, alk+2, f2tf(a0.z)); scatA(Af[s], alr, alk+3, f2tf(a0.w));
            scatA(Af[s], alr, alk+4, f2tf(a1.x)); scatA(Af[s], alr, alk+5, f2tf(a1.y));
            scatA(Af[s], alr, alk+6, f2tf(a1.z)); scatA(Af[s], alr, alk+7, f2tf(a1.w));
            scatB32(Bf[s], bn+0, bk, f2tf(b0.x));  scatB32(Bf[s], bn+1, bk, f2tf(b0.y));
            scatB32(Bf[s], bn+2, bk, f2tf(b0.z));  scatB32(Bf[s], bn+3, bk, f2tf(b0.w));
            scatB32(Bf[s], bn+4, bk, f2tf(b1.x));  scatB32(Bf[s], bn+5, bk, f2tf(b1.y));
            scatB32(Bf[s], bn+6, bk, f2tf(b1.z));  scatB32(Bf[s], bn+7, bk, f2tf(b1.w));
            scatB32(Bf[s], bn+8, bk, f2tf(b2.x));  scatB32(Bf[s], bn+9, bk, f2tf(b2.y));
            scatB32(Bf[s], bn+10, bk, f2tf(b2.z)); scatB32(Bf[s], bn+11, bk, f2tf(b2.w));
            scatB32(Bf[s], bn+12, bk, f2tf(b3.x)); scatB32(Bf[s], bn+13, bk, f2tf(b3.y));
            scatB32(Bf[s], bn+14, bk, f2tf(b3.z)); scatB32(Bf[s], bn+15, bk, f2tf(b3.w));
            __syncthreads();
        }
    }
    int g = lane >> 2, tq = lane & 3;
    #pragma unroll
    for(int mt=0;mt<4;mt++)
    #pragma unroll
    for(int i=0;i<2;i++){
        int gm = r0 + wm*64 + mt*16 + i*8 + g;
        if(gm>=M) continue;
        #pragma unroll
        for(int nt=0;nt<8;nt++){
            int gn = c0 + wn*64 + nt*8 + 2*tq;
            float2 v;
            v.x = alpha*acc[mt][nt][2*i];
            v.y = alpha*acc[mt][nt][2*i+1];
            long o = (long)gm*ldc + gn;
            if(D){
                float2 dv;
                dv.x = ((gm==gn  )?dconst:0.f) - v.x;
                dv.y = ((gm==gn+1)?dconst:0.f) - v.y;
                *(float2*)(D+o) = dv;
            }
            if(cmode){
                v.x = ((gm==gn  )?dconst:0.f) - v.x;
                v.y = ((gm==gn+1)?dconst:0.f) - v.y;
            }
            *(float2*)(C+o) = v;
        }
    }
}

// C = alpha * A @ B (NN), N=64 exactly. 128x64 block, 8 warps of 32x32.
// Rows gm<rowLo skipped (for direct token-major writes).
__global__ void __launch_bounds__(256,2) k_mma_nn64(
    const float* __restrict__ A, int lda, long sAb, long sAh,
    const float* __restrict__ B, int ldb, long sBb, long sBh,
    float* __restrict__ C, int ldc, long sCb, long sCh,
    int M, int K, float alpha, int rowLo)
{
    int z = blockIdx.z; int hh = z & 7; int bb = z >> 3;
    A += (long)bb*sAb + (long)hh*sAh;
    B += (long)bb*sBb + (long)hh*sBh;
    C += (long)bb*sCb + (long)hh*sCh;
    __shared__ uint32_t Af[2][2048];
    __shared__ uint32_t Bf[2][1024];
    int t = threadIdx.x, lane = t & 31, warp = t >> 5;
    int wm = warp >> 1, wn = warp & 1;
    int r0 = blockIdx.x*128;
    int alr = t >> 1, alk = (t & 1)*8;
    const float* Ap = A + (long)(r0+alr)*lda + alk;
    bool mA = (r0+alr) < M;
    int bk = t >> 4, bn = (t & 15)*4;
    const float* Bp = B + (long)bk*ldb + bn;
    const float4 z4 = make_float4(0.f,0.f,0.f,0.f);
    float4 a0,a1,b0;
    a0 = mA?ldg4(Ap):z4; a1 = mA?ldg4(Ap+4):z4;
    b0 = ldg4(Bp);
    {
        scatA(Af[0], alr, alk+0, f2tf(a0.x)); scatA(Af[0], alr, alk+1, f2tf(a0.y));
        scatA(Af[0], alr, alk+2, f2tf(a0.z)); scatA(Af[0], alr, alk+3, f2tf(a0.w));
        scatA(Af[0], alr, alk+4, f2tf(a1.x)); scatA(Af[0], alr, alk+5, f2tf(a1.y));
        scatA(Af[0], alr, alk+6, f2tf(a1.z)); scatA(Af[0], alr, alk+7, f2tf(a1.w));
        scatB8(Bf[0], bn+0, bk, f2tf(b0.x)); scatB8(Bf[0], bn+1, bk, f2tf(b0.y));
        scatB8(Bf[0], bn+2, bk, f2tf(b0.z)); scatB8(Bf[0], bn+3, bk, f2tf(b0.w));
    }
    __syncthreads();
    float acc[2][4][4];
    #pragma unroll
    for(int i=0;i<2;i++)
        #pragma unroll
        for(int j=0;j<4;j++)
            #pragma unroll
            for(int q=0;q<4;q++) acc[i][j][q]=0.f;
    int nk = K >> 4;
    for(int kt=0; kt<nk; kt++){
        if(kt+1<nk){
            long o = (long)(kt+1)*16;
            a0 = mA?ldg4(Ap+o):z4; a1 = mA?ldg4(Ap+o+4):z4;
            b0 = ldg4(Bp + o*ldb);
        }
        int buf = kt & 1;
        #pragma unroll
        for(int ks=0;ks<2;ks++){
            uint32_t af[2][4], bfr[4][2];
            #pragma unroll
            for(int mt=0;mt<2;mt++)
                *(uint4*)af[mt] = *(const uint4*)&Af[buf][(((ks<<3)+(wm<<1)+mt)<<7) + (lane<<2)];
            #pragma unroll
            for(int nt=0;nt<4;nt++)
                *(uint2*)bfr[nt] = *(const uint2*)&Bf[buf][(((ks<<3)+(wn<<2)+nt)<<6) + (lane<<1)];
            #pragma unroll
            for(int mt=0;mt<2;mt++)
                #pragma unroll
                for(int nt=0;nt<4;nt++)
                    mma8(acc[mt][nt], af[mt], bfr[nt]);
        }
        if(kt+1<nk){
            int s = (kt+1) & 1;
            scatA(Af[s], alr, alk+0, f2tf(a0.x)); scatA(Af[s], alr, alk+1, f2tf(a0.y));
            scatA(Af[s], alr, alk+2, f2tf(a0.z)); scatA(Af[s], alr, alk+3, f2tf(a0.w));
            scatA(Af[s], alr, alk+4, f2tf(a1.x)); scatA(Af[s], alr, alk+5, f2tf(a1.y));
            scatA(Af[s], alr, alk+6, f2tf(a1.z)); scatA(Af[s], alr, alk+7, f2tf(a1.w));
            scatB8(Bf[s], bn+0, bk, f2tf(b0.x)); scatB8(Bf[s], bn+1, bk, f2tf(b0.y));
            scatB8(Bf[s], bn+2, bk, f2tf(b0.z)); scatB8(Bf[s], bn+3, bk, f2tf(b0.w));
            __syncthreads();
        }
    }
    int g = lane >> 2, tq = lane & 3;
    #pragma unroll
    for(int mt=0;mt<2;mt++)
    #pragma unroll
    for(int i=0;i<2;i++){
        int gm = r0 + wm*32 + mt*16 + i*8 + g;
        if(gm >= M || gm < rowLo) continue;
        #pragma unroll
        for(int nt=0;nt<4;nt++){
            int gn = wn*32 + nt*8 + 2*tq;
            float2 v;
            v.x = alpha*acc[mt][nt][2*i];
            v.y = alpha*acc[mt][nt][2*i+1];
            *(float2*)(C + (long)gm*ldc + gn) = v;
        }
    }
}

// Fused GEMM+softmax: C = softmax_row(alpha * A @ B^T), K=64, N=256.
__global__ void __launch_bounds__(256,2) k_simsm(
    const float* __restrict__ A, int lda, long sAb, long sAh,
    const float* __restrict__ B, int ldb, long sBb, long sBh,
    float* __restrict__ C, int ldc, long sCb, long sCh,
    float alpha)
{
    int z = blockIdx.z; int hh = z & 7; int bb = z >> 3;
    A += (long)bb*sAb + (long)hh*sAh;
    B += (long)bb*sBb + (long)hh*sBh;
    C += (long)bb*sCb + (long)hh*sCh;
    __shared__ uint32_t As[64][20];
    __shared__ uint32_t Bs[256][20];
    __shared__ float red[64][4];
    int t = threadIdx.x;
    int lane = t & 31, warp = t >> 5;
    int wm = warp >> 2, wn = warp & 3;
    int r0 = blockIdx.x*64;
    int lrow = t >> 2, lk = (t & 3)*4;
    float acc[2][8][4];
    #pragma unroll
    for(int i=0;i<2;i++)
        #pragma unroll
        for(int j=0;j<8;j++)
            #pragma unroll
            for(int q=0;q<4;q++) acc[i][j][q]=0.f;
    for(int kt=0; kt<4; kt++){
        __syncthreads();
        {
            float4 va = ldg4(A + (long)(r0+lrow)*lda + kt*16 + lk);
            uint4 ua; ua.x=f2tf(va.x); ua.y=f2tf(va.y); ua.z=f2tf(va.z); ua.w=f2tf(va.w);
            *(uint4*)&As[lrow][lk] = ua;
        }
        #pragma unroll
        for(int i=0;i<4;i++){
            float4 vb = ldg4(B + (long)(i*64+lrow)*ldb + kt*16 + lk);
            uint4 ub; ub.x=f2tf(vb.x); ub.y=f2tf(vb.y); ub.z=f2tf(vb.z); ub.w=f2tf(vb.w);
            *(uint4*)&Bs[i*64+lrow][lk] = ub;
        }
        __syncthreads();
        #pragma unroll
        for(int ks=0;ks<2;ks++){
            int cc = ks*8 + (lane&3);
            uint32_t a[2][4], b[8][2];
            int rA = wm*32 + (lane>>2);
            #pragma unroll
            for(int mt=0;mt<2;mt++){
                a[mt][0]=As[rA+mt*16  ][cc];
                a[mt][1]=As[rA+mt*16+8][cc];
                a[mt][2]=As[rA+mt*16  ][cc+4];
                a[mt][3]=As[rA+mt*16+8][cc+4];
            }
            int rB = wn*64 + (lane>>2);
            #pragma unroll
            for(int nt=0;nt<8;nt++){
                b[nt][0]=Bs[rB+nt*8][cc];
                b[nt][1]=Bs[rB+nt*8][cc+4];
            }
            #pragma unroll
            for(int mt=0;mt<2;mt++)
                #pragma unroll
                for(int nt=0;nt<8;nt++)
                    mma8(acc[mt][nt], a[mt], b[nt]);
        }
    }
    int g = lane>>2, tq = lane&3;
    float pm[2][2];
    #pragma unroll
    for(int mt=0;mt<2;mt++)
        #pragma unroll
        for(int i=0;i<2;i++){
            float m = -1e30f;
            #pragma unroll
            for(int nt=0;nt<8;nt++){
                acc[mt][nt][2*i]   *= alpha;
                acc[mt][nt][2*i+1] *= alpha;
                m = fmaxf(m, fmaxf(acc[mt][nt][2*i], acc[mt][nt][2*i+1]));
            }
            m = fmaxf(m, __shfl_xor_sync(0xffffffffu, m, 1));
            m = fmaxf(m, __shfl_xor_sync(0xffffffffu, m, 2));
            pm[mt][i] = m;
        }
    if(tq==0){
        #pragma unroll
        for(int mt=0;mt<2;mt++)
            #pragma unroll
            for(int i=0;i<2;i++)
                red[wm*32+mt*16+i*8+g][wn] = pm[mt][i];
    }
    __syncthreads();
    float rmax[2][2];
    #pragma unroll
    for(int mt=0;mt<2;mt++)
        #pragma unroll
        for(int i=0;i<2;i++){
            int rid = wm*32+mt*16+i*8+g;
            rmax[mt][i] = fmaxf(fmaxf(red[rid][0],red[rid][1]), fmaxf(red[rid][2],red[rid][3]));
        }
    __syncthreads();
    float ps[2][2];
    #pragma unroll
    for(int mt=0;mt<2;mt++)
        #pragma unroll
        for(int i=0;i<2;i++){
            float s = 0.f;
            #pragma unroll
            for(int nt=0;nt<8;nt++){
                float e0 = __expf(acc[mt][nt][2*i]   - rmax[mt][i]);
                float e1 = __expf(acc[mt][nt][2*i+1] - rmax[mt][i]);
                acc[mt][nt][2*i]   = e0;
                acc[mt][nt][2*i+1] = e1;
                s += e0 + e1;
            }
            s += __shfl_xor_sync(0xffffffffu, s, 1);
            s += __shfl_xor_sync(0xffffffffu, s, 2);
            ps[mt][i] = s;
        }
    if(tq==0){
        #pragma unroll
        for(int mt=0;mt<2;mt++)
            #pragma unroll
            for(int i=0;i<2;i++)
                red[wm*32+mt*16+i*8+g][wn] = ps[mt][i];
    }
    __syncthreads();
    #pragma unroll
    for(int mt=0;mt<2;mt++)
        #pragma unroll
        for(int i=0;i<2;i++){
            int rid = wm*32+mt*16+i*8+g;
            float inv = 1.f/(red[rid][0]+red[rid][1]+red[rid][2]+red[rid][3]);
            long gm = r0 + rid;
            #pragma unroll
            for(int nt=0;nt<8;nt++){
                int gn = wn*64 + nt*8 + 2*tq;
                float2 v; v.x = acc[mt][nt][2*i]*inv; v.y = acc[mt][nt][2*i+1]*inv;
                *(float2*)(C + gm*ldc + gn) = v;
            }
        }
}

// ---------------- softmax over rows of length 4352, register-cached ----------------
__global__ void k_softmax4352(float* __restrict__ X){
    long row = blockIdx.x;
    float* x = X + row*4352;
    int t = threadIdx.x;
    __shared__ float red[256];
    float v[17]; float mx = -1e30f;
    #pragma unroll
    for(int i=0;i<17;i++){ v[i] = x[i*256+t]; mx = fmaxf(mx, v[i]); }
    red[t]=mx; __syncthreads();
    for(int k=128;k;k>>=1){ if(t<k) red[t]=fmaxf(red[t],red[t+k]); __syncthreads(); }
    mx = red[0]; __syncthreads();
    float s = 0.f;
    #pragma unroll
    for(int i=0;i<17;i++){ v[i] = __expf(v[i]-mx); s += v[i]; }
    red[t]=s; __syncthreads();
    for(int k=128;k;k>>=1){ if(t<k) red[t]+=red[t+k]; __syncthreads(); }
    float inv = 1.f/red[0];
    #pragma unroll
    for(int i=0;i<17;i++) x[i*256+t] = v[i]*inv;
}

// ---------------- landmarks (mean over 17 tokens), q scaled by 1/8 ----------------
__global__ void k_landmarks(const float* __restrict__ qkv, float* __restrict__ ql, float* __restrict__ kl){
    int idx = blockIdx.x;
    int mi = idx % 256; int hh = (idx/256) & 7; int b = idx / (256*8);
    int dh = threadIdx.x;
    float sq=0.f, sk=0.f;
    for(int j=0;j<LSUB;j++){
        long tok = (long)mi*LSUB + j;
        const float* base = qkv + ((long)b*4352 + tok)*1536 + hh*64 + dh;
        sq += base[0];
        sk += base[512];
    }
    long o = (long)idx*64 + dh;
    ql[o] = sq * (0.125f/LSUB);
    kl[o] = sk * (1.0f/LSUB);
}

// ---------------- pinv scalar reductions ----------------
__global__ void k_scal_init(){ if(threadIdx.x < 2) g_scal[threadIdx.x] = 0.f; }

__global__ void k_rowsum_max(const float* __restrict__ X){
    long row = blockIdx.x;
    const float* x = X + row*256;
    int t = threadIdx.x;
    __shared__ float red[256];
    red[t] = fabsf(x[t]); __syncthreads();
    for(int k=128;k;k>>=1){ if(t<k) red[t]+=red[t+k]; __syncthreads(); }
    if(t==0) atomicMax((int*)&g_scal[0], __float_as_int(red[0]));
}

__global__ void k_colsum_max(const float* __restrict__ X){
    int b = blockIdx.x; int j = threadIdx.x;
    const float* x = X + (long)b*65536;
    float s = 0.f;
    for(int i=0;i<256;i++) s += fabsf(x[i*256+j]);
    __shared__ float red[256];
    red[j]=s; __syncthreads();
    for(int k=128;k;k>>=1){ if(j<k) red[j]=fmaxf(red[j],red[j+k]); __syncthreads(); }
    if(j==0) atomicMax((int*)&g_scal[1], __float_as_int(red[0]));
}

__global__ void k_tr_scale(const float* __restrict__ X, float* __restrict__ Z){
    long idx = (long)blockIdx.x*256 + threadIdx.x;
    if(idx >= 64L*65536) return;
    float inv = 1.f/(g_scal[0]*g_scal[1]);
    int j = (int)(idx & 255); int i = (int)((idx>>8) & 255); long b = idx >> 16;
    Z[idx] = X[(b<<16) + ((long)j<<8) + i] * inv;
}

// ---------------- residual depthwise conv (k=33), writes token-major into ac ----------------
__global__ void k_resconv2(const float* __restrict__ qkv, const float* __restrict__ w,
                           float* __restrict__ ac){
    int bh = blockIdx.y; int hh = bh & 7; int b = bh >> 3;
    int t0 = blockIdx.x*64;
    __shared__ float sv[96][65];
    __shared__ float sw[33];
    int t = threadIdx.x;
    if(t < 33) sw[t] = w[hh*33 + t];
    const float* vb = qkv + ((long)b*4352)*1536 + 1024 + hh*64;
    for(int i=t;i<96*64;i+=256){
        int tok = t0 - 16 + (i>>6); int dh = i&63;
        sv[i>>6][dh] = (tok>=0 && tok<4352) ? vb[(long)tok*1536 + dh] : 0.f;
    }
    __syncthreads();
    for(int i=t;i<64*64;i+=256){
        int lt = i>>6, dh = i&63;
        int tok = t0 + lt;
        if(tok < 255) continue;
        float s = 0.f;
        #pragma unroll
        for(int j=0;j<33;j++) s = fmaf(sw[j], sv[lt+j][dh], s);
        ac[((long)b*4097 + (tok-255))*512 + hh*64 + dh] += s;
    }
}

// ---------------- transposes token<->planar ----------------
__global__ void k_h2planar(const float* __restrict__ h, float* __restrict__ cnn){
    __shared__ float tile[32][33];
    int b = blockIdx.z;
    int c0 = blockIdx.x*32, p0 = blockIdx.y*32;
    int tx = threadIdx.x, ty = threadIdx.y;
    for(int i=ty;i<32;i+=8)
        tile[i][tx] = h[((long)b*4097 + 1 + p0+i)*512 + c0+tx];
    __syncthreads();
    for(int i=ty;i<32;i+=8)
        cnn[((long)b*512 + c0+i)*4096 + p0+tx] = tile[tx][i];
}

__global__ void k_planar2h(const float* __restrict__ yp, float* __restrict__ h2){
    __shared__ float tile[32][33];
    int b = blockIdx.z;
    int c0 = blockIdx.x*32, p0 = blockIdx.y*32;
    int tx = threadIdx.x, ty = threadIdx.y;
    for(int i=ty;i<32;i+=8)
        tile[i][tx] = yp[((long)b*512 + c0+i)*4096 + p0+tx];
    __syncthreads();
    for(int i=ty;i<32;i+=8)
        h2[((long)b*4097 + 1 + p0+i)*512 + c0+tx] = tile[tx][i];
}

__global__ void k_cls_copy(const float* __restrict__ h, float* __restrict__ h2){
    int idx = blockIdx.x*256 + threadIdx.x;
    if(idx >= 8*512) return;
    int b = idx >> 9, c = idx & 511;
    h2[(long)b*4097*512 + c] = h[(long)b*4097*512 + c];
}

// ---------------- fused 7x7 + 5x5 + 3x3 depthwise conv, planar ----------------
__global__ void k_dwconv(const float* __restrict__ cnn,
                         const float* __restrict__ w7, const float* __restrict__ b7,
                         const float* __restrict__ w5, const float* __restrict__ b5,
                         const float* __restrict__ w3, const float* __restrict__ b3,
                         float* __restrict__ yp){
    int bc = blockIdx.x; int c = bc & 511;
    __shared__ float pl[64][65];
    __shared__ float ww[84];
    const float* in = cnn + (long)bc*4096;
    int t = threadIdx.x;
    for(int i=t;i<4096;i+=256) pl[i>>6][i&63] = in[i];
    if(t < 49)      ww[t]      = w7[c*49 + t];
    else if(t < 74) ww[t]      = w5[c*25 + t - 49];
    else if(t < 83) ww[t]      = w3[c*9  + t - 74];
    __syncthreads();
    float bias = b7[c] + b5[c] + b3[c];
    for(int i=t;i<4096;i+=256){
        int y = i >> 6, x = i & 63;
        float s = pl[y][x] + bias;
        #pragma unroll
        for(int ky=0;ky<7;ky++){ int yy=y+ky-3; if((unsigned)yy>=64u) continue;
            #pragma unroll
            for(int kx=0;kx<7;kx++){ int xx=x+kx-3; if((unsigned)xx>=64u) continue;
                s = fmaf(ww[ky*7+kx], pl[yy][xx], s); } }
        #pragma unroll
        for(int ky=0;ky<5;ky++){ int yy=y+ky-2; if((unsigned)yy>=64u) continue;
            #pragma unroll
            for(int kx=0;kx<5;kx++){ int xx=x+kx-2; if((unsigned)xx>=64u) continue;
                s = fmaf(ww[49+ky*5+kx], pl[yy][xx], s); } }
        #pragma unroll
        for(int ky=0;ky<3;ky++){ int yy=y+ky-1; if((unsigned)yy>=64u) continue;
            #pragma unroll
            for(int kx=0;kx<3;kx++){ int xx=x+kx-1; if((unsigned)xx>=64u) continue;
                s = fmaf(ww[74+ky*3+kx], pl[yy][xx], s); } }
        yp[(long)bc*4096 + i] = s;
    }
}

// ---------------- final output: (cls[8,512], feat[8,4096,512]) ----------------
__global__ void k_writeout(const float* __restrict__ h2, float* __restrict__ out){
    long idx = (long)blockIdx.x*256 + threadIdx.x;
    if(idx >= 8L*512 + 8L*4096*512) return;
    if(idx < 8*512){
        int b = (int)(idx >> 9), c = (int)(idx & 511);
        out[idx] = h2[((long)b*4097)*512 + c];
    } else {
        long r = idx - 4096;
        int c = (int)(r & 511); long q = r >> 9; int t = (int)(q % 4096); int b = (int)(q / 4096);
        out[idx] = h2[((long)b*4097 + 1 + t)*512 + c];
    }
}

// ================= host side =================
struct Ptrs {
    float *h,*h2,*xp,*qkv,*ql,*kl,*sim1,*sim3,*a2,*zA,*zB,*xz,*t1,*t2,*a3v,*tmp2,*ac,*cnn,*yp;
};

static void get_ptrs(Ptrs& p){
    cudaGetSymbolAddress((void**)&p.h,    g_h);
    cudaGetSymbolAddress((void**)&p.h2,   g_h2);
    cudaGetSymbolAddress((void**)&p.xp,   g_xp);
    cudaGetSymbolAddress((void**)&p.qkv,  g_qkv);
    cudaGetSymbolAddress((void**)&p.ql,   g_ql);
    cudaGetSymbolAddress((void**)&p.kl,   g_kl);
    cudaGetSymbolAddress((void**)&p.sim1, g_sim1);
    cudaGetSymbolAddress((void**)&p.sim3, g_sim3);
    cudaGetSymbolAddress((void**)&p.a2,   g_a2);
    cudaGetSymbolAddress((void**)&p.zA,   g_zA);
    cudaGetSymbolAddress((void**)&p.zB,   g_zB);
    cudaGetSymbolAddress((void**)&p.xz,   g_xz);
    cudaGetSymbolAddress((void**)&p.t1,   g_t1);
    cudaGetSymbolAddress((void**)&p.t2,   g_t2);
    cudaGetSymbolAddress((void**)&p.a3v,  g_a3v);
    cudaGetSymbolAddress((void**)&p.tmp2, g_tmp2);
    cudaGetSymbolAddress((void**)&p.ac,   g_ac);
    cudaGetSymbolAddress((void**)&p.cnn,  g_cnn);
    cudaGetSymbolAddress((void**)&p.yp,   g_yp);
}

static void attention(Ptrs& p, float* hbuf,
                      const float* lng, const float* lnb,
                      const float* qkvw, const float* outw, const float* outb,
                      const float* resw)
{
    const long SQKV_B = 4352L*1536;
    const long SQL    = 256L*64;
    const long SS1    = 4352L*256;
    const long SS3    = 256L*4352;
    const long SA2    = 65536L;
    const long SV64   = 256L*64;

    k_zero_pad<<<4080, 256>>>(p.xp);
    k_ln<<<8*4097, 256>>>(hbuf, lng, lnb, p.xp);

    // qkv = xp @ qkv_w^T   (34816 x 1536 x 512)
    k_mma_nt256<<<dim3(272,6,1), 256>>>(p.xp, 512, 0,0, qkvw, 512, 0,0,
                                        p.qkv, 1536, 0,0, 34816, 512, 1.f, nullptr, 0);

    k_landmarks<<<64*256, 64>>>(p.qkv, p.ql, p.kl);

    // a1 = softmax((q*scale) @ k_l^T) fused : (4352 x 256) per (b,h)
    k_simsm<<<dim3(68,1,64), 256>>>(p.qkv, 1536, SQKV_B, 64,
                                    p.kl, 64, 8*SQL, SQL,
                                    p.sim1, 256, 8*SS1, SS1, 0.125f);

    // a2 = softmax(q_l @ k_l^T) fused : (256 x 256)
    k_simsm<<<dim3(4,1,64), 256>>>(p.ql, 64, 8*SQL, SQL,
                                   p.kl, 64, 8*SQL, SQL,
                                   p.a2, 256, 8*SA2, SA2, 1.f);

    // sim3 = q_l @ k^T : (256 x 4352 x 64)
    k_mma_nt256<<<dim3(2,17,64), 256>>>(p.ql, 64, 8*SQL, SQL,
                                        p.qkv + 512, 1536, SQKV_B, 64,
                                        p.sim3, 4352, 8*SS3, SS3,
                                        256, 64, 1.f, nullptr, 0);
    k_softmax4352<<<64*256, 256>>>(p.sim3);

    // a3v = a3 @ v : (256 x 64 x 4352)
    k_mma_nn64<<<dim3(2,1,64), 256>>>(p.sim3, 4352, 8*SS3, SS3,
                                      p.qkv + 1024, 1536, SQKV_B, 64,
                                      p.a3v, 64, 8*SV64, SV64,
                                      256, 4352, 1.f, 0);

    // ---- Moore-Penrose pinv of a2 (6 iterations, idm fused in epilogues) ----
    k_scal_init<<<1, 32>>>();
    k_rowsum_max<<<64*256, 256>>>(p.a2);
    k_colsum_max<<<64, 256>>>(p.a2);
    k_tr_scale<<<16384, 256>>>(p.a2, p.zA);

    float* zc = p.zA; float* zn = p.zB;
    for(int it=0; it<6; it++){
        // xz = a2 @ z ; t1 = 7I - xz
        k_mma_nn256<<<dim3(2,1,64), 256>>>(p.a2, 256, 8*SA2, SA2, zc, 256, 8*SA2, SA2,
                                           p.xz, 256, 8*SA2, SA2, p.t1, 8*SA2, SA2,
                                           256, 256, 1.f, 7.f, 0);
        // t2 = 15I - xz @ t1
        k_mma_nn256<<<dim3(2,1,64), 256>>>(p.xz, 256, 8*SA2, SA2, p.t1, 256, 8*SA2, SA2,
                                           p.t2, 256, 8*SA2, SA2, nullptr, 0,0,
                                           256, 256, 1.f, 15.f, 1);
        // t1 = 13I - xz @ t2
        k_mma_nn256<<<dim3(2,1,64), 256>>>(p.xz, 256, 8*SA2, SA2, p.t2, 256, 8*SA2, SA2,
                                           p.t1, 256, 8*SA2, SA2, nullptr, 0,0,
                                           256, 256, 1.f, 13.f, 1);
        // zn = 0.25 * z @ t1
        k_mma_nn256<<<dim3(2,1,64), 256>>>(zc, 256, 8*SA2, SA2, p.t1, 256, 8*SA2, SA2,
                                           zn, 256, 8*SA2, SA2, nullptr, 0,0,
                                           256, 256, 0.25f, 0.f, 0);
        float* tmp = zc; zc = zn; zn = tmp;
    }

    // tmp2 = z @ a3v : (256 x 64 x 256)
    k_mma_nn64<<<dim3(2,1,64), 256>>>(zc, 256, 8*SA2, SA2, p.a3v, 64, 8*SV64, SV64,
                                      p.tmp2, 64, 8*SV64, SV64, 256, 256, 1.f, 0);
    // ac = a1 @ tmp2 written DIRECTLY token-major: (4352 x 64 x 256), rows >= 255 only
    k_mma_nn64<<<dim3(34,1,64), 256>>>(p.sim1, 256, 8*SS1, SS1, p.tmp2, 64, 8*SV64, SV64,
                                       p.ac - 255*512, 512, 4097L*512, 64,
                                       4352, 256, 1.f, 255);

    // residual depthwise conv (k=33 along sequence) added directly into ac
    k_resconv2<<<dim3(68,64), 256>>>(p.qkv, resw, p.ac);

    // hbuf += ac @ out_w^T + out_b
    k_mma_nt256<<<dim3(257,2,1), 256>>>(p.ac, 512, 0,0, outw, 512, 0,0,
                                        hbuf, 512, 0,0, 32776, 512, 1.f, outb, 1);
}

extern "C" void kernel_launch(void* const* d_in, const int* in_sizes, int n_in,
                              void* d_out, int out_size)
{
    const float* features = (const float*)d_in[0];
    const float* cls_tok  = (const float*)d_in[1];
    const float* ln1_g    = (const float*)d_in[2];
    const float* ln1_b    = (const float*)d_in[3];
    const float* qkv1_w   = (const float*)d_in[4];
    const float* out1_w   = (const float*)d_in[5];
    const float* out1_b   = (const float*)d_in[6];
    const float* res1_w   = (const float*)d_in[7];
    const float* p7_w     = (const float*)d_in[8];
    const float* p7_b     = (const float*)d_in[9];
    const float* p5_w     = (const float*)d_in[10];
    const float* p5_b     = (const float*)d_in[11];
    const float* p3_w     = (const float*)d_in[12];
    const float* p3_b     = (const float*)d_in[13];
    const float* ln2_g    = (const float*)d_in[14];
    const float* ln2_b    = (const float*)d_in[15];
    const float* qkv2_w   = (const float*)d_in[16];
    const float* out2_w   = (const float*)d_in[17];
    const float* out2_b   = (const float*)d_in[18];
    const float* res2_w   = (const float*)d_in[19];
    float* out = (float*)d_out;

    Ptrs p;
    get_ptrs(p);

    k_build_h<<<65552, 256>>>(features, cls_tok);

    attention(p, p.h, ln1_g, ln1_b, qkv1_w, out1_w, out1_b, res1_w);

    k_h2planar<<<dim3(16,128,8), dim3(32,8)>>>(p.h, p.cnn);
    k_dwconv<<<4096, 256>>>(p.cnn, p7_w, p7_b, p5_w, p5_b, p3_w, p3_b, p.yp);
    k_planar2h<<<dim3(16,128,8), dim3(32,8)>>>(p.yp, p.h2);
    k_cls_copy<<<16, 256>>>(p.h, p.h2);

    attention(p, p.h2, ln2_g, ln2_b, qkv2_w, out2_w, out2_b, res2_w);

    k_writeout<<<65552, 256>>>(p.h2, out);
}

// round 8
// speedup vs baseline: 1.2627x; 1.2627x over previous
#include <cuda_runtime.h>
#include <math.h>
#include <stdint.h>

// ---------------- problem constants ----------------
// B=8, C=512, HEADS=8, DH=64, tokens=4097 (cls+4096), pad=255 -> N=4352
// landmarks m=256, l=17, pinv iters=6, res kernel 33  (build r8: R6 base + TF32 nn64)
#define LSUB 17

// ---------------- device scratch ----------------
__device__ float g_h   [8L*4097*512];
__device__ float g_h2  [8L*4097*512];
__device__ float g_xp  [8L*4352*512];
__device__ float g_qkv [8L*4352*1536];
__device__ float g_ql  [64L*256*64];
__device__ float g_kl  [64L*256*64];
__device__ float g_sim1[64L*4352*256];
__device__ float g_sim3[64L*256*4352];
__device__ float g_a2  [64L*256*256];
__device__ float g_zA  [64L*256*256];
__device__ float g_zB  [64L*256*256];
__device__ float g_xz  [64L*256*256];
__device__ float g_t1  [64L*256*256];
__device__ float g_t2  [64L*256*256];
__device__ float g_a3v [64L*256*64];
__device__ float g_tmp2[64L*256*64];
__device__ float g_ac  [8L*4097*512];
__device__ float g_cnn [8L*512*4096];
__device__ float g_yp  [8L*512*4096];
__device__ float g_scal[2];

__device__ __forceinline__ float4 ldg4(const float* p){ return *(const float4*)p; }

// ---------------- tf32 mma helpers ----------------
__device__ __forceinline__ uint32_t f2tf(float x){
    uint32_t u; asm("cvt.rna.tf32.f32 %0, %1;" : "=r"(u) : "f"(x)); return u;
}
__device__ __forceinline__ uint4 cvt4(float4 v){
    uint4 u; u.x=f2tf(v.x); u.y=f2tf(v.y); u.z=f2tf(v.z); u.w=f2tf(v.w); return u;
}
__device__ __forceinline__ void mma8(float* d, const uint32_t* a, const uint32_t* b){
    asm("mma.sync.aligned.m16n8k8.row.col.f32.tf32.tf32.f32 "
        "{%0,%1,%2,%3}, {%4,%5,%6,%7}, {%8,%9}, {%0,%1,%2,%3};"
        : "+f"(d[0]),"+f"(d[1]),"+f"(d[2]),"+f"(d[3])
        : "r"(a[0]),"r"(a[1]),"r"(a[2]),"r"(a[3]), "r"(b[0]),"r"(b[1]));
}

// Fragment-major scatter (for k_mma_nn64): element (row,k) of 128x16 A tile
__device__ __forceinline__ void scatA(uint32_t* Af, int row, int k, uint32_t v){
    int ks=k>>3, kc=k&7;
    Af[(((ks<<3)+(row>>4))<<7) + ((((row&7)<<2)+(kc&3))<<2) + ((row>>3)&1) + ((kc>>2)<<1)] = v;
}
// B tile with 8 n-tiles (64 cols)
__device__ __forceinline__ void scatB8(uint32_t* Bf, int n, int k, uint32_t v){
    int ks=k>>3, kc=k&7;
    Bf[(((ks<<3)+(n>>3))<<6) + ((((n&7)<<2)+(kc&3))<<1) + (kc>>2)] = v;
}

// ---------------- small kernels ----------------
__global__ void k_build_h(const float* __restrict__ feat, const float* __restrict__ cls){
    long idx = (long)blockIdx.x*256 + threadIdx.x;
    if(idx >= 8L*4097*512) return;
    int c = idx & 511; long r = idx >> 9; int t = (int)(r % 4097); int b = (int)(r / 4097);
    g_h[idx] = (t==0) ? cls[c] : feat[((long)b*4096 + (t-1))*512 + c];
}

__global__ void k_zero_pad(float* __restrict__ xp){
    long idx = (long)blockIdx.x*256 + threadIdx.x;
    if(idx >= 8L*255*512) return;
    int c = idx & 511; long r = idx >> 9; int t = (int)(r % 255); int b = (int)(r / 255);
    xp[((long)b*4352 + t)*512 + c] = 0.f;
}

__global__ void k_ln(const float* __restrict__ h, const float* __restrict__ g,
                     const float* __restrict__ be, float* __restrict__ xp){
    long r = blockIdx.x;
    int b = (int)(r / 4097); int t = (int)(r % 4097);
    const float* x = h + r*512;
    float* y = xp + ((long)b*4352 + 255 + t)*512;
    int tid = threadIdx.x;
    __shared__ float red[256];
    float s = 0.f;
    for(int i=tid;i<512;i+=256) s += x[i];
    red[tid]=s; __syncthreads();
    for(int k=128;k;k>>=1){ if(tid<k) red[tid]+=red[tid+k]; __syncthreads(); }
    float mean = red[0] * (1.f/512.f); __syncthreads();
    float v = 0.f;
    for(int i=tid;i<512;i+=256){ float d=x[i]-mean; v += d*d; }
    red[tid]=v; __syncthreads();
    for(int k=128;k;k>>=1){ if(tid<k) red[tid]+=red[tid+k]; __syncthreads(); }
    float rstd = rsqrtf(red[0]*(1.f/512.f) + 1e-5f);
    for(int i=tid;i<512;i+=256) y[i] = (x[i]-mean)*rstd*g[i] + be[i];
}

// =====================================================================
// TF32 tensor-core GEMMs: 128x128 block, 8 warps of 64x32, BK=16 (R6 proven)
// =====================================================================

// C = alpha * A @ B^T (+bias)(+C)   A:(M,K) lda, B:(N,K) ldb   batched (b,h)
__global__ void __launch_bounds__(256,2) k_mma_nt(
    const float* __restrict__ A, int lda, long sAb, long sAh,
    const float* __restrict__ B, int ldb, long sBb, long sBh,
    float* __restrict__ C, int ldc, long sCb, long sCh,
    int M, int N, int K, float alpha, const float* __restrict__ bias, int acc)
{
    int z = blockIdx.z; int hh = z & 7; int bb = z >> 3;
    A += (long)bb*sAb + (long)hh*sAh;
    B += (long)bb*sBb + (long)hh*sBh;
    C += (long)bb*sCb + (long)hh*sCh;
    __shared__ uint32_t As[128][20];
    __shared__ uint32_t Bs[128][20];
    int t = threadIdx.x;
    int lane = t & 31, warp = t >> 5;
    int wm = warp >> 2, wn = warp & 3;
    int r0 = blockIdx.x*128, c0 = blockIdx.y*128;
    int lrow = t >> 2, lk = (t & 3)*4;
    const float* Ap0 = A + (long)(r0+lrow)*lda + lk;
    const float* Ap1 = A + (long)(r0+lrow+64)*lda + lk;
    const float* Bp0 = B + (long)(c0+lrow)*ldb + lk;
    const float* Bp1 = B + (long)(c0+lrow+64)*ldb + lk;
    bool mA0 = (r0+lrow)<M, mA1 = (r0+lrow+64)<M;
    bool mB0 = (c0+lrow)<N, mB1 = (c0+lrow+64)<N;
    const float4 z4 = make_float4(0.f,0.f,0.f,0.f);
    float4 pa0 = mA0?ldg4(Ap0):z4, pa1 = mA1?ldg4(Ap1):z4;
    float4 pb0 = mB0?ldg4(Bp0):z4, pb1 = mB1?ldg4(Bp1):z4;
    *(uint4*)&As[lrow][lk]    = cvt4(pa0);
    *(uint4*)&As[lrow+64][lk] = cvt4(pa1);
    *(uint4*)&Bs[lrow][lk]    = cvt4(pb0);
    *(uint4*)&Bs[lrow+64][lk] = cvt4(pb1);
    float accr[4][4][4];
    #pragma unroll
    for(int i=0;i<4;i++)
        #pragma unroll
        for(int j=0;j<4;j++)
            #pragma unroll
            for(int q=0;q<4;q++) accr[i][j][q]=0.f;
    int nk = K >> 4;
    for(int kt=0; kt<nk; kt++){
        __syncthreads();
        if(kt+1<nk){
            int o = (kt+1)*16;
            pa0 = mA0?ldg4(Ap0+o):z4; pa1 = mA1?ldg4(Ap1+o):z4;
            pb0 = mB0?ldg4(Bp0+o):z4; pb1 = mB1?ldg4(Bp1+o):z4;
        }
        #pragma unroll
        for(int ks=0;ks<2;ks++){
            int cc = ks*8 + (lane&3);
            uint32_t a[4][4], b[4][2];
            int rA = wm*64 + (lane>>2);
            #pragma unroll
            for(int mt=0;mt<4;mt++){
                a[mt][0]=As[rA+mt*16  ][cc];
                a[mt][1]=As[rA+mt*16+8][cc];
                a[mt][2]=As[rA+mt*16  ][cc+4];
                a[mt][3]=As[rA+mt*16+8][cc+4];
            }
            int rB = wn*32 + (lane>>2);
            #pragma unroll
            for(int nt=0;nt<4;nt++){
                b[nt][0]=Bs[rB+nt*8][cc];
                b[nt][1]=Bs[rB+nt*8][cc+4];
            }
            #pragma unroll
            for(int mt=0;mt<4;mt++)
                #pragma unroll
                for(int nt=0;nt<4;nt++)
                    mma8(accr[mt][nt], a[mt], b[nt]);
        }
        __syncthreads();
        if(kt+1<nk){
            *(uint4*)&As[lrow][lk]    = cvt4(pa0);
            *(uint4*)&As[lrow+64][lk] = cvt4(pa1);
            *(uint4*)&Bs[lrow][lk]    = cvt4(pb0);
            *(uint4*)&Bs[lrow+64][lk] = cvt4(pb1);
        }
    }
    #pragma unroll
    for(int mt=0;mt<4;mt++)
    #pragma unroll
    for(int i=0;i<2;i++){
        int gm = r0 + wm*64 + mt*16 + i*8 + (lane>>2);
        if(gm>=M) continue;
        #pragma unroll
        for(int nt=0;nt<4;nt++){
            int gn = c0 + wn*32 + nt*8 + 2*(lane&3);
            float2 v;
            v.x = alpha*accr[mt][nt][2*i];
            v.y = alpha*accr[mt][nt][2*i+1];
            if(bias){ v.x += bias[gn]; v.y += bias[gn+1]; }
            float* cp = C + (long)gm*ldc + gn;
            if(acc){ v.x += cp[0]; v.y += cp[1]; }
            *(float2*)cp = v;
        }
    }
}

// Fused GEMM+softmax: C = softmax_row(alpha * A @ B^T), K=64, N=256.
__global__ void __launch_bounds__(256,2) k_simsm(
    const float* __restrict__ A, int lda, long sAb, long sAh,
    const float* __restrict__ B, int ldb, long sBb, long sBh,
    float* __restrict__ C, int ldc, long sCb, long sCh,
    float alpha)
{
    int z = blockIdx.z; int hh = z & 7; int bb = z >> 3;
    A += (long)bb*sAb + (long)hh*sAh;
    B += (long)bb*sBb + (long)hh*sBh;
    C += (long)bb*sCb + (long)hh*sCh;
    __shared__ uint32_t As[64][20];
    __shared__ uint32_t Bs[256][20];
    __shared__ float red[64][4];
    int t = threadIdx.x;
    int lane = t & 31, warp = t >> 5;
    int wm = warp >> 2, wn = warp & 3;
    int r0 = blockIdx.x*64;
    int lrow = t >> 2, lk = (t & 3)*4;
    float acc[2][8][4];
    #pragma unroll
    for(int i=0;i<2;i++)
        #pragma unroll
        for(int j=0;j<8;j++)
            #pragma unroll
            for(int q=0;q<4;q++) acc[i][j][q]=0.f;
    for(int kt=0; kt<4; kt++){
        __syncthreads();
        *(uint4*)&As[lrow][lk] = cvt4(ldg4(A + (long)(r0+lrow)*lda + kt*16 + lk));
        #pragma unroll
        for(int i=0;i<4;i++)
            *(uint4*)&Bs[i*64+lrow][lk] = cvt4(ldg4(B + (long)(i*64+lrow)*ldb + kt*16 + lk));
        __syncthreads();
        #pragma unroll
        for(int ks=0;ks<2;ks++){
            int cc = ks*8 + (lane&3);
            uint32_t a[2][4], b[8][2];
            int rA = wm*32 + (lane>>2);
            #pragma unroll
            for(int mt=0;mt<2;mt++){
                a[mt][0]=As[rA+mt*16  ][cc];
                a[mt][1]=As[rA+mt*16+8][cc];
                a[mt][2]=As[rA+mt*16  ][cc+4];
                a[mt][3]=As[rA+mt*16+8][cc+4];
            }
            int rB = wn*64 + (lane>>2);
            #pragma unroll
            for(int nt=0;nt<8;nt++){
                b[nt][0]=Bs[rB+nt*8][cc];
                b[nt][1]=Bs[rB+nt*8][cc+4];
            }
            #pragma unroll
            for(int mt=0;mt<2;mt++)
                #pragma unroll
                for(int nt=0;nt<8;nt++)
                    mma8(acc[mt][nt], a[mt], b[nt]);
        }
    }
    int g = lane>>2, tq = lane&3;
    float pm[2][2];
    #pragma unroll
    for(int mt=0;mt<2;mt++)
        #pragma unroll
        for(int i=0;i<2;i++){
            float m = -1e30f;
            #pragma unroll
            for(int nt=0;nt<8;nt++){
                acc[mt][nt][2*i]   *= alpha;
                acc[mt][nt][2*i+1] *= alpha;
                m = fmaxf(m, fmaxf(acc[mt][nt][2*i], acc[mt][nt][2*i+1]));
            }
            m = fmaxf(m, __shfl_xor_sync(0xffffffffu, m, 1));
            m = fmaxf(m, __shfl_xor_sync(0xffffffffu, m, 2));
            pm[mt][i] = m;
        }
    if(tq==0){
        #pragma unroll
        for(int mt=0;mt<2;mt++)
            #pragma unroll
            for(int i=0;i<2;i++)
                red[wm*32+mt*16+i*8+g][wn] = pm[mt][i];
    }
    __syncthreads();
    float rmax[2][2];
    #pragma unroll
    for(int mt=0;mt<2;mt++)
        #pragma unroll
        for(int i=0;i<2;i++){
            int rid = wm*32+mt*16+i*8+g;
            rmax[mt][i] = fmaxf(fmaxf(red[rid][0],red[rid][1]), fmaxf(red[rid][2],red[rid][3]));
        }
    __syncthreads();
    float ps[2][2];
    #pragma unroll
    for(int mt=0;mt<2;mt++)
        #pragma unroll
        for(int i=0;i<2;i++){
            float s = 0.f;
            #pragma unroll
            for(int nt=0;nt<8;nt++){
                float e0 = __expf(acc[mt][nt][2*i]   - rmax[mt][i]);
                float e1 = __expf(acc[mt][nt][2*i+1] - rmax[mt][i]);
                acc[mt][nt][2*i]   = e0;
                acc[mt][nt][2*i+1] = e1;
                s += e0 + e1;
            }
            s += __shfl_xor_sync(0xffffffffu, s, 1);
            s += __shfl_xor_sync(0xffffffffu, s, 2);
            ps[mt][i] = s;
        }
    if(tq==0){
        #pragma unroll
        for(int mt=0;mt<2;mt++)
            #pragma unroll
            for(int i=0;i<2;i++)
                red[wm*32+mt*16+i*8+g][wn] = ps[mt][i];
    }
    __syncthreads();
    #pragma unroll
    for(int mt=0;mt<2;mt++)
        #pragma unroll
        for(int i=0;i<2;i++){
            int rid = wm*32+mt*16+i*8+g;
            float inv = 1.f/(red[rid][0]+red[rid][1]+red[rid][2]+red[rid][3]);
            long gm = r0 + rid;
            #pragma unroll
            for(int nt=0;nt<8;nt++){
                int gn = wn*64 + nt*8 + 2*tq;
                float2 v; v.x = acc[mt][nt][2*i]*inv; v.y = acc[mt][nt][2*i+1]*inv;
                *(float2*)(C + gm*ldc + gn) = v;
            }
        }
}

// C = alpha * A @ B  (NN), pinv epilogues (R6 proven).
__global__ void __launch_bounds__(256,2) k_mma_nn(
    const float* __restrict__ A, int lda, long sAb, long sAh,
    const float* __restrict__ B, int ldb, long sBb, long sBh,
    float* __restrict__ C, int ldc, long sCb, long sCh,
    float* __restrict__ D, long sDb, long sDh,
    int M, int N, int K, float alpha, float dconst, int cmode)
{
    int z = blockIdx.z; int hh = z & 7; int bb = z >> 3;
    A += (long)bb*sAb + (long)hh*sAh;
    B += (long)bb*sBb + (long)hh*sBh;
    C += (long)bb*sCb + (long)hh*sCh;
    if(D) D += (long)bb*sDb + (long)hh*sDh;
    __shared__ uint32_t As[128][20];
    __shared__ uint32_t Bs[16][136];
    int t = threadIdx.x;
    int lane = t & 31, warp = t >> 5;
    int wm = warp >> 2, wn = warp & 3;
    int r0 = blockIdx.x*128, c0 = blockIdx.y*128;
    int lrow = t >> 2, lk = (t & 3)*4;
    int bk = t >> 5, bn = (t & 31)*4;
    const float* Ap0 = A + (long)(r0+lrow)*lda + lk;
    const float* Ap1 = A + (long)(r0+lrow+64)*lda + lk;
    const float* Bq0 = B + (long)bk*ldb + c0 + bn;
    const float* Bq1 = B + (long)(bk+8)*ldb + c0 + bn;
    bool mA0 = (r0+lrow)<M, mA1 = (r0+lrow+64)<M;
    bool mBn = (c0+bn)<N;
    const float4 z4 = make_float4(0.f,0.f,0.f,0.f);
    float4 pa0 = mA0?ldg4(Ap0):z4, pa1 = mA1?ldg4(Ap1):z4;
    float4 pb0 = mBn?ldg4(Bq0):z4, pb1 = mBn?ldg4(Bq1):z4;
    *(uint4*)&As[lrow][lk]    = cvt4(pa0);
    *(uint4*)&As[lrow+64][lk] = cvt4(pa1);
    *(uint4*)&Bs[bk][bn]      = cvt4(pb0);
    *(uint4*)&Bs[bk+8][bn]    = cvt4(pb1);
    float accr[4][4][4];
    #pragma unroll
    for(int i=0;i<4;i++)
        #pragma unroll
        for(int j=0;j<4;j++)
            #pragma unroll
            for(int q=0;q<4;q++) accr[i][j][q]=0.f;
    int nk = K >> 4;
    for(int kt=0; kt<nk; kt++){
        __syncthreads();
        if(kt+1<nk){
            long o = (long)(kt+1)*16;
            pa0 = mA0?ldg4(Ap0+o):z4; pa1 = mA1?ldg4(Ap1+o):z4;
            pb0 = mBn?ldg4(Bq0+o*ldb):z4; pb1 = mBn?ldg4(Bq1+o*ldb):z4;
        }
        #pragma unroll
        for(int ks=0;ks<2;ks++){
            int cc = ks*8 + (lane&3);
            uint32_t a[4][4], b[4][2];
            int rA = wm*64 + (lane>>2);
            #pragma unroll
            for(int mt=0;mt<4;mt++){
                a[mt][0]=As[rA+mt*16  ][cc];
                a[mt][1]=As[rA+mt*16+8][cc];
                a[mt][2]=As[rA+mt*16  ][cc+4];
                a[mt][3]=As[rA+mt*16+8][cc+4];
            }
            int nB = wn*32 + (lane>>2);
            #pragma unroll
            for(int nt=0;nt<4;nt++){
                b[nt][0]=Bs[cc  ][nB+nt*8];
                b[nt][1]=Bs[cc+4][nB+nt*8];
            }
            #pragma unroll
            for(int mt=0;mt<4;mt++)
                #pragma unroll
                for(int nt=0;nt<4;nt++)
                    mma8(accr[mt][nt], a[mt], b[nt]);
        }
        __syncthreads();
        if(kt+1<nk){
            *(uint4*)&As[lrow][lk]    = cvt4(pa0);
            *(uint4*)&As[lrow+64][lk] = cvt4(pa1);
            *(uint4*)&Bs[bk][bn]      = cvt4(pb0);
            *(uint4*)&Bs[bk+8][bn]    = cvt4(pb1);
        }
    }
    #pragma unroll
    for(int mt=0;mt<4;mt++)
    #pragma unroll
    for(int i=0;i<2;i++){
        int gm = r0 + wm*64 + mt*16 + i*8 + (lane>>2);
        if(gm>=M) continue;
        #pragma unroll
        for(int nt=0;nt<4;nt++){
            int gn = c0 + wn*32 + nt*8 + 2*(lane&3);
            float2 v;
            v.x = alpha*accr[mt][nt][2*i];
            v.y = alpha*accr[mt][nt][2*i+1];
            long o = (long)gm*ldc + gn;
            if(D){
                float2 dv;
                dv.x = ((gm==gn  )?dconst:0.f) - v.x;
                dv.y = ((gm==gn+1)?dconst:0.f) - v.y;
                *(float2*)(D+o) = dv;
            }
            if(cmode){
                v.x = ((gm==gn  )?dconst:0.f) - v.x;
                v.y = ((gm==gn+1)?dconst:0.f) - v.y;
            }
            *(float2*)(C+o) = v;
        }
    }
}

// C = alpha * A @ B (NN, TF32), N=64. 128x64 block, 8 warps of 32x32. (R7 validated)
// Rows gm<rowLo skipped (direct token-major writes).
__global__ void __launch_bounds__(256,2) k_mma_nn64(
    const float* __restrict__ A, int lda, long sAb, long sAh,
    const float* __restrict__ B, int ldb, long sBb, long sBh,
    float* __restrict__ C, int ldc, long sCb, long sCh,
    int M, int K, float alpha, int rowLo)
{
    int z = blockIdx.z; int hh = z & 7; int bb = z >> 3;
    A += (long)bb*sAb + (long)hh*sAh;
    B += (long)bb*sBb + (long)hh*sBh;
    C += (long)bb*sCb + (long)hh*sCh;
    __shared__ uint32_t Af[2][2048];
    __shared__ uint32_t Bf[2][1024];
    int t = threadIdx.x, lane = t & 31, warp = t >> 5;
    int wm = warp >> 1, wn = warp & 1;
    int r0 = blockIdx.x*128;
    int alr = t >> 1, alk = (t & 1)*8;
    const float* Ap = A + (long)(r0+alr)*lda + alk;
    bool mA = (r0+alr) < M;
    int bk = t >> 4, bn = (t & 15)*4;
    const float* Bp = B + (long)bk*ldb + bn;
    const float4 z4 = make_float4(0.f,0.f,0.f,0.f);
    float4 a0,a1,b0;
    a0 = mA?ldg4(Ap):z4; a1 = mA?ldg4(Ap+4):z4;
    b0 = ldg4(Bp);
    {
        scatA(Af[0], alr, alk+0, f2tf(a0.x)); scatA(Af[0], alr, alk+1, f2tf(a0.y));
        scatA(Af[0], alr, alk+2, f2tf(a0.z)); scatA(Af[0], alr, alk+3, f2tf(a0.w));
        scatA(Af[0], alr, alk+4, f2tf(a1.x)); scatA(Af[0], alr, alk+5, f2tf(a1.y));
        scatA(Af[0], alr, alk+6, f2tf(a1.z)); scatA(Af[0], alr, alk+7, f2tf(a1.w));
        scatB8(Bf[0], bn+0, bk, f2tf(b0.x)); scatB8(Bf[0], bn+1, bk, f2tf(b0.y));
        scatB8(Bf[0], bn+2, bk, f2tf(b0.z)); scatB8(Bf[0], bn+3, bk, f2tf(b0.w));
    }
    __syncthreads();
    float acc[2][4][4];
    #pragma unroll
    for(int i=0;i<2;i++)
        #pragma unroll
        for(int j=0;j<4;j++)
            #pragma unroll
            for(int q=0;q<4;q++) acc[i][j][q]=0.f;
    int nk = K >> 4;
    for(int kt=0; kt<nk; kt++){
        if(kt+1<nk){
            long o = (long)(kt+1)*16;
            a0 = mA?ldg4(Ap+o):z4; a1 = mA?ldg4(Ap+o+4):z4;
            b0 = ldg4(Bp + o*ldb);
        }
        int buf = kt & 1;
        #pragma unroll
        for(int ks=0;ks<2;ks++){
            uint32_t af[2][4], bfr[4][2];
            #pragma unroll
            for(int mt=0;mt<2;mt++)
                *(uint4*)af[mt] = *(const uint4*)&Af[buf][(((ks<<3)+(wm<<1)+mt)<<7) + (lane<<2)];
            #pragma unroll
            for(int nt=0;nt<4;nt++)
                *(uint2*)bfr[nt] = *(const uint2*)&Bf[buf][(((ks<<3)+(wn<<2)+nt)<<6) + (lane<<1)];
            #pragma unroll
            for(int mt=0;mt<2;mt++)
                #pragma unroll
                for(int nt=0;nt<4;nt++)
                    mma8(acc[mt][nt], af[mt], bfr[nt]);
        }
        if(kt+1<nk){
            int s = (kt+1) & 1;
            scatA(Af[s], alr, alk+0, f2tf(a0.x)); scatA(Af[s], alr, alk+1, f2tf(a0.y));
            scatA(Af[s], alr, alk+2, f2tf(a0.z)); scatA(Af[s], alr, alk+3, f2tf(a0.w));
            scatA(Af[s], alr, alk+4, f2tf(a1.x)); scatA(Af[s], alr, alk+5, f2tf(a1.y));
            scatA(Af[s], alr, alk+6, f2tf(a1.z)); scatA(Af[s], alr, alk+7, f2tf(a1.w));
            scatB8(Bf[s], bn+0, bk, f2tf(b0.x)); scatB8(Bf[s], bn+1, bk, f2tf(b0.y));
            scatB8(Bf[s], bn+2, bk, f2tf(b0.z)); scatB8(Bf[s], bn+3, bk, f2tf(b0.w));
            __syncthreads();
        }
    }
    int g = lane >> 2, tq = lane & 3;
    #pragma unroll
    for(int mt=0;mt<2;mt++)
    #pragma unroll
    for(int i=0;i<2;i++){
        int gm = r0 + wm*32 + mt*16 + i*8 + g;
        if(gm >= M || gm < rowLo) continue;
        #pragma unroll
        for(int nt=0;nt<4;nt++){
            int gn = wn*32 + nt*8 + 2*tq;
            float2 v;
            v.x = alpha*acc[mt][nt][2*i];
            v.y = alpha*acc[mt][nt][2*i+1];
            *(float2*)(C + (long)gm*ldc + gn) = v;
        }
    }
}

// ---------------- softmax over rows of length 4352, register-cached ----------------
__global__ void k_softmax4352(float* __restrict__ X){
    long row = blockIdx.x;
    float* x = X + row*4352;
    int t = threadIdx.x;
    __shared__ float red[256];
    float v[17]; float mx = -1e30f;
    #pragma unroll
    for(int i=0;i<17;i++){ v[i] = x[i*256+t]; mx = fmaxf(mx, v[i]); }
    red[t]=mx; __syncthreads();
    for(int k=128;k;k>>=1){ if(t<k) red[t]=fmaxf(red[t],red[t+k]); __syncthreads(); }
    mx = red[0]; __syncthreads();
    float s = 0.f;
    #pragma unroll
    for(int i=0;i<17;i++){ v[i] = __expf(v[i]-mx); s += v[i]; }
    red[t]=s; __syncthreads();
    for(int k=128;k;k>>=1){ if(t<k) red[t]+=red[t+k]; __syncthreads(); }
    float inv = 1.f/red[0];
    #pragma unroll
    for(int i=0;i<17;i++) x[i*256+t] = v[i]*inv;
}

// ---------------- landmarks (mean over 17 tokens), q scaled by 1/8 ----------------
__global__ void k_landmarks(const float* __restrict__ qkv, float* __restrict__ ql, float* __restrict__ kl){
    int idx = blockIdx.x;
    int mi = idx % 256; int hh = (idx/256) & 7; int b = idx / (256*8);
    int dh = threadIdx.x;
    float sq=0.f, sk=0.f;
    for(int j=0;j<LSUB;j++){
        long tok = (long)mi*LSUB + j;
        const float* base = qkv + ((long)b*4352 + tok)*1536 + hh*64 + dh;
        sq += base[0];
        sk += base[512];
    }
    long o = (long)idx*64 + dh;
    ql[o] = sq * (0.125f/LSUB);
    kl[o] = sk * (1.0f/LSUB);
}

// ---------------- pinv scalar reductions ----------------
__global__ void k_scal_init(){ if(threadIdx.x < 2) g_scal[threadIdx.x] = 0.f; }

__global__ void k_rowsum_max(const float* __restrict__ X){
    long row = blockIdx.x;
    const float* x = X + row*256;
    int t = threadIdx.x;
    __shared__ float red[256];
    red[t] = fabsf(x[t]); __syncthreads();
    for(int k=128;k;k>>=1){ if(t<k) red[t]+=red[t+k]; __syncthreads(); }
    if(t==0) atomicMax((int*)&g_scal[0], __float_as_int(red[0]));
}

__global__ void k_colsum_max(const float* __restrict__ X){
    int b = blockIdx.x; int j = threadIdx.x;
    const float* x = X + (long)b*65536;
    float s = 0.f;
    for(int i=0;i<256;i++) s += fabsf(x[i*256+j]);
    __shared__ float red[256];
    red[j]=s; __syncthreads();
    for(int k=128;k;k>>=1){ if(j<k) red[j]=fmaxf(red[j],red[j+k]); __syncthreads(); }
    if(j==0) atomicMax((int*)&g_scal[1], __float_as_int(red[0]));
}

__global__ void k_tr_scale(const float* __restrict__ X, float* __restrict__ Z){
    long idx = (long)blockIdx.x*256 + threadIdx.x;
    if(idx >= 64L*65536) return;
    float inv = 1.f/(g_scal[0]*g_scal[1]);
    int j = (int)(idx & 255); int i = (int)((idx>>8) & 255); long b = idx >> 16;
    Z[idx] = X[(b<<16) + ((long)j<<8) + i] * inv;
}

// ---------------- residual depthwise conv (k=33), writes token-major into ac ----------------
__global__ void k_resconv2(const float* __restrict__ qkv, const float* __restrict__ w,
                           float* __restrict__ ac){
    int bh = blockIdx.y; int hh = bh & 7; int b = bh >> 3;
    int t0 = blockIdx.x*64;
    __shared__ float sv[96][65];
    __shared__ float sw[33];
    int t = threadIdx.x;
    if(t < 33) sw[t] = w[hh*33 + t];
    const float* vb = qkv + ((long)b*4352)*1536 + 1024 + hh*64;
    for(int i=t;i<96*64;i+=256){
        int tok = t0 - 16 + (i>>6); int dh = i&63;
        sv[i>>6][dh] = (tok>=0 && tok<4352) ? vb[(long)tok*1536 + dh] : 0.f;
    }
    __syncthreads();
    for(int i=t;i<64*64;i+=256){
        int lt = i>>6, dh = i&63;
        int tok = t0 + lt;
        if(tok < 255) continue;
        float s = 0.f;
        #pragma unroll
        for(int j=0;j<33;j++) s = fmaf(sw[j], sv[lt+j][dh], s);
        ac[((long)b*4097 + (tok-255))*512 + hh*64 + dh] += s;
    }
}

// ---------------- transposes token<->planar ----------------
__global__ void k_h2planar(const float* __restrict__ h, float* __restrict__ cnn){
    __shared__ float tile[32][33];
    int b = blockIdx.z;
    int c0 = blockIdx.x*32, p0 = blockIdx.y*32;
    int tx = threadIdx.x, ty = threadIdx.y;
    for(int i=ty;i<32;i+=8)
        tile[i][tx] = h[((long)b*4097 + 1 + p0+i)*512 + c0+tx];
    __syncthreads();
    for(int i=ty;i<32;i+=8)
        cnn[((long)b*512 + c0+i)*4096 + p0+tx] = tile[tx][i];
}

__global__ void k_planar2h(const float* __restrict__ yp, float* __restrict__ h2){
    __shared__ float tile[32][33];
    int b = blockIdx.z;
    int c0 = blockIdx.x*32, p0 = blockIdx.y*32;
    int tx = threadIdx.x, ty = threadIdx.y;
    for(int i=ty;i<32;i+=8)
        tile[i][tx] = yp[((long)b*512 + c0+i)*4096 + p0+tx];
    __syncthreads();
    for(int i=ty;i<32;i+=8)
        h2[((long)b*4097 + 1 + p0+i)*512 + c0+tx] = tile[tx][i];
}

__global__ void k_cls_copy(const float* __restrict__ h, float* __restrict__ h2){
    int idx = blockIdx.x*256 + threadIdx.x;
    if(idx >= 8*512) return;
    int b = idx >> 9, c = idx & 511;
    h2[(long)b*4097*512 + c] = h[(long)b*4097*512 + c];
}

// ---------------- fused 7x7 + 5x5 + 3x3 depthwise conv, planar ----------------
__global__ void k_dwconv(const float* __restrict__ cnn,
                         const float* __restrict__ w7, const float* __restrict__ b7,
                         const float* __restrict__ w5, const float* __restrict__ b5,
                         const float* __restrict__ w3, const float* __restrict__ b3,
                         float* __restrict__ yp){
    int bc = blockIdx.x; int c = bc & 511;
    __shared__ float pl[64][65];
    __shared__ float ww[84];
    const float* in = cnn + (long)bc*4096;
    int t = threadIdx.x;
    for(int i=t;i<4096;i+=256) pl[i>>6][i&63] = in[i];
    if(t < 49)      ww[t]      = w7[c*49 + t];
    else if(t < 74) ww[t]      = w5[c*25 + t - 49];
    else if(t < 83) ww[t]      = w3[c*9  + t - 74];
    __syncthreads();
    float bias = b7[c] + b5[c] + b3[c];
    for(int i=t;i<4096;i+=256){
        int y = i >> 6, x = i & 63;
        float s = pl[y][x] + bias;
        #pragma unroll
        for(int ky=0;ky<7;ky++){ int yy=y+ky-3; if((unsigned)yy>=64u) continue;
            #pragma unroll
            for(int kx=0;kx<7;kx++){ int xx=x+kx-3; if((unsigned)xx>=64u) continue;
                s = fmaf(ww[ky*7+kx], pl[yy][xx], s); } }
        #pragma unroll
        for(int ky=0;ky<5;ky++){ int yy=y+ky-2; if((unsigned)yy>=64u) continue;
            #pragma unroll
            for(int kx=0;kx<5;kx++){ int xx=x+kx-2; if((unsigned)xx>=64u) continue;
                s = fmaf(ww[49+ky*5+kx], pl[yy][xx], s); } }
        #pragma unroll
        for(int ky=0;ky<3;ky++){ int yy=y+ky-1; if((unsigned)yy>=64u) continue;
            #pragma unroll
            for(int kx=0;kx<3;kx++){ int xx=x+kx-1; if((unsigned)xx>=64u) continue;
                s = fmaf(ww[74+ky*3+kx], pl[yy][xx], s); } }
        yp[(long)bc*4096 + i] = s;
    }
}

// ---------------- final output: (cls[8,512], feat[8,4096,512]) ----------------
__global__ void k_writeout(const float* __restrict__ h2, float* __restrict__ out){
    long idx = (long)blockIdx.x*256 + threadIdx.x;
    if(idx >= 8L*512 + 8L*4096*512) return;
    if(idx < 8*512){
        int b = (int)(idx >> 9), c = (int)(idx & 511);
        out[idx] = h2[((long)b*4097)*512 + c];
    } else {
        long r = idx - 4096;
        int c = (int)(r & 511); long q = r >> 9; int t = (int)(q % 4096); int b = (int)(q / 4096);
        out[idx] = h2[((long)b*4097 + 1 + t)*512 + c];
    }
}

// ================= host side =================
struct Ptrs {
    float *h,*h2,*xp,*qkv,*ql,*kl,*sim1,*sim3,*a2,*zA,*zB,*xz,*t1,*t2,*a3v,*tmp2,*ac,*cnn,*yp;
};

static void get_ptrs(Ptrs& p){
    cudaGetSymbolAddress((void**)&p.h,    g_h);
    cudaGetSymbolAddress((void**)&p.h2,   g_h2);
    cudaGetSymbolAddress((void**)&p.xp,   g_xp);
    cudaGetSymbolAddress((void**)&p.qkv,  g_qkv);
    cudaGetSymbolAddress((void**)&p.ql,   g_ql);
    cudaGetSymbolAddress((void**)&p.kl,   g_kl);
    cudaGetSymbolAddress((void**)&p.sim1, g_sim1);
    cudaGetSymbolAddress((void**)&p.sim3, g_sim3);
    cudaGetSymbolAddress((void**)&p.a2,   g_a2);
    cudaGetSymbolAddress((void**)&p.zA,   g_zA);
    cudaGetSymbolAddress((void**)&p.zB,   g_zB);
    cudaGetSymbolAddress((void**)&p.xz,   g_xz);
    cudaGetSymbolAddress((void**)&p.t1,   g_t1);
    cudaGetSymbolAddress((void**)&p.t2,   g_t2);
    cudaGetSymbolAddress((void**)&p.a3v,  g_a3v);
    cudaGetSymbolAddress((void**)&p.tmp2, g_tmp2);
    cudaGetSymbolAddress((void**)&p.ac,   g_ac);
    cudaGetSymbolAddress((void**)&p.cnn,  g_cnn);
    cudaGetSymbolAddress((void**)&p.yp,   g_yp);
}

static void attention(Ptrs& p, float* hbuf,
                      const float* lng, const float* lnb,
                      const float* qkvw, const float* outw, const float* outb,
                      const float* resw)
{
    const long SQKV_B = 4352L*1536;
    const long SQL    = 256L*64;
    const long SS1    = 4352L*256;
    const long SS3    = 256L*4352;
    const long SA2    = 65536L;
    const long SV64   = 256L*64;

    k_zero_pad<<<4080, 256>>>(p.xp);
    k_ln<<<8*4097, 256>>>(hbuf, lng, lnb, p.xp);

    // qkv = xp @ qkv_w^T   (34816 x 1536 x 512)
    k_mma_nt<<<dim3(272,12,1), 256>>>(p.xp, 512, 0,0, qkvw, 512, 0,0,
                                      p.qkv, 1536, 0,0, 34816, 1536, 512, 1.f, nullptr, 0);

    k_landmarks<<<64*256, 64>>>(p.qkv, p.ql, p.kl);

    // a1 = softmax((q*scale) @ k_l^T) fused : (4352 x 256) per (b,h)
    k_simsm<<<dim3(68,1,64), 256>>>(p.qkv, 1536, SQKV_B, 64,
                                    p.kl, 64, 8*SQL, SQL,
                                    p.sim1, 256, 8*SS1, SS1, 0.125f);

    // a2 = softmax(q_l @ k_l^T) fused : (256 x 256)
    k_simsm<<<dim3(4,1,64), 256>>>(p.ql, 64, 8*SQL, SQL,
                                   p.kl, 64, 8*SQL, SQL,
                                   p.a2, 256, 8*SA2, SA2, 1.f);

    // sim3 = q_l @ k^T : (256 x 4352 x 64)
    k_mma_nt<<<dim3(2,34,64), 256>>>(p.ql, 64, 8*SQL, SQL,
                                     p.qkv + 512, 1536, SQKV_B, 64,
                                     p.sim3, 4352, 8*SS3, SS3,
                                     256, 4352, 64, 1.f, nullptr, 0);
    k_softmax4352<<<64*256, 256>>>(p.sim3);

    // a3v = a3 @ v : (256 x 64 x 4352)   [TF32]
    k_mma_nn64<<<dim3(2,1,64), 256>>>(p.sim3, 4352, 8*SS3, SS3,
                                      p.qkv + 1024, 1536, SQKV_B, 64,
                                      p.a3v, 64, 8*SV64, SV64,
                                      256, 4352, 1.f, 0);

    // ---- Moore-Penrose pinv of a2 (6 iterations, idm fused in epilogues) ----
    k_scal_init<<<1, 32>>>();
    k_rowsum_max<<<64*256, 256>>>(p.a2);
    k_colsum_max<<<64, 256>>>(p.a2);
    k_tr_scale<<<16384, 256>>>(p.a2, p.zA);

    float* zc = p.zA; float* zn = p.zB;
    for(int it=0; it<6; it++){
        // xz = a2 @ z ; t1 = 7I - xz
        k_mma_nn<<<dim3(2,2,64), 256>>>(p.a2, 256, 8*SA2, SA2, zc, 256, 8*SA2, SA2,
                                        p.xz, 256, 8*SA2, SA2, p.t1, 8*SA2, SA2,
                                        256,256,256, 1.f, 7.f, 0);
        // t2 = 15I - xz @ t1
        k_mma_nn<<<dim3(2,2,64), 256>>>(p.xz, 256, 8*SA2, SA2, p.t1, 256, 8*SA2, SA2,
                                        p.t2, 256, 8*SA2, SA2, nullptr, 0,0,
                                        256,256,256, 1.f, 15.f, 1);
        // t1 = 13I - xz @ t2
        k_mma_nn<<<dim3(2,2,64), 256>>>(p.xz, 256, 8*SA2, SA2, p.t2, 256, 8*SA2, SA2,
                                        p.t1, 256, 8*SA2, SA2, nullptr, 0,0,
                                        256,256,256, 1.f, 13.f, 1);
        // zn = 0.25 * z @ t1
        k_mma_nn<<<dim3(2,2,64), 256>>>(zc, 256, 8*SA2, SA2, p.t1, 256, 8*SA2, SA2,
                                        zn, 256, 8*SA2, SA2, nullptr, 0,0,
                                        256,256,256, 0.25f, 0.f, 0);
        float* tmp = zc; zc = zn; zn = tmp;
    }

    // tmp2 = z @ a3v : (256 x 64 x 256)   [TF32]
    k_mma_nn64<<<dim3(2,1,64), 256>>>(zc, 256, 8*SA2, SA2, p.a3v, 64, 8*SV64, SV64,
                                      p.tmp2, 64, 8*SV64, SV64, 256, 256, 1.f, 0);
    // ac = a1 @ tmp2 direct token-major : (4352 x 64 x 256), rows >= 255 only   [TF32]
    k_mma_nn64<<<dim3(34,1,64), 256>>>(p.sim1, 256, 8*SS1, SS1, p.tmp2, 64, 8*SV64, SV64,
                                       p.ac - 255*512, 512, 4097L*512, 64,
                                       4352, 256, 1.f, 255);

    // residual depthwise conv (k=33 along sequence) added directly into ac
    k_resconv2<<<dim3(68,64), 256>>>(p.qkv, resw, p.ac);

    // hbuf += ac @ out_w^T + out_b
    k_mma_nt<<<dim3(257,4,1), 256>>>(p.ac, 512, 0,0, outw, 512, 0,0,
                                     hbuf, 512, 0,0, 32776, 512, 512, 1.f, outb, 1);
}

extern "C" void kernel_launch(void* const* d_in, const int* in_sizes, int n_in,
                              void* d_out, int out_size)
{
    const float* features = (const float*)d_in[0];
    const float* cls_tok  = (const float*)d_in[1];
    const float* ln1_g    = (const float*)d_in[2];
    const float* ln1_b    = (const float*)d_in[3];
    const float* qkv1_w   = (const float*)d_in[4];
    const float* out1_w   = (const float*)d_in[5];
    const float* out1_b   = (const float*)d_in[6];
    const float* res1_w   = (const float*)d_in[7];
    const float* p7_w     = (const float*)d_in[8];
    const float* p7_b     = (const float*)d_in[9];
    const float* p5_w     = (const float*)d_in[10];
    const float* p5_b     = (const float*)d_in[11];
    const float* p3_w     = (const float*)d_in[12];
    const float* p3_b     = (const float*)d_in[13];
    const float* ln2_g    = (const float*)d_in[14];
    const float* ln2_b    = (const float*)d_in[15];
    const float* qkv2_w   = (const float*)d_in[16];
    const float* out2_w   = (const float*)d_in[17];
    const float* out2_b   = (const float*)d_in[18];
    const float* res2_w   = (const float*)d_in[19];
    float* out = (float*)d_out;

    Ptrs p;
    get_ptrs(p);

    k_build_h<<<65552, 256>>>(features, cls_tok);

    attention(p, p.h, ln1_g, ln1_b, qkv1_w, out1_w, out1_b, res1_w);

    k_h2planar<<<dim3(16,128,8), dim3(32,8)>>>(p.h, p.cnn);
    k_dwconv<<<4096, 256>>>(p.cnn, p7_w, p7_b, p5_w, p5_b, p3_w, p3_b, p.yp);
    k_planar2h<<<dim3(16,128,8), dim3(32,8)>>>(p.yp, p.h2);
    k_cls_copy<<<16, 256>>>(p.h, p.h2);

    attention(p, p.h2, ln2_g, ln2_b, qkv2_w, out2_w, out2_b, res2_w);

    k_writeout<<<65552, 256>>>(p.h2, out);
}

// round 11
// speedup vs baseline: 1.3263x; 1.0503x over previous
#include <cuda_runtime.h>
#include <math.h>
#include <stdint.h>

// ---------------- problem constants ----------------
// B=8, C=512, HEADS=8, DH=64, tokens=4097 (cls+4096), pad=255 -> N=4352
// landmarks m=256, l=17, pinv iters=6, res kernel 33  (build r10: attnout retry)
#define LSUB 17

// ---------------- device scratch ----------------
__device__ float g_h   [8L*4097*512];
__device__ float g_h2  [8L*4097*512];
__device__ float g_xp  [8L*4352*512];
__device__ float g_qkv [8L*4352*1536];
__device__ float g_ql  [64L*256*64];
__device__ float g_kl  [64L*256*64];
__device__ float g_sim3[64L*256*4352];
__device__ float g_a2  [64L*256*256];
__device__ float g_zA  [64L*256*256];
__device__ float g_zB  [64L*256*256];
__device__ float g_xz  [64L*256*256];
__device__ float g_t1  [64L*256*256];
__device__ float g_t2  [64L*256*256];
__device__ float g_a3v [64L*256*64];
__device__ float g_tmp2[64L*256*64];
__device__ float g_ac  [8L*4097*512];
__device__ float g_cnn [8L*512*4096];
__device__ float g_yp  [8L*512*4096];
__device__ float g_scal[2];

__device__ __forceinline__ float4 ldg4(const float* p){ return *(const float4*)p; }

// ---------------- tf32 mma helpers ----------------
__device__ __forceinline__ uint32_t f2tf(float x){
    uint32_t u; asm("cvt.rna.tf32.f32 %0, %1;" : "=r"(u) : "f"(x)); return u;
}
__device__ __forceinline__ uint4 cvt4(float4 v){
    uint4 u; u.x=f2tf(v.x); u.y=f2tf(v.y); u.z=f2tf(v.z); u.w=f2tf(v.w); return u;
}
__device__ __forceinline__ void mma8(float* d, const uint32_t* a, const uint32_t* b){
    asm("mma.sync.aligned.m16n8k8.row.col.f32.tf32.tf32.f32 "
        "{%0,%1,%2,%3}, {%4,%5,%6,%7}, {%8,%9}, {%0,%1,%2,%3};"
        : "+f"(d[0]),"+f"(d[1]),"+f"(d[2]),"+f"(d[3])
        : "r"(a[0]),"r"(a[1]),"r"(a[2]),"r"(a[3]), "r"(b[0]),"r"(b[1]));
}

// Fragment-major scatter (for k_mma_nn64): element (row,k) of 128x16 A tile
__device__ __forceinline__ void scatA(uint32_t* Af, int row, int k, uint32_t v){
    int ks=k>>3, kc=k&7;
    Af[(((ks<<3)+(row>>4))<<7) + ((((row&7)<<2)+(kc&3))<<2) + ((row>>3)&1) + ((kc>>2)<<1)] = v;
}
// B tile with 8 n-tiles (64 cols)
__device__ __forceinline__ void scatB8(uint32_t* Bf, int n, int k, uint32_t v){
    int ks=k>>3, kc=k&7;
    Bf[(((ks<<3)+(n>>3))<<6) + ((((n&7)<<2)+(kc&3))<<1) + (kc>>2)] = v;
}

// ---------------- small kernels ----------------
__global__ void k_build_h(const float* __restrict__ feat, const float* __restrict__ cls){
    long idx = (long)blockIdx.x*256 + threadIdx.x;
    if(idx >= 8L*4097*512) return;
    int c = idx & 511; long r = idx >> 9; int t = (int)(r % 4097); int b = (int)(r / 4097);
    g_h[idx] = (t==0) ? cls[c] : feat[((long)b*4096 + (t-1))*512 + c];
}

__global__ void k_zero_pad(float* __restrict__ xp){
    long idx = (long)blockIdx.x*256 + threadIdx.x;
    if(idx >= 8L*255*512) return;
    int c = idx & 511; long r = idx >> 9; int t = (int)(r % 255); int b = (int)(r / 255);
    xp[((long)b*4352 + t)*512 + c] = 0.f;
}

__global__ void k_ln(const float* __restrict__ h, const float* __restrict__ g,
                     const float* __restrict__ be, float* __restrict__ xp){
    long r = blockIdx.x;
    int b = (int)(r / 4097); int t = (int)(r % 4097);
    const float* x = h + r*512;
    float* y = xp + ((long)b*4352 + 255 + t)*512;
    int tid = threadIdx.x;
    __shared__ float red[256];
    float s = 0.f;
    for(int i=tid;i<512;i+=256) s += x[i];
    red[tid]=s; __syncthreads();
    for(int k=128;k;k>>=1){ if(tid<k) red[tid]+=red[tid+k]; __syncthreads(); }
    float mean = red[0] * (1.f/512.f); __syncthreads();
    float v = 0.f;
    for(int i=tid;i<512;i+=256){ float d=x[i]-mean; v += d*d; }
    red[tid]=v; __syncthreads();
    for(int k=128;k;k>>=1){ if(tid<k) red[tid]+=red[tid+k]; __syncthreads(); }
    float rstd = rsqrtf(red[0]*(1.f/512.f) + 1e-5f);
    for(int i=tid;i<512;i+=256) y[i] = (x[i]-mean)*rstd*g[i] + be[i];
}

// =====================================================================
// TF32 tensor-core GEMMs: 128x128 block, 8 warps of 64x32, BK=16 (proven)
// =====================================================================

// C = alpha * A @ B^T (+bias)(+C)   A:(M,K) lda, B:(N,K) ldb   batched (b,h)
__global__ void __launch_bounds__(256,2) k_mma_nt(
    const float* __restrict__ A, int lda, long sAb, long sAh,
    const float* __restrict__ B, int ldb, long sBb, long sBh,
    float* __restrict__ C, int ldc, long sCb, long sCh,
    int M, int N, int K, float alpha, const float* __restrict__ bias, int acc)
{
    int z = blockIdx.z; int hh = z & 7; int bb = z >> 3;
    A += (long)bb*sAb + (long)hh*sAh;
    B += (long)bb*sBb + (long)hh*sBh;
    C += (long)bb*sCb + (long)hh*sCh;
    __shared__ uint32_t As[128][20];
    __shared__ uint32_t Bs[128][20];
    int t = threadIdx.x;
    int lane = t & 31, warp = t >> 5;
    int wm = warp >> 2, wn = warp & 3;
    int r0 = blockIdx.x*128, c0 = blockIdx.y*128;
    int lrow = t >> 2, lk = (t & 3)*4;
    const float* Ap0 = A + (long)(r0+lrow)*lda + lk;
    const float* Ap1 = A + (long)(r0+lrow+64)*lda + lk;
    const float* Bp0 = B + (long)(c0+lrow)*ldb + lk;
    const float* Bp1 = B + (long)(c0+lrow+64)*ldb + lk;
    bool mA0 = (r0+lrow)<M, mA1 = (r0+lrow+64)<M;
    bool mB0 = (c0+lrow)<N, mB1 = (c0+lrow+64)<N;
    const float4 z4 = make_float4(0.f,0.f,0.f,0.f);
    float4 pa0 = mA0?ldg4(Ap0):z4, pa1 = mA1?ldg4(Ap1):z4;
    float4 pb0 = mB0?ldg4(Bp0):z4, pb1 = mB1?ldg4(Bp1):z4;
    *(uint4*)&As[lrow][lk]    = cvt4(pa0);
    *(uint4*)&As[lrow+64][lk] = cvt4(pa1);
    *(uint4*)&Bs[lrow][lk]    = cvt4(pb0);
    *(uint4*)&Bs[lrow+64][lk] = cvt4(pb1);
    float accr[4][4][4];
    #pragma unroll
    for(int i=0;i<4;i++)
        #pragma unroll
        for(int j=0;j<4;j++)
            #pragma unroll
            for(int q=0;q<4;q++) accr[i][j][q]=0.f;
    int nk = K >> 4;
    for(int kt=0; kt<nk; kt++){
        __syncthreads();
        if(kt+1<nk){
            int o = (kt+1)*16;
            pa0 = mA0?ldg4(Ap0+o):z4; pa1 = mA1?ldg4(Ap1+o):z4;
            pb0 = mB0?ldg4(Bp0+o):z4; pb1 = mB1?ldg4(Bp1+o):z4;
        }
        #pragma unroll
        for(int ks=0;ks<2;ks++){
            int cc = ks*8 + (lane&3);
            uint32_t a[4][4], b[4][2];
            int rA = wm*64 + (lane>>2);
            #pragma unroll
            for(int mt=0;mt<4;mt++){
                a[mt][0]=As[rA+mt*16  ][cc];
                a[mt][1]=As[rA+mt*16+8][cc];
                a[mt][2]=As[rA+mt*16  ][cc+4];
                a[mt][3]=As[rA+mt*16+8][cc+4];
            }
            int rB = wn*32 + (lane>>2);
            #pragma unroll
            for(int nt=0;nt<4;nt++){
                b[nt][0]=Bs[rB+nt*8][cc];
                b[nt][1]=Bs[rB+nt*8][cc+4];
            }
            #pragma unroll
            for(int mt=0;mt<4;mt++)
                #pragma unroll
                for(int nt=0;nt<4;nt++)
                    mma8(accr[mt][nt], a[mt], b[nt]);
        }
        __syncthreads();
        if(kt+1<nk){
            *(uint4*)&As[lrow][lk]    = cvt4(pa0);
            *(uint4*)&As[lrow+64][lk] = cvt4(pa1);
            *(uint4*)&Bs[lrow][lk]    = cvt4(pb0);
            *(uint4*)&Bs[lrow+64][lk] = cvt4(pb1);
        }
    }
    #pragma unroll
    for(int mt=0;mt<4;mt++)
    #pragma unroll
    for(int i=0;i<2;i++){
        int gm = r0 + wm*64 + mt*16 + i*8 + (lane>>2);
        if(gm>=M) continue;
        #pragma unroll
        for(int nt=0;nt<4;nt++){
            int gn = c0 + wn*32 + nt*8 + 2*(lane&3);
            float2 v;
            v.x = alpha*accr[mt][nt][2*i];
            v.y = alpha*accr[mt][nt][2*i+1];
            if(bias){ v.x += bias[gn]; v.y += bias[gn+1]; }
            float* cp = C + (long)gm*ldc + gn;
            if(acc){ v.x += cp[0]; v.y += cp[1]; }
            *(float2*)cp = v;
        }
    }
}

// Fused GEMM+softmax: C = softmax_row(alpha * A @ B^T), K=64, N=256.
__global__ void __launch_bounds__(256,2) k_simsm(
    const float* __restrict__ A, int lda, long sAb, long sAh,
    const float* __restrict__ B, int ldb, long sBb, long sBh,
    float* __restrict__ C, int ldc, long sCb, long sCh,
    float alpha)
{
    int z = blockIdx.z; int hh = z & 7; int bb = z >> 3;
    A += (long)bb*sAb + (long)hh*sAh;
    B += (long)bb*sBb + (long)hh*sBh;
    C += (long)bb*sCb + (long)hh*sCh;
    __shared__ uint32_t As[64][20];
    __shared__ uint32_t Bs[256][20];
    __shared__ float red[64][4];
    int t = threadIdx.x;
    int lane = t & 31, warp = t >> 5;
    int wm = warp >> 2, wn = warp & 3;
    int r0 = blockIdx.x*64;
    int lrow = t >> 2, lk = (t & 3)*4;
    float acc[2][8][4];
    #pragma unroll
    for(int i=0;i<2;i++)
        #pragma unroll
        for(int j=0;j<8;j++)
            #pragma unroll
            for(int q=0;q<4;q++) acc[i][j][q]=0.f;
    for(int kt=0; kt<4; kt++){
        __syncthreads();
        *(uint4*)&As[lrow][lk] = cvt4(ldg4(A + (long)(r0+lrow)*lda + kt*16 + lk));
        #pragma unroll
        for(int i=0;i<4;i++)
            *(uint4*)&Bs[i*64+lrow][lk] = cvt4(ldg4(B + (long)(i*64+lrow)*ldb + kt*16 + lk));
        __syncthreads();
        #pragma unroll
        for(int ks=0;ks<2;ks++){
            int cc = ks*8 + (lane&3);
            uint32_t a[2][4], b[8][2];
            int rA = wm*32 + (lane>>2);
            #pragma unroll
            for(int mt=0;mt<2;mt++){
                a[mt][0]=As[rA+mt*16  ][cc];
                a[mt][1]=As[rA+mt*16+8][cc];
                a[mt][2]=As[rA+mt*16  ][cc+4];
                a[mt][3]=As[rA+mt*16+8][cc+4];
            }
            int rB = wn*64 + (lane>>2);
            #pragma unroll
            for(int nt=0;nt<8;nt++){
                b[nt][0]=Bs[rB+nt*8][cc];
                b[nt][1]=Bs[rB+nt*8][cc+4];
            }
            #pragma unroll
            for(int mt=0;mt<2;mt++)
                #pragma unroll
                for(int nt=0;nt<8;nt++)
                    mma8(acc[mt][nt], a[mt], b[nt]);
        }
    }
    int g = lane>>2, tq = lane&3;
    float pm[2][2];
    #pragma unroll
    for(int mt=0;mt<2;mt++)
        #pragma unroll
        for(int i=0;i<2;i++){
            float m = -1e30f;
            #pragma unroll
            for(int nt=0;nt<8;nt++){
                acc[mt][nt][2*i]   *= alpha;
                acc[mt][nt][2*i+1] *= alpha;
                m = fmaxf(m, fmaxf(acc[mt][nt][2*i], acc[mt][nt][2*i+1]));
            }
            m = fmaxf(m, __shfl_xor_sync(0xffffffffu, m, 1));
            m = fmaxf(m, __shfl_xor_sync(0xffffffffu, m, 2));
            pm[mt][i] = m;
        }
    if(tq==0){
        #pragma unroll
        for(int mt=0;mt<2;mt++)
            #pragma unroll
            for(int i=0;i<2;i++)
                red[wm*32+mt*16+i*8+g][wn] = pm[mt][i];
    }
    __syncthreads();
    float rmax[2][2];
    #pragma unroll
    for(int mt=0;mt<2;mt++)
        #pragma unroll
        for(int i=0;i<2;i++){
            int rid = wm*32+mt*16+i*8+g;
            rmax[mt][i] = fmaxf(fmaxf(red[rid][0],red[rid][1]), fmaxf(red[rid][2],red[rid][3]));
        }
    __syncthreads();
    float ps[2][2];
    #pragma unroll
    for(int mt=0;mt<2;mt++)
        #pragma unroll
        for(int i=0;i<2;i++){
            float s = 0.f;
            #pragma unroll
            for(int nt=0;nt<8;nt++){
                float e0 = __expf(acc[mt][nt][2*i]   - rmax[mt][i]);
                float e1 = __expf(acc[mt][nt][2*i+1] - rmax[mt][i]);
                acc[mt][nt][2*i]   = e0;
                acc[mt][nt][2*i+1] = e1;
                s += e0 + e1;
            }
            s += __shfl_xor_sync(0xffffffffu, s, 1);
            s += __shfl_xor_sync(0xffffffffu, s, 2);
            ps[mt][i] = s;
        }
    if(tq==0){
        #pragma unroll
        for(int mt=0;mt<2;mt++)
            #pragma unroll
            for(int i=0;i<2;i++)
                red[wm*32+mt*16+i*8+g][wn] = ps[mt][i];
    }
    __syncthreads();
    #pragma unroll
    for(int mt=0;mt<2;mt++)
        #pragma unroll
        for(int i=0;i<2;i++){
            int rid = wm*32+mt*16+i*8+g;
            float inv = 1.f/(red[rid][0]+red[rid][1]+red[rid][2]+red[rid][3]);
            long gm = r0 + rid;
            #pragma unroll
            for(int nt=0;nt<8;nt++){
                int gn = wn*64 + nt*8 + 2*tq;
                float2 v; v.x = acc[mt][nt][2*i]*inv; v.y = acc[mt][nt][2*i+1]*inv;
                *(float2*)(C + gm*ldc + gn) = v;
            }
        }
}

// =====================================================================
// Fused attention output: ac[token] = softmax(alpha * q @ kl^T) @ tmp2
// Block: 64 padded-token rows. Phase 1 = simsm body; Phase 2 = chunked P@tmp2.
// Writes DIRECTLY token-major into ac (rows with padded index >= 255).
// =====================================================================
__global__ void __launch_bounds__(256,2) k_attnout(
    const float* __restrict__ Q, int ldq, long sQb, long sQh,
    const float* __restrict__ KL, long sKL,
    const float* __restrict__ T2, long sT2,
    float* __restrict__ AC, float alpha)
{
    int z = blockIdx.z; int hh = z & 7; int bb = z >> 3;
    const float* A = Q  + (long)bb*sQb + (long)hh*sQh;
    const float* B = KL + (long)z*sKL;
    const float* T = T2 + (long)z*sT2;
    __shared__ char smem_raw[35840];
    __shared__ float red[64][4];
    uint32_t (*As)[20] = (uint32_t(*)[20])smem_raw;              // 64x20  (5120 B)
    uint32_t (*Bs)[20] = (uint32_t(*)[20])(smem_raw + 5120);     // 256x20 (20480 B)
    uint32_t (*Pf)[68] = (uint32_t(*)[68])smem_raw;              // 64x68  (17408 B) phase 2
    uint32_t (*Ts)[72] = (uint32_t(*)[72])(smem_raw + 17408);    // 64x72  (18432 B) phase 2
    int t = threadIdx.x;
    int lane = t & 31, warp = t >> 5;
    int wm = warp >> 2, wn = warp & 3;
    int r0 = blockIdx.x*64;
    int lrow = t >> 2, lk = (t & 3)*4;
    int g = lane>>2, tq = lane&3;
    float acc[2][8][4];
    #pragma unroll
    for(int i=0;i<2;i++)
        #pragma unroll
        for(int j=0;j<8;j++)
            #pragma unroll
            for(int q=0;q<4;q++) acc[i][j][q]=0.f;
    // ---- phase 1: S = alpha * q @ kl^T ----
    for(int kt=0; kt<4; kt++){
        __syncthreads();
        *(uint4*)&As[lrow][lk] = cvt4(ldg4(A + (long)(r0+lrow)*ldq + kt*16 + lk));
        #pragma unroll
        for(int i=0;i<4;i++)
            *(uint4*)&Bs[i*64+lrow][lk] = cvt4(ldg4(B + (long)(i*64+lrow)*64 + kt*16 + lk));
        __syncthreads();
        #pragma unroll
        for(int ks=0;ks<2;ks++){
            int cc = ks*8 + tq;
            uint32_t a[2][4], b[8][2];
            int rA = wm*32 + g;
            #pragma unroll
            for(int mt=0;mt<2;mt++){
                a[mt][0]=As[rA+mt*16  ][cc];
                a[mt][1]=As[rA+mt*16+8][cc];
                a[mt][2]=As[rA+mt*16  ][cc+4];
                a[mt][3]=As[rA+mt*16+8][cc+4];
            }
            int rB = wn*64 + g;
            #pragma unroll
            for(int nt=0;nt<8;nt++){
                b[nt][0]=Bs[rB+nt*8][cc];
                b[nt][1]=Bs[rB+nt*8][cc+4];
            }
            #pragma unroll
            for(int mt=0;mt<2;mt++)
                #pragma unroll
                for(int nt=0;nt<8;nt++)
                    mma8(acc[mt][nt], a[mt], b[nt]);
        }
    }
    // ---- softmax (row max / exp / row sum), normalized P kept in acc ----
    float pm[2][2];
    #pragma unroll
    for(int mt=0;mt<2;mt++)
        #pragma unroll
        for(int i=0;i<2;i++){
            float m = -1e30f;
            #pragma unroll
            for(int nt=0;nt<8;nt++){
                acc[mt][nt][2*i]   *= alpha;
                acc[mt][nt][2*i+1] *= alpha;
                m = fmaxf(m, fmaxf(acc[mt][nt][2*i], acc[mt][nt][2*i+1]));
            }
            m = fmaxf(m, __shfl_xor_sync(0xffffffffu, m, 1));
            m = fmaxf(m, __shfl_xor_sync(0xffffffffu, m, 2));
            pm[mt][i] = m;
        }
    if(tq==0){
        #pragma unroll
        for(int mt=0;mt<2;mt++)
            #pragma unroll
            for(int i=0;i<2;i++)
                red[wm*32+mt*16+i*8+g][wn] = pm[mt][i];
    }
    __syncthreads();
    float rmax[2][2];
    #pragma unroll
    for(int mt=0;mt<2;mt++)
        #pragma unroll
        for(int i=0;i<2;i++){
            int rid = wm*32+mt*16+i*8+g;
            rmax[mt][i] = fmaxf(fmaxf(red[rid][0],red[rid][1]), fmaxf(red[rid][2],red[rid][3]));
        }
    __syncthreads();
    float ps[2][2];
    #pragma unroll
    for(int mt=0;mt<2;mt++)
        #pragma unroll
        for(int i=0;i<2;i++){
            float s = 0.f;
            #pragma unroll
            for(int nt=0;nt<8;nt++){
                float e0 = __expf(acc[mt][nt][2*i]   - rmax[mt][i]);
                float e1 = __expf(acc[mt][nt][2*i+1] - rmax[mt][i]);
                acc[mt][nt][2*i]   = e0;
                acc[mt][nt][2*i+1] = e1;
                s += e0 + e1;
            }
            s += __shfl_xor_sync(0xffffffffu, s, 1);
            s += __shfl_xor_sync(0xffffffffu, s, 2);
            ps[mt][i] = s;
        }
    if(tq==0){
        #pragma unroll
        for(int mt=0;mt<2;mt++)
            #pragma unroll
            for(int i=0;i<2;i++)
                red[wm*32+mt*16+i*8+g][wn] = ps[mt][i];
    }
    __syncthreads();
    float inv2[2][2];
    #pragma unroll
    for(int mt=0;mt<2;mt++)
        #pragma unroll
        for(int i=0;i<2;i++){
            int rid = wm*32+mt*16+i*8+g;
            inv2[mt][i] = 1.f/(red[rid][0]+red[rid][1]+red[rid][2]+red[rid][3]);
            #pragma unroll
            for(int nt=0;nt<8;nt++){
                acc[mt][nt][2*i]   *= inv2[mt][i];
                acc[mt][nt][2*i+1] *= inv2[mt][i];
            }
        }
    // ---- phase 2: O = P @ tmp2, chunked over landmark dim ----
    int wm2 = warp >> 1, wn2 = warp & 1;
    float acc2[4][4];
    #pragma unroll
    for(int j=0;j<4;j++)
        #pragma unroll
        for(int q=0;q<4;q++) acc2[j][q]=0.f;
    for(int ch=0; ch<4; ch++){
        __syncthreads();   // previous chunk consumed / phase-1 smem free
        if(wn == ch){
            #pragma unroll
            for(int mt=0;mt<2;mt++)
                #pragma unroll
                for(int i=0;i<2;i++){
                    int row_l = wm*32+mt*16+i*8+g;
                    #pragma unroll
                    for(int nt=0;nt<8;nt++){
                        int col_l = nt*8 + 2*tq;
                        Pf[row_l][col_l]   = f2tf(acc[mt][nt][2*i]);
                        Pf[row_l][col_l+1] = f2tf(acc[mt][nt][2*i+1]);
                    }
                }
        }
        {   // load tmp2 rows [64ch, 64ch+64) -> Ts[k][n]
            int kl_ = t >> 2, cb = (t & 3)*16;
            const float* Tp = T + (long)(64*ch + kl_)*64 + cb;
            #pragma unroll
            for(int j=0;j<4;j++){
                float4 v = ldg4(Tp + j*4);
                Ts[kl_][cb+j*4+0] = f2tf(v.x);
                Ts[kl_][cb+j*4+1] = f2tf(v.y);
                Ts[kl_][cb+j*4+2] = f2tf(v.z);
                Ts[kl_][cb+j*4+3] = f2tf(v.w);
            }
        }
        __syncthreads();
        #pragma unroll
        for(int kk=0;kk<8;kk++){
            int cc = kk*8 + tq;
            uint32_t a[4], b[4][2];
            a[0]=Pf[wm2*16+g  ][cc];
            a[1]=Pf[wm2*16+8+g][cc];
            a[2]=Pf[wm2*16+g  ][cc+4];
            a[3]=Pf[wm2*16+8+g][cc+4];
            #pragma unroll
            for(int nt=0;nt<4;nt++){
                int n = wn2*32 + nt*8 + g;
                b[nt][0]=Ts[cc  ][n];
                b[nt][1]=Ts[cc+4][n];
            }
            #pragma unroll
            for(int nt=0;nt<4;nt++)
                mma8(acc2[nt], a, b[nt]);
        }
    }
    // ---- write token-major into ac ----
    #pragma unroll
    for(int i=0;i<2;i++){
        int gm = r0 + wm2*16 + i*8 + g;      // padded token index
        if(gm < 255) continue;
        float* dst = AC + ((long)bb*4097 + (gm-255))*512 + hh*64;
        #pragma unroll
        for(int nt=0;nt<4;nt++){
            int gn = wn2*32 + nt*8 + 2*tq;
            float2 v; v.x = acc2[nt][2*i]; v.y = acc2[nt][2*i+1];
            *(float2*)(dst + gn) = v;
        }
    }
}

// C = alpha * A @ B  (NN), pinv epilogues (proven).
__global__ void __launch_bounds__(256,2) k_mma_nn(
    const float* __restrict__ A, int lda, long sAb, long sAh,
    const float* __restrict__ B, int ldb, long sBb, long sBh,
    float* __restrict__ C, int ldc, long sCb, long sCh,
    float* __restrict__ D, long sDb, long sDh,
    int M, int N, int K, float alpha, float dconst, int cmode)
{
    int z = blockIdx.z; int hh = z & 7; int bb = z >> 3;
    A += (long)bb*sAb + (long)hh*sAh;
    B += (long)bb*sBb + (long)hh*sBh;
    C += (long)bb*sCb + (long)hh*sCh;
    if(D) D += (long)bb*sDb + (long)hh*sDh;
    __shared__ uint32_t As[128][20];
    __shared__ uint32_t Bs[16][136];
    int t = threadIdx.x;
    int lane = t & 31, warp = t >> 5;
    int wm = warp >> 2, wn = warp & 3;
    int r0 = blockIdx.x*128, c0 = blockIdx.y*128;
    int lrow = t >> 2, lk = (t & 3)*4;
    int bk = t >> 5, bn = (t & 31)*4;
    const float* Ap0 = A + (long)(r0+lrow)*lda + lk;
    const float* Ap1 = A + (long)(r0+lrow+64)*lda + lk;
    const float* Bq0 = B + (long)bk*ldb + c0 + bn;
    const float* Bq1 = B + (long)(bk+8)*ldb + c0 + bn;
    bool mA0 = (r0+lrow)<M, mA1 = (r0+lrow+64)<M;
    bool mBn = (c0+bn)<N;
    const float4 z4 = make_float4(0.f,0.f,0.f,0.f);
    float4 pa0 = mA0?ldg4(Ap0):z4, pa1 = mA1?ldg4(Ap1):z4;
    float4 pb0 = mBn?ldg4(Bq0):z4, pb1 = mBn?ldg4(Bq1):z4;
    *(uint4*)&As[lrow][lk]    = cvt4(pa0);
    *(uint4*)&As[lrow+64][lk] = cvt4(pa1);
    *(uint4*)&Bs[bk][bn]      = cvt4(pb0);
    *(uint4*)&Bs[bk+8][bn]    = cvt4(pb1);
    float accr[4][4][4];
    #pragma unroll
    for(int i=0;i<4;i++)
        #pragma unroll
        for(int j=0;j<4;j++)
            #pragma unroll
            for(int q=0;q<4;q++) accr[i][j][q]=0.f;
    int nk = K >> 4;
    for(int kt=0; kt<nk; kt++){
        __syncthreads();
        if(kt+1<nk){
            long o = (long)(kt+1)*16;
            pa0 = mA0?ldg4(Ap0+o):z4; pa1 = mA1?ldg4(Ap1+o):z4;
            pb0 = mBn?ldg4(Bq0+o*ldb):z4; pb1 = mBn?ldg4(Bq1+o*ldb):z4;
        }
        #pragma unroll
        for(int ks=0;ks<2;ks++){
            int cc = ks*8 + (lane&3);
            uint32_t a[4][4], b[4][2];
            int rA = wm*64 + (lane>>2);
            #pragma unroll
            for(int mt=0;mt<4;mt++){
                a[mt][0]=As[rA+mt*16  ][cc];
                a[mt][1]=As[rA+mt*16+8][cc];
                a[mt][2]=As[rA+mt*16  ][cc+4];
                a[mt][3]=As[rA+mt*16+8][cc+4];
            }
            int nB = wn*32 + (lane>>2);
            #pragma unroll
            for(int nt=0;nt<4;nt++){
                b[nt][0]=Bs[cc  ][nB+nt*8];
                b[nt][1]=Bs[cc+4][nB+nt*8];
            }
            #pragma unroll
            for(int mt=0;mt<4;mt++)
                #pragma unroll
                for(int nt=0;nt<4;nt++)
                    mma8(accr[mt][nt], a[mt], b[nt]);
        }
        __syncthreads();
        if(kt+1<nk){
            *(uint4*)&As[lrow][lk]    = cvt4(pa0);
            *(uint4*)&As[lrow+64][lk] = cvt4(pa1);
            *(uint4*)&Bs[bk][bn]      = cvt4(pb0);
            *(uint4*)&Bs[bk+8][bn]    = cvt4(pb1);
        }
    }
    #pragma unroll
    for(int mt=0;mt<4;mt++)
    #pragma unroll
    for(int i=0;i<2;i++){
        int gm = r0 + wm*64 + mt*16 + i*8 + (lane>>2);
        if(gm>=M) continue;
        #pragma unroll
        for(int nt=0;nt<4;nt++){
            int gn = c0 + wn*32 + nt*8 + 2*(lane&3);
            float2 v;
            v.x = alpha*accr[mt][nt][2*i];
            v.y = alpha*accr[mt][nt][2*i+1];
            long o = (long)gm*ldc + gn;
            if(D){
                float2 dv;
                dv.x = ((gm==gn  )?dconst:0.f) - v.x;
                dv.y = ((gm==gn+1)?dconst:0.f) - v.y;
                *(float2*)(D+o) = dv;
            }
            if(cmode){
                v.x = ((gm==gn  )?dconst:0.f) - v.x;
                v.y = ((gm==gn+1)?dconst:0.f) - v.y;
            }
            *(float2*)(C+o) = v;
        }
    }
}

// C = alpha * A @ B (NN, TF32), N=64. 128x64 block, 8 warps of 32x32.
__global__ void __launch_bounds__(256,2) k_mma_nn64(
    const float* __restrict__ A, int lda, long sAb, long sAh,
    const float* __restrict__ B, int ldb, long sBb, long sBh,
    float* __restrict__ C, int ldc, long sCb, long sCh,
    int M, int K, float alpha, int rowLo)
{
    int z = blockIdx.z; int hh = z & 7; int bb = z >> 3;
    A += (long)bb*sAb + (long)hh*sAh;
    B += (long)bb*sBb + (long)hh*sBh;
    C += (long)bb*sCb + (long)hh*sCh;
    __shared__ uint32_t Af[2][2048];
    __shared__ uint32_t Bf[2][1024];
    int t = threadIdx.x, lane = t & 31, warp = t >> 5;
    int wm = warp >> 1, wn = warp & 1;
    int r0 = blockIdx.x*128;
    int alr = t >> 1, alk = (t & 1)*8;
    const float* Ap = A + (long)(r0+alr)*lda + alk;
    bool mA = (r0+alr) < M;
    int bk = t >> 4, bn = (t & 15)*4;
    const float* Bp = B + (long)bk*ldb + bn;
    const float4 z4 = make_float4(0.f,0.f,0.f,0.f);
    float4 a0,a1,b0;
    a0 = mA?ldg4(Ap):z4; a1 = mA?ldg4(Ap+4):z4;
    b0 = ldg4(Bp);
    {
        scatA(Af[0], alr, alk+0, f2tf(a0.x)); scatA(Af[0], alr, alk+1, f2tf(a0.y));
        scatA(Af[0], alr, alk+2, f2tf(a0.z)); scatA(Af[0], alr, alk+3, f2tf(a0.w));
        scatA(Af[0], alr, alk+4, f2tf(a1.x)); scatA(Af[0], alr, alk+5, f2tf(a1.y));
        scatA(Af[0], alr, alk+6, f2tf(a1.z)); scatA(Af[0], alr, alk+7, f2tf(a1.w));
        scatB8(Bf[0], bn+0, bk, f2tf(b0.x)); scatB8(Bf[0], bn+1, bk, f2tf(b0.y));
        scatB8(Bf[0], bn+2, bk, f2tf(b0.z)); scatB8(Bf[0], bn+3, bk, f2tf(b0.w));
    }
    __syncthreads();
    float acc[2][4][4];
    #pragma unroll
    for(int i=0;i<2;i++)
        #pragma unroll
        for(int j=0;j<4;j++)
            #pragma unroll
            for(int q=0;q<4;q++) acc[i][j][q]=0.f;
    int nk = K >> 4;
    for(int kt=0; kt<nk; kt++){
        if(kt+1<nk){
            long o = (long)(kt+1)*16;
            a0 = mA?ldg4(Ap+o):z4; a1 = mA?ldg4(Ap+o+4):z4;
            b0 = ldg4(Bp + o*ldb);
        }
        int buf = kt & 1;
        #pragma unroll
        for(int ks=0;ks<2;ks++){
            uint32_t af[2][4], bfr[4][2];
            #pragma unroll
            for(int mt=0;mt<2;mt++)
                *(uint4*)af[mt] = *(const uint4*)&Af[buf][(((ks<<3)+(wm<<1)+mt)<<7) + (lane<<2)];
            #pragma unroll
            for(int nt=0;nt<4;nt++)
                *(uint2*)bfr[nt] = *(const uint2*)&Bf[buf][(((ks<<3)+(wn<<2)+nt)<<6) + (lane<<1)];
            #pragma unroll
            for(int mt=0;mt<2;mt++)
                #pragma unroll
                for(int nt=0;nt<4;nt++)
                    mma8(acc[mt][nt], af[mt], bfr[nt]);
        }
        if(kt+1<nk){
            int s = (kt+1) & 1;
            scatA(Af[s], alr, alk+0, f2tf(a0.x)); scatA(Af[s], alr, alk+1, f2tf(a0.y));
            scatA(Af[s], alr, alk+2, f2tf(a0.z)); scatA(Af[s], alr, alk+3, f2tf(a0.w));
            scatA(Af[s], alr, alk+4, f2tf(a1.x)); scatA(Af[s], alr, alk+5, f2tf(a1.y));
            scatA(Af[s], alr, alk+6, f2tf(a1.z)); scatA(Af[s], alr, alk+7, f2tf(a1.w));
            scatB8(Bf[s], bn+0, bk, f2tf(b0.x)); scatB8(Bf[s], bn+1, bk, f2tf(b0.y));
            scatB8(Bf[s], bn+2, bk, f2tf(b0.z)); scatB8(Bf[s], bn+3, bk, f2tf(b0.w));
            __syncthreads();
        }
    }
    int g = lane >> 2, tq = lane & 3;
    #pragma unroll
    for(int mt=0;mt<2;mt++)
    #pragma unroll
    for(int i=0;i<2;i++){
        int gm = r0 + wm*32 + mt*16 + i*8 + g;
        if(gm >= M || gm < rowLo) continue;
        #pragma unroll
        for(int nt=0;nt<4;nt++){
            int gn = wn*32 + nt*8 + 2*tq;
            float2 v;
            v.x = alpha*acc[mt][nt][2*i];
            v.y = alpha*acc[mt][nt][2*i+1];
            *(float2*)(C + (long)gm*ldc + gn) = v;
        }
    }
}

// ---------------- softmax over rows of length 4352, register-cached ----------------
__global__ void k_softmax4352(float* __restrict__ X){
    long row = blockIdx.x;
    float* x = X + row*4352;
    int t = threadIdx.x;
    __shared__ float red[256];
    float v[17]; float mx = -1e30f;
    #pragma unroll
    for(int i=0;i<17;i++){ v[i] = x[i*256+t]; mx = fmaxf(mx, v[i]); }
    red[t]=mx; __syncthreads();
    for(int k=128;k;k>>=1){ if(t<k) red[t]=fmaxf(red[t],red[t+k]); __syncthreads(); }
    mx = red[0]; __syncthreads();
    float s = 0.f;
    #pragma unroll
    for(int i=0;i<17;i++){ v[i] = __expf(v[i]-mx); s += v[i]; }
    red[t]=s; __syncthreads();
    for(int k=128;k;k>>=1){ if(t<k) red[t]+=red[t+k]; __syncthreads(); }
    float inv = 1.f/red[0];
    #pragma unroll
    for(int i=0;i<17;i++) x[i*256+t] = v[i]*inv;
}

// ---------------- landmarks (mean over 17 tokens), q scaled by 1/8 ----------------
__global__ void k_landmarks(const float* __restrict__ qkv, float* __restrict__ ql, float* __restrict__ kl){
    int idx = blockIdx.x;
    int mi = idx % 256; int hh = (idx/256) & 7; int b = idx / (256*8);
    int dh = threadIdx.x;
    float sq=0.f, sk=0.f;
    for(int j=0;j<LSUB;j++){
        long tok = (long)mi*LSUB + j;
        const float* base = qkv + ((long)b*4352 + tok)*1536 + hh*64 + dh;
        sq += base[0];
        sk += base[512];
    }
    long o = (long)idx*64 + dh;
    ql[o] = sq * (0.125f/LSUB);
    kl[o] = sk * (1.0f/LSUB);
}

// ---------------- pinv scalar reductions ----------------
__global__ void k_scal_init(){ if(threadIdx.x < 2) g_scal[threadIdx.x] = 0.f; }

__global__ void k_rowsum_max(const float* __restrict__ X){
    long row = blockIdx.x;
    const float* x = X + row*256;
    int t = threadIdx.x;
    __shared__ float red[256];
    red[t] = fabsf(x[t]); __syncthreads();
    for(int k=128;k;k>>=1){ if(t<k) red[t]+=red[t+k]; __syncthreads(); }
    if(t==0) atomicMax((int*)&g_scal[0], __float_as_int(red[0]));
}

__global__ void k_colsum_max(const float* __restrict__ X){
    int b = blockIdx.x; int j = threadIdx.x;
    const float* x = X + (long)b*65536;
    float s = 0.f;
    for(int i=0;i<256;i++) s += fabsf(x[i*256+j]);
    __shared__ float red[256];
    red[j]=s; __syncthreads();
    for(int k=128;k;k>>=1){ if(j<k) red[j]=fmaxf(red[j],red[j+k]); __syncthreads(); }
    if(j==0) atomicMax((int*)&g_scal[1], __float_as_int(red[0]));
}

__global__ void k_tr_scale(const float* __restrict__ X, float* __restrict__ Z){
    long idx = (long)blockIdx.x*256 + threadIdx.x;
    if(idx >= 64L*65536) return;
    float inv = 1.f/(g_scal[0]*g_scal[1]);
    int j = (int)(idx & 255); int i = (int)((idx>>8) & 255); long b = idx >> 16;
    Z[idx] = X[(b<<16) + ((long)j<<8) + i] * inv;
}

// ---------------- residual depthwise conv (k=33), writes token-major into ac ----------------
__global__ void k_resconv2(const float* __restrict__ qkv, const float* __restrict__ w,
                           float* __restrict__ ac){
    int bh = blockIdx.y; int hh = bh & 7; int b = bh >> 3;
    int t0 = blockIdx.x*64;
    __shared__ float sv[96][65];
    __shared__ float sw[33];
    int t = threadIdx.x;
    if(t < 33) sw[t] = w[hh*33 + t];
    const float* vb = qkv + ((long)b*4352)*1536 + 1024 + hh*64;
    for(int i=t;i<96*64;i+=256){
        int tok = t0 - 16 + (i>>6); int dh = i&63;
        sv[i>>6][dh] = (tok>=0 && tok<4352) ? vb[(long)tok*1536 + dh] : 0.f;
    }
    __syncthreads();
    for(int i=t;i<64*64;i+=256){
        int lt = i>>6, dh = i&63;
        int tok = t0 + lt;
        if(tok < 255) continue;
        float s = 0.f;
        #pragma unroll
        for(int j=0;j<33;j++) s = fmaf(sw[j], sv[lt+j][dh], s);
        ac[((long)b*4097 + (tok-255))*512 + hh*64 + dh] += s;
    }
}

// ---------------- transposes token<->planar ----------------
__global__ void k_h2planar(const float* __restrict__ h, float* __restrict__ cnn){
    __shared__ float tile[32][33];
    int b = blockIdx.z;
    int c0 = blockIdx.x*32, p0 = blockIdx.y*32;
    int tx = threadIdx.x, ty = threadIdx.y;
    for(int i=ty;i<32;i+=8)
        tile[i][tx] = h[((long)b*4097 + 1 + p0+i)*512 + c0+tx];
    __syncthreads();
    for(int i=ty;i<32;i+=8)
        cnn[((long)b*512 + c0+i)*4096 + p0+tx] = tile[tx][i];
}

__global__ void k_planar2h(const float* __restrict__ yp, float* __restrict__ h2){
    __shared__ float tile[32][33];
    int b = blockIdx.z;
    int c0 = blockIdx.x*32, p0 = blockIdx.y*32;
    int tx = threadIdx.x, ty = threadIdx.y;
    for(int i=ty;i<32;i+=8)
        tile[i][tx] = yp[((long)b*512 + c0+i)*4096 + p0+tx];
    __syncthreads();
    for(int i=ty;i<32;i+=8)
        h2[((long)b*4097 + 1 + p0+i)*512 + c0+tx] = tile[tx][i];
}

__global__ void k_cls_copy(const float* __restrict__ h, float* __restrict__ h2){
    int idx = blockIdx.x*256 + threadIdx.x;
    if(idx >= 8*512) return;
    int b = idx >> 9, c = idx & 511;
    h2[(long)b*4097*512 + c] = h[(long)b*4097*512 + c];
}

// ---------------- fused 7x7 + 5x5 + 3x3 depthwise conv, planar ----------------
__global__ void k_dwconv(const float* __restrict__ cnn,
                         const float* __restrict__ w7, const float* __restrict__ b7,
                         const float* __restrict__ w5, const float* __restrict__ b5,
                         const float* __restrict__ w3, const float* __restrict__ b3,
                         float* __restrict__ yp){
    int bc = blockIdx.x; int c = bc & 511;
    __shared__ float pl[64][65];
    __shared__ float ww[84];
    const float* in = cnn + (long)bc*4096;
    int t = threadIdx.x;
    for(int i=t;i<4096;i+=256) pl[i>>6][i&63] = in[i];
    if(t < 49)      ww[t]      = w7[c*49 + t];
    else if(t < 74) ww[t]      = w5[c*25 + t - 49];
    else if(t < 83) ww[t]      = w3[c*9  + t - 74];
    __syncthreads();
    float bias = b7[c] + b5[c] + b3[c];
    for(int i=t;i<4096;i+=256){
        int y = i >> 6, x = i & 63;
        float s = pl[y][x] + bias;
        #pragma unroll
        for(int ky=0;ky<7;ky++){ int yy=y+ky-3; if((unsigned)yy>=64u) continue;
            #pragma unroll
            for(int kx=0;kx<7;kx++){ int xx=x+kx-3; if((unsigned)xx>=64u) continue;
                s = fmaf(ww[ky*7+kx], pl[yy][xx], s); } }
        #pragma unroll
        for(int ky=0;ky<5;ky++){ int yy=y+ky-2; if((unsigned)yy>=64u) continue;
            #pragma unroll
            for(int kx=0;kx<5;kx++){ int xx=x+kx-2; if((unsigned)xx>=64u) continue;
                s = fmaf(ww[49+ky*5+kx], pl[yy][xx], s); } }
        #pragma unroll
        for(int ky=0;ky<3;ky++){ int yy=y+ky-1; if((unsigned)yy>=64u) continue;
            #pragma unroll
            for(int kx=0;kx<3;kx++){ int xx=x+kx-1; if((unsigned)xx>=64u) continue;
                s = fmaf(ww[74+ky*3+kx], pl[yy][xx], s); } }
        yp[(long)bc*4096 + i] = s;
    }
}

// ---------------- final output: (cls[8,512], feat[8,4096,512]) ----------------
__global__ void k_writeout(const float* __restrict__ h2, float* __restrict__ out){
    long idx = (long)blockIdx.x*256 + threadIdx.x;
    if(idx >= 8L*512 + 8L*4096*512) return;
    if(idx < 8*512){
        int b = (int)(idx >> 9), c = (int)(idx & 511);
        out[idx] = h2[((long)b*4097)*512 + c];
    } else {
        long r = idx - 4096;
        int c = (int)(r & 511); long q = r >> 9; int t = (int)(q % 4096); int b = (int)(q / 4096);
        out[idx] = h2[((long)b*4097 + 1 + t)*512 + c];
    }
}

// ================= host side =================
struct Ptrs {
    float *h,*h2,*xp,*qkv,*ql,*kl,*sim3,*a2,*zA,*zB,*xz,*t1,*t2,*a3v,*tmp2,*ac,*cnn,*yp;
};

static void get_ptrs(Ptrs& p){
    cudaGetSymbolAddress((void**)&p.h,    g_h);
    cudaGetSymbolAddress((void**)&p.h2,   g_h2);
    cudaGetSymbolAddress((void**)&p.xp,   g_xp);
    cudaGetSymbolAddress((void**)&p.qkv,  g_qkv);
    cudaGetSymbolAddress((void**)&p.ql,   g_ql);
    cudaGetSymbolAddress((void**)&p.kl,   g_kl);
    cudaGetSymbolAddress((void**)&p.sim3, g_sim3);
    cudaGetSymbolAddress((void**)&p.a2,   g_a2);
    cudaGetSymbolAddress((void**)&p.zA,   g_zA);
    cudaGetSymbolAddress((void**)&p.zB,   g_zB);
    cudaGetSymbolAddress((void**)&p.xz,   g_xz);
    cudaGetSymbolAddress((void**)&p.t1,   g_t1);
    cudaGetSymbolAddress((void**)&p.t2,   g_t2);
    cudaGetSymbolAddress((void**)&p.a3v,  g_a3v);
    cudaGetSymbolAddress((void**)&p.tmp2, g_tmp2);
    cudaGetSymbolAddress((void**)&p.ac,   g_ac);
    cudaGetSymbolAddress((void**)&p.cnn,  g_cnn);
    cudaGetSymbolAddress((void**)&p.yp,   g_yp);
}

static void attention(Ptrs& p, float* hbuf,
                      const float* lng, const float* lnb,
                      const float* qkvw, const float* outw, const float* outb,
                      const float* resw)
{
    const long SQKV_B = 4352L*1536;
    const long SQL    = 256L*64;
    const long SS3    = 256L*4352;
    const long SA2    = 65536L;
    const long SV64   = 256L*64;

    k_zero_pad<<<4080, 256>>>(p.xp);
    k_ln<<<8*4097, 256>>>(hbuf, lng, lnb, p.xp);

    // qkv = xp @ qkv_w^T   (34816 x 1536 x 512)
    k_mma_nt<<<dim3(272,12,1), 256>>>(p.xp, 512, 0,0, qkvw, 512, 0,0,
                                      p.qkv, 1536, 0,0, 34816, 1536, 512, 1.f, nullptr, 0);

    k_landmarks<<<64*256, 64>>>(p.qkv, p.ql, p.kl);

    // a2 = softmax(q_l @ k_l^T) fused : (256 x 256)
    k_simsm<<<dim3(4,1,64), 256>>>(p.ql, 64, 8*SQL, SQL,
                                   p.kl, 64, 8*SQL, SQL,
                                   p.a2, 256, 8*SA2, SA2, 1.f);

    // sim3 = q_l @ k^T : (256 x 4352 x 64)
    k_mma_nt<<<dim3(2,34,64), 256>>>(p.ql, 64, 8*SQL, SQL,
                                     p.qkv + 512, 1536, SQKV_B, 64,
                                     p.sim3, 4352, 8*SS3, SS3,
                                     256, 4352, 64, 1.f, nullptr, 0);
    k_softmax4352<<<64*256, 256>>>(p.sim3);

    // a3v = a3 @ v : (256 x 64 x 4352)   [TF32]
    k_mma_nn64<<<dim3(2,1,64), 256>>>(p.sim3, 4352, 8*SS3, SS3,
                                      p.qkv + 1024, 1536, SQKV_B, 64,
                                      p.a3v, 64, 8*SV64, SV64,
                                      256, 4352, 1.f, 0);

    // ---- Moore-Penrose pinv of a2 (6 iterations, idm fused in epilogues) ----
    k_scal_init<<<1, 32>>>();
    k_rowsum_max<<<64*256, 256>>>(p.a2);
    k_colsum_max<<<64, 256>>>(p.a2);
    k_tr_scale<<<16384, 256>>>(p.a2, p.zA);

    float* zc = p.zA; float* zn = p.zB;
    for(int it=0; it<6; it++){
        k_mma_nn<<<dim3(2,2,64), 256>>>(p.a2, 256, 8*SA2, SA2, zc, 256, 8*SA2, SA2,
                                        p.xz, 256, 8*SA2, SA2, p.t1, 8*SA2, SA2,
                                        256,256,256, 1.f, 7.f, 0);
        k_mma_nn<<<dim3(2,2,64), 256>>>(p.xz, 256, 8*SA2, SA2, p.t1, 256, 8*SA2, SA2,
                                        p.t2, 256, 8*SA2, SA2, nullptr, 0,0,
                                        256,256,256, 1.f, 15.f, 1);
        k_mma_nn<<<dim3(2,2,64), 256>>>(p.xz, 256, 8*SA2, SA2, p.t2, 256, 8*SA2, SA2,
                                        p.t1, 256, 8*SA2, SA2, nullptr, 0,0,
                                        256,256,256, 1.f, 13.f, 1);
        k_mma_nn<<<dim3(2,2,64), 256>>>(zc, 256, 8*SA2, SA2, p.t1, 256, 8*SA2, SA2,
                                        zn, 256, 8*SA2, SA2, nullptr, 0,0,
                                        256,256,256, 0.25f, 0.f, 0);
        float* tmp = zc; zc = zn; zn = tmp;
    }

    // tmp2 = z @ a3v : (256 x 64 x 256)   [TF32]
    k_mma_nn64<<<dim3(2,1,64), 256>>>(zc, 256, 8*SA2, SA2, p.a3v, 64, 8*SV64, SV64,
                                      p.tmp2, 64, 8*SV64, SV64, 256, 256, 1.f, 0);

    // ac = softmax(q*scale @ kl^T) @ tmp2, fused, direct token-major
    k_attnout<<<dim3(68,1,64), 256>>>(p.qkv, 1536, SQKV_B, 64,
                                      p.kl, SQL, p.tmp2, SV64,
                                      p.ac, 0.125f);

    // residual depthwise conv (k=33 along sequence) added directly into ac
    k_resconv2<<<dim3(68,64), 256>>>(p.qkv, resw, p.ac);

    // hbuf += ac @ out_w^T + out_b
    k_mma_nt<<<dim3(257,4,1), 256>>>(p.ac, 512, 0,0, outw, 512, 0,0,
                                     hbuf, 512, 0,0, 32776, 512, 512, 1.f, outb, 1);
}

extern "C" void kernel_launch(void* const* d_in, const int* in_sizes, int n_in,
                              void* d_out, int out_size)
{
    const float* features = (const float*)d_in[0];
    const float* cls_tok  = (const float*)d_in[1];
    const float* ln1_g    = (const float*)d_in[2];
    const float* ln1_b    = (const float*)d_in[3];
    const float* qkv1_w   = (const float*)d_in[4];
    const float* out1_w   = (const float*)d_in[5];
    const float* out1_b   = (const float*)d_in[6];
    const float* res1_w   = (const float*)d_in[7];
    const float* p7_w     = (const float*)d_in[8];
    const float* p7_b     = (const float*)d_in[9];
    const float* p5_w     = (const float*)d_in[10];
    const float* p5_b     = (const float*)d_in[11];
    const float* p3_w     = (const float*)d_in[12];
    const float* p3_b     = (const float*)d_in[13];
    const float* ln2_g    = (const float*)d_in[14];
    const float* ln2_b    = (const float*)d_in[15];
    const float* qkv2_w   = (const float*)d_in[16];
    const float* out2_w   = (const float*)d_in[17];
    const float* out2_b   = (const float*)d_in[18];
    const float* res2_w   = (const float*)d_in[19];
    float* out = (float*)d_out;

    Ptrs p;
    get_ptrs(p);

    k_build_h<<<65552, 256>>>(features, cls_tok);

    attention(p, p.h, ln1_g, ln1_b, qkv1_w, out1_w, out1_b, res1_w);

    k_h2planar<<<dim3(16,128,8), dim3(32,8)>>>(p.h, p.cnn);
    k_dwconv<<<4096, 256>>>(p.cnn, p7_w, p7_b, p5_w, p5_b, p3_w, p3_b, p.yp);
    k_planar2h<<<dim3(16,128,8), dim3(32,8)>>>(p.yp, p.h2);
    k_cls_copy<<<16, 256>>>(p.h, p.h2);

    attention(p, p.h2, ln2_g, ln2_b, qkv2_w, out2_w, out2_b, res2_w);

    k_writeout<<<65552, 256>>>(p.h2, out);
}

// round 12
// speedup vs baseline: 1.4875x; 1.1215x over previous
#include <cuda_runtime.h>
#include <math.h>
#include <stdint.h>

// ---------------- problem constants ----------------
// B=8, C=512, HEADS=8, DH=64, tokens=4097 (cls+4096), pad=255 -> N=4352
// landmarks m=256, l=17, pinv iters=6, res kernel 33  (build r12: flash sim3+softmax+a3v)
#define LSUB 17

// ---------------- device scratch ----------------
__device__ float g_h   [8L*4097*512];
__device__ float g_h2  [8L*4097*512];
__device__ float g_xp  [8L*4352*512];
__device__ float g_qkv [8L*4352*1536];
__device__ float g_ql  [64L*256*64];
__device__ float g_kl  [64L*256*64];
__device__ float g_a2  [64L*256*256];
__device__ float g_zA  [64L*256*256];
__device__ float g_zB  [64L*256*256];
__device__ float g_xz  [64L*256*256];
__device__ float g_t1  [64L*256*256];
__device__ float g_t2  [64L*256*256];
__device__ float g_a3v [64L*256*64];
__device__ float g_tmp2[64L*256*64];
__device__ float g_ac  [8L*4097*512];
__device__ float g_cnn [8L*512*4096];
__device__ float g_yp  [8L*512*4096];
__device__ float g_scal[2];

__device__ __forceinline__ float4 ldg4(const float* p){ return *(const float4*)p; }

// ---------------- tf32 mma helpers ----------------
__device__ __forceinline__ uint32_t f2tf(float x){
    uint32_t u; asm("cvt.rna.tf32.f32 %0, %1;" : "=r"(u) : "f"(x)); return u;
}
__device__ __forceinline__ uint4 cvt4(float4 v){
    uint4 u; u.x=f2tf(v.x); u.y=f2tf(v.y); u.z=f2tf(v.z); u.w=f2tf(v.w); return u;
}
__device__ __forceinline__ void mma8(float* d, const uint32_t* a, const uint32_t* b){
    asm("mma.sync.aligned.m16n8k8.row.col.f32.tf32.tf32.f32 "
        "{%0,%1,%2,%3}, {%4,%5,%6,%7}, {%8,%9}, {%0,%1,%2,%3};"
        : "+f"(d[0]),"+f"(d[1]),"+f"(d[2]),"+f"(d[3])
        : "r"(a[0]),"r"(a[1]),"r"(a[2]),"r"(a[3]), "r"(b[0]),"r"(b[1]));
}

// Fragment-major scatter (for k_mma_nn64): element (row,k) of 128x16 A tile
__device__ __forceinline__ void scatA(uint32_t* Af, int row, int k, uint32_t v){
    int ks=k>>3, kc=k&7;
    Af[(((ks<<3)+(row>>4))<<7) + ((((row&7)<<2)+(kc&3))<<2) + ((row>>3)&1) + ((kc>>2)<<1)] = v;
}
// B tile with 8 n-tiles (64 cols)
__device__ __forceinline__ void scatB8(uint32_t* Bf, int n, int k, uint32_t v){
    int ks=k>>3, kc=k&7;
    Bf[(((ks<<3)+(n>>3))<<6) + ((((n&7)<<2)+(kc&3))<<1) + (kc>>2)] = v;
}

// ---------------- small kernels ----------------
__global__ void k_build_h(const float* __restrict__ feat, const float* __restrict__ cls){
    long idx = (long)blockIdx.x*256 + threadIdx.x;
    if(idx >= 8L*4097*512) return;
    int c = idx & 511; long r = idx >> 9; int t = (int)(r % 4097); int b = (int)(r / 4097);
    g_h[idx] = (t==0) ? cls[c] : feat[((long)b*4096 + (t-1))*512 + c];
}

__global__ void k_zero_pad(float* __restrict__ xp){
    long idx = (long)blockIdx.x*256 + threadIdx.x;
    if(idx >= 8L*255*512) return;
    int c = idx & 511; long r = idx >> 9; int t = (int)(r % 255); int b = (int)(r / 255);
    xp[((long)b*4352 + t)*512 + c] = 0.f;
}

__global__ void k_ln(const float* __restrict__ h, const float* __restrict__ g,
                     const float* __restrict__ be, float* __restrict__ xp){
    long r = blockIdx.x;
    int b = (int)(r / 4097); int t = (int)(r % 4097);
    const float* x = h + r*512;
    float* y = xp + ((long)b*4352 + 255 + t)*512;
    int tid = threadIdx.x;
    __shared__ float red[256];
    float s = 0.f;
    for(int i=tid;i<512;i+=256) s += x[i];
    red[tid]=s; __syncthreads();
    for(int k=128;k;k>>=1){ if(tid<k) red[tid]+=red[tid+k]; __syncthreads(); }
    float mean = red[0] * (1.f/512.f); __syncthreads();
    float v = 0.f;
    for(int i=tid;i<512;i+=256){ float d=x[i]-mean; v += d*d; }
    red[tid]=v; __syncthreads();
    for(int k=128;k;k>>=1){ if(tid<k) red[tid]+=red[tid+k]; __syncthreads(); }
    float rstd = rsqrtf(red[0]*(1.f/512.f) + 1e-5f);
    for(int i=tid;i<512;i+=256) y[i] = (x[i]-mean)*rstd*g[i] + be[i];
}

// =====================================================================
// TF32 tensor-core GEMMs: 128x128 block, 8 warps of 64x32, BK=16 (proven)
// =====================================================================

// C = alpha * A @ B^T (+bias)(+C)   A:(M,K) lda, B:(N,K) ldb   batched (b,h)
__global__ void __launch_bounds__(256,2) k_mma_nt(
    const float* __restrict__ A, int lda, long sAb, long sAh,
    const float* __restrict__ B, int ldb, long sBb, long sBh,
    float* __restrict__ C, int ldc, long sCb, long sCh,
    int M, int N, int K, float alpha, const float* __restrict__ bias, int acc)
{
    int z = blockIdx.z; int hh = z & 7; int bb = z >> 3;
    A += (long)bb*sAb + (long)hh*sAh;
    B += (long)bb*sBb + (long)hh*sBh;
    C += (long)bb*sCb + (long)hh*sCh;
    __shared__ uint32_t As[128][20];
    __shared__ uint32_t Bs[128][20];
    int t = threadIdx.x;
    int lane = t & 31, warp = t >> 5;
    int wm = warp >> 2, wn = warp & 3;
    int r0 = blockIdx.x*128, c0 = blockIdx.y*128;
    int lrow = t >> 2, lk = (t & 3)*4;
    const float* Ap0 = A + (long)(r0+lrow)*lda + lk;
    const float* Ap1 = A + (long)(r0+lrow+64)*lda + lk;
    const float* Bp0 = B + (long)(c0+lrow)*ldb + lk;
    const float* Bp1 = B + (long)(c0+lrow+64)*ldb + lk;
    bool mA0 = (r0+lrow)<M, mA1 = (r0+lrow+64)<M;
    bool mB0 = (c0+lrow)<N, mB1 = (c0+lrow+64)<N;
    const float4 z4 = make_float4(0.f,0.f,0.f,0.f);
    float4 pa0 = mA0?ldg4(Ap0):z4, pa1 = mA1?ldg4(Ap1):z4;
    float4 pb0 = mB0?ldg4(Bp0):z4, pb1 = mB1?ldg4(Bp1):z4;
    *(uint4*)&As[lrow][lk]    = cvt4(pa0);
    *(uint4*)&As[lrow+64][lk] = cvt4(pa1);
    *(uint4*)&Bs[lrow][lk]    = cvt4(pb0);
    *(uint4*)&Bs[lrow+64][lk] = cvt4(pb1);
    float accr[4][4][4];
    #pragma unroll
    for(int i=0;i<4;i++)
        #pragma unroll
        for(int j=0;j<4;j++)
            #pragma unroll
            for(int q=0;q<4;q++) accr[i][j][q]=0.f;
    int nk = K >> 4;
    for(int kt=0; kt<nk; kt++){
        __syncthreads();
        if(kt+1<nk){
            int o = (kt+1)*16;
            pa0 = mA0?ldg4(Ap0+o):z4; pa1 = mA1?ldg4(Ap1+o):z4;
            pb0 = mB0?ldg4(Bp0+o):z4; pb1 = mB1?ldg4(Bp1+o):z4;
        }
        #pragma unroll
        for(int ks=0;ks<2;ks++){
            int cc = ks*8 + (lane&3);
            uint32_t a[4][4], b[4][2];
            int rA = wm*64 + (lane>>2);
            #pragma unroll
            for(int mt=0;mt<4;mt++){
                a[mt][0]=As[rA+mt*16  ][cc];
                a[mt][1]=As[rA+mt*16+8][cc];
                a[mt][2]=As[rA+mt*16  ][cc+4];
                a[mt][3]=As[rA+mt*16+8][cc+4];
            }
            int rB = wn*32 + (lane>>2);
            #pragma unroll
            for(int nt=0;nt<4;nt++){
                b[nt][0]=Bs[rB+nt*8][cc];
                b[nt][1]=Bs[rB+nt*8][cc+4];
            }
            #pragma unroll
            for(int mt=0;mt<4;mt++)
                #pragma unroll
                for(int nt=0;nt<4;nt++)
                    mma8(accr[mt][nt], a[mt], b[nt]);
        }
        __syncthreads();
        if(kt+1<nk){
            *(uint4*)&As[lrow][lk]    = cvt4(pa0);
            *(uint4*)&As[lrow+64][lk] = cvt4(pa1);
            *(uint4*)&Bs[lrow][lk]    = cvt4(pb0);
            *(uint4*)&Bs[lrow+64][lk] = cvt4(pb1);
        }
    }
    #pragma unroll
    for(int mt=0;mt<4;mt++)
    #pragma unroll
    for(int i=0;i<2;i++){
        int gm = r0 + wm*64 + mt*16 + i*8 + (lane>>2);
        if(gm>=M) continue;
        #pragma unroll
        for(int nt=0;nt<4;nt++){
            int gn = c0 + wn*32 + nt*8 + 2*(lane&3);
            float2 v;
            v.x = alpha*accr[mt][nt][2*i];
            v.y = alpha*accr[mt][nt][2*i+1];
            if(bias){ v.x += bias[gn]; v.y += bias[gn+1]; }
            float* cp = C + (long)gm*ldc + gn;
            if(acc){ v.x += cp[0]; v.y += cp[1]; }
            *(float2*)cp = v;
        }
    }
}

// Fused GEMM+softmax: C = softmax_row(alpha * A @ B^T), K=64, N=256.
__global__ void __launch_bounds__(256,2) k_simsm(
    const float* __restrict__ A, int lda, long sAb, long sAh,
    const float* __restrict__ B, int ldb, long sBb, long sBh,
    float* __restrict__ C, int ldc, long sCb, long sCh,
    float alpha)
{
    int z = blockIdx.z; int hh = z & 7; int bb = z >> 3;
    A += (long)bb*sAb + (long)hh*sAh;
    B += (long)bb*sBb + (long)hh*sBh;
    C += (long)bb*sCb + (long)hh*sCh;
    __shared__ uint32_t As[64][20];
    __shared__ uint32_t Bs[256][20];
    __shared__ float red[64][4];
    int t = threadIdx.x;
    int lane = t & 31, warp = t >> 5;
    int wm = warp >> 2, wn = warp & 3;
    int r0 = blockIdx.x*64;
    int lrow = t >> 2, lk = (t & 3)*4;
    float acc[2][8][4];
    #pragma unroll
    for(int i=0;i<2;i++)
        #pragma unroll
        for(int j=0;j<8;j++)
            #pragma unroll
            for(int q=0;q<4;q++) acc[i][j][q]=0.f;
    for(int kt=0; kt<4; kt++){
        __syncthreads();
        *(uint4*)&As[lrow][lk] = cvt4(ldg4(A + (long)(r0+lrow)*lda + kt*16 + lk));
        #pragma unroll
        for(int i=0;i<4;i++)
            *(uint4*)&Bs[i*64+lrow][lk] = cvt4(ldg4(B + (long)(i*64+lrow)*ldb + kt*16 + lk));
        __syncthreads();
        #pragma unroll
        for(int ks=0;ks<2;ks++){
            int cc = ks*8 + (lane&3);
            uint32_t a[2][4], b[8][2];
            int rA = wm*32 + (lane>>2);
            #pragma unroll
            for(int mt=0;mt<2;mt++){
                a[mt][0]=As[rA+mt*16  ][cc];
                a[mt][1]=As[rA+mt*16+8][cc];
                a[mt][2]=As[rA+mt*16  ][cc+4];
                a[mt][3]=As[rA+mt*16+8][cc+4];
            }
            int rB = wn*64 + (lane>>2);
            #pragma unroll
            for(int nt=0;nt<8;nt++){
                b[nt][0]=Bs[rB+nt*8][cc];
                b[nt][1]=Bs[rB+nt*8][cc+4];
            }
            #pragma unroll
            for(int mt=0;mt<2;mt++)
                #pragma unroll
                for(int nt=0;nt<8;nt++)
                    mma8(acc[mt][nt], a[mt], b[nt]);
        }
    }
    int g = lane>>2, tq = lane&3;
    float pm[2][2];
    #pragma unroll
    for(int mt=0;mt<2;mt++)
        #pragma unroll
        for(int i=0;i<2;i++){
            float m = -1e30f;
            #pragma unroll
            for(int nt=0;nt<8;nt++){
                acc[mt][nt][2*i]   *= alpha;
                acc[mt][nt][2*i+1] *= alpha;
                m = fmaxf(m, fmaxf(acc[mt][nt][2*i], acc[mt][nt][2*i+1]));
            }
            m = fmaxf(m, __shfl_xor_sync(0xffffffffu, m, 1));
            m = fmaxf(m, __shfl_xor_sync(0xffffffffu, m, 2));
            pm[mt][i] = m;
        }
    if(tq==0){
        #pragma unroll
        for(int mt=0;mt<2;mt++)
            #pragma unroll
            for(int i=0;i<2;i++)
                red[wm*32+mt*16+i*8+g][wn] = pm[mt][i];
    }
    __syncthreads();
    float rmax[2][2];
    #pragma unroll
    for(int mt=0;mt<2;mt++)
        #pragma unroll
        for(int i=0;i<2;i++){
            int rid = wm*32+mt*16+i*8+g;
            rmax[mt][i] = fmaxf(fmaxf(red[rid][0],red[rid][1]), fmaxf(red[rid][2],red[rid][3]));
        }
    __syncthreads();
    float ps[2][2];
    #pragma unroll
    for(int mt=0;mt<2;mt++)
        #pragma unroll
        for(int i=0;i<2;i++){
            float s = 0.f;
            #pragma unroll
            for(int nt=0;nt<8;nt++){
                float e0 = __expf(acc[mt][nt][2*i]   - rmax[mt][i]);
                float e1 = __expf(acc[mt][nt][2*i+1] - rmax[mt][i]);
                acc[mt][nt][2*i]   = e0;
                acc[mt][nt][2*i+1] = e1;
                s += e0 + e1;
            }
            s += __shfl_xor_sync(0xffffffffu, s, 1);
            s += __shfl_xor_sync(0xffffffffu, s, 2);
            ps[mt][i] = s;
        }
    if(tq==0){
        #pragma unroll
        for(int mt=0;mt<2;mt++)
            #pragma unroll
            for(int i=0;i<2;i++)
                red[wm*32+mt*16+i*8+g][wn] = ps[mt][i];
    }
    __syncthreads();
    #pragma unroll
    for(int mt=0;mt<2;mt++)
        #pragma unroll
        for(int i=0;i<2;i++){
            int rid = wm*32+mt*16+i*8+g;
            float inv = 1.f/(red[rid][0]+red[rid][1]+red[rid][2]+red[rid][3]);
            long gm = r0 + rid;
            #pragma unroll
            for(int nt=0;nt<8;nt++){
                int gn = wn*64 + nt*8 + 2*tq;
                float2 v; v.x = acc[mt][nt][2*i]*inv; v.y = acc[mt][nt][2*i+1]*inv;
                *(float2*)(C + gm*ldc + gn) = v;
            }
        }
}

// =====================================================================
// Flash-style fused sim3+softmax+a3v:
//   a3v[z] = softmax_row(ql @ k^T) @ v   per (b,h), online softmax over 17
//   chunks of 256 keys. Block = 64 landmark rows. Dynamic smem 55040 B.
// =====================================================================
__global__ void __launch_bounds__(256,2) k_flash3(
    const float* __restrict__ QL, long sQL,
    const float* __restrict__ QKV, long sQKVb,
    float* __restrict__ Ov, long sO)
{
    extern __shared__ char dyn[];
    uint32_t (*Qs)[68] = (uint32_t(*)[68])dyn;                   // 64x68  (17408) persistent
    uint32_t (*Ks)[20] = (uint32_t(*)[20])(dyn + 17408);         // 256x20 (20480) phase 1
    uint32_t (*Pf)[68] = (uint32_t(*)[68])(dyn + 17408);         // 64x68  (17408) phase 2 overlay
    uint32_t (*Vs)[72] = (uint32_t(*)[72])(dyn + 17408 + 17408); // 64x72  (18432) phase 2
    float (*red)[4] = (float(*)[4])(dyn + 53248);                // 64x4   (1024)
    float* m_run = (float*)(dyn + 54272);                        // 64
    float* l_run = (float*)(dyn + 54528);                        // 64
    float* sf    = (float*)(dyn + 54784);                        // 64     total 55040
    int z = blockIdx.z; int hh = z & 7; int bb = z >> 3;
    const float* Q  = QL  + (long)z*sQL;
    const float* Kg = QKV + (long)bb*sQKVb + 512  + hh*64;
    const float* Vg = QKV + (long)bb*sQKVb + 1024 + hh*64;
    float* Og = Ov + (long)z*sO;
    int t = threadIdx.x, lane = t & 31, warp = t >> 5;
    int wm = warp >> 2, wn = warp & 3;      // phase 1: 2x32 rows, 4x64 cols
    int wm2 = warp >> 1, wn2 = warp & 1;    // phase 2: 4x16 rows, 2x32 cols
    int g = lane >> 2, tq = lane & 3;
    int r0 = blockIdx.x*64;
    {   // load Q (64x64) once
        int row = t >> 2, cb = (t & 3)*16;
        const float* qp = Q + (long)(r0+row)*64 + cb;
        #pragma unroll
        for(int j=0;j<4;j++){
            float4 v = ldg4(qp + j*4);
            Qs[row][cb+j*4+0]=f2tf(v.x); Qs[row][cb+j*4+1]=f2tf(v.y);
            Qs[row][cb+j*4+2]=f2tf(v.z); Qs[row][cb+j*4+3]=f2tf(v.w);
        }
    }
    if(t < 64){ m_run[t] = -1e30f; l_run[t] = 0.f; }
    float acc2[4][4];
    #pragma unroll
    for(int j=0;j<4;j++)
        #pragma unroll
        for(int q=0;q<4;q++) acc2[j][q]=0.f;
    for(int ch=0; ch<17; ch++){
        long kc0 = (long)ch*256;
        float acc[2][8][4];
        #pragma unroll
        for(int i=0;i<2;i++)
            #pragma unroll
            for(int j=0;j<8;j++)
                #pragma unroll
                for(int q=0;q<4;q++) acc[i][j][q]=0.f;
        // ---- phase 1: S = ql @ K_chunk^T (scale already in ql) ----
        for(int kt=0; kt<4; kt++){
            __syncthreads();
            int lrow = t >> 2, lk = (t & 3)*4;
            #pragma unroll
            for(int i=0;i<4;i++){
                int row = i*64 + lrow;
                *(uint4*)&Ks[row][lk] = cvt4(ldg4(Kg + (kc0+row)*1536 + kt*16 + lk));
            }
            __syncthreads();
            #pragma unroll
            for(int ks=0;ks<2;ks++){
                int cc = ks*8 + tq, qc = kt*16 + cc;
                uint32_t a[2][4], b[8][2];
                int rA = wm*32 + g;
                #pragma unroll
                for(int mt=0;mt<2;mt++){
                    a[mt][0]=Qs[rA+mt*16  ][qc];
                    a[mt][1]=Qs[rA+mt*16+8][qc];
                    a[mt][2]=Qs[rA+mt*16  ][qc+4];
                    a[mt][3]=Qs[rA+mt*16+8][qc+4];
                }
                int rB = wn*64 + g;
                #pragma unroll
                for(int nt=0;nt<8;nt++){
                    b[nt][0]=Ks[rB+nt*8][cc];
                    b[nt][1]=Ks[rB+nt*8][cc+4];
                }
                #pragma unroll
                for(int mt=0;mt<2;mt++)
                    #pragma unroll
                    for(int nt=0;nt<8;nt++)
                        mma8(acc[mt][nt], a[mt], b[nt]);
            }
        }
        // ---- online softmax: chunk max ----
        float pm[2][2];
        #pragma unroll
        for(int mt=0;mt<2;mt++)
            #pragma unroll
            for(int i=0;i<2;i++){
                float m = -1e30f;
                #pragma unroll
                for(int nt=0;nt<8;nt++)
                    m = fmaxf(m, fmaxf(acc[mt][nt][2*i], acc[mt][nt][2*i+1]));
                m = fmaxf(m, __shfl_xor_sync(0xffffffffu, m, 1));
                m = fmaxf(m, __shfl_xor_sync(0xffffffffu, m, 2));
                pm[mt][i] = m;
            }
        if(tq==0){
            #pragma unroll
            for(int mt=0;mt<2;mt++)
                #pragma unroll
                for(int i=0;i<2;i++)
                    red[wm*32+mt*16+i*8+g][wn] = pm[mt][i];
        }
        __syncthreads();
        float mn_[2][2];
        #pragma unroll
        for(int mt=0;mt<2;mt++)
            #pragma unroll
            for(int i=0;i<2;i++){
                int rid = wm*32+mt*16+i*8+g;
                float cm = fmaxf(fmaxf(red[rid][0],red[rid][1]), fmaxf(red[rid][2],red[rid][3]));
                mn_[mt][i] = fmaxf(m_run[rid], cm);
            }
        __syncthreads();
        // ---- exp + chunk sum ----
        float ps[2][2];
        #pragma unroll
        for(int mt=0;mt<2;mt++)
            #pragma unroll
            for(int i=0;i<2;i++){
                float s = 0.f;
                #pragma unroll
                for(int nt=0;nt<8;nt++){
                    float e0 = __expf(acc[mt][nt][2*i]   - mn_[mt][i]);
                    float e1 = __expf(acc[mt][nt][2*i+1] - mn_[mt][i]);
                    acc[mt][nt][2*i]   = e0;
                    acc[mt][nt][2*i+1] = e1;
                    s += e0 + e1;
                }
                s += __shfl_xor_sync(0xffffffffu, s, 1);
                s += __shfl_xor_sync(0xffffffffu, s, 2);
                ps[mt][i] = s;
            }
        if(tq==0){
            #pragma unroll
            for(int mt=0;mt<2;mt++)
                #pragma unroll
                for(int i=0;i<2;i++)
                    red[wm*32+mt*16+i*8+g][wn] = ps[mt][i];
        }
        __syncthreads();
        // ---- single-lane running-stat update ----
        if(wn==0 && tq==0){
            #pragma unroll
            for(int mt=0;mt<2;mt++)
                #pragma unroll
                for(int i=0;i<2;i++){
                    int rid = wm*32+mt*16+i*8+g;
                    float ct = red[rid][0]+red[rid][1]+red[rid][2]+red[rid][3];
                    float mn = mn_[mt][i];
                    float f  = __expf(m_run[rid] - mn);
                    l_run[rid] = l_run[rid]*f + ct;
                    m_run[rid] = mn;
                    sf[rid] = f;
                }
        }
        __syncthreads();
        // ---- rescale O accumulator (phase-2 row mapping) ----
        #pragma unroll
        for(int i=0;i<2;i++){
            float f2 = sf[wm2*16 + i*8 + g];
            #pragma unroll
            for(int nt=0;nt<4;nt++){ acc2[nt][2*i]*=f2; acc2[nt][2*i+1]*=f2; }
        }
        // ---- phase 2: O += P @ V_chunk, 4 sub-chunks of 64 keys ----
        for(int sub=0; sub<4; sub++){
            __syncthreads();
            if(wn == sub){
                #pragma unroll
                for(int mt=0;mt<2;mt++)
                    #pragma unroll
                    for(int i=0;i<2;i++){
                        int rl = wm*32+mt*16+i*8+g;
                        #pragma unroll
                        for(int nt=0;nt<8;nt++){
                            int cl = nt*8 + 2*tq;
                            Pf[rl][cl]   = f2tf(acc[mt][nt][2*i]);
                            Pf[rl][cl+1] = f2tf(acc[mt][nt][2*i+1]);
                        }
                    }
            }
            {
                int kl = t >> 2, cb = (t & 3)*16;
                const float* vp = Vg + (kc0 + sub*64 + kl)*1536 + cb;
                #pragma unroll
                for(int j=0;j<4;j++){
                    float4 v = ldg4(vp + j*4);
                    Vs[kl][cb+j*4+0]=f2tf(v.x); Vs[kl][cb+j*4+1]=f2tf(v.y);
                    Vs[kl][cb+j*4+2]=f2tf(v.z); Vs[kl][cb+j*4+3]=f2tf(v.w);
                }
            }
            __syncthreads();
            #pragma unroll
            for(int kk=0;kk<8;kk++){
                int cc = kk*8 + tq;
                uint32_t a[4], b[4][2];
                a[0]=Pf[wm2*16+g  ][cc];
                a[1]=Pf[wm2*16+8+g][cc];
                a[2]=Pf[wm2*16+g  ][cc+4];
                a[3]=Pf[wm2*16+8+g][cc+4];
                #pragma unroll
                for(int nt=0;nt<4;nt++){
                    int n = wn2*32 + nt*8 + g;
                    b[nt][0]=Vs[cc  ][n];
                    b[nt][1]=Vs[cc+4][n];
                }
                #pragma unroll
                for(int nt=0;nt<4;nt++)
                    mma8(acc2[nt], a, b[nt]);
            }
        }
    }
    // ---- normalize and write a3v ----
    #pragma unroll
    for(int i=0;i<2;i++){
        int row = wm2*16 + i*8 + g;
        float linv = 1.f/l_run[row];
        float* dst = Og + (long)(r0+row)*64;
        #pragma unroll
        for(int nt=0;nt<4;nt++){
            int col = wn2*32 + nt*8 + 2*tq;
            float2 v; v.x = acc2[nt][2*i]*linv; v.y = acc2[nt][2*i+1]*linv;
            *(float2*)(dst + col) = v;
        }
    }
}

// =====================================================================
// Fused attention output: ac[token] = softmax(alpha * q @ kl^T) @ tmp2
// =====================================================================
__global__ void __launch_bounds__(256,2) k_attnout(
    const float* __restrict__ Q, int ldq, long sQb, long sQh,
    const float* __restrict__ KL, long sKL,
    const float* __restrict__ T2, long sT2,
    float* __restrict__ AC, float alpha)
{
    int z = blockIdx.z; int hh = z & 7; int bb = z >> 3;
    const float* A = Q  + (long)bb*sQb + (long)hh*sQh;
    const float* B = KL + (long)z*sKL;
    const float* T = T2 + (long)z*sT2;
    __shared__ char smem_raw[35840];
    __shared__ float red[64][4];
    uint32_t (*As)[20] = (uint32_t(*)[20])smem_raw;
    uint32_t (*Bs)[20] = (uint32_t(*)[20])(smem_raw + 5120);
    uint32_t (*Pf)[68] = (uint32_t(*)[68])smem_raw;
    uint32_t (*Ts)[72] = (uint32_t(*)[72])(smem_raw + 17408);
    int t = threadIdx.x;
    int lane = t & 31, warp = t >> 5;
    int wm = warp >> 2, wn = warp & 3;
    int r0 = blockIdx.x*64;
    int lrow = t >> 2, lk = (t & 3)*4;
    int g = lane>>2, tq = lane&3;
    float acc[2][8][4];
    #pragma unroll
    for(int i=0;i<2;i++)
        #pragma unroll
        for(int j=0;j<8;j++)
            #pragma unroll
            for(int q=0;q<4;q++) acc[i][j][q]=0.f;
    for(int kt=0; kt<4; kt++){
        __syncthreads();
        *(uint4*)&As[lrow][lk] = cvt4(ldg4(A + (long)(r0+lrow)*ldq + kt*16 + lk));
        #pragma unroll
        for(int i=0;i<4;i++)
            *(uint4*)&Bs[i*64+lrow][lk] = cvt4(ldg4(B + (long)(i*64+lrow)*64 + kt*16 + lk));
        __syncthreads();
        #pragma unroll
        for(int ks=0;ks<2;ks++){
            int cc = ks*8 + tq;
            uint32_t a[2][4], b[8][2];
            int rA = wm*32 + g;
            #pragma unroll
            for(int mt=0;mt<2;mt++){
                a[mt][0]=As[rA+mt*16  ][cc];
                a[mt][1]=As[rA+mt*16+8][cc];
                a[mt][2]=As[rA+mt*16  ][cc+4];
                a[mt][3]=As[rA+mt*16+8][cc+4];
            }
            int rB = wn*64 + g;
            #pragma unroll
            for(int nt=0;nt<8;nt++){
                b[nt][0]=Bs[rB+nt*8][cc];
                b[nt][1]=Bs[rB+nt*8][cc+4];
            }
            #pragma unroll
            for(int mt=0;mt<2;mt++)
                #pragma unroll
                for(int nt=0;nt<8;nt++)
                    mma8(acc[mt][nt], a[mt], b[nt]);
        }
    }
    float pm[2][2];
    #pragma unroll
    for(int mt=0;mt<2;mt++)
        #pragma unroll
        for(int i=0;i<2;i++){
            float m = -1e30f;
            #pragma unroll
            for(int nt=0;nt<8;nt++){
                acc[mt][nt][2*i]   *= alpha;
                acc[mt][nt][2*i+1] *= alpha;
                m = fmaxf(m, fmaxf(acc[mt][nt][2*i], acc[mt][nt][2*i+1]));
            }
            m = fmaxf(m, __shfl_xor_sync(0xffffffffu, m, 1));
            m = fmaxf(m, __shfl_xor_sync(0xffffffffu, m, 2));
            pm[mt][i] = m;
        }
    if(tq==0){
        #pragma unroll
        for(int mt=0;mt<2;mt++)
            #pragma unroll
            for(int i=0;i<2;i++)
                red[wm*32+mt*16+i*8+g][wn] = pm[mt][i];
    }
    __syncthreads();
    float rmax[2][2];
    #pragma unroll
    for(int mt=0;mt<2;mt++)
        #pragma unroll
        for(int i=0;i<2;i++){
            int rid = wm*32+mt*16+i*8+g;
            rmax[mt][i] = fmaxf(fmaxf(red[rid][0],red[rid][1]), fmaxf(red[rid][2],red[rid][3]));
        }
    __syncthreads();
    float ps[2][2];
    #pragma unroll
    for(int mt=0;mt<2;mt++)
        #pragma unroll
        for(int i=0;i<2;i++){
            float s = 0.f;
            #pragma unroll
            for(int nt=0;nt<8;nt++){
                float e0 = __expf(acc[mt][nt][2*i]   - rmax[mt][i]);
                float e1 = __expf(acc[mt][nt][2*i+1] - rmax[mt][i]);
                acc[mt][nt][2*i]   = e0;
                acc[mt][nt][2*i+1] = e1;
                s += e0 + e1;
            }
            s += __shfl_xor_sync(0xffffffffu, s, 1);
            s += __shfl_xor_sync(0xffffffffu, s, 2);
            ps[mt][i] = s;
        }
    if(tq==0){
        #pragma unroll
        for(int mt=0;mt<2;mt++)
            #pragma unroll
            for(int i=0;i<2;i++)
                red[wm*32+mt*16+i*8+g][wn] = ps[mt][i];
    }
    __syncthreads();
    float inv2[2][2];
    #pragma unroll
    for(int mt=0;mt<2;mt++)
        #pragma unroll
        for(int i=0;i<2;i++){
            int rid = wm*32+mt*16+i*8+g;
            inv2[mt][i] = 1.f/(red[rid][0]+red[rid][1]+red[rid][2]+red[rid][3]);
            #pragma unroll
            for(int nt=0;nt<8;nt++){
                acc[mt][nt][2*i]   *= inv2[mt][i];
                acc[mt][nt][2*i+1] *= inv2[mt][i];
            }
        }
    int wm2 = warp >> 1, wn2 = warp & 1;
    float acc2[4][4];
    #pragma unroll
    for(int j=0;j<4;j++)
        #pragma unroll
        for(int q=0;q<4;q++) acc2[j][q]=0.f;
    for(int ch=0; ch<4; ch++){
        __syncthreads();
        if(wn == ch){
            #pragma unroll
            for(int mt=0;mt<2;mt++)
                #pragma unroll
                for(int i=0;i<2;i++){
                    int row_l = wm*32+mt*16+i*8+g;
                    #pragma unroll
                    for(int nt=0;nt<8;nt++){
                        int col_l = nt*8 + 2*tq;
                        Pf[row_l][col_l]   = f2tf(acc[mt][nt][2*i]);
                        Pf[row_l][col_l+1] = f2tf(acc[mt][nt][2*i+1]);
                    }
                }
        }
        {
            int kl_ = t >> 2, cb = (t & 3)*16;
            const float* Tp = T + (long)(64*ch + kl_)*64 + cb;
            #pragma unroll
            for(int j=0;j<4;j++){
                float4 v = ldg4(Tp + j*4);
                Ts[kl_][cb+j*4+0] = f2tf(v.x);
                Ts[kl_][cb+j*4+1] = f2tf(v.y);
                Ts[kl_][cb+j*4+2] = f2tf(v.z);
                Ts[kl_][cb+j*4+3] = f2tf(v.w);
            }
        }
        __syncthreads();
        #pragma unroll
        for(int kk=0;kk<8;kk++){
            int cc = kk*8 + tq;
            uint32_t a[4], b[4][2];
            a[0]=Pf[wm2*16+g  ][cc];
            a[1]=Pf[wm2*16+8+g][cc];
            a[2]=Pf[wm2*16+g  ][cc+4];
            a[3]=Pf[wm2*16+8+g][cc+4];
            #pragma unroll
            for(int nt=0;nt<4;nt++){
                int n = wn2*32 + nt*8 + g;
                b[nt][0]=Ts[cc  ][n];
                b[nt][1]=Ts[cc+4][n];
            }
            #pragma unroll
            for(int nt=0;nt<4;nt++)
                mma8(acc2[nt], a, b[nt]);
        }
    }
    #pragma unroll
    for(int i=0;i<2;i++){
        int gm = r0 + wm2*16 + i*8 + g;
        if(gm < 255) continue;
        float* dst = AC + ((long)bb*4097 + (gm-255))*512 + hh*64;
        #pragma unroll
        for(int nt=0;nt<4;nt++){
            int gn = wn2*32 + nt*8 + 2*tq;
            float2 v; v.x = acc2[nt][2*i]; v.y = acc2[nt][2*i+1];
            *(float2*)(dst + gn) = v;
        }
    }
}

// C = alpha * A @ B  (NN), pinv epilogues (proven).
__global__ void __launch_bounds__(256,2) k_mma_nn(
    const float* __restrict__ A, int lda, long sAb, long sAh,
    const float* __restrict__ B, int ldb, long sBb, long sBh,
    float* __restrict__ C, int ldc, long sCb, long sCh,
    float* __restrict__ D, long sDb, long sDh,
    int M, int N, int K, float alpha, float dconst, int cmode)
{
    int z = blockIdx.z; int hh = z & 7; int bb = z >> 3;
    A += (long)bb*sAb + (long)hh*sAh;
    B += (long)bb*sBb + (long)hh*sBh;
    C += (long)bb*sCb + (long)hh*sCh;
    if(D) D += (long)bb*sDb + (long)hh*sDh;
    __shared__ uint32_t As[128][20];
    __shared__ uint32_t Bs[16][136];
    int t = threadIdx.x;
    int lane = t & 31, warp = t >> 5;
    int wm = warp >> 2, wn = warp & 3;
    int r0 = blockIdx.x*128, c0 = blockIdx.y*128;
    int lrow = t >> 2, lk = (t & 3)*4;
    int bk = t >> 5, bn = (t & 31)*4;
    const float* Ap0 = A + (long)(r0+lrow)*lda + lk;
    const float* Ap1 = A + (long)(r0+lrow+64)*lda + lk;
    const float* Bq0 = B + (long)bk*ldb + c0 + bn;
    const float* Bq1 = B + (long)(bk+8)*ldb + c0 + bn;
    bool mA0 = (r0+lrow)<M, mA1 = (r0+lrow+64)<M;
    bool mBn = (c0+bn)<N;
    const float4 z4 = make_float4(0.f,0.f,0.f,0.f);
    float4 pa0 = mA0?ldg4(Ap0):z4, pa1 = mA1?ldg4(Ap1):z4;
    float4 pb0 = mBn?ldg4(Bq0):z4, pb1 = mBn?ldg4(Bq1):z4;
    *(uint4*)&As[lrow][lk]    = cvt4(pa0);
    *(uint4*)&As[lrow+64][lk] = cvt4(pa1);
    *(uint4*)&Bs[bk][bn]      = cvt4(pb0);
    *(uint4*)&Bs[bk+8][bn]    = cvt4(pb1);
    float accr[4][4][4];
    #pragma unroll
    for(int i=0;i<4;i++)
        #pragma unroll
        for(int j=0;j<4;j++)
            #pragma unroll
            for(int q=0;q<4;q++) accr[i][j][q]=0.f;
    int nk = K >> 4;
    for(int kt=0; kt<nk; kt++){
        __syncthreads();
        if(kt+1<nk){
            long o = (long)(kt+1)*16;
            pa0 = mA0?ldg4(Ap0+o):z4; pa1 = mA1?ldg4(Ap1+o):z4;
            pb0 = mBn?ldg4(Bq0+o*ldb):z4; pb1 = mBn?ldg4(Bq1+o*ldb):z4;
        }
        #pragma unroll
        for(int ks=0;ks<2;ks++){
            int cc = ks*8 + (lane&3);
            uint32_t a[4][4], b[4][2];
            int rA = wm*64 + (lane>>2);
            #pragma unroll
            for(int mt=0;mt<4;mt++){
                a[mt][0]=As[rA+mt*16  ][cc];
                a[mt][1]=As[rA+mt*16+8][cc];
                a[mt][2]=As[rA+mt*16  ][cc+4];
                a[mt][3]=As[rA+mt*16+8][cc+4];
            }
            int nB = wn*32 + (lane>>2);
            #pragma unroll
            for(int nt=0;nt<4;nt++){
                b[nt][0]=Bs[cc  ][nB+nt*8];
                b[nt][1]=Bs[cc+4][nB+nt*8];
            }
            #pragma unroll
            for(int mt=0;mt<4;mt++)
                #pragma unroll
                for(int nt=0;nt<4;nt++)
                    mma8(accr[mt][nt], a[mt], b[nt]);
        }
        __syncthreads();
        if(kt+1<nk){
            *(uint4*)&As[lrow][lk]    = cvt4(pa0);
            *(uint4*)&As[lrow+64][lk] = cvt4(pa1);
            *(uint4*)&Bs[bk][bn]      = cvt4(pb0);
            *(uint4*)&Bs[bk+8][bn]    = cvt4(pb1);
        }
    }
    #pragma unroll
    for(int mt=0;mt<4;mt++)
    #pragma unroll
    for(int i=0;i<2;i++){
        int gm = r0 + wm*64 + mt*16 + i*8 + (lane>>2);
        if(gm>=M) continue;
        #pragma unroll
        for(int nt=0;nt<4;nt++){
            int gn = c0 + wn*32 + nt*8 + 2*(lane&3);
            float2 v;
            v.x = alpha*accr[mt][nt][2*i];
            v.y = alpha*accr[mt][nt][2*i+1];
            long o = (long)gm*ldc + gn;
            if(D){
                float2 dv;
                dv.x = ((gm==gn  )?dconst:0.f) - v.x;
                dv.y = ((gm==gn+1)?dconst:0.f) - v.y;
                *(float2*)(D+o) = dv;
            }
            if(cmode){
                v.x = ((gm==gn  )?dconst:0.f) - v.x;
                v.y = ((gm==gn+1)?dconst:0.f) - v.y;
            }
            *(float2*)(C+o) = v;
        }
    }
}

// C = alpha * A @ B (NN, TF32), N=64. 128x64 block, 8 warps of 32x32.
__global__ void __launch_bounds__(256,2) k_mma_nn64(
    const float* __restrict__ A, int lda, long sAb, long sAh,
    const float* __restrict__ B, int ldb, long sBb, long sBh,
    float* __restrict__ C, int ldc, long sCb, long sCh,
    int M, int K, float alpha, int rowLo)
{
    int z = blockIdx.z; int hh = z & 7; int bb = z >> 3;
    A += (long)bb*sAb + (long)hh*sAh;
    B += (long)bb*sBb + (long)hh*sBh;
    C += (long)bb*sCb + (long)hh*sCh;
    __shared__ uint32_t Af[2][2048];
    __shared__ uint32_t Bf[2][1024];
    int t = threadIdx.x, lane = t & 31, warp = t >> 5;
    int wm = warp >> 1, wn = warp & 1;
    int r0 = blockIdx.x*128;
    int alr = t >> 1, alk = (t & 1)*8;
    const float* Ap = A + (long)(r0+alr)*lda + alk;
    bool mA = (r0+alr) < M;
    int bk = t >> 4, bn = (t & 15)*4;
    const float* Bp = B + (long)bk*ldb + bn;
    const float4 z4 = make_float4(0.f,0.f,0.f,0.f);
    float4 a0,a1,b0;
    a0 = mA?ldg4(Ap):z4; a1 = mA?ldg4(Ap+4):z4;
    b0 = ldg4(Bp);
    {
        scatA(Af[0], alr, alk+0, f2tf(a0.x)); scatA(Af[0], alr, alk+1, f2tf(a0.y));
        scatA(Af[0], alr, alk+2, f2tf(a0.z)); scatA(Af[0], alr, alk+3, f2tf(a0.w));
        scatA(Af[0], alr, alk+4, f2tf(a1.x)); scatA(Af[0], alr, alk+5, f2tf(a1.y));
        scatA(Af[0], alr, alk+6, f2tf(a1.z)); scatA(Af[0], alr, alk+7, f2tf(a1.w));
        scatB8(Bf[0], bn+0, bk, f2tf(b0.x)); scatB8(Bf[0], bn+1, bk, f2tf(b0.y));
        scatB8(Bf[0], bn+2, bk, f2tf(b0.z)); scatB8(Bf[0], bn+3, bk, f2tf(b0.w));
    }
    __syncthreads();
    float acc[2][4][4];
    #pragma unroll
    for(int i=0;i<2;i++)
        #pragma unroll
        for(int j=0;j<4;j++)
            #pragma unroll
            for(int q=0;q<4;q++) acc[i][j][q]=0.f;
    int nk = K >> 4;
    for(int kt=0; kt<nk; kt++){
        if(kt+1<nk){
            long o = (long)(kt+1)*16;
            a0 = mA?ldg4(Ap+o):z4; a1 = mA?ldg4(Ap+o+4):z4;
            b0 = ldg4(Bp + o*ldb);
        }
        int buf = kt & 1;
        #pragma unroll
        for(int ks=0;ks<2;ks++){
            uint32_t af[2][4], bfr[4][2];
            #pragma unroll
            for(int mt=0;mt<2;mt++)
                *(uint4*)af[mt] = *(const uint4*)&Af[buf][(((ks<<3)+(wm<<1)+mt)<<7) + (lane<<2)];
            #pragma unroll
            for(int nt=0;nt<4;nt++)
                *(uint2*)bfr[nt] = *(const uint2*)&Bf[buf][(((ks<<3)+(wn<<2)+nt)<<6) + (lane<<1)];
            #pragma unroll
            for(int mt=0;mt<2;mt++)
                #pragma unroll
                for(int nt=0;nt<4;nt++)
                    mma8(acc[mt][nt], af[mt], bfr[nt]);
        }
        if(kt+1<nk){
            int s = (kt+1) & 1;
            scatA(Af[s], alr, alk+0, f2tf(a0.x)); scatA(Af[s], alr, alk+1, f2tf(a0.y));
            scatA(Af[s], alr, alk+2, f2tf(a0.z)); scatA(Af[s], alr, alk+3, f2tf(a0.w));
            scatA(Af[s], alr, alk+4, f2tf(a1.x)); scatA(Af[s], alr, alk+5, f2tf(a1.y));
            scatA(Af[s], alr, alk+6, f2tf(a1.z)); scatA(Af[s], alr, alk+7, f2tf(a1.w));
            scatB8(Bf[s], bn+0, bk, f2tf(b0.x)); scatB8(Bf[s], bn+1, bk, f2tf(b0.y));
            scatB8(Bf[s], bn+2, bk, f2tf(b0.z)); scatB8(Bf[s], bn+3, bk, f2tf(b0.w));
            __syncthreads();
        }
    }
    int g = lane >> 2, tq = lane & 3;
    #pragma unroll
    for(int mt=0;mt<2;mt++)
    #pragma unroll
    for(int i=0;i<2;i++){
        int gm = r0 + wm*32 + mt*16 + i*8 + g;
        if(gm >= M || gm < rowLo) continue;
        #pragma unroll
        for(int nt=0;nt<4;nt++){
            int gn = wn*32 + nt*8 + 2*tq;
            float2 v;
            v.x = alpha*acc[mt][nt][2*i];
            v.y = alpha*acc[mt][nt][2*i+1];
            *(float2*)(C + (long)gm*ldc + gn) = v;
        }
    }
}

// ---------------- landmarks (mean over 17 tokens), q scaled by 1/8 ----------------
__global__ void k_landmarks(const float* __restrict__ qkv, float* __restrict__ ql, float* __restrict__ kl){
    int idx = blockIdx.x;
    int mi = idx % 256; int hh = (idx/256) & 7; int b = idx / (256*8);
    int dh = threadIdx.x;
    float sq=0.f, sk=0.f;
    for(int j=0;j<LSUB;j++){
        long tok = (long)mi*LSUB + j;
        const float* base = qkv + ((long)b*4352 + tok)*1536 + hh*64 + dh;
        sq += base[0];
        sk += base[512];
    }
    long o = (long)idx*64 + dh;
    ql[o] = sq * (0.125f/LSUB);
    kl[o] = sk * (1.0f/LSUB);
}

// ---------------- pinv scalar reductions ----------------
__global__ void k_scal_init(){ if(threadIdx.x < 2) g_scal[threadIdx.x] = 0.f; }

__global__ void k_rowsum_max(const float* __restrict__ X){
    long row = blockIdx.x;
    const float* x = X + row*256;
    int t = threadIdx.x;
    __shared__ float red[256];
    red[t] = fabsf(x[t]); __syncthreads();
    for(int k=128;k;k>>=1){ if(t<k) red[t]+=red[t+k]; __syncthreads(); }
    if(t==0) atomicMax((int*)&g_scal[0], __float_as_int(red[0]));
}

__global__ void k_colsum_max(const float* __restrict__ X){
    int b = blockIdx.x; int j = threadIdx.x;
    const float* x = X + (long)b*65536;
    float s = 0.f;
    for(int i=0;i<256;i++) s += fabsf(x[i*256+j]);
    __shared__ float red[256];
    red[j]=s; __syncthreads();
    for(int k=128;k;k>>=1){ if(j<k) red[j]=fmaxf(red[j],red[j+k]); __syncthreads(); }
    if(j==0) atomicMax((int*)&g_scal[1], __float_as_int(red[0]));
}

__global__ void k_tr_scale(const float* __restrict__ X, float* __restrict__ Z){
    long idx = (long)blockIdx.x*256 + threadIdx.x;
    if(idx >= 64L*65536) return;
    float inv = 1.f/(g_scal[0]*g_scal[1]);
    int j = (int)(idx & 255); int i = (int)((idx>>8) & 255); long b = idx >> 16;
    Z[idx] = X[(b<<16) + ((long)j<<8) + i] * inv;
}

// ---------------- residual depthwise conv (k=33), writes token-major into ac ----------------
__global__ void k_resconv2(const float* __restrict__ qkv, const float* __restrict__ w,
                           float* __restrict__ ac){
    int bh = blockIdx.y; int hh = bh & 7; int b = bh >> 3;
    int t0 = blockIdx.x*64;
    __shared__ float sv[96][65];
    __shared__ float sw[33];
    int t = threadIdx.x;
    if(t < 33) sw[t] = w[hh*33 + t];
    const float* vb = qkv + ((long)b*4352)*1536 + 1024 + hh*64;
    for(int i=t;i<96*64;i+=256){
        int tok = t0 - 16 + (i>>6); int dh = i&63;
        sv[i>>6][dh] = (tok>=0 && tok<4352) ? vb[(long)tok*1536 + dh] : 0.f;
    }
    __syncthreads();
    for(int i=t;i<64*64;i+=256){
        int lt = i>>6, dh = i&63;
        int tok = t0 + lt;
        if(tok < 255) continue;
        float s = 0.f;
        #pragma unroll
        for(int j=0;j<33;j++) s = fmaf(sw[j], sv[lt+j][dh], s);
        ac[((long)b*4097 + (tok-255))*512 + hh*64 + dh] += s;
    }
}

// ---------------- transposes token<->planar ----------------
__global__ void k_h2planar(const float* __restrict__ h, float* __restrict__ cnn){
    __shared__ float tile[32][33];
    int b = blockIdx.z;
    int c0 = blockIdx.x*32, p0 = blockIdx.y*32;
    int tx = threadIdx.x, ty = threadIdx.y;
    for(int i=ty;i<32;i+=8)
        tile[i][tx] = h[((long)b*4097 + 1 + p0+i)*512 + c0+tx];
    __syncthreads();
    for(int i=ty;i<32;i+=8)
        cnn[((long)b*512 + c0+i)*4096 + p0+tx] = tile[tx][i];
}

__global__ void k_planar2h(const float* __restrict__ yp, float* __restrict__ h2){
    __shared__ float tile[32][33];
    int b = blockIdx.z;
    int c0 = blockIdx.x*32, p0 = blockIdx.y*32;
    int tx = threadIdx.x, ty = threadIdx.y;
    for(int i=ty;i<32;i+=8)
        tile[i][tx] = yp[((long)b*512 + c0+i)*4096 + p0+tx];
    __syncthreads();
    for(int i=ty;i<32;i+=8)
        h2[((long)b*4097 + 1 + p0+i)*512 + c0+tx] = tile[tx][i];
}

__global__ void k_cls_copy(const float* __restrict__ h, float* __restrict__ h2){
    int idx = blockIdx.x*256 + threadIdx.x;
    if(idx >= 8*512) return;
    int b = idx >> 9, c = idx & 511;
    h2[(long)b*4097*512 + c] = h[(long)b*4097*512 + c];
}

// ---------------- fused 7x7 + 5x5 + 3x3 depthwise conv, planar ----------------
__global__ void k_dwconv(const float* __restrict__ cnn,
                         const float* __restrict__ w7, const float* __restrict__ b7,
                         const float* __restrict__ w5, const float* __restrict__ b5,
                         const float* __restrict__ w3, const float* __restrict__ b3,
                         float* __restrict__ yp){
    int bc = blockIdx.x; int c = bc & 511;
    __shared__ float pl[64][65];
    __shared__ float ww[84];
    const float* in = cnn + (long)bc*4096;
    int t = threadIdx.x;
    for(int i=t;i<4096;i+=256) pl[i>>6][i&63] = in[i];
    if(t < 49)      ww[t]      = w7[c*49 + t];
    else if(t < 74) ww[t]      = w5[c*25 + t - 49];
    else if(t < 83) ww[t]      = w3[c*9  + t - 74];
    __syncthreads();
    float bias = b7[c] + b5[c] + b3[c];
    for(int i=t;i<4096;i+=256){
        int y = i >> 6, x = i & 63;
        float s = pl[y][x] + bias;
        #pragma unroll
        for(int ky=0;ky<7;ky++){ int yy=y+ky-3; if((unsigned)yy>=64u) continue;
            #pragma unroll
            for(int kx=0;kx<7;kx++){ int xx=x+kx-3; if((unsigned)xx>=64u) continue;
                s = fmaf(ww[ky*7+kx], pl[yy][xx], s); } }
        #pragma unroll
        for(int ky=0;ky<5;ky++){ int yy=y+ky-2; if((unsigned)yy>=64u) continue;
            #pragma unroll
            for(int kx=0;kx<5;kx++){ int xx=x+kx-2; if((unsigned)xx>=64u) continue;
                s = fmaf(ww[49+ky*5+kx], pl[yy][xx], s); } }
        #pragma unroll
        for(int ky=0;ky<3;ky++){ int yy=y+ky-1; if((unsigned)yy>=64u) continue;
            #pragma unroll
            for(int kx=0;kx<3;kx++){ int xx=x+kx-1; if((unsigned)xx>=64u) continue;
                s = fmaf(ww[74+ky*3+kx], pl[yy][xx], s); } }
        yp[(long)bc*4096 + i] = s;
    }
}

// ---------------- final output: (cls[8,512], feat[8,4096,512]) ----------------
__global__ void k_writeout(const float* __restrict__ h2, float* __restrict__ out){
    long idx = (long)blockIdx.x*256 + threadIdx.x;
    if(idx >= 8L*512 + 8L*4096*512) return;
    if(idx < 8*512){
        int b = (int)(idx >> 9), c = (int)(idx & 511);
        out[idx] = h2[((long)b*4097)*512 + c];
    } else {
        long r = idx - 4096;
        int c = (int)(r & 511); long q = r >> 9; int t = (int)(q % 4096); int b = (int)(q / 4096);
        out[idx] = h2[((long)b*4097 + 1 + t)*512 + c];
    }
}

// ================= host side =================
struct Ptrs {
    float *h,*h2,*xp,*qkv,*ql,*kl,*a2,*zA,*zB,*xz,*t1,*t2,*a3v,*tmp2,*ac,*cnn,*yp;
};

static void get_ptrs(Ptrs& p){
    cudaGetSymbolAddress((void**)&p.h,    g_h);
    cudaGetSymbolAddress((void**)&p.h2,   g_h2);
    cudaGetSymbolAddress((void**)&p.xp,   g_xp);
    cudaGetSymbolAddress((void**)&p.qkv,  g_qkv);
    cudaGetSymbolAddress((void**)&p.ql,   g_ql);
    cudaGetSymbolAddress((void**)&p.kl,   g_kl);
    cudaGetSymbolAddress((void**)&p.a2,   g_a2);
    cudaGetSymbolAddress((void**)&p.zA,   g_zA);
    cudaGetSymbolAddress((void**)&p.zB,   g_zB);
    cudaGetSymbolAddress((void**)&p.xz,   g_xz);
    cudaGetSymbolAddress((void**)&p.t1,   g_t1);
    cudaGetSymbolAddress((void**)&p.t2,   g_t2);
    cudaGetSymbolAddress((void**)&p.a3v,  g_a3v);
    cudaGetSymbolAddress((void**)&p.tmp2, g_tmp2);
    cudaGetSymbolAddress((void**)&p.ac,   g_ac);
    cudaGetSymbolAddress((void**)&p.cnn,  g_cnn);
    cudaGetSymbolAddress((void**)&p.yp,   g_yp);
}

static void attention(Ptrs& p, float* hbuf,
                      const float* lng, const float* lnb,
                      const float* qkvw, const float* outw, const float* outb,
                      const float* resw)
{
    const long SQKV_B = 4352L*1536;
    const long SQL    = 256L*64;
    const long SA2    = 65536L;
    const long SV64   = 256L*64;

    k_zero_pad<<<4080, 256>>>(p.xp);
    k_ln<<<8*4097, 256>>>(hbuf, lng, lnb, p.xp);

    // qkv = xp @ qkv_w^T   (34816 x 1536 x 512)
    k_mma_nt<<<dim3(272,12,1), 256>>>(p.xp, 512, 0,0, qkvw, 512, 0,0,
                                      p.qkv, 1536, 0,0, 34816, 1536, 512, 1.f, nullptr, 0);

    k_landmarks<<<64*256, 64>>>(p.qkv, p.ql, p.kl);

    // a2 = softmax(q_l @ k_l^T) fused : (256 x 256)
    k_simsm<<<dim3(4,1,64), 256>>>(p.ql, 64, 8*SQL, SQL,
                                   p.kl, 64, 8*SQL, SQL,
                                   p.a2, 256, 8*SA2, SA2, 1.f);

    // a3v = softmax(q_l @ k^T) @ v, flash-fused (no sim3 materialization)
    k_flash3<<<dim3(4,1,64), 256, 55040>>>(p.ql, SQL, p.qkv, SQKV_B, p.a3v, SV64);

    // ---- Moore-Penrose pinv of a2 (6 iterations, idm fused in epilogues) ----
    k_scal_init<<<1, 32>>>();
    k_rowsum_max<<<64*256, 256>>>(p.a2);
    k_colsum_max<<<64, 256>>>(p.a2);
    k_tr_scale<<<16384, 256>>>(p.a2, p.zA);

    float* zc = p.zA; float* zn = p.zB;
    for(int it=0; it<6; it++){
        k_mma_nn<<<dim3(2,2,64), 256>>>(p.a2, 256, 8*SA2, SA2, zc, 256, 8*SA2, SA2,
                                        p.xz, 256, 8*SA2, SA2, p.t1, 8*SA2, SA2,
                                        256,256,256, 1.f, 7.f, 0);
        k_mma_nn<<<dim3(2,2,64), 256>>>(p.xz, 256, 8*SA2, SA2, p.t1, 256, 8*SA2, SA2,
                                        p.t2, 256, 8*SA2, SA2, nullptr, 0,0,
                                        256,256,256, 1.f, 15.f, 1);
        k_mma_nn<<<dim3(2,2,64), 256>>>(p.xz, 256, 8*SA2, SA2, p.t2, 256, 8*SA2, SA2,
                                        p.t1, 256, 8*SA2, SA2, nullptr, 0,0,
                                        256,256,256, 1.f, 13.f, 1);
        k_mma_nn<<<dim3(2,2,64), 256>>>(zc, 256, 8*SA2, SA2, p.t1, 256, 8*SA2, SA2,
                                        zn, 256, 8*SA2, SA2, nullptr, 0,0,
                                        256,256,256, 0.25f, 0.f, 0);
        float* tmp = zc; zc = zn; zn = tmp;
    }

    // tmp2 = z @ a3v : (256 x 64 x 256)   [TF32]
    k_mma_nn64<<<dim3(2,1,64), 256>>>(zc, 256, 8*SA2, SA2, p.a3v, 64, 8*SV64, SV64,
                                      p.tmp2, 64, 8*SV64, SV64, 256, 256, 1.f, 0);

    // ac = softmax(q*scale @ kl^T) @ tmp2, fused, direct token-major
    k_attnout<<<dim3(68,1,64), 256>>>(p.qkv, 1536, SQKV_B, 64,
                                      p.kl, SQL, p.tmp2, SV64,
                                      p.ac, 0.125f);

    // residual depthwise conv (k=33 along sequence) added directly into ac
    k_resconv2<<<dim3(68,64), 256>>>(p.qkv, resw, p.ac);

    // hbuf += ac @ out_w^T + out_b
    k_mma_nt<<<dim3(257,4,1), 256>>>(p.ac, 512, 0,0, outw, 512, 0,0,
                                     hbuf, 512, 0,0, 32776, 512, 512, 1.f, outb, 1);
}

extern "C" void kernel_launch(void* const* d_in, const int* in_sizes, int n_in,
                              void* d_out, int out_size)
{
    const float* features = (const float*)d_in[0];
    const float* cls_tok  = (const float*)d_in[1];
    const float* ln1_g    = (const float*)d_in[2];
    const float* ln1_b    = (const float*)d_in[3];
    const float* qkv1_w   = (const float*)d_in[4];
    const float* out1_w   = (const float*)d_in[5];
    const float* out1_b   = (const float*)d_in[6];
    const float* res1_w   = (const float*)d_in[7];
    const float* p7_w     = (const float*)d_in[8];
    const float* p7_b     = (const float*)d_in[9];
    const float* p5_w     = (const float*)d_in[10];
    const float* p5_b     = (const float*)d_in[11];
    const float* p3_w     = (const float*)d_in[12];
    const float* p3_b     = (const float*)d_in[13];
    const float* ln2_g    = (const float*)d_in[14];
    const float* ln2_b    = (const float*)d_in[15];
    const float* qkv2_w   = (const float*)d_in[16];
    const float* out2_w   = (const float*)d_in[17];
    const float* out2_b   = (const float*)d_in[18];
    const float* res2_w   = (const float*)d_in[19];
    float* out = (float*)d_out;

    cudaFuncSetAttribute(k_flash3, cudaFuncAttributeMaxDynamicSharedMemorySize, 55040);

    Ptrs p;
    get_ptrs(p);

    k_build_h<<<65552, 256>>>(features, cls_tok);

    attention(p, p.h, ln1_g, ln1_b, qkv1_w, out1_w, out1_b, res1_w);

    k_h2planar<<<dim3(16,128,8), dim3(32,8)>>>(p.h, p.cnn);
    k_dwconv<<<4096, 256>>>(p.cnn, p7_w, p7_b, p5_w, p5_b, p3_w, p3_b, p.yp);
    k_planar2h<<<dim3(16,128,8), dim3(32,8)>>>(p.yp, p.h2);
    k_cls_copy<<<16, 256>>>(p.h, p.h2);

    attention(p, p.h2, ln2_g, ln2_b, qkv2_w, out2_w, out2_b, res2_w);

    k_writeout<<<65552, 256>>>(p.h2, out);
}

// round 13
// speedup vs baseline: 1.5026x; 1.0101x over previous
#include <cuda_runtime.h>
#include <math.h>
#include <stdint.h>

// ---------------- problem constants ----------------
// B=8, C=512, HEADS=8, DH=64, tokens=4097 (cls+4096), pad=255 -> N=4352
// landmarks m=256, l=17, pinv iters=6, res kernel 33  (build r13: dbuf GEMMs, single zero_pad)
#define LSUB 17

// ---------------- device scratch ----------------
__device__ float g_h   [8L*4097*512];
__device__ float g_h2  [8L*4097*512];
__device__ float g_xp  [8L*4352*512];
__device__ float g_qkv [8L*4352*1536];
__device__ float g_ql  [64L*256*64];
__device__ float g_kl  [64L*256*64];
__device__ float g_a2  [64L*256*256];
__device__ float g_zA  [64L*256*256];
__device__ float g_zB  [64L*256*256];
__device__ float g_xz  [64L*256*256];
__device__ float g_t1  [64L*256*256];
__device__ float g_t2  [64L*256*256];
__device__ float g_a3v [64L*256*64];
__device__ float g_tmp2[64L*256*64];
__device__ float g_ac  [8L*4097*512];
__device__ float g_cnn [8L*512*4096];
__device__ float g_yp  [8L*512*4096];
__device__ float g_scal[2];

__device__ __forceinline__ float4 ldg4(const float* p){ return *(const float4*)p; }

// ---------------- tf32 mma helpers ----------------
__device__ __forceinline__ uint32_t f2tf(float x){
    uint32_t u; asm("cvt.rna.tf32.f32 %0, %1;" : "=r"(u) : "f"(x)); return u;
}
__device__ __forceinline__ uint4 cvt4(float4 v){
    uint4 u; u.x=f2tf(v.x); u.y=f2tf(v.y); u.z=f2tf(v.z); u.w=f2tf(v.w); return u;
}
__device__ __forceinline__ void mma8(float* d, const uint32_t* a, const uint32_t* b){
    asm("mma.sync.aligned.m16n8k8.row.col.f32.tf32.tf32.f32 "
        "{%0,%1,%2,%3}, {%4,%5,%6,%7}, {%8,%9}, {%0,%1,%2,%3};"
        : "+f"(d[0]),"+f"(d[1]),"+f"(d[2]),"+f"(d[3])
        : "r"(a[0]),"r"(a[1]),"r"(a[2]),"r"(a[3]), "r"(b[0]),"r"(b[1]));
}

// Fragment-major scatter (for k_mma_nn64): element (row,k) of 128x16 A tile
__device__ __forceinline__ void scatA(uint32_t* Af, int row, int k, uint32_t v){
    int ks=k>>3, kc=k&7;
    Af[(((ks<<3)+(row>>4))<<7) + ((((row&7)<<2)+(kc&3))<<2) + ((row>>3)&1) + ((kc>>2)<<1)] = v;
}
// B tile with 8 n-tiles (64 cols)
__device__ __forceinline__ void scatB8(uint32_t* Bf, int n, int k, uint32_t v){
    int ks=k>>3, kc=k&7;
    Bf[(((ks<<3)+(n>>3))<<6) + ((((n&7)<<2)+(kc&3))<<1) + (kc>>2)] = v;
}

// ---------------- small kernels ----------------
__global__ void k_build_h(const float* __restrict__ feat, const float* __restrict__ cls){
    long idx = (long)blockIdx.x*256 + threadIdx.x;
    if(idx >= 8L*4097*512) return;
    int c = idx & 511; long r = idx >> 9; int t = (int)(r % 4097); int b = (int)(r / 4097);
    g_h[idx] = (t==0) ? cls[c] : feat[((long)b*4096 + (t-1))*512 + c];
}

__global__ void k_zero_pad(float* __restrict__ xp){
    long idx = (long)blockIdx.x*256 + threadIdx.x;
    if(idx >= 8L*255*512) return;
    int c = idx & 511; long r = idx >> 9; int t = (int)(r % 255); int b = (int)(r / 255);
    xp[((long)b*4352 + t)*512 + c] = 0.f;
}

__global__ void k_ln(const float* __restrict__ h, const float* __restrict__ g,
                     const float* __restrict__ be, float* __restrict__ xp){
    long r = blockIdx.x;
    int b = (int)(r / 4097); int t = (int)(r % 4097);
    const float* x = h + r*512;
    float* y = xp + ((long)b*4352 + 255 + t)*512;
    int tid = threadIdx.x;
    __shared__ float red[256];
    float s = 0.f;
    for(int i=tid;i<512;i+=256) s += x[i];
    red[tid]=s; __syncthreads();
    for(int k=128;k;k>>=1){ if(tid<k) red[tid]+=red[tid+k]; __syncthreads(); }
    float mean = red[0] * (1.f/512.f); __syncthreads();
    float v = 0.f;
    for(int i=tid;i<512;i+=256){ float d=x[i]-mean; v += d*d; }
    red[tid]=v; __syncthreads();
    for(int k=128;k;k>>=1){ if(tid<k) red[tid]+=red[tid+k]; __syncthreads(); }
    float rstd = rsqrtf(red[0]*(1.f/512.f) + 1e-5f);
    for(int i=tid;i<512;i+=256) y[i] = (x[i]-mean)*rstd*g[i] + be[i];
}

// =====================================================================
// TF32 tensor-core GEMMs: 128x128 block, 8 warps of 64x32, BK=16,
// 2-stage smem double buffer (one sync per ktile)
// =====================================================================

// C = alpha * A @ B^T (+bias)(+C)   A:(M,K) lda, B:(N,K) ldb   batched (b,h)
__global__ void __launch_bounds__(256,2) k_mma_nt(
    const float* __restrict__ A, int lda, long sAb, long sAh,
    const float* __restrict__ B, int ldb, long sBb, long sBh,
    float* __restrict__ C, int ldc, long sCb, long sCh,
    int M, int N, int K, float alpha, const float* __restrict__ bias, int acc)
{
    int z = blockIdx.z; int hh = z & 7; int bb = z >> 3;
    A += (long)bb*sAb + (long)hh*sAh;
    B += (long)bb*sBb + (long)hh*sBh;
    C += (long)bb*sCb + (long)hh*sCh;
    __shared__ uint32_t As[2][128][20];
    __shared__ uint32_t Bs[2][128][20];
    int t = threadIdx.x;
    int lane = t & 31, warp = t >> 5;
    int wm = warp >> 2, wn = warp & 3;
    int r0 = blockIdx.x*128, c0 = blockIdx.y*128;
    int lrow = t >> 2, lk = (t & 3)*4;
    const float* Ap0 = A + (long)(r0+lrow)*lda + lk;
    const float* Ap1 = A + (long)(r0+lrow+64)*lda + lk;
    const float* Bp0 = B + (long)(c0+lrow)*ldb + lk;
    const float* Bp1 = B + (long)(c0+lrow+64)*ldb + lk;
    bool mA0 = (r0+lrow)<M, mA1 = (r0+lrow+64)<M;
    bool mB0 = (c0+lrow)<N, mB1 = (c0+lrow+64)<N;
    const float4 z4 = make_float4(0.f,0.f,0.f,0.f);
    float4 pa0 = mA0?ldg4(Ap0):z4, pa1 = mA1?ldg4(Ap1):z4;
    float4 pb0 = mB0?ldg4(Bp0):z4, pb1 = mB1?ldg4(Bp1):z4;
    *(uint4*)&As[0][lrow][lk]    = cvt4(pa0);
    *(uint4*)&As[0][lrow+64][lk] = cvt4(pa1);
    *(uint4*)&Bs[0][lrow][lk]    = cvt4(pb0);
    *(uint4*)&Bs[0][lrow+64][lk] = cvt4(pb1);
    __syncthreads();
    float accr[4][4][4];
    #pragma unroll
    for(int i=0;i<4;i++)
        #pragma unroll
        for(int j=0;j<4;j++)
            #pragma unroll
            for(int q=0;q<4;q++) accr[i][j][q]=0.f;
    int nk = K >> 4;
    for(int kt=0; kt<nk; kt++){
        int buf = kt & 1;
        if(kt+1<nk){
            int o = (kt+1)*16;
            pa0 = mA0?ldg4(Ap0+o):z4; pa1 = mA1?ldg4(Ap1+o):z4;
            pb0 = mB0?ldg4(Bp0+o):z4; pb1 = mB1?ldg4(Bp1+o):z4;
        }
        #pragma unroll
        for(int ks=0;ks<2;ks++){
            int cc = ks*8 + (lane&3);
            uint32_t a[4][4], b[4][2];
            int rA = wm*64 + (lane>>2);
            #pragma unroll
            for(int mt=0;mt<4;mt++){
                a[mt][0]=As[buf][rA+mt*16  ][cc];
                a[mt][1]=As[buf][rA+mt*16+8][cc];
                a[mt][2]=As[buf][rA+mt*16  ][cc+4];
                a[mt][3]=As[buf][rA+mt*16+8][cc+4];
            }
            int rB = wn*32 + (lane>>2);
            #pragma unroll
            for(int nt=0;nt<4;nt++){
                b[nt][0]=Bs[buf][rB+nt*8][cc];
                b[nt][1]=Bs[buf][rB+nt*8][cc+4];
            }
            #pragma unroll
            for(int mt=0;mt<4;mt++)
                #pragma unroll
                for(int nt=0;nt<4;nt++)
                    mma8(accr[mt][nt], a[mt], b[nt]);
        }
        if(kt+1<nk){
            int s = (kt+1) & 1;
            *(uint4*)&As[s][lrow][lk]    = cvt4(pa0);
            *(uint4*)&As[s][lrow+64][lk] = cvt4(pa1);
            *(uint4*)&Bs[s][lrow][lk]    = cvt4(pb0);
            *(uint4*)&Bs[s][lrow+64][lk] = cvt4(pb1);
            __syncthreads();
        }
    }
    #pragma unroll
    for(int mt=0;mt<4;mt++)
    #pragma unroll
    for(int i=0;i<2;i++){
        int gm = r0 + wm*64 + mt*16 + i*8 + (lane>>2);
        if(gm>=M) continue;
        #pragma unroll
        for(int nt=0;nt<4;nt++){
            int gn = c0 + wn*32 + nt*8 + 2*(lane&3);
            float2 v;
            v.x = alpha*accr[mt][nt][2*i];
            v.y = alpha*accr[mt][nt][2*i+1];
            if(bias){ v.x += bias[gn]; v.y += bias[gn+1]; }
            float* cp = C + (long)gm*ldc + gn;
            if(acc){ v.x += cp[0]; v.y += cp[1]; }
            *(float2*)cp = v;
        }
    }
}

// Fused GEMM+softmax: C = softmax_row(alpha * A @ B^T), K=64, N=256.
__global__ void __launch_bounds__(256,2) k_simsm(
    const float* __restrict__ A, int lda, long sAb, long sAh,
    const float* __restrict__ B, int ldb, long sBb, long sBh,
    float* __restrict__ C, int ldc, long sCb, long sCh,
    float alpha)
{
    int z = blockIdx.z; int hh = z & 7; int bb = z >> 3;
    A += (long)bb*sAb + (long)hh*sAh;
    B += (long)bb*sBb + (long)hh*sBh;
    C += (long)bb*sCb + (long)hh*sCh;
    __shared__ uint32_t As[64][20];
    __shared__ uint32_t Bs[256][20];
    __shared__ float red[64][4];
    int t = threadIdx.x;
    int lane = t & 31, warp = t >> 5;
    int wm = warp >> 2, wn = warp & 3;
    int r0 = blockIdx.x*64;
    int lrow = t >> 2, lk = (t & 3)*4;
    float acc[2][8][4];
    #pragma unroll
    for(int i=0;i<2;i++)
        #pragma unroll
        for(int j=0;j<8;j++)
            #pragma unroll
            for(int q=0;q<4;q++) acc[i][j][q]=0.f;
    for(int kt=0; kt<4; kt++){
        __syncthreads();
        *(uint4*)&As[lrow][lk] = cvt4(ldg4(A + (long)(r0+lrow)*lda + kt*16 + lk));
        #pragma unroll
        for(int i=0;i<4;i++)
            *(uint4*)&Bs[i*64+lrow][lk] = cvt4(ldg4(B + (long)(i*64+lrow)*ldb + kt*16 + lk));
        __syncthreads();
        #pragma unroll
        for(int ks=0;ks<2;ks++){
            int cc = ks*8 + (lane&3);
            uint32_t a[2][4], b[8][2];
            int rA = wm*32 + (lane>>2);
            #pragma unroll
            for(int mt=0;mt<2;mt++){
                a[mt][0]=As[rA+mt*16  ][cc];
                a[mt][1]=As[rA+mt*16+8][cc];
                a[mt][2]=As[rA+mt*16  ][cc+4];
                a[mt][3]=As[rA+mt*16+8][cc+4];
            }
            int rB = wn*64 + (lane>>2);
            #pragma unroll
            for(int nt=0;nt<8;nt++){
                b[nt][0]=Bs[rB+nt*8][cc];
                b[nt][1]=Bs[rB+nt*8][cc+4];
            }
            #pragma unroll
            for(int mt=0;mt<2;mt++)
                #pragma unroll
                for(int nt=0;nt<8;nt++)
                    mma8(acc[mt][nt], a[mt], b[nt]);
        }
    }
    int g = lane>>2, tq = lane&3;
    float pm[2][2];
    #pragma unroll
    for(int mt=0;mt<2;mt++)
        #pragma unroll
        for(int i=0;i<2;i++){
            float m = -1e30f;
            #pragma unroll
            for(int nt=0;nt<8;nt++){
                acc[mt][nt][2*i]   *= alpha;
                acc[mt][nt][2*i+1] *= alpha;
                m = fmaxf(m, fmaxf(acc[mt][nt][2*i], acc[mt][nt][2*i+1]));
            }
            m = fmaxf(m, __shfl_xor_sync(0xffffffffu, m, 1));
            m = fmaxf(m, __shfl_xor_sync(0xffffffffu, m, 2));
            pm[mt][i] = m;
        }
    if(tq==0){
        #pragma unroll
        for(int mt=0;mt<2;mt++)
            #pragma unroll
            for(int i=0;i<2;i++)
                red[wm*32+mt*16+i*8+g][wn] = pm[mt][i];
    }
    __syncthreads();
    float rmax[2][2];
    #pragma unroll
    for(int mt=0;mt<2;mt++)
        #pragma unroll
        for(int i=0;i<2;i++){
            int rid = wm*32+mt*16+i*8+g;
            rmax[mt][i] = fmaxf(fmaxf(red[rid][0],red[rid][1]), fmaxf(red[rid][2],red[rid][3]));
        }
    __syncthreads();
    float ps[2][2];
    #pragma unroll
    for(int mt=0;mt<2;mt++)
        #pragma unroll
        for(int i=0;i<2;i++){
            float s = 0.f;
            #pragma unroll
            for(int nt=0;nt<8;nt++){
                float e0 = __expf(acc[mt][nt][2*i]   - rmax[mt][i]);
                float e1 = __expf(acc[mt][nt][2*i+1] - rmax[mt][i]);
                acc[mt][nt][2*i]   = e0;
                acc[mt][nt][2*i+1] = e1;
                s += e0 + e1;
            }
            s += __shfl_xor_sync(0xffffffffu, s, 1);
            s += __shfl_xor_sync(0xffffffffu, s, 2);
            ps[mt][i] = s;
        }
    if(tq==0){
        #pragma unroll
        for(int mt=0;mt<2;mt++)
            #pragma unroll
            for(int i=0;i<2;i++)
                red[wm*32+mt*16+i*8+g][wn] = ps[mt][i];
    }
    __syncthreads();
    #pragma unroll
    for(int mt=0;mt<2;mt++)
        #pragma unroll
        for(int i=0;i<2;i++){
            int rid = wm*32+mt*16+i*8+g;
            float inv = 1.f/(red[rid][0]+red[rid][1]+red[rid][2]+red[rid][3]);
            long gm = r0 + rid;
            #pragma unroll
            for(int nt=0;nt<8;nt++){
                int gn = wn*64 + nt*8 + 2*tq;
                float2 v; v.x = acc[mt][nt][2*i]*inv; v.y = acc[mt][nt][2*i+1]*inv;
                *(float2*)(C + gm*ldc + gn) = v;
            }
        }
}

// =====================================================================
// Flash-style fused sim3+softmax+a3v (proven R12)
// =====================================================================
__global__ void __launch_bounds__(256,2) k_flash3(
    const float* __restrict__ QL, long sQL,
    const float* __restrict__ QKV, long sQKVb,
    float* __restrict__ Ov, long sO)
{
    extern __shared__ char dyn[];
    uint32_t (*Qs)[68] = (uint32_t(*)[68])dyn;
    uint32_t (*Ks)[20] = (uint32_t(*)[20])(dyn + 17408);
    uint32_t (*Pf)[68] = (uint32_t(*)[68])(dyn + 17408);
    uint32_t (*Vs)[72] = (uint32_t(*)[72])(dyn + 17408 + 17408);
    float (*red)[4] = (float(*)[4])(dyn + 53248);
    float* m_run = (float*)(dyn + 54272);
    float* l_run = (float*)(dyn + 54528);
    float* sf    = (float*)(dyn + 54784);
    int z = blockIdx.z; int hh = z & 7; int bb = z >> 3;
    const float* Q  = QL  + (long)z*sQL;
    const float* Kg = QKV + (long)bb*sQKVb + 512  + hh*64;
    const float* Vg = QKV + (long)bb*sQKVb + 1024 + hh*64;
    float* Og = Ov + (long)z*sO;
    int t = threadIdx.x, lane = t & 31, warp = t >> 5;
    int wm = warp >> 2, wn = warp & 3;
    int wm2 = warp >> 1, wn2 = warp & 1;
    int g = lane >> 2, tq = lane & 3;
    int r0 = blockIdx.x*64;
    {
        int row = t >> 2, cb = (t & 3)*16;
        const float* qp = Q + (long)(r0+row)*64 + cb;
        #pragma unroll
        for(int j=0;j<4;j++){
            float4 v = ldg4(qp + j*4);
            Qs[row][cb+j*4+0]=f2tf(v.x); Qs[row][cb+j*4+1]=f2tf(v.y);
            Qs[row][cb+j*4+2]=f2tf(v.z); Qs[row][cb+j*4+3]=f2tf(v.w);
        }
    }
    if(t < 64){ m_run[t] = -1e30f; l_run[t] = 0.f; }
    float acc2[4][4];
    #pragma unroll
    for(int j=0;j<4;j++)
        #pragma unroll
        for(int q=0;q<4;q++) acc2[j][q]=0.f;
    for(int ch=0; ch<17; ch++){
        long kc0 = (long)ch*256;
        float acc[2][8][4];
        #pragma unroll
        for(int i=0;i<2;i++)
            #pragma unroll
            for(int j=0;j<8;j++)
                #pragma unroll
                for(int q=0;q<4;q++) acc[i][j][q]=0.f;
        for(int kt=0; kt<4; kt++){
            __syncthreads();
            int lrow = t >> 2, lk = (t & 3)*4;
            #pragma unroll
            for(int i=0;i<4;i++){
                int row = i*64 + lrow;
                *(uint4*)&Ks[row][lk] = cvt4(ldg4(Kg + (kc0+row)*1536 + kt*16 + lk));
            }
            __syncthreads();
            #pragma unroll
            for(int ks=0;ks<2;ks++){
                int cc = ks*8 + tq, qc = kt*16 + cc;
                uint32_t a[2][4], b[8][2];
                int rA = wm*32 + g;
                #pragma unroll
                for(int mt=0;mt<2;mt++){
                    a[mt][0]=Qs[rA+mt*16  ][qc];
                    a[mt][1]=Qs[rA+mt*16+8][qc];
                    a[mt][2]=Qs[rA+mt*16  ][qc+4];
                    a[mt][3]=Qs[rA+mt*16+8][qc+4];
                }
                int rB = wn*64 + g;
                #pragma unroll
                for(int nt=0;nt<8;nt++){
                    b[nt][0]=Ks[rB+nt*8][cc];
                    b[nt][1]=Ks[rB+nt*8][cc+4];
                }
                #pragma unroll
                for(int mt=0;mt<2;mt++)
                    #pragma unroll
                    for(int nt=0;nt<8;nt++)
                        mma8(acc[mt][nt], a[mt], b[nt]);
            }
        }
        float pm[2][2];
        #pragma unroll
        for(int mt=0;mt<2;mt++)
            #pragma unroll
            for(int i=0;i<2;i++){
                float m = -1e30f;
                #pragma unroll
                for(int nt=0;nt<8;nt++)
                    m = fmaxf(m, fmaxf(acc[mt][nt][2*i], acc[mt][nt][2*i+1]));
                m = fmaxf(m, __shfl_xor_sync(0xffffffffu, m, 1));
                m = fmaxf(m, __shfl_xor_sync(0xffffffffu, m, 2));
                pm[mt][i] = m;
            }
        if(tq==0){
            #pragma unroll
            for(int mt=0;mt<2;mt++)
                #pragma unroll
                for(int i=0;i<2;i++)
                    red[wm*32+mt*16+i*8+g][wn] = pm[mt][i];
        }
        __syncthreads();
        float mn_[2][2];
        #pragma unroll
        for(int mt=0;mt<2;mt++)
            #pragma unroll
            for(int i=0;i<2;i++){
                int rid = wm*32+mt*16+i*8+g;
                float cm = fmaxf(fmaxf(red[rid][0],red[rid][1]), fmaxf(red[rid][2],red[rid][3]));
                mn_[mt][i] = fmaxf(m_run[rid], cm);
            }
        __syncthreads();
        float ps[2][2];
        #pragma unroll
        for(int mt=0;mt<2;mt++)
            #pragma unroll
            for(int i=0;i<2;i++){
                float s = 0.f;
                #pragma unroll
                for(int nt=0;nt<8;nt++){
                    float e0 = __expf(acc[mt][nt][2*i]   - mn_[mt][i]);
                    float e1 = __expf(acc[mt][nt][2*i+1] - mn_[mt][i]);
                    acc[mt][nt][2*i]   = e0;
                    acc[mt][nt][2*i+1] = e1;
                    s += e0 + e1;
                }
                s += __shfl_xor_sync(0xffffffffu, s, 1);
                s += __shfl_xor_sync(0xffffffffu, s, 2);
                ps[mt][i] = s;
            }
        if(tq==0){
            #pragma unroll
            for(int mt=0;mt<2;mt++)
                #pragma unroll
                for(int i=0;i<2;i++)
                    red[wm*32+mt*16+i*8+g][wn] = ps[mt][i];
        }
        __syncthreads();
        if(wn==0 && tq==0){
            #pragma unroll
            for(int mt=0;mt<2;mt++)
                #pragma unroll
                for(int i=0;i<2;i++){
                    int rid = wm*32+mt*16+i*8+g;
                    float ct = red[rid][0]+red[rid][1]+red[rid][2]+red[rid][3];
                    float mn = mn_[mt][i];
                    float f  = __expf(m_run[rid] - mn);
                    l_run[rid] = l_run[rid]*f + ct;
                    m_run[rid] = mn;
                    sf[rid] = f;
                }
        }
        __syncthreads();
        #pragma unroll
        for(int i=0;i<2;i++){
            float f2 = sf[wm2*16 + i*8 + g];
            #pragma unroll
            for(int nt=0;nt<4;nt++){ acc2[nt][2*i]*=f2; acc2[nt][2*i+1]*=f2; }
        }
        for(int sub=0; sub<4; sub++){
            __syncthreads();
            if(wn == sub){
                #pragma unroll
                for(int mt=0;mt<2;mt++)
                    #pragma unroll
                    for(int i=0;i<2;i++){
                        int rl = wm*32+mt*16+i*8+g;
                        #pragma unroll
                        for(int nt=0;nt<8;nt++){
                            int cl = nt*8 + 2*tq;
                            Pf[rl][cl]   = f2tf(acc[mt][nt][2*i]);
                            Pf[rl][cl+1] = f2tf(acc[mt][nt][2*i+1]);
                        }
                    }
            }
            {
                int kl = t >> 2, cb = (t & 3)*16;
                const float* vp = Vg + (kc0 + sub*64 + kl)*1536 + cb;
                #pragma unroll
                for(int j=0;j<4;j++){
                    float4 v = ldg4(vp + j*4);
                    Vs[kl][cb+j*4+0]=f2tf(v.x); Vs[kl][cb+j*4+1]=f2tf(v.y);
                    Vs[kl][cb+j*4+2]=f2tf(v.z); Vs[kl][cb+j*4+3]=f2tf(v.w);
                }
            }
            __syncthreads();
            #pragma unroll
            for(int kk=0;kk<8;kk++){
                int cc = kk*8 + tq;
                uint32_t a[4], b[4][2];
                a[0]=Pf[wm2*16+g  ][cc];
                a[1]=Pf[wm2*16+8+g][cc];
                a[2]=Pf[wm2*16+g  ][cc+4];
                a[3]=Pf[wm2*16+8+g][cc+4];
                #pragma unroll
                for(int nt=0;nt<4;nt++){
                    int n = wn2*32 + nt*8 + g;
                    b[nt][0]=Vs[cc  ][n];
                    b[nt][1]=Vs[cc+4][n];
                }
                #pragma unroll
                for(int nt=0;nt<4;nt++)
                    mma8(acc2[nt], a, b[nt]);
            }
        }
    }
    #pragma unroll
    for(int i=0;i<2;i++){
        int row = wm2*16 + i*8 + g;
        float linv = 1.f/l_run[row];
        float* dst = Og + (long)(r0+row)*64;
        #pragma unroll
        for(int nt=0;nt<4;nt++){
            int col = wn2*32 + nt*8 + 2*tq;
            float2 v; v.x = acc2[nt][2*i]*linv; v.y = acc2[nt][2*i+1]*linv;
            *(float2*)(dst + col) = v;
        }
    }
}

// =====================================================================
// Fused attention output: ac[token] = softmax(alpha * q @ kl^T) @ tmp2  (proven)
// =====================================================================
__global__ void __launch_bounds__(256,2) k_attnout(
    const float* __restrict__ Q, int ldq, long sQb, long sQh,
    const float* __restrict__ KL, long sKL,
    const float* __restrict__ T2, long sT2,
    float* __restrict__ AC, float alpha)
{
    int z = blockIdx.z; int hh = z & 7; int bb = z >> 3;
    const float* A = Q  + (long)bb*sQb + (long)hh*sQh;
    const float* B = KL + (long)z*sKL;
    const float* T = T2 + (long)z*sT2;
    __shared__ char smem_raw[35840];
    __shared__ float red[64][4];
    uint32_t (*As)[20] = (uint32_t(*)[20])smem_raw;
    uint32_t (*Bs)[20] = (uint32_t(*)[20])(smem_raw + 5120);
    uint32_t (*Pf)[68] = (uint32_t(*)[68])smem_raw;
    uint32_t (*Ts)[72] = (uint32_t(*)[72])(smem_raw + 17408);
    int t = threadIdx.x;
    int lane = t & 31, warp = t >> 5;
    int wm = warp >> 2, wn = warp & 3;
    int r0 = blockIdx.x*64;
    int lrow = t >> 2, lk = (t & 3)*4;
    int g = lane>>2, tq = lane&3;
    float acc[2][8][4];
    #pragma unroll
    for(int i=0;i<2;i++)
        #pragma unroll
        for(int j=0;j<8;j++)
            #pragma unroll
            for(int q=0;q<4;q++) acc[i][j][q]=0.f;
    for(int kt=0; kt<4; kt++){
        __syncthreads();
        *(uint4*)&As[lrow][lk] = cvt4(ldg4(A + (long)(r0+lrow)*ldq + kt*16 + lk));
        #pragma unroll
        for(int i=0;i<4;i++)
            *(uint4*)&Bs[i*64+lrow][lk] = cvt4(ldg4(B + (long)(i*64+lrow)*64 + kt*16 + lk));
        __syncthreads();
        #pragma unroll
        for(int ks=0;ks<2;ks++){
            int cc = ks*8 + tq;
            uint32_t a[2][4], b[8][2];
            int rA = wm*32 + g;
            #pragma unroll
            for(int mt=0;mt<2;mt++){
                a[mt][0]=As[rA+mt*16  ][cc];
                a[mt][1]=As[rA+mt*16+8][cc];
                a[mt][2]=As[rA+mt*16  ][cc+4];
                a[mt][3]=As[rA+mt*16+8][cc+4];
            }
            int rB = wn*64 + g;
            #pragma unroll
            for(int nt=0;nt<8;nt++){
                b[nt][0]=Bs[rB+nt*8][cc];
                b[nt][1]=Bs[rB+nt*8][cc+4];
            }
            #pragma unroll
            for(int mt=0;mt<2;mt++)
                #pragma unroll
                for(int nt=0;nt<8;nt++)
                    mma8(acc[mt][nt], a[mt], b[nt]);
        }
    }
    float pm[2][2];
    #pragma unroll
    for(int mt=0;mt<2;mt++)
        #pragma unroll
        for(int i=0;i<2;i++){
            float m = -1e30f;
            #pragma unroll
            for(int nt=0;nt<8;nt++){
                acc[mt][nt][2*i]   *= alpha;
                acc[mt][nt][2*i+1] *= alpha;
                m = fmaxf(m, fmaxf(acc[mt][nt][2*i], acc[mt][nt][2*i+1]));
            }
            m = fmaxf(m, __shfl_xor_sync(0xffffffffu, m, 1));
            m = fmaxf(m, __shfl_xor_sync(0xffffffffu, m, 2));
            pm[mt][i] = m;
        }
    if(tq==0){
        #pragma unroll
        for(int mt=0;mt<2;mt++)
            #pragma unroll
            for(int i=0;i<2;i++)
                red[wm*32+mt*16+i*8+g][wn] = pm[mt][i];
    }
    __syncthreads();
    float rmax[2][2];
    #pragma unroll
    for(int mt=0;mt<2;mt++)
        #pragma unroll
        for(int i=0;i<2;i++){
            int rid = wm*32+mt*16+i*8+g;
            rmax[mt][i] = fmaxf(fmaxf(red[rid][0],red[rid][1]), fmaxf(red[rid][2],red[rid][3]));
        }
    __syncthreads();
    float ps[2][2];
    #pragma unroll
    for(int mt=0;mt<2;mt++)
        #pragma unroll
        for(int i=0;i<2;i++){
            float s = 0.f;
            #pragma unroll
            for(int nt=0;nt<8;nt++){
                float e0 = __expf(acc[mt][nt][2*i]   - rmax[mt][i]);
                float e1 = __expf(acc[mt][nt][2*i+1] - rmax[mt][i]);
                acc[mt][nt][2*i]   = e0;
                acc[mt][nt][2*i+1] = e1;
                s += e0 + e1;
            }
            s += __shfl_xor_sync(0xffffffffu, s, 1);
            s += __shfl_xor_sync(0xffffffffu, s, 2);
            ps[mt][i] = s;
        }
    if(tq==0){
        #pragma unroll
        for(int mt=0;mt<2;mt++)
            #pragma unroll
            for(int i=0;i<2;i++)
                red[wm*32+mt*16+i*8+g][wn] = ps[mt][i];
    }
    __syncthreads();
    float inv2[2][2];
    #pragma unroll
    for(int mt=0;mt<2;mt++)
        #pragma unroll
        for(int i=0;i<2;i++){
            int rid = wm*32+mt*16+i*8+g;
            inv2[mt][i] = 1.f/(red[rid][0]+red[rid][1]+red[rid][2]+red[rid][3]);
            #pragma unroll
            for(int nt=0;nt<8;nt++){
                acc[mt][nt][2*i]   *= inv2[mt][i];
                acc[mt][nt][2*i+1] *= inv2[mt][i];
            }
        }
    int wm2 = warp >> 1, wn2 = warp & 1;
    float acc2[4][4];
    #pragma unroll
    for(int j=0;j<4;j++)
        #pragma unroll
        for(int q=0;q<4;q++) acc2[j][q]=0.f;
    for(int ch=0; ch<4; ch++){
        __syncthreads();
        if(wn == ch){
            #pragma unroll
            for(int mt=0;mt<2;mt++)
                #pragma unroll
                for(int i=0;i<2;i++){
                    int row_l = wm*32+mt*16+i*8+g;
                    #pragma unroll
                    for(int nt=0;nt<8;nt++){
                        int col_l = nt*8 + 2*tq;
                        Pf[row_l][col_l]   = f2tf(acc[mt][nt][2*i]);
                        Pf[row_l][col_l+1] = f2tf(acc[mt][nt][2*i+1]);
                    }
                }
        }
        {
            int kl_ = t >> 2, cb = (t & 3)*16;
            const float* Tp = T + (long)(64*ch + kl_)*64 + cb;
            #pragma unroll
            for(int j=0;j<4;j++){
                float4 v = ldg4(Tp + j*4);
                Ts[kl_][cb+j*4+0] = f2tf(v.x);
                Ts[kl_][cb+j*4+1] = f2tf(v.y);
                Ts[kl_][cb+j*4+2] = f2tf(v.z);
                Ts[kl_][cb+j*4+3] = f2tf(v.w);
            }
        }
        __syncthreads();
        #pragma unroll
        for(int kk=0;kk<8;kk++){
            int cc = kk*8 + tq;
            uint32_t a[4], b[4][2];
            a[0]=Pf[wm2*16+g  ][cc];
            a[1]=Pf[wm2*16+8+g][cc];
            a[2]=Pf[wm2*16+g  ][cc+4];
            a[3]=Pf[wm2*16+8+g][cc+4];
            #pragma unroll
            for(int nt=0;nt<4;nt++){
                int n = wn2*32 + nt*8 + g;
                b[nt][0]=Ts[cc  ][n];
                b[nt][1]=Ts[cc+4][n];
            }
            #pragma unroll
            for(int nt=0;nt<4;nt++)
                mma8(acc2[nt], a, b[nt]);
        }
    }
    #pragma unroll
    for(int i=0;i<2;i++){
        int gm = r0 + wm2*16 + i*8 + g;
        if(gm < 255) continue;
        float* dst = AC + ((long)bb*4097 + (gm-255))*512 + hh*64;
        #pragma unroll
        for(int nt=0;nt<4;nt++){
            int gn = wn2*32 + nt*8 + 2*tq;
            float2 v; v.x = acc2[nt][2*i]; v.y = acc2[nt][2*i+1];
            *(float2*)(dst + gn) = v;
        }
    }
}

// C = alpha * A @ B  (NN), pinv epilogues, 2-stage double buffer.
__global__ void __launch_bounds__(256,2) k_mma_nn(
    const float* __restrict__ A, int lda, long sAb, long sAh,
    const float* __restrict__ B, int ldb, long sBb, long sBh,
    float* __restrict__ C, int ldc, long sCb, long sCh,
    float* __restrict__ D, long sDb, long sDh,
    int M, int N, int K, float alpha, float dconst, int cmode)
{
    int z = blockIdx.z; int hh = z & 7; int bb = z >> 3;
    A += (long)bb*sAb + (long)hh*sAh;
    B += (long)bb*sBb + (long)hh*sBh;
    C += (long)bb*sCb + (long)hh*sCh;
    if(D) D += (long)bb*sDb + (long)hh*sDh;
    __shared__ uint32_t As[2][128][20];
    __shared__ uint32_t Bs[2][16][136];
    int t = threadIdx.x;
    int lane = t & 31, warp = t >> 5;
    int wm = warp >> 2, wn = warp & 3;
    int r0 = blockIdx.x*128, c0 = blockIdx.y*128;
    int lrow = t >> 2, lk = (t & 3)*4;
    int bk = t >> 5, bn = (t & 31)*4;
    const float* Ap0 = A + (long)(r0+lrow)*lda + lk;
    const float* Ap1 = A + (long)(r0+lrow+64)*lda + lk;
    const float* Bq0 = B + (long)bk*ldb + c0 + bn;
    const float* Bq1 = B + (long)(bk+8)*ldb + c0 + bn;
    bool mA0 = (r0+lrow)<M, mA1 = (r0+lrow+64)<M;
    bool mBn = (c0+bn)<N;
    const float4 z4 = make_float4(0.f,0.f,0.f,0.f);
    float4 pa0 = mA0?ldg4(Ap0):z4, pa1 = mA1?ldg4(Ap1):z4;
    float4 pb0 = mBn?ldg4(Bq0):z4, pb1 = mBn?ldg4(Bq1):z4;
    *(uint4*)&As[0][lrow][lk]    = cvt4(pa0);
    *(uint4*)&As[0][lrow+64][lk] = cvt4(pa1);
    *(uint4*)&Bs[0][bk][bn]      = cvt4(pb0);
    *(uint4*)&Bs[0][bk+8][bn]    = cvt4(pb1);
    __syncthreads();
    float accr[4][4][4];
    #pragma unroll
    for(int i=0;i<4;i++)
        #pragma unroll
        for(int j=0;j<4;j++)
            #pragma unroll
            for(int q=0;q<4;q++) accr[i][j][q]=0.f;
    int nk = K >> 4;
    for(int kt=0; kt<nk; kt++){
        int buf = kt & 1;
        if(kt+1<nk){
            long o = (long)(kt+1)*16;
            pa0 = mA0?ldg4(Ap0+o):z4; pa1 = mA1?ldg4(Ap1+o):z4;
            pb0 = mBn?ldg4(Bq0+o*ldb):z4; pb1 = mBn?ldg4(Bq1+o*ldb):z4;
        }
        #pragma unroll
        for(int ks=0;ks<2;ks++){
            int cc = ks*8 + (lane&3);
            uint32_t a[4][4], b[4][2];
            int rA = wm*64 + (lane>>2);
            #pragma unroll
            for(int mt=0;mt<4;mt++){
                a[mt][0]=As[buf][rA+mt*16  ][cc];
                a[mt][1]=As[buf][rA+mt*16+8][cc];
                a[mt][2]=As[buf][rA+mt*16  ][cc+4];
                a[mt][3]=As[buf][rA+mt*16+8][cc+4];
            }
            int nB = wn*32 + (lane>>2);
            #pragma unroll
            for(int nt=0;nt<4;nt++){
                b[nt][0]=Bs[buf][cc  ][nB+nt*8];
                b[nt][1]=Bs[buf][cc+4][nB+nt*8];
            }
            #pragma unroll
            for(int mt=0;mt<4;mt++)
                #pragma unroll
                for(int nt=0;nt<4;nt++)
                    mma8(accr[mt][nt], a[mt], b[nt]);
        }
        if(kt+1<nk){
            int s = (kt+1) & 1;
            *(uint4*)&As[s][lrow][lk]    = cvt4(pa0);
            *(uint4*)&As[s][lrow+64][lk] = cvt4(pa1);
            *(uint4*)&Bs[s][bk][bn]      = cvt4(pb0);
            *(uint4*)&Bs[s][bk+8][bn]    = cvt4(pb1);
            __syncthreads();
        }
    }
    #pragma unroll
    for(int mt=0;mt<4;mt++)
    #pragma unroll
    for(int i=0;i<2;i++){
        int gm = r0 + wm*64 + mt*16 + i*8 + (lane>>2);
        if(gm>=M) continue;
        #pragma unroll
        for(int nt=0;nt<4;nt++){
            int gn = c0 + wn*32 + nt*8 + 2*(lane&3);
            float2 v;
            v.x = alpha*accr[mt][nt][2*i];
            v.y = alpha*accr[mt][nt][2*i+1];
            long o = (long)gm*ldc + gn;
            if(D){
                float2 dv;
                dv.x = ((gm==gn  )?dconst:0.f) - v.x;
                dv.y = ((gm==gn+1)?dconst:0.f) - v.y;
                *(float2*)(D+o) = dv;
            }
            if(cmode){
                v.x = ((gm==gn  )?dconst:0.f) - v.x;
                v.y = ((gm==gn+1)?dconst:0.f) - v.y;
            }
            *(float2*)(C+o) = v;
        }
    }
}

// C = alpha * A @ B (NN, TF32), N=64. 128x64 block, 8 warps of 32x32. (proven)
__global__ void __launch_bounds__(256,2) k_mma_nn64(
    const float* __restrict__ A, int lda, long sAb, long sAh,
    const float* __restrict__ B, int ldb, long sBb, long sBh,
    float* __restrict__ C, int ldc, long sCb, long sCh,
    int M, int K, float alpha, int rowLo)
{
    int z = blockIdx.z; int hh = z & 7; int bb = z >> 3;
    A += (long)bb*sAb + (long)hh*sAh;
    B += (long)bb*sBb + (long)hh*sBh;
    C += (long)bb*sCb + (long)hh*sCh;
    __shared__ uint32_t Af[2][2048];
    __shared__ uint32_t Bf[2][1024];
    int t = threadIdx.x, lane = t & 31, warp = t >> 5;
    int wm = warp >> 1, wn = warp & 1;
    int r0 = blockIdx.x*128;
    int alr = t >> 1, alk = (t & 1)*8;
    const float* Ap = A + (long)(r0+alr)*lda + alk;
    bool mA = (r0+alr) < M;
    int bk = t >> 4, bn = (t & 15)*4;
    const float* Bp = B + (long)bk*ldb + bn;
    const float4 z4 = make_float4(0.f,0.f,0.f,0.f);
    float4 a0,a1,b0;
    a0 = mA?ldg4(Ap):z4; a1 = mA?ldg4(Ap+4):z4;
    b0 = ldg4(Bp);
    {
        scatA(Af[0], alr, alk+0, f2tf(a0.x)); scatA(Af[0], alr, alk+1, f2tf(a0.y));
        scatA(Af[0], alr, alk+2, f2tf(a0.z)); scatA(Af[0], alr, alk+3, f2tf(a0.w));
        scatA(Af[0], alr, alk+4, f2tf(a1.x)); scatA(Af[0], alr, alk+5, f2tf(a1.y));
        scatA(Af[0], alr, alk+6, f2tf(a1.z)); scatA(Af[0], alr, alk+7, f2tf(a1.w));
        scatB8(Bf[0], bn+0, bk, f2tf(b0.x)); scatB8(Bf[0], bn+1, bk, f2tf(b0.y));
        scatB8(Bf[0], bn+2, bk, f2tf(b0.z)); scatB8(Bf[0], bn+3, bk, f2tf(b0.w));
    }
    __syncthreads();
    float acc[2][4][4];
    #pragma unroll
    for(int i=0;i<2;i++)
        #pragma unroll
        for(int j=0;j<4;j++)
            #pragma unroll
            for(int q=0;q<4;q++) acc[i][j][q]=0.f;
    int nk = K >> 4;
    for(int kt=0; kt<nk; kt++){
        if(kt+1<nk){
            long o = (long)(kt+1)*16;
            a0 = mA?ldg4(Ap+o):z4; a1 = mA?ldg4(Ap+o+4):z4;
            b0 = ldg4(Bp + o*ldb);
        }
        int buf = kt & 1;
        #pragma unroll
        for(int ks=0;ks<2;ks++){
            uint32_t af[2][4], bfr[4][2];
            #pragma unroll
            for(int mt=0;mt<2;mt++)
                *(uint4*)af[mt] = *(const uint4*)&Af[buf][(((ks<<3)+(wm<<1)+mt)<<7) + (lane<<2)];
            #pragma unroll
            for(int nt=0;nt<4;nt++)
                *(uint2*)bfr[nt] = *(const uint2*)&Bf[buf][(((ks<<3)+(wn<<2)+nt)<<6) + (lane<<1)];
            #pragma unroll
            for(int mt=0;mt<2;mt++)
                #pragma unroll
                for(int nt=0;nt<4;nt++)
                    mma8(acc[mt][nt], af[mt], bfr[nt]);
        }
        if(kt+1<nk){
            int s = (kt+1) & 1;
            scatA(Af[s], alr, alk+0, f2tf(a0.x)); scatA(Af[s], alr, alk+1, f2tf(a0.y));
            scatA(Af[s], alr, alk+2, f2tf(a0.z)); scatA(Af[s], alr, alk+3, f2tf(a0.w));
            scatA(Af[s], alr, alk+4, f2tf(a1.x)); scatA(Af[s], alr, alk+5, f2tf(a1.y));
            scatA(Af[s], alr, alk+6, f2tf(a1.z)); scatA(Af[s], alr, alk+7, f2tf(a1.w));
            scatB8(Bf[s], bn+0, bk, f2tf(b0.x)); scatB8(Bf[s], bn+1, bk, f2tf(b0.y));
            scatB8(Bf[s], bn+2, bk, f2tf(b0.z)); scatB8(Bf[s], bn+3, bk, f2tf(b0.w));
            __syncthreads();
        }
    }
    int g = lane >> 2, tq = lane & 3;
    #pragma unroll
    for(int mt=0;mt<2;mt++)
    #pragma unroll
    for(int i=0;i<2;i++){
        int gm = r0 + wm*32 + mt*16 + i*8 + g;
        if(gm >= M || gm < rowLo) continue;
        #pragma unroll
        for(int nt=0;nt<4;nt++){
            int gn = wn*32 + nt*8 + 2*tq;
            float2 v;
            v.x = alpha*acc[mt][nt][2*i];
            v.y = alpha*acc[mt][nt][2*i+1];
            *(float2*)(C + (long)gm*ldc + gn) = v;
        }
    }
}

// ---------------- landmarks (mean over 17 tokens), q scaled by 1/8 ----------------
__global__ void k_landmarks(const float* __restrict__ qkv, float* __restrict__ ql, float* __restrict__ kl){
    int idx = blockIdx.x;
    int mi = idx % 256; int hh = (idx/256) & 7; int b = idx / (256*8);
    int dh = threadIdx.x;
    float sq=0.f, sk=0.f;
    for(int j=0;j<LSUB;j++){
        long tok = (long)mi*LSUB + j;
        const float* base = qkv + ((long)b*4352 + tok)*1536 + hh*64 + dh;
        sq += base[0];
        sk += base[512];
    }
    long o = (long)idx*64 + dh;
    ql[o] = sq * (0.125f/LSUB);
    kl[o] = sk * (1.0f/LSUB);
}

// ---------------- pinv scalar reductions ----------------
__global__ void k_scal_init(){ if(threadIdx.x < 2) g_scal[threadIdx.x] = 0.f; }

__global__ void k_rowsum_max(const float* __restrict__ X){
    long row = blockIdx.x;
    const float* x = X + row*256;
    int t = threadIdx.x;
    __shared__ float red[256];
    red[t] = fabsf(x[t]); __syncthreads();
    for(int k=128;k;k>>=1){ if(t<k) red[t]+=red[t+k]; __syncthreads(); }
    if(t==0) atomicMax((int*)&g_scal[0], __float_as_int(red[0]));
}

__global__ void k_colsum_max(const float* __restrict__ X){
    int b = blockIdx.x; int j = threadIdx.x;
    const float* x = X + (long)b*65536;
    float s = 0.f;
    for(int i=0;i<256;i++) s += fabsf(x[i*256+j]);
    __shared__ float red[256];
    red[j]=s; __syncthreads();
    for(int k=128;k;k>>=1){ if(j<k) red[j]=fmaxf(red[j],red[j+k]); __syncthreads(); }
    if(j==0) atomicMax((int*)&g_scal[1], __float_as_int(red[0]));
}

__global__ void k_tr_scale(const float* __restrict__ X, float* __restrict__ Z){
    long idx = (long)blockIdx.x*256 + threadIdx.x;
    if(idx >= 64L*65536) return;
    float inv = 1.f/(g_scal[0]*g_scal[1]);
    int j = (int)(idx & 255); int i = (int)((idx>>8) & 255); long b = idx >> 16;
    Z[idx] = X[(b<<16) + ((long)j<<8) + i] * inv;
}

// ---------------- residual depthwise conv (k=33), writes token-major into ac ----------------
__global__ void k_resconv2(const float* __restrict__ qkv, const float* __restrict__ w,
                           float* __restrict__ ac){
    int bh = blockIdx.y; int hh = bh & 7; int b = bh >> 3;
    int t0 = blockIdx.x*64;
    __shared__ float sv[96][65];
    __shared__ float sw[33];
    int t = threadIdx.x;
    if(t < 33) sw[t] = w[hh*33 + t];
    const float* vb = qkv + ((long)b*4352)*1536 + 1024 + hh*64;
    for(int i=t;i<96*64;i+=256){
        int tok = t0 - 16 + (i>>6); int dh = i&63;
        sv[i>>6][dh] = (tok>=0 && tok<4352) ? vb[(long)tok*1536 + dh] : 0.f;
    }
    __syncthreads();
    for(int i=t;i<64*64;i+=256){
        int lt = i>>6, dh = i&63;
        int tok = t0 + lt;
        if(tok < 255) continue;
        float s = 0.f;
        #pragma unroll
        for(int j=0;j<33;j++) s = fmaf(sw[j], sv[lt+j][dh], s);
        ac[((long)b*4097 + (tok-255))*512 + hh*64 + dh] += s;
    }
}

// ---------------- transposes token<->planar ----------------
__global__ void k_h2planar(const float* __restrict__ h, float* __restrict__ cnn){
    __shared__ float tile[32][33];
    int b = blockIdx.z;
    int c0 = blockIdx.x*32, p0 = blockIdx.y*32;
    int tx = threadIdx.x, ty = threadIdx.y;
    for(int i=ty;i<32;i+=8)
        tile[i][tx] = h[((long)b*4097 + 1 + p0+i)*512 + c0+tx];
    __syncthreads();
    for(int i=ty;i<32;i+=8)
        cnn[((long)b*512 + c0+i)*4096 + p0+tx] = tile[tx][i];
}

__global__ void k_planar2h(const float* __restrict__ yp, float* __restrict__ h2){
    __shared__ float tile[32][33];
    int b = blockIdx.z;
    int c0 = blockIdx.x*32, p0 = blockIdx.y*32;
    int tx = threadIdx.x, ty = threadIdx.y;
    for(int i=ty;i<32;i+=8)
        tile[i][tx] = yp[((long)b*512 + c0+i)*4096 + p0+tx];
    __syncthreads();
    for(int i=ty;i<32;i+=8)
        h2[((long)b*4097 + 1 + p0+i)*512 + c0+tx] = tile[tx][i];
}

__global__ void k_cls_copy(const float* __restrict__ h, float* __restrict__ h2){
    int idx = blockIdx.x*256 + threadIdx.x;
    if(idx >= 8*512) return;
    int b = idx >> 9, c = idx & 511;
    h2[(long)b*4097*512 + c] = h[(long)b*4097*512 + c];
}

// ---------------- fused 7x7 + 5x5 + 3x3 depthwise conv, planar ----------------
__global__ void k_dwconv(const float* __restrict__ cnn,
                         const float* __restrict__ w7, const float* __restrict__ b7,
                         const float* __restrict__ w5, const float* __restrict__ b5,
                         const float* __restrict__ w3, const float* __restrict__ b3,
                         float* __restrict__ yp){
    int bc = blockIdx.x; int c = bc & 511;
    __shared__ float pl[64][65];
    __shared__ float ww[84];
    const float* in = cnn + (long)bc*4096;
    int t = threadIdx.x;
    for(int i=t;i<4096;i+=256) pl[i>>6][i&63] = in[i];
    if(t < 49)      ww[t]      = w7[c*49 + t];
    else if(t < 74) ww[t]      = w5[c*25 + t - 49];
    else if(t < 83) ww[t]      = w3[c*9  + t - 74];
    __syncthreads();
    float bias = b7[c] + b5[c] + b3[c];
    for(int i=t;i<4096;i+=256){
        int y = i >> 6, x = i & 63;
        float s = pl[y][x] + bias;
        #pragma unroll
        for(int ky=0;ky<7;ky++){ int yy=y+ky-3; if((unsigned)yy>=64u) continue;
            #pragma unroll
            for(int kx=0;kx<7;kx++){ int xx=x+kx-3; if((unsigned)xx>=64u) continue;
                s = fmaf(ww[ky*7+kx], pl[yy][xx], s); } }
        #pragma unroll
        for(int ky=0;ky<5;ky++){ int yy=y+ky-2; if((unsigned)yy>=64u) continue;
            #pragma unroll
            for(int kx=0;kx<5;kx++){ int xx=x+kx-2; if((unsigned)xx>=64u) continue;
                s = fmaf(ww[49+ky*5+kx], pl[yy][xx], s); } }
        #pragma unroll
        for(int ky=0;ky<3;ky++){ int yy=y+ky-1; if((unsigned)yy>=64u) continue;
            #pragma unroll
            for(int kx=0;kx<3;kx++){ int xx=x+kx-1; if((unsigned)xx>=64u) continue;
                s = fmaf(ww[74+ky*3+kx], pl[yy][xx], s); } }
        yp[(long)bc*4096 + i] = s;
    }
}

// ---------------- final output: (cls[8,512], feat[8,4096,512]) ----------------
__global__ void k_writeout(const float* __restrict__ h2, float* __restrict__ out){
    long idx = (long)blockIdx.x*256 + threadIdx.x;
    if(idx >= 8L*512 + 8L*4096*512) return;
    if(idx < 8*512){
        int b = (int)(idx >> 9), c = (int)(idx & 511);
        out[idx] = h2[((long)b*4097)*512 + c];
    } else {
        long r = idx - 4096;
        int c = (int)(r & 511); long q = r >> 9; int t = (int)(q % 4096); int b = (int)(q / 4096);
        out[idx] = h2[((long)b*4097 + 1 + t)*512 + c];
    }
}

// ================= host side =================
struct Ptrs {
    float *h,*h2,*xp,*qkv,*ql,*kl,*a2,*zA,*zB,*xz,*t1,*t2,*a3v,*tmp2,*ac,*cnn,*yp;
};

static void get_ptrs(Ptrs& p){
    cudaGetSymbolAddress((void**)&p.h,    g_h);
    cudaGetSymbolAddress((void**)&p.h2,   g_h2);
    cudaGetSymbolAddress((void**)&p.xp,   g_xp);
    cudaGetSymbolAddress((void**)&p.qkv,  g_qkv);
    cudaGetSymbolAddress((void**)&p.ql,   g_ql);
    cudaGetSymbolAddress((void**)&p.kl,   g_kl);
    cudaGetSymbolAddress((void**)&p.a2,   g_a2);
    cudaGetSymbolAddress((void**)&p.zA,   g_zA);
    cudaGetSymbolAddress((void**)&p.zB,   g_zB);
    cudaGetSymbolAddress((void**)&p.xz,   g_xz);
    cudaGetSymbolAddress((void**)&p.t1,   g_t1);
    cudaGetSymbolAddress((void**)&p.t2,   g_t2);
    cudaGetSymbolAddress((void**)&p.a3v,  g_a3v);
    cudaGetSymbolAddress((void**)&p.tmp2, g_tmp2);
    cudaGetSymbolAddress((void**)&p.ac,   g_ac);
    cudaGetSymbolAddress((void**)&p.cnn,  g_cnn);
    cudaGetSymbolAddress((void**)&p.yp,   g_yp);
}

static void attention(Ptrs& p, float* hbuf,
                      const float* lng, const float* lnb,
                      const float* qkvw, const float* outw, const float* outb,
                      const float* resw)
{
    const long SQKV_B = 4352L*1536;
    const long SQL    = 256L*64;
    const long SA2    = 65536L;
    const long SV64   = 256L*64;

    k_ln<<<8*4097, 256>>>(hbuf, lng, lnb, p.xp);

    // qkv = xp @ qkv_w^T   (34816 x 1536 x 512)
    k_mma_nt<<<dim3(272,12,1), 256>>>(p.xp, 512, 0,0, qkvw, 512, 0,0,
                                      p.qkv, 1536, 0,0, 34816, 1536, 512, 1.f, nullptr, 0);

    k_landmarks<<<64*256, 64>>>(p.qkv, p.ql, p.kl);

    // a2 = softmax(q_l @ k_l^T) fused : (256 x 256)
    k_simsm<<<dim3(4,1,64), 256>>>(p.ql, 64, 8*SQL, SQL,
                                   p.kl, 64, 8*SQL, SQL,
                                   p.a2, 256, 8*SA2, SA2, 1.f);

    // a3v = softmax(q_l @ k^T) @ v, flash-fused
    k_flash3<<<dim3(4,1,64), 256, 55040>>>(p.ql, SQL, p.qkv, SQKV_B, p.a3v, SV64);

    // ---- Moore-Penrose pinv of a2 (6 iterations, idm fused in epilogues) ----
    k_scal_init<<<1, 32>>>();
    k_rowsum_max<<<64*256, 256>>>(p.a2);
    k_colsum_max<<<64, 256>>>(p.a2);
    k_tr_scale<<<16384, 256>>>(p.a2, p.zA);

    float* zc = p.zA; float* zn = p.zB;
    for(int it=0; it<6; it++){
        k_mma_nn<<<dim3(2,2,64), 256>>>(p.a2, 256, 8*SA2, SA2, zc, 256, 8*SA2, SA2,
                                        p.xz, 256, 8*SA2, SA2, p.t1, 8*SA2, SA2,
                                        256,256,256, 1.f, 7.f, 0);
        k_mma_nn<<<dim3(2,2,64), 256>>>(p.xz, 256, 8*SA2, SA2, p.t1, 256, 8*SA2, SA2,
                                        p.t2, 256, 8*SA2, SA2, nullptr, 0,0,
                                        256,256,256, 1.f, 15.f, 1);
        k_mma_nn<<<dim3(2,2,64), 256>>>(p.xz, 256, 8*SA2, SA2, p.t2, 256, 8*SA2, SA2,
                                        p.t1, 256, 8*SA2, SA2, nullptr, 0,0,
                                        256,256,256, 1.f, 13.f, 1);
        k_mma_nn<<<dim3(2,2,64), 256>>>(zc, 256, 8*SA2, SA2, p.t1, 256, 8*SA2, SA2,
                                        zn, 256, 8*SA2, SA2, nullptr, 0,0,
                                        256,256,256, 0.25f, 0.f, 0);
        float* tmp = zc; zc = zn; zn = tmp;
    }

    // tmp2 = z @ a3v : (256 x 64 x 256)   [TF32]
    k_mma_nn64<<<dim3(2,1,64), 256>>>(zc, 256, 8*SA2, SA2, p.a3v, 64, 8*SV64, SV64,
                                      p.tmp2, 64, 8*SV64, SV64, 256, 256, 1.f, 0);

    // ac = softmax(q*scale @ kl^T) @ tmp2, fused, direct token-major
    k_attnout<<<dim3(68,1,64), 256>>>(p.qkv, 1536, SQKV_B, 64,
                                      p.kl, SQL, p.tmp2, SV64,
                                      p.ac, 0.125f);

    // residual depthwise conv (k=33 along sequence) added directly into ac
    k_resconv2<<<dim3(68,64), 256>>>(p.qkv, resw, p.ac);

    // hbuf += ac @ out_w^T + out_b
    k_mma_nt<<<dim3(257,4,1), 256>>>(p.ac, 512, 0,0, outw, 512, 0,0,
                                     hbuf, 512, 0,0, 32776, 512, 512, 1.f, outb, 1);
}

extern "C" void kernel_launch(void* const* d_in, const int* in_sizes, int n_in,
                              void* d_out, int out_size)
{
    const float* features = (const float*)d_in[0];
    const float* cls_tok  = (const float*)d_in[1];
    const float* ln1_g    = (const float*)d_in[2];
    const float* ln1_b    = (const float*)d_in[3];
    const float* qkv1_w   = (const float*)d_in[4];
    const float* out1_w   = (const float*)d_in[5];
    const float* out1_b   = (const float*)d_in[6];
    const float* res1_w   = (const float*)d_in[7];
    const float* p7_w     = (const float*)d_in[8];
    const float* p7_b     = (const float*)d_in[9];
    const float* p5_w     = (const float*)d_in[10];
    const float* p5_b     = (const float*)d_in[11];
    const float* p3_w     = (const float*)d_in[12];
    const float* p3_b     = (const float*)d_in[13];
    const float* ln2_g    = (const float*)d_in[14];
    const float* ln2_b    = (const float*)d_in[15];
    const float* qkv2_w   = (const float*)d_in[16];
    const float* out2_w   = (const float*)d_in[17];
    const float* out2_b   = (const float*)d_in[18];
    const float* res2_w   = (const float*)d_in[19];
    float* out = (float*)d_out;

    cudaFuncSetAttribute(k_flash3, cudaFuncAttributeMaxDynamicSharedMemorySize, 55040);

    Ptrs p;
    get_ptrs(p);

    k_build_h<<<65552, 256>>>(features, cls_tok);
    k_zero_pad<<<4080, 256>>>(p.xp);     // pad rows stay zero for both blocks

    attention(p, p.h, ln1_g, ln1_b, qkv1_w, out1_w, out1_b, res1_w);

    k_h2planar<<<dim3(16,128,8), dim3(32,8)>>>(p.h, p.cnn);
    k_dwconv<<<4096, 256>>>(p.cnn, p7_w, p7_b, p5_w, p5_b, p3_w, p3_b, p.yp);
    k_planar2h<<<dim3(16,128,8), dim3(32,8)>>>(p.yp, p.h2);
    k_cls_copy<<<16, 256>>>(p.h, p.h2);

    attention(p, p.h2, ln2_g, ln2_b, qkv2_w, out2_w, out2_b, res2_w);

    k_writeout<<<65552, 256>>>(p.h2, out);
}

// round 14
// speedup vs baseline: 1.5541x; 1.0343x over previous
#include <cuda_runtime.h>
#include <math.h>
#include <stdint.h>

// ---------------- problem constants ----------------
// B=8, C=512, HEADS=8, DH=64, tokens=4097 (cls+4096), pad=255 -> N=4352
// landmarks m=256, l=17, pinv iters=6, res kernel 33  (build r14: side-stream overlap)
#define LSUB 17

// ---------------- device scratch ----------------
__device__ float g_h   [8L*4097*512];
__device__ float g_h2  [8L*4097*512];
__device__ float g_xp  [8L*4352*512];
__device__ float g_qkv [8L*4352*1536];
__device__ float g_ql  [64L*256*64];
__device__ float g_kl  [64L*256*64];
__device__ float g_a2  [64L*256*256];
__device__ float g_zA  [64L*256*256];
__device__ float g_zB  [64L*256*256];
__device__ float g_xz  [64L*256*256];
__device__ float g_t1  [64L*256*256];
__device__ float g_t2  [64L*256*256];
__device__ float g_a3v [64L*256*64];
__device__ float g_tmp2[64L*256*64];
__device__ float g_ac  [8L*4097*512];
__device__ float g_cnn [8L*512*4096];
__device__ float g_yp  [8L*512*4096];
__device__ float g_scal[2];

__device__ __forceinline__ float4 ldg4(const float* p){ return *(const float4*)p; }

// ---------------- tf32 mma helpers ----------------
__device__ __forceinline__ uint32_t f2tf(float x){
    uint32_t u; asm("cvt.rna.tf32.f32 %0, %1;" : "=r"(u) : "f"(x)); return u;
}
__device__ __forceinline__ uint4 cvt4(float4 v){
    uint4 u; u.x=f2tf(v.x); u.y=f2tf(v.y); u.z=f2tf(v.z); u.w=f2tf(v.w); return u;
}
__device__ __forceinline__ void mma8(float* d, const uint32_t* a, const uint32_t* b){
    asm("mma.sync.aligned.m16n8k8.row.col.f32.tf32.tf32.f32 "
        "{%0,%1,%2,%3}, {%4,%5,%6,%7}, {%8,%9}, {%0,%1,%2,%3};"
        : "+f"(d[0]),"+f"(d[1]),"+f"(d[2]),"+f"(d[3])
        : "r"(a[0]),"r"(a[1]),"r"(a[2]),"r"(a[3]), "r"(b[0]),"r"(b[1]));
}

// Fragment-major scatter (for k_mma_nn64): element (row,k) of 128x16 A tile
__device__ __forceinline__ void scatA(uint32_t* Af, int row, int k, uint32_t v){
    int ks=k>>3, kc=k&7;
    Af[(((ks<<3)+(row>>4))<<7) + ((((row&7)<<2)+(kc&3))<<2) + ((row>>3)&1) + ((kc>>2)<<1)] = v;
}
// B tile with 8 n-tiles (64 cols)
__device__ __forceinline__ void scatB8(uint32_t* Bf, int n, int k, uint32_t v){
    int ks=k>>3, kc=k&7;
    Bf[(((ks<<3)+(n>>3))<<6) + ((((n&7)<<2)+(kc&3))<<1) + (kc>>2)] = v;
}

// ---------------- small kernels ----------------
__global__ void k_build_h(const float* __restrict__ feat, const float* __restrict__ cls){
    long idx = (long)blockIdx.x*256 + threadIdx.x;
    if(idx >= 8L*4097*512) return;
    int c = idx & 511; long r = idx >> 9; int t = (int)(r % 4097); int b = (int)(r / 4097);
    g_h[idx] = (t==0) ? cls[c] : feat[((long)b*4096 + (t-1))*512 + c];
}

__global__ void k_zero_pad(float* __restrict__ xp){
    long idx = (long)blockIdx.x*256 + threadIdx.x;
    if(idx >= 8L*255*512) return;
    int c = idx & 511; long r = idx >> 9; int t = (int)(r % 255); int b = (int)(r / 255);
    xp[((long)b*4352 + t)*512 + c] = 0.f;
}

__global__ void k_ln(const float* __restrict__ h, const float* __restrict__ g,
                     const float* __restrict__ be, float* __restrict__ xp){
    long r = blockIdx.x;
    int b = (int)(r / 4097); int t = (int)(r % 4097);
    const float* x = h + r*512;
    float* y = xp + ((long)b*4352 + 255 + t)*512;
    int tid = threadIdx.x;
    __shared__ float red[256];
    float s = 0.f;
    for(int i=tid;i<512;i+=256) s += x[i];
    red[tid]=s; __syncthreads();
    for(int k=128;k;k>>=1){ if(tid<k) red[tid]+=red[tid+k]; __syncthreads(); }
    float mean = red[0] * (1.f/512.f); __syncthreads();
    float v = 0.f;
    for(int i=tid;i<512;i+=256){ float d=x[i]-mean; v += d*d; }
    red[tid]=v; __syncthreads();
    for(int k=128;k;k>>=1){ if(tid<k) red[tid]+=red[tid+k]; __syncthreads(); }
    float rstd = rsqrtf(red[0]*(1.f/512.f) + 1e-5f);
    for(int i=tid;i<512;i+=256) y[i] = (x[i]-mean)*rstd*g[i] + be[i];
}

// =====================================================================
// TF32 tensor-core GEMMs: 128x128 block, 8 warps of 64x32, BK=16,
// 2-stage smem double buffer (one sync per ktile)
// =====================================================================

// C = alpha * A @ B^T (+bias)(+C)   A:(M,K) lda, B:(N,K) ldb   batched (b,h)
__global__ void __launch_bounds__(256,2) k_mma_nt(
    const float* __restrict__ A, int lda, long sAb, long sAh,
    const float* __restrict__ B, int ldb, long sBb, long sBh,
    float* __restrict__ C, int ldc, long sCb, long sCh,
    int M, int N, int K, float alpha, const float* __restrict__ bias, int acc)
{
    int z = blockIdx.z; int hh = z & 7; int bb = z >> 3;
    A += (long)bb*sAb + (long)hh*sAh;
    B += (long)bb*sBb + (long)hh*sBh;
    C += (long)bb*sCb + (long)hh*sCh;
    __shared__ uint32_t As[2][128][20];
    __shared__ uint32_t Bs[2][128][20];
    int t = threadIdx.x;
    int lane = t & 31, warp = t >> 5;
    int wm = warp >> 2, wn = warp & 3;
    int r0 = blockIdx.x*128, c0 = blockIdx.y*128;
    int lrow = t >> 2, lk = (t & 3)*4;
    const float* Ap0 = A + (long)(r0+lrow)*lda + lk;
    const float* Ap1 = A + (long)(r0+lrow+64)*lda + lk;
    const float* Bp0 = B + (long)(c0+lrow)*ldb + lk;
    const float* Bp1 = B + (long)(c0+lrow+64)*ldb + lk;
    bool mA0 = (r0+lrow)<M, mA1 = (r0+lrow+64)<M;
    bool mB0 = (c0+lrow)<N, mB1 = (c0+lrow+64)<N;
    const float4 z4 = make_float4(0.f,0.f,0.f,0.f);
    float4 pa0 = mA0?ldg4(Ap0):z4, pa1 = mA1?ldg4(Ap1):z4;
    float4 pb0 = mB0?ldg4(Bp0):z4, pb1 = mB1?ldg4(Bp1):z4;
    *(uint4*)&As[0][lrow][lk]    = cvt4(pa0);
    *(uint4*)&As[0][lrow+64][lk] = cvt4(pa1);
    *(uint4*)&Bs[0][lrow][lk]    = cvt4(pb0);
    *(uint4*)&Bs[0][lrow+64][lk] = cvt4(pb1);
    __syncthreads();
    float accr[4][4][4];
    #pragma unroll
    for(int i=0;i<4;i++)
        #pragma unroll
        for(int j=0;j<4;j++)
            #pragma unroll
            for(int q=0;q<4;q++) accr[i][j][q]=0.f;
    int nk = K >> 4;
    for(int kt=0; kt<nk; kt++){
        int buf = kt & 1;
        if(kt+1<nk){
            int o = (kt+1)*16;
            pa0 = mA0?ldg4(Ap0+o):z4; pa1 = mA1?ldg4(Ap1+o):z4;
            pb0 = mB0?ldg4(Bp0+o):z4; pb1 = mB1?ldg4(Bp1+o):z4;
        }
        #pragma unroll
        for(int ks=0;ks<2;ks++){
            int cc = ks*8 + (lane&3);
            uint32_t a[4][4], b[4][2];
            int rA = wm*64 + (lane>>2);
            #pragma unroll
            for(int mt=0;mt<4;mt++){
                a[mt][0]=As[buf][rA+mt*16  ][cc];
                a[mt][1]=As[buf][rA+mt*16+8][cc];
                a[mt][2]=As[buf][rA+mt*16  ][cc+4];
                a[mt][3]=As[buf][rA+mt*16+8][cc+4];
            }
            int rB = wn*32 + (lane>>2);
            #pragma unroll
            for(int nt=0;nt<4;nt++){
                b[nt][0]=Bs[buf][rB+nt*8][cc];
                b[nt][1]=Bs[buf][rB+nt*8][cc+4];
            }
            #pragma unroll
            for(int mt=0;mt<4;mt++)
                #pragma unroll
                for(int nt=0;nt<4;nt++)
                    mma8(accr[mt][nt], a[mt], b[nt]);
        }
        if(kt+1<nk){
            int s = (kt+1) & 1;
            *(uint4*)&As[s][lrow][lk]    = cvt4(pa0);
            *(uint4*)&As[s][lrow+64][lk] = cvt4(pa1);
            *(uint4*)&Bs[s][lrow][lk]    = cvt4(pb0);
            *(uint4*)&Bs[s][lrow+64][lk] = cvt4(pb1);
            __syncthreads();
        }
    }
    #pragma unroll
    for(int mt=0;mt<4;mt++)
    #pragma unroll
    for(int i=0;i<2;i++){
        int gm = r0 + wm*64 + mt*16 + i*8 + (lane>>2);
        if(gm>=M) continue;
        #pragma unroll
        for(int nt=0;nt<4;nt++){
            int gn = c0 + wn*32 + nt*8 + 2*(lane&3);
            float2 v;
            v.x = alpha*accr[mt][nt][2*i];
            v.y = alpha*accr[mt][nt][2*i+1];
            if(bias){ v.x += bias[gn]; v.y += bias[gn+1]; }
            float* cp = C + (long)gm*ldc + gn;
            if(acc){ v.x += cp[0]; v.y += cp[1]; }
            *(float2*)cp = v;
        }
    }
}

// Fused GEMM+softmax: C = softmax_row(alpha * A @ B^T), K=64, N=256.
__global__ void __launch_bounds__(256,2) k_simsm(
    const float* __restrict__ A, int lda, long sAb, long sAh,
    const float* __restrict__ B, int ldb, long sBb, long sBh,
    float* __restrict__ C, int ldc, long sCb, long sCh,
    float alpha)
{
    int z = blockIdx.z; int hh = z & 7; int bb = z >> 3;
    A += (long)bb*sAb + (long)hh*sAh;
    B += (long)bb*sBb + (long)hh*sBh;
    C += (long)bb*sCb + (long)hh*sCh;
    __shared__ uint32_t As[64][20];
    __shared__ uint32_t Bs[256][20];
    __shared__ float red[64][4];
    int t = threadIdx.x;
    int lane = t & 31, warp = t >> 5;
    int wm = warp >> 2, wn = warp & 3;
    int r0 = blockIdx.x*64;
    int lrow = t >> 2, lk = (t & 3)*4;
    float acc[2][8][4];
    #pragma unroll
    for(int i=0;i<2;i++)
        #pragma unroll
        for(int j=0;j<8;j++)
            #pragma unroll
            for(int q=0;q<4;q++) acc[i][j][q]=0.f;
    for(int kt=0; kt<4; kt++){
        __syncthreads();
        *(uint4*)&As[lrow][lk] = cvt4(ldg4(A + (long)(r0+lrow)*lda + kt*16 + lk));
        #pragma unroll
        for(int i=0;i<4;i++)
            *(uint4*)&Bs[i*64+lrow][lk] = cvt4(ldg4(B + (long)(i*64+lrow)*ldb + kt*16 + lk));
        __syncthreads();
        #pragma unroll
        for(int ks=0;ks<2;ks++){
            int cc = ks*8 + (lane&3);
            uint32_t a[2][4], b[8][2];
            int rA = wm*32 + (lane>>2);
            #pragma unroll
            for(int mt=0;mt<2;mt++){
                a[mt][0]=As[rA+mt*16  ][cc];
                a[mt][1]=As[rA+mt*16+8][cc];
                a[mt][2]=As[rA+mt*16  ][cc+4];
                a[mt][3]=As[rA+mt*16+8][cc+4];
            }
            int rB = wn*64 + (lane>>2);
            #pragma unroll
            for(int nt=0;nt<8;nt++){
                b[nt][0]=Bs[rB+nt*8][cc];
                b[nt][1]=Bs[rB+nt*8][cc+4];
            }
            #pragma unroll
            for(int mt=0;mt<2;mt++)
                #pragma unroll
                for(int nt=0;nt<8;nt++)
                    mma8(acc[mt][nt], a[mt], b[nt]);
        }
    }
    int g = lane>>2, tq = lane&3;
    float pm[2][2];
    #pragma unroll
    for(int mt=0;mt<2;mt++)
        #pragma unroll
        for(int i=0;i<2;i++){
            float m = -1e30f;
            #pragma unroll
            for(int nt=0;nt<8;nt++){
                acc[mt][nt][2*i]   *= alpha;
                acc[mt][nt][2*i+1] *= alpha;
                m = fmaxf(m, fmaxf(acc[mt][nt][2*i], acc[mt][nt][2*i+1]));
            }
            m = fmaxf(m, __shfl_xor_sync(0xffffffffu, m, 1));
            m = fmaxf(m, __shfl_xor_sync(0xffffffffu, m, 2));
            pm[mt][i] = m;
        }
    if(tq==0){
        #pragma unroll
        for(int mt=0;mt<2;mt++)
            #pragma unroll
            for(int i=0;i<2;i++)
                red[wm*32+mt*16+i*8+g][wn] = pm[mt][i];
    }
    __syncthreads();
    float rmax[2][2];
    #pragma unroll
    for(int mt=0;mt<2;mt++)
        #pragma unroll
        for(int i=0;i<2;i++){
            int rid = wm*32+mt*16+i*8+g;
            rmax[mt][i] = fmaxf(fmaxf(red[rid][0],red[rid][1]), fmaxf(red[rid][2],red[rid][3]));
        }
    __syncthreads();
    float ps[2][2];
    #pragma unroll
    for(int mt=0;mt<2;mt++)
        #pragma unroll
        for(int i=0;i<2;i++){
            float s = 0.f;
            #pragma unroll
            for(int nt=0;nt<8;nt++){
                float e0 = __expf(acc[mt][nt][2*i]   - rmax[mt][i]);
                float e1 = __expf(acc[mt][nt][2*i+1] - rmax[mt][i]);
                acc[mt][nt][2*i]   = e0;
                acc[mt][nt][2*i+1] = e1;
                s += e0 + e1;
            }
            s += __shfl_xor_sync(0xffffffffu, s, 1);
            s += __shfl_xor_sync(0xffffffffu, s, 2);
            ps[mt][i] = s;
        }
    if(tq==0){
        #pragma unroll
        for(int mt=0;mt<2;mt++)
            #pragma unroll
            for(int i=0;i<2;i++)
                red[wm*32+mt*16+i*8+g][wn] = ps[mt][i];
    }
    __syncthreads();
    #pragma unroll
    for(int mt=0;mt<2;mt++)
        #pragma unroll
        for(int i=0;i<2;i++){
            int rid = wm*32+mt*16+i*8+g;
            float inv = 1.f/(red[rid][0]+red[rid][1]+red[rid][2]+red[rid][3]);
            long gm = r0 + rid;
            #pragma unroll
            for(int nt=0;nt<8;nt++){
                int gn = wn*64 + nt*8 + 2*tq;
                float2 v; v.x = acc[mt][nt][2*i]*inv; v.y = acc[mt][nt][2*i+1]*inv;
                *(float2*)(C + gm*ldc + gn) = v;
            }
        }
}

// =====================================================================
// Flash-style fused sim3+softmax+a3v (proven R12)
// =====================================================================
__global__ void __launch_bounds__(256,2) k_flash3(
    const float* __restrict__ QL, long sQL,
    const float* __restrict__ QKV, long sQKVb,
    float* __restrict__ Ov, long sO)
{
    extern __shared__ char dyn[];
    uint32_t (*Qs)[68] = (uint32_t(*)[68])dyn;
    uint32_t (*Ks)[20] = (uint32_t(*)[20])(dyn + 17408);
    uint32_t (*Pf)[68] = (uint32_t(*)[68])(dyn + 17408);
    uint32_t (*Vs)[72] = (uint32_t(*)[72])(dyn + 17408 + 17408);
    float (*red)[4] = (float(*)[4])(dyn + 53248);
    float* m_run = (float*)(dyn + 54272);
    float* l_run = (float*)(dyn + 54528);
    float* sf    = (float*)(dyn + 54784);
    int z = blockIdx.z; int hh = z & 7; int bb = z >> 3;
    const float* Q  = QL  + (long)z*sQL;
    const float* Kg = QKV + (long)bb*sQKVb + 512  + hh*64;
    const float* Vg = QKV + (long)bb*sQKVb + 1024 + hh*64;
    float* Og = Ov + (long)z*sO;
    int t = threadIdx.x, lane = t & 31, warp = t >> 5;
    int wm = warp >> 2, wn = warp & 3;
    int wm2 = warp >> 1, wn2 = warp & 1;
    int g = lane >> 2, tq = lane & 3;
    int r0 = blockIdx.x*64;
    {
        int row = t >> 2, cb = (t & 3)*16;
        const float* qp = Q + (long)(r0+row)*64 + cb;
        #pragma unroll
        for(int j=0;j<4;j++){
            float4 v = ldg4(qp + j*4);
            Qs[row][cb+j*4+0]=f2tf(v.x); Qs[row][cb+j*4+1]=f2tf(v.y);
            Qs[row][cb+j*4+2]=f2tf(v.z); Qs[row][cb+j*4+3]=f2tf(v.w);
        }
    }
    if(t < 64){ m_run[t] = -1e30f; l_run[t] = 0.f; }
    float acc2[4][4];
    #pragma unroll
    for(int j=0;j<4;j++)
        #pragma unroll
        for(int q=0;q<4;q++) acc2[j][q]=0.f;
    for(int ch=0; ch<17; ch++){
        long kc0 = (long)ch*256;
        float acc[2][8][4];
        #pragma unroll
        for(int i=0;i<2;i++)
            #pragma unroll
            for(int j=0;j<8;j++)
                #pragma unroll
                for(int q=0;q<4;q++) acc[i][j][q]=0.f;
        for(int kt=0; kt<4; kt++){
            __syncthreads();
            int lrow = t >> 2, lk = (t & 3)*4;
            #pragma unroll
            for(int i=0;i<4;i++){
                int row = i*64 + lrow;
                *(uint4*)&Ks[row][lk] = cvt4(ldg4(Kg + (kc0+row)*1536 + kt*16 + lk));
            }
            __syncthreads();
            #pragma unroll
            for(int ks=0;ks<2;ks++){
                int cc = ks*8 + tq, qc = kt*16 + cc;
                uint32_t a[2][4], b[8][2];
                int rA = wm*32 + g;
                #pragma unroll
                for(int mt=0;mt<2;mt++){
                    a[mt][0]=Qs[rA+mt*16  ][qc];
                    a[mt][1]=Qs[rA+mt*16+8][qc];
                    a[mt][2]=Qs[rA+mt*16  ][qc+4];
                    a[mt][3]=Qs[rA+mt*16+8][qc+4];
                }
                int rB = wn*64 + g;
                #pragma unroll
                for(int nt=0;nt<8;nt++){
                    b[nt][0]=Ks[rB+nt*8][cc];
                    b[nt][1]=Ks[rB+nt*8][cc+4];
                }
                #pragma unroll
                for(int mt=0;mt<2;mt++)
                    #pragma unroll
                    for(int nt=0;nt<8;nt++)
                        mma8(acc[mt][nt], a[mt], b[nt]);
            }
        }
        float pm[2][2];
        #pragma unroll
        for(int mt=0;mt<2;mt++)
            #pragma unroll
            for(int i=0;i<2;i++){
                float m = -1e30f;
                #pragma unroll
                for(int nt=0;nt<8;nt++)
                    m = fmaxf(m, fmaxf(acc[mt][nt][2*i], acc[mt][nt][2*i+1]));
                m = fmaxf(m, __shfl_xor_sync(0xffffffffu, m, 1));
                m = fmaxf(m, __shfl_xor_sync(0xffffffffu, m, 2));
                pm[mt][i] = m;
            }
        if(tq==0){
            #pragma unroll
            for(int mt=0;mt<2;mt++)
                #pragma unroll
                for(int i=0;i<2;i++)
                    red[wm*32+mt*16+i*8+g][wn] = pm[mt][i];
        }
        __syncthreads();
        float mn_[2][2];
        #pragma unroll
        for(int mt=0;mt<2;mt++)
            #pragma unroll
            for(int i=0;i<2;i++){
                int rid = wm*32+mt*16+i*8+g;
                float cm = fmaxf(fmaxf(red[rid][0],red[rid][1]), fmaxf(red[rid][2],red[rid][3]));
                mn_[mt][i] = fmaxf(m_run[rid], cm);
            }
        __syncthreads();
        float ps[2][2];
        #pragma unroll
        for(int mt=0;mt<2;mt++)
            #pragma unroll
            for(int i=0;i<2;i++){
                float s = 0.f;
                #pragma unroll
                for(int nt=0;nt<8;nt++){
                    float e0 = __expf(acc[mt][nt][2*i]   - mn_[mt][i]);
                    float e1 = __expf(acc[mt][nt][2*i+1] - mn_[mt][i]);
                    acc[mt][nt][2*i]   = e0;
                    acc[mt][nt][2*i+1] = e1;
                    s += e0 + e1;
                }
                s += __shfl_xor_sync(0xffffffffu, s, 1);
                s += __shfl_xor_sync(0xffffffffu, s, 2);
                ps[mt][i] = s;
            }
        if(tq==0){
            #pragma unroll
            for(int mt=0;mt<2;mt++)
                #pragma unroll
                for(int i=0;i<2;i++)
                    red[wm*32+mt*16+i*8+g][wn] = ps[mt][i];
        }
        __syncthreads();
        if(wn==0 && tq==0){
            #pragma unroll
            for(int mt=0;mt<2;mt++)
                #pragma unroll
                for(int i=0;i<2;i++){
                    int rid = wm*32+mt*16+i*8+g;
                    float ct = red[rid][0]+red[rid][1]+red[rid][2]+red[rid][3];
                    float mn = mn_[mt][i];
                    float f  = __expf(m_run[rid] - mn);
                    l_run[rid] = l_run[rid]*f + ct;
                    m_run[rid] = mn;
                    sf[rid] = f;
                }
        }
        __syncthreads();
        #pragma unroll
        for(int i=0;i<2;i++){
            float f2 = sf[wm2*16 + i*8 + g];
            #pragma unroll
            for(int nt=0;nt<4;nt++){ acc2[nt][2*i]*=f2; acc2[nt][2*i+1]*=f2; }
        }
        for(int sub=0; sub<4; sub++){
            __syncthreads();
            if(wn == sub){
                #pragma unroll
                for(int mt=0;mt<2;mt++)
                    #pragma unroll
                    for(int i=0;i<2;i++){
                        int rl = wm*32+mt*16+i*8+g;
                        #pragma unroll
                        for(int nt=0;nt<8;nt++){
                            int cl = nt*8 + 2*tq;
                            Pf[rl][cl]   = f2tf(acc[mt][nt][2*i]);
                            Pf[rl][cl+1] = f2tf(acc[mt][nt][2*i+1]);
                        }
                    }
            }
            {
                int kl = t >> 2, cb = (t & 3)*16;
                const float* vp = Vg + (kc0 + sub*64 + kl)*1536 + cb;
                #pragma unroll
                for(int j=0;j<4;j++){
                    float4 v = ldg4(vp + j*4);
                    Vs[kl][cb+j*4+0]=f2tf(v.x); Vs[kl][cb+j*4+1]=f2tf(v.y);
                    Vs[kl][cb+j*4+2]=f2tf(v.z); Vs[kl][cb+j*4+3]=f2tf(v.w);
                }
            }
            __syncthreads();
            #pragma unroll
            for(int kk=0;kk<8;kk++){
                int cc = kk*8 + tq;
                uint32_t a[4], b[4][2];
                a[0]=Pf[wm2*16+g  ][cc];
                a[1]=Pf[wm2*16+8+g][cc];
                a[2]=Pf[wm2*16+g  ][cc+4];
                a[3]=Pf[wm2*16+8+g][cc+4];
                #pragma unroll
                for(int nt=0;nt<4;nt++){
                    int n = wn2*32 + nt*8 + g;
                    b[nt][0]=Vs[cc  ][n];
                    b[nt][1]=Vs[cc+4][n];
                }
                #pragma unroll
                for(int nt=0;nt<4;nt++)
                    mma8(acc2[nt], a, b[nt]);
            }
        }
    }
    #pragma unroll
    for(int i=0;i<2;i++){
        int row = wm2*16 + i*8 + g;
        float linv = 1.f/l_run[row];
        float* dst = Og + (long)(r0+row)*64;
        #pragma unroll
        for(int nt=0;nt<4;nt++){
            int col = wn2*32 + nt*8 + 2*tq;
            float2 v; v.x = acc2[nt][2*i]*linv; v.y = acc2[nt][2*i+1]*linv;
            *(float2*)(dst + col) = v;
        }
    }
}

// =====================================================================
// Fused attention output: ac[token] += softmax(alpha * q @ kl^T) @ tmp2
// (resconv2 now writes ac first; this adds — sum order preserved exactly)
// =====================================================================
__global__ void __launch_bounds__(256,2) k_attnout(
    const float* __restrict__ Q, int ldq, long sQb, long sQh,
    const float* __restrict__ KL, long sKL,
    const float* __restrict__ T2, long sT2,
    float* __restrict__ AC, float alpha)
{
    int z = blockIdx.z; int hh = z & 7; int bb = z >> 3;
    const float* A = Q  + (long)bb*sQb + (long)hh*sQh;
    const float* B = KL + (long)z*sKL;
    const float* T = T2 + (long)z*sT2;
    __shared__ char smem_raw[35840];
    __shared__ float red[64][4];
    uint32_t (*As)[20] = (uint32_t(*)[20])smem_raw;
    uint32_t (*Bs)[20] = (uint32_t(*)[20])(smem_raw + 5120);
    uint32_t (*Pf)[68] = (uint32_t(*)[68])smem_raw;
    uint32_t (*Ts)[72] = (uint32_t(*)[72])(smem_raw + 17408);
    int t = threadIdx.x;
    int lane = t & 31, warp = t >> 5;
    int wm = warp >> 2, wn = warp & 3;
    int r0 = blockIdx.x*64;
    int lrow = t >> 2, lk = (t & 3)*4;
    int g = lane>>2, tq = lane&3;
    float acc[2][8][4];
    #pragma unroll
    for(int i=0;i<2;i++)
        #pragma unroll
        for(int j=0;j<8;j++)
            #pragma unroll
            for(int q=0;q<4;q++) acc[i][j][q]=0.f;
    for(int kt=0; kt<4; kt++){
        __syncthreads();
        *(uint4*)&As[lrow][lk] = cvt4(ldg4(A + (long)(r0+lrow)*ldq + kt*16 + lk));
        #pragma unroll
        for(int i=0;i<4;i++)
            *(uint4*)&Bs[i*64+lrow][lk] = cvt4(ldg4(B + (long)(i*64+lrow)*64 + kt*16 + lk));
        __syncthreads();
        #pragma unroll
        for(int ks=0;ks<2;ks++){
            int cc = ks*8 + tq;
            uint32_t a[2][4], b[8][2];
            int rA = wm*32 + g;
            #pragma unroll
            for(int mt=0;mt<2;mt++){
                a[mt][0]=As[rA+mt*16  ][cc];
                a[mt][1]=As[rA+mt*16+8][cc];
                a[mt][2]=As[rA+mt*16  ][cc+4];
                a[mt][3]=As[rA+mt*16+8][cc+4];
            }
            int rB = wn*64 + g;
            #pragma unroll
            for(int nt=0;nt<8;nt++){
                b[nt][0]=Bs[rB+nt*8][cc];
                b[nt][1]=Bs[rB+nt*8][cc+4];
            }
            #pragma unroll
            for(int mt=0;mt<2;mt++)
                #pragma unroll
                for(int nt=0;nt<8;nt++)
                    mma8(acc[mt][nt], a[mt], b[nt]);
        }
    }
    float pm[2][2];
    #pragma unroll
    for(int mt=0;mt<2;mt++)
        #pragma unroll
        for(int i=0;i<2;i++){
            float m = -1e30f;
            #pragma unroll
            for(int nt=0;nt<8;nt++){
                acc[mt][nt][2*i]   *= alpha;
                acc[mt][nt][2*i+1] *= alpha;
                m = fmaxf(m, fmaxf(acc[mt][nt][2*i], acc[mt][nt][2*i+1]));
            }
            m = fmaxf(m, __shfl_xor_sync(0xffffffffu, m, 1));
            m = fmaxf(m, __shfl_xor_sync(0xffffffffu, m, 2));
            pm[mt][i] = m;
        }
    if(tq==0){
        #pragma unroll
        for(int mt=0;mt<2;mt++)
            #pragma unroll
            for(int i=0;i<2;i++)
                red[wm*32+mt*16+i*8+g][wn] = pm[mt][i];
    }
    __syncthreads();
    float rmax[2][2];
    #pragma unroll
    for(int mt=0;mt<2;mt++)
        #pragma unroll
        for(int i=0;i<2;i++){
            int rid = wm*32+mt*16+i*8+g;
            rmax[mt][i] = fmaxf(fmaxf(red[rid][0],red[rid][1]), fmaxf(red[rid][2],red[rid][3]));
        }
    __syncthreads();
    float ps[2][2];
    #pragma unroll
    for(int mt=0;mt<2;mt++)
        #pragma unroll
        for(int i=0;i<2;i++){
            float s = 0.f;
            #pragma unroll
            for(int nt=0;nt<8;nt++){
                float e0 = __expf(acc[mt][nt][2*i]   - rmax[mt][i]);
                float e1 = __expf(acc[mt][nt][2*i+1] - rmax[mt][i]);
                acc[mt][nt][2*i]   = e0;
                acc[mt][nt][2*i+1] = e1;
                s += e0 + e1;
            }
            s += __shfl_xor_sync(0xffffffffu, s, 1);
            s += __shfl_xor_sync(0xffffffffu, s, 2);
            ps[mt][i] = s;
        }
    if(tq==0){
        #pragma unroll
        for(int mt=0;mt<2;mt++)
            #pragma unroll
            for(int i=0;i<2;i++)
                red[wm*32+mt*16+i*8+g][wn] = ps[mt][i];
    }
    __syncthreads();
    float inv2[2][2];
    #pragma unroll
    for(int mt=0;mt<2;mt++)
        #pragma unroll
        for(int i=0;i<2;i++){
            int rid = wm*32+mt*16+i*8+g;
            inv2[mt][i] = 1.f/(red[rid][0]+red[rid][1]+red[rid][2]+red[rid][3]);
            #pragma unroll
            for(int nt=0;nt<8;nt++){
                acc[mt][nt][2*i]   *= inv2[mt][i];
                acc[mt][nt][2*i+1] *= inv2[mt][i];
            }
        }
    int wm2 = warp >> 1, wn2 = warp & 1;
    float acc2[4][4];
    #pragma unroll
    for(int j=0;j<4;j++)
        #pragma unroll
        for(int q=0;q<4;q++) acc2[j][q]=0.f;
    for(int ch=0; ch<4; ch++){
        __syncthreads();
        if(wn == ch){
            #pragma unroll
            for(int mt=0;mt<2;mt++)
                #pragma unroll
                for(int i=0;i<2;i++){
                    int row_l = wm*32+mt*16+i*8+g;
                    #pragma unroll
                    for(int nt=0;nt<8;nt++){
                        int col_l = nt*8 + 2*tq;
                        Pf[row_l][col_l]   = f2tf(acc[mt][nt][2*i]);
                        Pf[row_l][col_l+1] = f2tf(acc[mt][nt][2*i+1]);
                    }
                }
        }
        {
            int kl_ = t >> 2, cb = (t & 3)*16;
            const float* Tp = T + (long)(64*ch + kl_)*64 + cb;
            #pragma unroll
            for(int j=0;j<4;j++){
                float4 v = ldg4(Tp + j*4);
                Ts[kl_][cb+j*4+0] = f2tf(v.x);
                Ts[kl_][cb+j*4+1] = f2tf(v.y);
                Ts[kl_][cb+j*4+2] = f2tf(v.z);
                Ts[kl_][cb+j*4+3] = f2tf(v.w);
            }
        }
        __syncthreads();
        #pragma unroll
        for(int kk=0;kk<8;kk++){
            int cc = kk*8 + tq;
            uint32_t a[4], b[4][2];
            a[0]=Pf[wm2*16+g  ][cc];
            a[1]=Pf[wm2*16+8+g][cc];
            a[2]=Pf[wm2*16+g  ][cc+4];
            a[3]=Pf[wm2*16+8+g][cc+4];
            #pragma unroll
            for(int nt=0;nt<4;nt++){
                int n = wn2*32 + nt*8 + g;
                b[nt][0]=Ts[cc  ][n];
                b[nt][1]=Ts[cc+4][n];
            }
            #pragma unroll
            for(int nt=0;nt<4;nt++)
                mma8(acc2[nt], a, b[nt]);
        }
    }
    #pragma unroll
    for(int i=0;i<2;i++){
        int gm = r0 + wm2*16 + i*8 + g;
        if(gm < 255) continue;
        float* dst = AC + ((long)bb*4097 + (gm-255))*512 + hh*64;
        #pragma unroll
        for(int nt=0;nt<4;nt++){
            int gn = wn2*32 + nt*8 + 2*tq;
            float2 o = *(float2*)(dst + gn);
            float2 v; v.x = acc2[nt][2*i] + o.x; v.y = acc2[nt][2*i+1] + o.y;
            *(float2*)(dst + gn) = v;
        }
    }
}

// C = alpha * A @ B  (NN), pinv epilogues, 2-stage double buffer.
__global__ void __launch_bounds__(256,2) k_mma_nn(
    const float* __restrict__ A, int lda, long sAb, long sAh,
    const float* __restrict__ B, int ldb, long sBb, long sBh,
    float* __restrict__ C, int ldc, long sCb, long sCh,
    float* __restrict__ D, long sDb, long sDh,
    int M, int N, int K, float alpha, float dconst, int cmode)
{
    int z = blockIdx.z; int hh = z & 7; int bb = z >> 3;
    A += (long)bb*sAb + (long)hh*sAh;
    B += (long)bb*sBb + (long)hh*sBh;
    C += (long)bb*sCb + (long)hh*sCh;
    if(D) D += (long)bb*sDb + (long)hh*sDh;
    __shared__ uint32_t As[2][128][20];
    __shared__ uint32_t Bs[2][16][136];
    int t = threadIdx.x;
    int lane = t & 31, warp = t >> 5;
    int wm = warp >> 2, wn = warp & 3;
    int r0 = blockIdx.x*128, c0 = blockIdx.y*128;
    int lrow = t >> 2, lk = (t & 3)*4;
    int bk = t >> 5, bn = (t & 31)*4;
    const float* Ap0 = A + (long)(r0+lrow)*lda + lk;
    const float* Ap1 = A + (long)(r0+lrow+64)*lda + lk;
    const float* Bq0 = B + (long)bk*ldb + c0 + bn;
    const float* Bq1 = B + (long)(bk+8)*ldb + c0 + bn;
    bool mA0 = (r0+lrow)<M, mA1 = (r0+lrow+64)<M;
    bool mBn = (c0+bn)<N;
    const float4 z4 = make_float4(0.f,0.f,0.f,0.f);
    float4 pa0 = mA0?ldg4(Ap0):z4, pa1 = mA1?ldg4(Ap1):z4;
    float4 pb0 = mBn?ldg4(Bq0):z4, pb1 = mBn?ldg4(Bq1):z4;
    *(uint4*)&As[0][lrow][lk]    = cvt4(pa0);
    *(uint4*)&As[0][lrow+64][lk] = cvt4(pa1);
    *(uint4*)&Bs[0][bk][bn]      = cvt4(pb0);
    *(uint4*)&Bs[0][bk+8][bn]    = cvt4(pb1);
    __syncthreads();
    float accr[4][4][4];
    #pragma unroll
    for(int i=0;i<4;i++)
        #pragma unroll
        for(int j=0;j<4;j++)
            #pragma unroll
            for(int q=0;q<4;q++) accr[i][j][q]=0.f;
    int nk = K >> 4;
    for(int kt=0; kt<nk; kt++){
        int buf = kt & 1;
        if(kt+1<nk){
            long o = (long)(kt+1)*16;
            pa0 = mA0?ldg4(Ap0+o):z4; pa1 = mA1?ldg4(Ap1+o):z4;
            pb0 = mBn?ldg4(Bq0+o*ldb):z4; pb1 = mBn?ldg4(Bq1+o*ldb):z4;
        }
        #pragma unroll
        for(int ks=0;ks<2;ks++){
            int cc = ks*8 + (lane&3);
            uint32_t a[4][4], b[4][2];
            int rA = wm*64 + (lane>>2);
            #pragma unroll
            for(int mt=0;mt<4;mt++){
                a[mt][0]=As[buf][rA+mt*16  ][cc];
                a[mt][1]=As[buf][rA+mt*16+8][cc];
                a[mt][2]=As[buf][rA+mt*16  ][cc+4];
                a[mt][3]=As[buf][rA+mt*16+8][cc+4];
            }
            int nB = wn*32 + (lane>>2);
            #pragma unroll
            for(int nt=0;nt<4;nt++){
                b[nt][0]=Bs[buf][cc  ][nB+nt*8];
                b[nt][1]=Bs[buf][cc+4][nB+nt*8];
            }
            #pragma unroll
            for(int mt=0;mt<4;mt++)
                #pragma unroll
                for(int nt=0;nt<4;nt++)
                    mma8(accr[mt][nt], a[mt], b[nt]);
        }
        if(kt+1<nk){
            int s = (kt+1) & 1;
            *(uint4*)&As[s][lrow][lk]    = cvt4(pa0);
            *(uint4*)&As[s][lrow+64][lk] = cvt4(pa1);
            *(uint4*)&Bs[s][bk][bn]      = cvt4(pb0);
            *(uint4*)&Bs[s][bk+8][bn]    = cvt4(pb1);
            __syncthreads();
        }
    }
    #pragma unroll
    for(int mt=0;mt<4;mt++)
    #pragma unroll
    for(int i=0;i<2;i++){
        int gm = r0 + wm*64 + mt*16 + i*8 + (lane>>2);
        if(gm>=M) continue;
        #pragma unroll
        for(int nt=0;nt<4;nt++){
            int gn = c0 + wn*32 + nt*8 + 2*(lane&3);
            float2 v;
            v.x = alpha*accr[mt][nt][2*i];
            v.y = alpha*accr[mt][nt][2*i+1];
            long o = (long)gm*ldc + gn;
            if(D){
                float2 dv;
                dv.x = ((gm==gn  )?dconst:0.f) - v.x;
                dv.y = ((gm==gn+1)?dconst:0.f) - v.y;
                *(float2*)(D+o) = dv;
            }
            if(cmode){
                v.x = ((gm==gn  )?dconst:0.f) - v.x;
                v.y = ((gm==gn+1)?dconst:0.f) - v.y;
            }
            *(float2*)(C+o) = v;
        }
    }
}

// C = alpha * A @ B (NN, TF32), N=64. 128x64 block, 8 warps of 32x32. (proven)
__global__ void __launch_bounds__(256,2) k_mma_nn64(
    const float* __restrict__ A, int lda, long sAb, long sAh,
    const float* __restrict__ B, int ldb, long sBb, long sBh,
    float* __restrict__ C, int ldc, long sCb, long sCh,
    int M, int K, float alpha, int rowLo)
{
    int z = blockIdx.z; int hh = z & 7; int bb = z >> 3;
    A += (long)bb*sAb + (long)hh*sAh;
    B += (long)bb*sBb + (long)hh*sBh;
    C += (long)bb*sCb + (long)hh*sCh;
    __shared__ uint32_t Af[2][2048];
    __shared__ uint32_t Bf[2][1024];
    int t = threadIdx.x, lane = t & 31, warp = t >> 5;
    int wm = warp >> 1, wn = warp & 1;
    int r0 = blockIdx.x*128;
    int alr = t >> 1, alk = (t & 1)*8;
    const float* Ap = A + (long)(r0+alr)*lda + alk;
    bool mA = (r0+alr) < M;
    int bk = t >> 4, bn = (t & 15)*4;
    const float* Bp = B + (long)bk*ldb + bn;
    const float4 z4 = make_float4(0.f,0.f,0.f,0.f);
    float4 a0,a1,b0;
    a0 = mA?ldg4(Ap):z4; a1 = mA?ldg4(Ap+4):z4;
    b0 = ldg4(Bp);
    {
        scatA(Af[0], alr, alk+0, f2tf(a0.x)); scatA(Af[0], alr, alk+1, f2tf(a0.y));
        scatA(Af[0], alr, alk+2, f2tf(a0.z)); scatA(Af[0], alr, alk+3, f2tf(a0.w));
        scatA(Af[0], alr, alk+4, f2tf(a1.x)); scatA(Af[0], alr, alk+5, f2tf(a1.y));
        scatA(Af[0], alr, alk+6, f2tf(a1.z)); scatA(Af[0], alr, alk+7, f2tf(a1.w));
        scatB8(Bf[0], bn+0, bk, f2tf(b0.x)); scatB8(Bf[0], bn+1, bk, f2tf(b0.y));
        scatB8(Bf[0], bn+2, bk, f2tf(b0.z)); scatB8(Bf[0], bn+3, bk, f2tf(b0.w));
    }
    __syncthreads();
    float acc[2][4][4];
    #pragma unroll
    for(int i=0;i<2;i++)
        #pragma unroll
        for(int j=0;j<4;j++)
            #pragma unroll
            for(int q=0;q<4;q++) acc[i][j][q]=0.f;
    int nk = K >> 4;
    for(int kt=0; kt<nk; kt++){
        if(kt+1<nk){
            long o = (long)(kt+1)*16;
            a0 = mA?ldg4(Ap+o):z4; a1 = mA?ldg4(Ap+o+4):z4;
            b0 = ldg4(Bp + o*ldb);
        }
        int buf = kt & 1;
        #pragma unroll
        for(int ks=0;ks<2;ks++){
            uint32_t af[2][4], bfr[4][2];
            #pragma unroll
            for(int mt=0;mt<2;mt++)
                *(uint4*)af[mt] = *(const uint4*)&Af[buf][(((ks<<3)+(wm<<1)+mt)<<7) + (lane<<2)];
            #pragma unroll
            for(int nt=0;nt<4;nt++)
                *(uint2*)bfr[nt] = *(const uint2*)&Bf[buf][(((ks<<3)+(wn<<2)+nt)<<6) + (lane<<1)];
            #pragma unroll
            for(int mt=0;mt<2;mt++)
                #pragma unroll
                for(int nt=0;nt<4;nt++)
                    mma8(acc[mt][nt], af[mt], bfr[nt]);
        }
        if(kt+1<nk){
            int s = (kt+1) & 1;
            scatA(Af[s], alr, alk+0, f2tf(a0.x)); scatA(Af[s], alr, alk+1, f2tf(a0.y));
            scatA(Af[s], alr, alk+2, f2tf(a0.z)); scatA(Af[s], alr, alk+3, f2tf(a0.w));
            scatA(Af[s], alr, alk+4, f2tf(a1.x)); scatA(Af[s], alr, alk+5, f2tf(a1.y));
            scatA(Af[s], alr, alk+6, f2tf(a1.z)); scatA(Af[s], alr, alk+7, f2tf(a1.w));
            scatB8(Bf[s], bn+0, bk, f2tf(b0.x)); scatB8(Bf[s], bn+1, bk, f2tf(b0.y));
            scatB8(Bf[s], bn+2, bk, f2tf(b0.z)); scatB8(Bf[s], bn+3, bk, f2tf(b0.w));
            __syncthreads();
        }
    }
    int g = lane >> 2, tq = lane & 3;
    #pragma unroll
    for(int mt=0;mt<2;mt++)
    #pragma unroll
    for(int i=0;i<2;i++){
        int gm = r0 + wm*32 + mt*16 + i*8 + g;
        if(gm >= M || gm < rowLo) continue;
        #pragma unroll
        for(int nt=0;nt<4;nt++){
            int gn = wn*32 + nt*8 + 2*tq;
            float2 v;
            v.x = alpha*acc[mt][nt][2*i];
            v.y = alpha*acc[mt][nt][2*i+1];
            *(float2*)(C + (long)gm*ldc + gn) = v;
        }
    }
}

// ---------------- landmarks (mean over 17 tokens), q scaled by 1/8 ----------------
__global__ void k_landmarks(const float* __restrict__ qkv, float* __restrict__ ql, float* __restrict__ kl){
    int idx = blockIdx.x;
    int mi = idx % 256; int hh = (idx/256) & 7; int b = idx / (256*8);
    int dh = threadIdx.x;
    float sq=0.f, sk=0.f;
    for(int j=0;j<LSUB;j++){
        long tok = (long)mi*LSUB + j;
        const float* base = qkv + ((long)b*4352 + tok)*1536 + hh*64 + dh;
        sq += base[0];
        sk += base[512];
    }
    long o = (long)idx*64 + dh;
    ql[o] = sq * (0.125f/LSUB);
    kl[o] = sk * (1.0f/LSUB);
}

// ---------------- pinv scalar reductions ----------------
__global__ void k_scal_init(){ if(threadIdx.x < 2) g_scal[threadIdx.x] = 0.f; }

__global__ void k_rowsum_max(const float* __restrict__ X){
    long row = blockIdx.x;
    const float* x = X + row*256;
    int t = threadIdx.x;
    __shared__ float red[256];
    red[t] = fabsf(x[t]); __syncthreads();
    for(int k=128;k;k>>=1){ if(t<k) red[t]+=red[t+k]; __syncthreads(); }
    if(t==0) atomicMax((int*)&g_scal[0], __float_as_int(red[0]));
}

__global__ void k_colsum_max(const float* __restrict__ X){
    int b = blockIdx.x; int j = threadIdx.x;
    const float* x = X + (long)b*65536;
    float s = 0.f;
    for(int i=0;i<256;i++) s += fabsf(x[i*256+j]);
    __shared__ float red[256];
    red[j]=s; __syncthreads();
    for(int k=128;k;k>>=1){ if(j<k) red[j]=fmaxf(red[j],red[j+k]); __syncthreads(); }
    if(j==0) atomicMax((int*)&g_scal[1], __float_as_int(red[0]));
}

__global__ void k_tr_scale(const float* __restrict__ X, float* __restrict__ Z){
    long idx = (long)blockIdx.x*256 + threadIdx.x;
    if(idx >= 64L*65536) return;
    float inv = 1.f/(g_scal[0]*g_scal[1]);
    int j = (int)(idx & 255); int i = (int)((idx>>8) & 255); long b = idx >> 16;
    Z[idx] = X[(b<<16) + ((long)j<<8) + i] * inv;
}

// ---------------- residual depthwise conv (k=33), WRITES token-major into ac ----------------
__global__ void k_resconv2(const float* __restrict__ qkv, const float* __restrict__ w,
                           float* __restrict__ ac){
    int bh = blockIdx.y; int hh = bh & 7; int b = bh >> 3;
    int t0 = blockIdx.x*64;
    __shared__ float sv[96][65];
    __shared__ float sw[33];
    int t = threadIdx.x;
    if(t < 33) sw[t] = w[hh*33 + t];
    const float* vb = qkv + ((long)b*4352)*1536 + 1024 + hh*64;
    for(int i=t;i<96*64;i+=256){
        int tok = t0 - 16 + (i>>6); int dh = i&63;
        sv[i>>6][dh] = (tok>=0 && tok<4352) ? vb[(long)tok*1536 + dh] : 0.f;
    }
    __syncthreads();
    for(int i=t;i<64*64;i+=256){
        int lt = i>>6, dh = i&63;
        int tok = t0 + lt;
        if(tok < 255) continue;
        float s = 0.f;
        #pragma unroll
        for(int j=0;j<33;j++) s = fmaf(sw[j], sv[lt+j][dh], s);
        ac[((long)b*4097 + (tok-255))*512 + hh*64 + dh] = s;
    }
}

// ---------------- transposes token<->planar ----------------
__global__ void k_h2planar(const float* __restrict__ h, float* __restrict__ cnn){
    __shared__ float tile[32][33];
    int b = blockIdx.z;
    int c0 = blockIdx.x*32, p0 = blockIdx.y*32;
    int tx = threadIdx.x, ty = threadIdx.y;
    for(int i=ty;i<32;i+=8)
        tile[i][tx] = h[((long)b*4097 + 1 + p0+i)*512 + c0+tx];
    __syncthreads();
    for(int i=ty;i<32;i+=8)
        cnn[((long)b*512 + c0+i)*4096 + p0+tx] = tile[tx][i];
}

__global__ void k_planar2h(const float* __restrict__ yp, float* __restrict__ h2){
    __shared__ float tile[32][33];
    int b = blockIdx.z;
    int c0 = blockIdx.x*32, p0 = blockIdx.y*32;
    int tx = threadIdx.x, ty = threadIdx.y;
    for(int i=ty;i<32;i+=8)
        tile[i][tx] = yp[((long)b*512 + c0+i)*4096 + p0+tx];
    __syncthreads();
    for(int i=ty;i<32;i+=8)
        h2[((long)b*4097 + 1 + p0+i)*512 + c0+tx] = tile[tx][i];
}

__global__ void k_cls_copy(const float* __restrict__ h, float* __restrict__ h2){
    int idx = blockIdx.x*256 + threadIdx.x;
    if(idx >= 8*512) return;
    int b = idx >> 9, c = idx & 511;
    h2[(long)b*4097*512 + c] = h[(long)b*4097*512 + c];
}

// ---------------- fused 7x7 + 5x5 + 3x3 depthwise conv, planar ----------------
__global__ void k_dwconv(const float* __restrict__ cnn,
                         const float* __restrict__ w7, const float* __restrict__ b7,
                         const float* __restrict__ w5, const float* __restrict__ b5,
                         const float* __restrict__ w3, const float* __restrict__ b3,
                         float* __restrict__ yp){
    int bc = blockIdx.x; int c = bc & 511;
    __shared__ float pl[64][65];
    __shared__ float ww[84];
    const float* in = cnn + (long)bc*4096;
    int t = threadIdx.x;
    for(int i=t;i<4096;i+=256) pl[i>>6][i&63] = in[i];
    if(t < 49)      ww[t]      = w7[c*49 + t];
    else if(t < 74) ww[t]      = w5[c*25 + t - 49];
    else if(t < 83) ww[t]      = w3[c*9  + t - 74];
    __syncthreads();
    float bias = b7[c] + b5[c] + b3[c];
    for(int i=t;i<4096;i+=256){
        int y = i >> 6, x = i & 63;
        float s = pl[y][x] + bias;
        #pragma unroll
        for(int ky=0;ky<7;ky++){ int yy=y+ky-3; if((unsigned)yy>=64u) continue;
            #pragma unroll
            for(int kx=0;kx<7;kx++){ int xx=x+kx-3; if((unsigned)xx>=64u) continue;
                s = fmaf(ww[ky*7+kx], pl[yy][xx], s); } }
        #pragma unroll
        for(int ky=0;ky<5;ky++){ int yy=y+ky-2; if((unsigned)yy>=64u) continue;
            #pragma unroll
            for(int kx=0;kx<5;kx++){ int xx=x+kx-2; if((unsigned)xx>=64u) continue;
                s = fmaf(ww[49+ky*5+kx], pl[yy][xx], s); } }
        #pragma unroll
        for(int ky=0;ky<3;ky++){ int yy=y+ky-1; if((unsigned)yy>=64u) continue;
            #pragma unroll
            for(int kx=0;kx<3;kx++){ int xx=x+kx-1; if((unsigned)xx>=64u) continue;
                s = fmaf(ww[74+ky*3+kx], pl[yy][xx], s); } }
        yp[(long)bc*4096 + i] = s;
    }
}

// ---------------- final output: (cls[8,512], feat[8,4096,512]) ----------------
__global__ void k_writeout(const float* __restrict__ h2, float* __restrict__ out){
    long idx = (long)blockIdx.x*256 + threadIdx.x;
    if(idx >= 8L*512 + 8L*4096*512) return;
    if(idx < 8*512){
        int b = (int)(idx >> 9), c = (int)(idx & 511);
        out[idx] = h2[((long)b*4097)*512 + c];
    } else {
        long r = idx - 4096;
        int c = (int)(r & 511); long q = r >> 9; int t = (int)(q % 4096); int b = (int)(q / 4096);
        out[idx] = h2[((long)b*4097 + 1 + t)*512 + c];
    }
}

// ================= host side =================
struct Ptrs {
    float *h,*h2,*xp,*qkv,*ql,*kl,*a2,*zA,*zB,*xz,*t1,*t2,*a3v,*tmp2,*ac,*cnn,*yp;
};

static void get_ptrs(Ptrs& p){
    cudaGetSymbolAddress((void**)&p.h,    g_h);
    cudaGetSymbolAddress((void**)&p.h2,   g_h2);
    cudaGetSymbolAddress((void**)&p.xp,   g_xp);
    cudaGetSymbolAddress((void**)&p.qkv,  g_qkv);
    cudaGetSymbolAddress((void**)&p.ql,   g_ql);
    cudaGetSymbolAddress((void**)&p.kl,   g_kl);
    cudaGetSymbolAddress((void**)&p.a2,   g_a2);
    cudaGetSymbolAddress((void**)&p.zA,   g_zA);
    cudaGetSymbolAddress((void**)&p.zB,   g_zB);
    cudaGetSymbolAddress((void**)&p.xz,   g_xz);
    cudaGetSymbolAddress((void**)&p.t1,   g_t1);
    cudaGetSymbolAddress((void**)&p.t2,   g_t2);
    cudaGetSymbolAddress((void**)&p.a3v,  g_a3v);
    cudaGetSymbolAddress((void**)&p.tmp2, g_tmp2);
    cudaGetSymbolAddress((void**)&p.ac,   g_ac);
    cudaGetSymbolAddress((void**)&p.cnn,  g_cnn);
    cudaGetSymbolAddress((void**)&p.yp,   g_yp);
}

static void attention(Ptrs& p, float* hbuf,
                      const float* lng, const float* lnb,
                      const float* qkvw, const float* outw, const float* outb,
                      const float* resw,
                      cudaStream_t side, cudaEvent_t evFork, cudaEvent_t evA3v, cudaEvent_t evJoin)
{
    const long SQKV_B = 4352L*1536;
    const long SQL    = 256L*64;
    const long SA2    = 65536L;
    const long SV64   = 256L*64;

    k_ln<<<8*4097, 256>>>(hbuf, lng, lnb, p.xp);

    // qkv = xp @ qkv_w^T   (34816 x 1536 x 512)
    k_mma_nt<<<dim3(272,12,1), 256>>>(p.xp, 512, 0,0, qkvw, 512, 0,0,
                                      p.qkv, 1536, 0,0, 34816, 1536, 512, 1.f, nullptr, 0);

    k_landmarks<<<64*256, 64>>>(p.qkv, p.ql, p.kl);

    // ---- fork: flash3 + resconv2 run on side stream, overlapping the pinv chain ----
    cudaEventRecord(evFork, 0);
    cudaStreamWaitEvent(side, evFork, 0);
    k_flash3<<<dim3(4,1,64), 256, 55040, side>>>(p.ql, SQL, p.qkv, SQKV_B, p.a3v, SV64);
    cudaEventRecord(evA3v, side);
    k_resconv2<<<dim3(68,64), 256, 0, side>>>(p.qkv, resw, p.ac);
    cudaEventRecord(evJoin, side);

    // ---- legacy stream: a2 softmax + pinv chain ----
    k_simsm<<<dim3(4,1,64), 256>>>(p.ql, 64, 8*SQL, SQL,
                                   p.kl, 64, 8*SQL, SQL,
                                   p.a2, 256, 8*SA2, SA2, 1.f);
    k_scal_init<<<1, 32>>>();
    k_rowsum_max<<<64*256, 256>>>(p.a2);
    k_colsum_max<<<64, 256>>>(p.a2);
    k_tr_scale<<<16384, 256>>>(p.a2, p.zA);

    float* zc = p.zA; float* zn = p.zB;
    for(int it=0; it<6; it++){
        k_mma_nn<<<dim3(2,2,64), 256>>>(p.a2, 256, 8*SA2, SA2, zc, 256, 8*SA2, SA2,
                                        p.xz, 256, 8*SA2, SA2, p.t1, 8*SA2, SA2,
                                        256,256,256, 1.f, 7.f, 0);
        k_mma_nn<<<dim3(2,2,64), 256>>>(p.xz, 256, 8*SA2, SA2, p.t1, 256, 8*SA2, SA2,
                                        p.t2, 256, 8*SA2, SA2, nullptr, 0,0,
                                        256,256,256, 1.f, 15.f, 1);
        k_mma_nn<<<dim3(2,2,64), 256>>>(p.xz, 256, 8*SA2, SA2, p.t2, 256, 8*SA2, SA2,
                                        p.t1, 256, 8*SA2, SA2, nullptr, 0,0,
                                        256,256,256, 1.f, 13.f, 1);
        k_mma_nn<<<dim3(2,2,64), 256>>>(zc, 256, 8*SA2, SA2, p.t1, 256, 8*SA2, SA2,
                                        zn, 256, 8*SA2, SA2, nullptr, 0,0,
                                        256,256,256, 0.25f, 0.f, 0);
        float* tmp = zc; zc = zn; zn = tmp;
    }

    // join a3v before tmp2
    cudaStreamWaitEvent(0, evA3v, 0);
    k_mma_nn64<<<dim3(2,1,64), 256>>>(zc, 256, 8*SA2, SA2, p.a3v, 64, 8*SV64, SV64,
                                      p.tmp2, 64, 8*SV64, SV64, 256, 256, 1.f, 0);

    // join resconv2 before attnout (attnout adds into ac)
    cudaStreamWaitEvent(0, evJoin, 0);
    k_attnout<<<dim3(68,1,64), 256>>>(p.qkv, 1536, SQKV_B, 64,
                                      p.kl, SQL, p.tmp2, SV64,
                                      p.ac, 0.125f);

    // hbuf += ac @ out_w^T + out_b
    k_mma_nt<<<dim3(257,4,1), 256>>>(p.ac, 512, 0,0, outw, 512, 0,0,
                                     hbuf, 512, 0,0, 32776, 512, 512, 1.f, outb, 1);
}

extern "C" void kernel_launch(void* const* d_in, const int* in_sizes, int n_in,
                              void* d_out, int out_size)
{
    const float* features = (const float*)d_in[0];
    const float* cls_tok  = (const float*)d_in[1];
    const float* ln1_g    = (const float*)d_in[2];
    const float* ln1_b    = (const float*)d_in[3];
    const float* qkv1_w   = (const float*)d_in[4];
    const float* out1_w   = (const float*)d_in[5];
    const float* out1_b   = (const float*)d_in[6];
    const float* res1_w   = (const float*)d_in[7];
    const float* p7_w     = (const float*)d_in[8];
    const float* p7_b     = (const float*)d_in[9];
    const float* p5_w     = (const float*)d_in[10];
    const float* p5_b     = (const float*)d_in[11];
    const float* p3_w     = (const float*)d_in[12];
    const float* p3_b     = (const float*)d_in[13];
    const float* ln2_g    = (const float*)d_in[14];
    const float* ln2_b    = (const float*)d_in[15];
    const float* qkv2_w   = (const float*)d_in[16];
    const float* out2_w   = (const float*)d_in[17];
    const float* out2_b   = (const float*)d_in[18];
    const float* res2_w   = (const float*)d_in[19];
    float* out = (float*)d_out;

    cudaFuncSetAttribute(k_flash3, cudaFuncAttributeMaxDynamicSharedMemorySize, 55040);

    // Side stream + events, created once on first (uncaptured) call. Constant
    // across calls -> identical captured work every capture.
    static cudaStream_t side = nullptr;
    static cudaEvent_t ev[6];
    if(side == nullptr){
        cudaStreamCreateWithFlags(&side, cudaStreamNonBlocking);
        for(int i=0;i<6;i++) cudaEventCreateWithFlags(&ev[i], cudaEventDisableTiming);
    }

    Ptrs p;
    get_ptrs(p);

    k_build_h<<<65552, 256>>>(features, cls_tok);
    k_zero_pad<<<4080, 256>>>(p.xp);     // pad rows stay zero for both blocks

    attention(p, p.h, ln1_g, ln1_b, qkv1_w, out1_w, out1_b, res1_w,
              side, ev[0], ev[1], ev[2]);

    k_h2planar<<<dim3(16,128,8), dim3(32,8)>>>(p.h, p.cnn);
    k_dwconv<<<4096, 256>>>(p.cnn, p7_w, p7_b, p5_w, p5_b, p3_w, p3_b, p.yp);
    k_planar2h<<<dim3(16,128,8), dim3(32,8)>>>(p.yp, p.h2);
    k_cls_copy<<<16, 256>>>(p.h, p.h2);

    attention(p, p.h2, ln2_g, ln2_b, qkv2_w, out2_w, out2_b, res2_w,
              side, ev[3], ev[4], ev[5]);

    k_writeout<<<65552, 256>>>(p.h2, out);
}

// round 15
// speedup vs baseline: 1.5984x; 1.0285x over previous
#include <cuda_runtime.h>
#include <math.h>
#include <stdint.h>

// ---------------- problem constants ----------------
// B=8, C=512, HEADS=8, DH=64, tokens=4097 (cls+4096), pad=255 -> N=4352
// landmarks m=256, l=17, pinv iters=6, res kernel 33  (build r15: LN fused into qkv GEMM)
#define LSUB 17

// ---------------- device scratch ----------------
__device__ float g_h   [8L*4097*512];
__device__ float g_h2  [8L*4097*512];
__device__ float g_stat[8L*4097*2];
__device__ float g_qkv [8L*4352*1536];
__device__ float g_ql  [64L*256*64];
__device__ float g_kl  [64L*256*64];
__device__ float g_a2  [64L*256*256];
__device__ float g_zA  [64L*256*256];
__device__ float g_zB  [64L*256*256];
__device__ float g_xz  [64L*256*256];
__device__ float g_t1  [64L*256*256];
__device__ float g_t2  [64L*256*256];
__device__ float g_a3v [64L*256*64];
__device__ float g_tmp2[64L*256*64];
__device__ float g_ac  [8L*4097*512];
__device__ float g_cnn [8L*512*4096];
__device__ float g_yp  [8L*512*4096];
__device__ float g_scal[2];

__device__ __forceinline__ float4 ldg4(const float* p){ return *(const float4*)p; }

// ---------------- tf32 mma helpers ----------------
__device__ __forceinline__ uint32_t f2tf(float x){
    uint32_t u; asm("cvt.rna.tf32.f32 %0, %1;" : "=r"(u) : "f"(x)); return u;
}
__device__ __forceinline__ uint4 cvt4(float4 v){
    uint4 u; u.x=f2tf(v.x); u.y=f2tf(v.y); u.z=f2tf(v.z); u.w=f2tf(v.w); return u;
}
__device__ __forceinline__ void mma8(float* d, const uint32_t* a, const uint32_t* b){
    asm("mma.sync.aligned.m16n8k8.row.col.f32.tf32.tf32.f32 "
        "{%0,%1,%2,%3}, {%4,%5,%6,%7}, {%8,%9}, {%0,%1,%2,%3};"
        : "+f"(d[0]),"+f"(d[1]),"+f"(d[2]),"+f"(d[3])
        : "r"(a[0]),"r"(a[1]),"r"(a[2]),"r"(a[3]), "r"(b[0]),"r"(b[1]));
}

// Fragment-major scatter (for k_mma_nn64): element (row,k) of 128x16 A tile
__device__ __forceinline__ void scatA(uint32_t* Af, int row, int k, uint32_t v){
    int ks=k>>3, kc=k&7;
    Af[(((ks<<3)+(row>>4))<<7) + ((((row&7)<<2)+(kc&3))<<2) + ((row>>3)&1) + ((kc>>2)<<1)] = v;
}
// B tile with 8 n-tiles (64 cols)
__device__ __forceinline__ void scatB8(uint32_t* Bf, int n, int k, uint32_t v){
    int ks=k>>3, kc=k&7;
    Bf[(((ks<<3)+(n>>3))<<6) + ((((n&7)<<2)+(kc&3))<<1) + (kc>>2)] = v;
}

// ---------------- small kernels ----------------
__global__ void k_build_h(const float* __restrict__ feat, const float* __restrict__ cls){
    long idx = (long)blockIdx.x*256 + threadIdx.x;
    if(idx >= 8L*4097*512) return;
    int c = idx & 511; long r = idx >> 9; int t = (int)(r % 4097); int b = (int)(r / 4097);
    g_h[idx] = (t==0) ? cls[c] : feat[((long)b*4096 + (t-1))*512 + c];
}

// LN row stats: one warp per token row, one pass (mean, rstd)
__global__ void k_lnstat(const float* __restrict__ h, float* __restrict__ stat){
    long row = (long)blockIdx.x*8 + (threadIdx.x >> 5);
    if(row >= 8L*4097) return;
    int lane = threadIdx.x & 31;
    const float* x = h + row*512;
    float s = 0.f, s2 = 0.f;
    #pragma unroll
    for(int i=0;i<4;i++){
        float4 v = ldg4(x + lane*4 + i*128);
        s  += v.x + v.y + v.z + v.w;
        s2 += v.x*v.x + v.y*v.y + v.z*v.z + v.w*v.w;
    }
    #pragma unroll
    for(int o=16;o;o>>=1){
        s  += __shfl_xor_sync(0xffffffffu, s,  o);
        s2 += __shfl_xor_sync(0xffffffffu, s2, o);
    }
    if(lane == 0){
        float mean = s * (1.f/512.f);
        float var  = s2 * (1.f/512.f) - mean*mean;
        stat[2*row]   = mean;
        stat[2*row+1] = rsqrtf(var + 1e-5f);
    }
}

// =====================================================================
// TF32 tensor-core GEMMs: 128x128 block, 8 warps of 64x32, BK=16,
// 2-stage smem double buffer (one sync per ktile)
// =====================================================================

// qkv GEMM with LN fused on the A side:
// A[padded gm][k] = (pt<255) ? 0 : (h[b*4097+pt-255][k]-mean)*rstd*gamma[k]+beta[k]
// C = A @ B^T.  B:(N,K) weights.  M = 34816 padded rows (8 x 4352).
__global__ void __launch_bounds__(256,2) k_mma_nt_ln(
    const float* __restrict__ H, const float* __restrict__ stat,
    const float* __restrict__ gam, const float* __restrict__ bet,
    const float* __restrict__ B, int ldb,
    float* __restrict__ C, int ldc,
    int N, int K)
{
    __shared__ uint32_t As[2][128][20];
    __shared__ uint32_t Bs[2][128][20];
    int t = threadIdx.x;
    int lane = t & 31, warp = t >> 5;
    int wm = warp >> 2, wn = warp & 3;
    int r0 = blockIdx.x*128, c0 = blockIdx.y*128;
    int lrow = t >> 2, lk = (t & 3)*4;
    // row mapping for the two A rows this thread loads
    int gm0 = r0+lrow, gm1 = r0+lrow+64;
    int b0_ = gm0/4352, p0_ = gm0%4352;
    int b1_ = gm1/4352, p1_ = gm1%4352;
    bool v0 = p0_ >= 255, v1 = p1_ >= 255;
    long hr0 = (long)b0_*4097 + (p0_-255);
    long hr1 = (long)b1_*4097 + (p1_-255);
    float mu0=0.f, rs0=0.f, mu1=0.f, rs1=0.f;
    if(v0){ mu0 = stat[2*hr0]; rs0 = stat[2*hr0+1]; }
    if(v1){ mu1 = stat[2*hr1]; rs1 = stat[2*hr1+1]; }
    const float* Hp0 = H + hr0*512 + lk;
    const float* Hp1 = H + hr1*512 + lk;
    const float* Bp0 = B + (long)(c0+lrow)*ldb + lk;
    const float* Bp1 = B + (long)(c0+lrow+64)*ldb + lk;
    const float4 z4 = make_float4(0.f,0.f,0.f,0.f);
    float4 pa0 = v0?ldg4(Hp0):z4, pa1 = v1?ldg4(Hp1):z4;
    float4 pg = ldg4(gam + lk), pb = ldg4(bet + lk);
    float4 pb0 = ldg4(Bp0), pb1 = ldg4(Bp1);
    {
        float4 a0, a1;
        a0.x=(pa0.x-mu0)*rs0*pg.x+pb.x; a0.y=(pa0.y-mu0)*rs0*pg.y+pb.y;
        a0.z=(pa0.z-mu0)*rs0*pg.z+pb.z; a0.w=(pa0.w-mu0)*rs0*pg.w+pb.w;
        a1.x=(pa1.x-mu1)*rs1*pg.x+pb.x; a1.y=(pa1.y-mu1)*rs1*pg.y+pb.y;
        a1.z=(pa1.z-mu1)*rs1*pg.z+pb.z; a1.w=(pa1.w-mu1)*rs1*pg.w+pb.w;
        if(!v0) a0 = z4;
        if(!v1) a1 = z4;
        *(uint4*)&As[0][lrow][lk]    = cvt4(a0);
        *(uint4*)&As[0][lrow+64][lk] = cvt4(a1);
        *(uint4*)&Bs[0][lrow][lk]    = cvt4(pb0);
        *(uint4*)&Bs[0][lrow+64][lk] = cvt4(pb1);
    }
    __syncthreads();
    float accr[4][4][4];
    #pragma unroll
    for(int i=0;i<4;i++)
        #pragma unroll
        for(int j=0;j<4;j++)
            #pragma unroll
            for(int q=0;q<4;q++) accr[i][j][q]=0.f;
    int nk = K >> 4;
    for(int kt=0; kt<nk; kt++){
        int buf = kt & 1;
        if(kt+1<nk){
            int o = (kt+1)*16;
            pa0 = v0?ldg4(Hp0+o):z4; pa1 = v1?ldg4(Hp1+o):z4;
            pg = ldg4(gam + o + lk); pb = ldg4(bet + o + lk);
            pb0 = ldg4(Bp0+o); pb1 = ldg4(Bp1+o);
        }
        #pragma unroll
        for(int ks=0;ks<2;ks++){
            int cc = ks*8 + (lane&3);
            uint32_t a[4][4], b[4][2];
            int rA = wm*64 + (lane>>2);
            #pragma unroll
            for(int mt=0;mt<4;mt++){
                a[mt][0]=As[buf][rA+mt*16  ][cc];
                a[mt][1]=As[buf][rA+mt*16+8][cc];
                a[mt][2]=As[buf][rA+mt*16  ][cc+4];
                a[mt][3]=As[buf][rA+mt*16+8][cc+4];
            }
            int rB = wn*32 + (lane>>2);
            #pragma unroll
            for(int nt=0;nt<4;nt++){
                b[nt][0]=Bs[buf][rB+nt*8][cc];
                b[nt][1]=Bs[buf][rB+nt*8][cc+4];
            }
            #pragma unroll
            for(int mt=0;mt<4;mt++)
                #pragma unroll
                for(int nt=0;nt<4;nt++)
                    mma8(accr[mt][nt], a[mt], b[nt]);
        }
        if(kt+1<nk){
            int s = (kt+1) & 1;
            float4 a0, a1;
            a0.x=(pa0.x-mu0)*rs0*pg.x+pb.x; a0.y=(pa0.y-mu0)*rs0*pg.y+pb.y;
            a0.z=(pa0.z-mu0)*rs0*pg.z+pb.z; a0.w=(pa0.w-mu0)*rs0*pg.w+pb.w;
            a1.x=(pa1.x-mu1)*rs1*pg.x+pb.x; a1.y=(pa1.y-mu1)*rs1*pg.y+pb.y;
            a1.z=(pa1.z-mu1)*rs1*pg.z+pb.z; a1.w=(pa1.w-mu1)*rs1*pg.w+pb.w;
            if(!v0) a0 = z4;
            if(!v1) a1 = z4;
            *(uint4*)&As[s][lrow][lk]    = cvt4(a0);
            *(uint4*)&As[s][lrow+64][lk] = cvt4(a1);
            *(uint4*)&Bs[s][lrow][lk]    = cvt4(pb0);
            *(uint4*)&Bs[s][lrow+64][lk] = cvt4(pb1);
            __syncthreads();
        }
    }
    #pragma unroll
    for(int mt=0;mt<4;mt++)
    #pragma unroll
    for(int i=0;i<2;i++){
        int gm = r0 + wm*64 + mt*16 + i*8 + (lane>>2);
        #pragma unroll
        for(int nt=0;nt<4;nt++){
            int gn = c0 + wn*32 + nt*8 + 2*(lane&3);
            float2 v;
            v.x = accr[mt][nt][2*i];
            v.y = accr[mt][nt][2*i+1];
            *(float2*)(C + (long)gm*ldc + gn) = v;
        }
    }
}

// C = alpha * A @ B^T (+bias)(+C)   A:(M,K) lda, B:(N,K) ldb   batched (b,h)
__global__ void __launch_bounds__(256,2) k_mma_nt(
    const float* __restrict__ A, int lda, long sAb, long sAh,
    const float* __restrict__ B, int ldb, long sBb, long sBh,
    float* __restrict__ C, int ldc, long sCb, long sCh,
    int M, int N, int K, float alpha, const float* __restrict__ bias, int acc)
{
    int z = blockIdx.z; int hh = z & 7; int bb = z >> 3;
    A += (long)bb*sAb + (long)hh*sAh;
    B += (long)bb*sBb + (long)hh*sBh;
    C += (long)bb*sCb + (long)hh*sCh;
    __shared__ uint32_t As[2][128][20];
    __shared__ uint32_t Bs[2][128][20];
    int t = threadIdx.x;
    int lane = t & 31, warp = t >> 5;
    int wm = warp >> 2, wn = warp & 3;
    int r0 = blockIdx.x*128, c0 = blockIdx.y*128;
    int lrow = t >> 2, lk = (t & 3)*4;
    const float* Ap0 = A + (long)(r0+lrow)*lda + lk;
    const float* Ap1 = A + (long)(r0+lrow+64)*lda + lk;
    const float* Bp0 = B + (long)(c0+lrow)*ldb + lk;
    const float* Bp1 = B + (long)(c0+lrow+64)*ldb + lk;
    bool mA0 = (r0+lrow)<M, mA1 = (r0+lrow+64)<M;
    bool mB0 = (c0+lrow)<N, mB1 = (c0+lrow+64)<N;
    const float4 z4 = make_float4(0.f,0.f,0.f,0.f);
    float4 pa0 = mA0?ldg4(Ap0):z4, pa1 = mA1?ldg4(Ap1):z4;
    float4 pb0 = mB0?ldg4(Bp0):z4, pb1 = mB1?ldg4(Bp1):z4;
    *(uint4*)&As[0][lrow][lk]    = cvt4(pa0);
    *(uint4*)&As[0][lrow+64][lk] = cvt4(pa1);
    *(uint4*)&Bs[0][lrow][lk]    = cvt4(pb0);
    *(uint4*)&Bs[0][lrow+64][lk] = cvt4(pb1);
    __syncthreads();
    float accr[4][4][4];
    #pragma unroll
    for(int i=0;i<4;i++)
        #pragma unroll
        for(int j=0;j<4;j++)
            #pragma unroll
            for(int q=0;q<4;q++) accr[i][j][q]=0.f;
    int nk = K >> 4;
    for(int kt=0; kt<nk; kt++){
        int buf = kt & 1;
        if(kt+1<nk){
            int o = (kt+1)*16;
            pa0 = mA0?ldg4(Ap0+o):z4; pa1 = mA1?ldg4(Ap1+o):z4;
            pb0 = mB0?ldg4(Bp0+o):z4; pb1 = mB1?ldg4(Bp1+o):z4;
        }
        #pragma unroll
        for(int ks=0;ks<2;ks++){
            int cc = ks*8 + (lane&3);
            uint32_t a[4][4], b[4][2];
            int rA = wm*64 + (lane>>2);
            #pragma unroll
            for(int mt=0;mt<4;mt++){
                a[mt][0]=As[buf][rA+mt*16  ][cc];
                a[mt][1]=As[buf][rA+mt*16+8][cc];
                a[mt][2]=As[buf][rA+mt*16  ][cc+4];
                a[mt][3]=As[buf][rA+mt*16+8][cc+4];
            }
            int rB = wn*32 + (lane>>2);
            #pragma unroll
            for(int nt=0;nt<4;nt++){
                b[nt][0]=Bs[buf][rB+nt*8][cc];
                b[nt][1]=Bs[buf][rB+nt*8][cc+4];
            }
            #pragma unroll
            for(int mt=0;mt<4;mt++)
                #pragma unroll
                for(int nt=0;nt<4;nt++)
                    mma8(accr[mt][nt], a[mt], b[nt]);
        }
        if(kt+1<nk){
            int s = (kt+1) & 1;
            *(uint4*)&As[s][lrow][lk]    = cvt4(pa0);
            *(uint4*)&As[s][lrow+64][lk] = cvt4(pa1);
            *(uint4*)&Bs[s][lrow][lk]    = cvt4(pb0);
            *(uint4*)&Bs[s][lrow+64][lk] = cvt4(pb1);
            __syncthreads();
        }
    }
    #pragma unroll
    for(int mt=0;mt<4;mt++)
    #pragma unroll
    for(int i=0;i<2;i++){
        int gm = r0 + wm*64 + mt*16 + i*8 + (lane>>2);
        if(gm>=M) continue;
        #pragma unroll
        for(int nt=0;nt<4;nt++){
            int gn = c0 + wn*32 + nt*8 + 2*(lane&3);
            float2 v;
            v.x = alpha*accr[mt][nt][2*i];
            v.y = alpha*accr[mt][nt][2*i+1];
            if(bias){ v.x += bias[gn]; v.y += bias[gn+1]; }
            float* cp = C + (long)gm*ldc + gn;
            if(acc){ v.x += cp[0]; v.y += cp[1]; }
            *(float2*)cp = v;
        }
    }
}

// Fused GEMM+softmax: C = softmax_row(alpha * A @ B^T), K=64, N=256.
__global__ void __launch_bounds__(256,2) k_simsm(
    const float* __restrict__ A, int lda, long sAb, long sAh,
    const float* __restrict__ B, int ldb, long sBb, long sBh,
    float* __restrict__ C, int ldc, long sCb, long sCh,
    float alpha)
{
    int z = blockIdx.z; int hh = z & 7; int bb = z >> 3;
    A += (long)bb*sAb + (long)hh*sAh;
    B += (long)bb*sBb + (long)hh*sBh;
    C += (long)bb*sCb + (long)hh*sCh;
    __shared__ uint32_t As[64][20];
    __shared__ uint32_t Bs[256][20];
    __shared__ float red[64][4];
    int t = threadIdx.x;
    int lane = t & 31, warp = t >> 5;
    int wm = warp >> 2, wn = warp & 3;
    int r0 = blockIdx.x*64;
    int lrow = t >> 2, lk = (t & 3)*4;
    float acc[2][8][4];
    #pragma unroll
    for(int i=0;i<2;i++)
        #pragma unroll
        for(int j=0;j<8;j++)
            #pragma unroll
            for(int q=0;q<4;q++) acc[i][j][q]=0.f;
    for(int kt=0; kt<4; kt++){
        __syncthreads();
        *(uint4*)&As[lrow][lk] = cvt4(ldg4(A + (long)(r0+lrow)*lda + kt*16 + lk));
        #pragma unroll
        for(int i=0;i<4;i++)
            *(uint4*)&Bs[i*64+lrow][lk] = cvt4(ldg4(B + (long)(i*64+lrow)*ldb + kt*16 + lk));
        __syncthreads();
        #pragma unroll
        for(int ks=0;ks<2;ks++){
            int cc = ks*8 + (lane&3);
            uint32_t a[2][4], b[8][2];
            int rA = wm*32 + (lane>>2);
            #pragma unroll
            for(int mt=0;mt<2;mt++){
                a[mt][0]=As[rA+mt*16  ][cc];
                a[mt][1]=As[rA+mt*16+8][cc];
                a[mt][2]=As[rA+mt*16  ][cc+4];
                a[mt][3]=As[rA+mt*16+8][cc+4];
            }
            int rB = wn*64 + (lane>>2);
            #pragma unroll
            for(int nt=0;nt<8;nt++){
                b[nt][0]=Bs[rB+nt*8][cc];
                b[nt][1]=Bs[rB+nt*8][cc+4];
            }
            #pragma unroll
            for(int mt=0;mt<2;mt++)
                #pragma unroll
                for(int nt=0;nt<8;nt++)
                    mma8(acc[mt][nt], a[mt], b[nt]);
        }
    }
    int g = lane>>2, tq = lane&3;
    float pm[2][2];
    #pragma unroll
    for(int mt=0;mt<2;mt++)
        #pragma unroll
        for(int i=0;i<2;i++){
            float m = -1e30f;
            #pragma unroll
            for(int nt=0;nt<8;nt++){
                acc[mt][nt][2*i]   *= alpha;
                acc[mt][nt][2*i+1] *= alpha;
                m = fmaxf(m, fmaxf(acc[mt][nt][2*i], acc[mt][nt][2*i+1]));
            }
            m = fmaxf(m, __shfl_xor_sync(0xffffffffu, m, 1));
            m = fmaxf(m, __shfl_xor_sync(0xffffffffu, m, 2));
            pm[mt][i] = m;
        }
    if(tq==0){
        #pragma unroll
        for(int mt=0;mt<2;mt++)
            #pragma unroll
            for(int i=0;i<2;i++)
                red[wm*32+mt*16+i*8+g][wn] = pm[mt][i];
    }
    __syncthreads();
    float rmax[2][2];
    #pragma unroll
    for(int mt=0;mt<2;mt++)
        #pragma unroll
        for(int i=0;i<2;i++){
            int rid = wm*32+mt*16+i*8+g;
            rmax[mt][i] = fmaxf(fmaxf(red[rid][0],red[rid][1]), fmaxf(red[rid][2],red[rid][3]));
        }
    __syncthreads();
    float ps[2][2];
    #pragma unroll
    for(int mt=0;mt<2;mt++)
        #pragma unroll
        for(int i=0;i<2;i++){
            float s = 0.f;
            #pragma unroll
            for(int nt=0;nt<8;nt++){
                float e0 = __expf(acc[mt][nt][2*i]   - rmax[mt][i]);
                float e1 = __expf(acc[mt][nt][2*i+1] - rmax[mt][i]);
                acc[mt][nt][2*i]   = e0;
                acc[mt][nt][2*i+1] = e1;
                s += e0 + e1;
            }
            s += __shfl_xor_sync(0xffffffffu, s, 1);
            s += __shfl_xor_sync(0xffffffffu, s, 2);
            ps[mt][i] = s;
        }
    if(tq==0){
        #pragma unroll
        for(int mt=0;mt<2;mt++)
            #pragma unroll
            for(int i=0;i<2;i++)
                red[wm*32+mt*16+i*8+g][wn] = ps[mt][i];
    }
    __syncthreads();
    #pragma unroll
    for(int mt=0;mt<2;mt++)
        #pragma unroll
        for(int i=0;i<2;i++){
            int rid = wm*32+mt*16+i*8+g;
            float inv = 1.f/(red[rid][0]+red[rid][1]+red[rid][2]+red[rid][3]);
            long gm = r0 + rid;
            #pragma unroll
            for(int nt=0;nt<8;nt++){
                int gn = wn*64 + nt*8 + 2*tq;
                float2 v; v.x = acc[mt][nt][2*i]*inv; v.y = acc[mt][nt][2*i+1]*inv;
                *(float2*)(C + gm*ldc + gn) = v;
            }
        }
}

// =====================================================================
// Flash-style fused sim3+softmax+a3v (proven R12)
// =====================================================================
__global__ void __launch_bounds__(256,2) k_flash3(
    const float* __restrict__ QL, long sQL,
    const float* __restrict__ QKV, long sQKVb,
    float* __restrict__ Ov, long sO)
{
    extern __shared__ char dyn[];
    uint32_t (*Qs)[68] = (uint32_t(*)[68])dyn;
    uint32_t (*Ks)[20] = (uint32_t(*)[20])(dyn + 17408);
    uint32_t (*Pf)[68] = (uint32_t(*)[68])(dyn + 17408);
    uint32_t (*Vs)[72] = (uint32_t(*)[72])(dyn + 17408 + 17408);
    float (*red)[4] = (float(*)[4])(dyn + 53248);
    float* m_run = (float*)(dyn + 54272);
    float* l_run = (float*)(dyn + 54528);
    float* sf    = (float*)(dyn + 54784);
    int z = blockIdx.z; int hh = z & 7; int bb = z >> 3;
    const float* Q  = QL  + (long)z*sQL;
    const float* Kg = QKV + (long)bb*sQKVb + 512  + hh*64;
    const float* Vg = QKV + (long)bb*sQKVb + 1024 + hh*64;
    float* Og = Ov + (long)z*sO;
    int t = threadIdx.x, lane = t & 31, warp = t >> 5;
    int wm = warp >> 2, wn = warp & 3;
    int wm2 = warp >> 1, wn2 = warp & 1;
    int g = lane >> 2, tq = lane & 3;
    int r0 = blockIdx.x*64;
    {
        int row = t >> 2, cb = (t & 3)*16;
        const float* qp = Q + (long)(r0+row)*64 + cb;
        #pragma unroll
        for(int j=0;j<4;j++){
            float4 v = ldg4(qp + j*4);
            Qs[row][cb+j*4+0]=f2tf(v.x); Qs[row][cb+j*4+1]=f2tf(v.y);
            Qs[row][cb+j*4+2]=f2tf(v.z); Qs[row][cb+j*4+3]=f2tf(v.w);
        }
    }
    if(t < 64){ m_run[t] = -1e30f; l_run[t] = 0.f; }
    float acc2[4][4];
    #pragma unroll
    for(int j=0;j<4;j++)
        #pragma unroll
        for(int q=0;q<4;q++) acc2[j][q]=0.f;
    for(int ch=0; ch<17; ch++){
        long kc0 = (long)ch*256;
        float acc[2][8][4];
        #pragma unroll
        for(int i=0;i<2;i++)
            #pragma unroll
            for(int j=0;j<8;j++)
                #pragma unroll
                for(int q=0;q<4;q++) acc[i][j][q]=0.f;
        for(int kt=0; kt<4; kt++){
            __syncthreads();
            int lrow = t >> 2, lk = (t & 3)*4;
            #pragma unroll
            for(int i=0;i<4;i++){
                int row = i*64 + lrow;
                *(uint4*)&Ks[row][lk] = cvt4(ldg4(Kg + (kc0+row)*1536 + kt*16 + lk));
            }
            __syncthreads();
            #pragma unroll
            for(int ks=0;ks<2;ks++){
                int cc = ks*8 + tq, qc = kt*16 + cc;
                uint32_t a[2][4], b[8][2];
                int rA = wm*32 + g;
                #pragma unroll
                for(int mt=0;mt<2;mt++){
                    a[mt][0]=Qs[rA+mt*16  ][qc];
                    a[mt][1]=Qs[rA+mt*16+8][qc];
                    a[mt][2]=Qs[rA+mt*16  ][qc+4];
                    a[mt][3]=Qs[rA+mt*16+8][qc+4];
                }
                int rB = wn*64 + g;
                #pragma unroll
                for(int nt=0;nt<8;nt++){
                    b[nt][0]=Ks[rB+nt*8][cc];
                    b[nt][1]=Ks[rB+nt*8][cc+4];
                }
                #pragma unroll
                for(int mt=0;mt<2;mt++)
                    #pragma unroll
                    for(int nt=0;nt<8;nt++)
                        mma8(acc[mt][nt], a[mt], b[nt]);
            }
        }
        float pm[2][2];
        #pragma unroll
        for(int mt=0;mt<2;mt++)
            #pragma unroll
            for(int i=0;i<2;i++){
                float m = -1e30f;
                #pragma unroll
                for(int nt=0;nt<8;nt++)
                    m = fmaxf(m, fmaxf(acc[mt][nt][2*i], acc[mt][nt][2*i+1]));
                m = fmaxf(m, __shfl_xor_sync(0xffffffffu, m, 1));
                m = fmaxf(m, __shfl_xor_sync(0xffffffffu, m, 2));
                pm[mt][i] = m;
            }
        if(tq==0){
            #pragma unroll
            for(int mt=0;mt<2;mt++)
                #pragma unroll
                for(int i=0;i<2;i++)
                    red[wm*32+mt*16+i*8+g][wn] = pm[mt][i];
        }
        __syncthreads();
        float mn_[2][2];
        #pragma unroll
        for(int mt=0;mt<2;mt++)
            #pragma unroll
            for(int i=0;i<2;i++){
                int rid = wm*32+mt*16+i*8+g;
                float cm = fmaxf(fmaxf(red[rid][0],red[rid][1]), fmaxf(red[rid][2],red[rid][3]));
                mn_[mt][i] = fmaxf(m_run[rid], cm);
            }
        __syncthreads();
        float ps[2][2];
        #pragma unroll
        for(int mt=0;mt<2;mt++)
            #pragma unroll
            for(int i=0;i<2;i++){
                float s = 0.f;
                #pragma unroll
                for(int nt=0;nt<8;nt++){
                    float e0 = __expf(acc[mt][nt][2*i]   - mn_[mt][i]);
                    float e1 = __expf(acc[mt][nt][2*i+1] - mn_[mt][i]);
                    acc[mt][nt][2*i]   = e0;
                    acc[mt][nt][2*i+1] = e1;
                    s += e0 + e1;
                }
                s += __shfl_xor_sync(0xffffffffu, s, 1);
                s += __shfl_xor_sync(0xffffffffu, s, 2);
                ps[mt][i] = s;
            }
        if(tq==0){
            #pragma unroll
            for(int mt=0;mt<2;mt++)
                #pragma unroll
                for(int i=0;i<2;i++)
                    red[wm*32+mt*16+i*8+g][wn] = ps[mt][i];
        }
        __syncthreads();
        if(wn==0 && tq==0){
            #pragma unroll
            for(int mt=0;mt<2;mt++)
                #pragma unroll
                for(int i=0;i<2;i++){
                    int rid = wm*32+mt*16+i*8+g;
                    float ct = red[rid][0]+red[rid][1]+red[rid][2]+red[rid][3];
                    float mn = mn_[mt][i];
                    float f  = __expf(m_run[rid] - mn);
                    l_run[rid] = l_run[rid]*f + ct;
                    m_run[rid] = mn;
                    sf[rid] = f;
                }
        }
        __syncthreads();
        #pragma unroll
        for(int i=0;i<2;i++){
            float f2 = sf[wm2*16 + i*8 + g];
            #pragma unroll
            for(int nt=0;nt<4;nt++){ acc2[nt][2*i]*=f2; acc2[nt][2*i+1]*=f2; }
        }
        for(int sub=0; sub<4; sub++){
            __syncthreads();
            if(wn == sub){
                #pragma unroll
                for(int mt=0;mt<2;mt++)
                    #pragma unroll
                    for(int i=0;i<2;i++){
                        int rl = wm*32+mt*16+i*8+g;
                        #pragma unroll
                        for(int nt=0;nt<8;nt++){
                            int cl = nt*8 + 2*tq;
                            Pf[rl][cl]   = f2tf(acc[mt][nt][2*i]);
                            Pf[rl][cl+1] = f2tf(acc[mt][nt][2*i+1]);
                        }
                    }
            }
            {
                int kl = t >> 2, cb = (t & 3)*16;
                const float* vp = Vg + (kc0 + sub*64 + kl)*1536 + cb;
                #pragma unroll
                for(int j=0;j<4;j++){
                    float4 v = ldg4(vp + j*4);
                    Vs[kl][cb+j*4+0]=f2tf(v.x); Vs[kl][cb+j*4+1]=f2tf(v.y);
                    Vs[kl][cb+j*4+2]=f2tf(v.z); Vs[kl][cb+j*4+3]=f2tf(v.w);
                }
            }
            __syncthreads();
            #pragma unroll
            for(int kk=0;kk<8;kk++){
                int cc = kk*8 + tq;
                uint32_t a[4], b[4][2];
                a[0]=Pf[wm2*16+g  ][cc];
                a[1]=Pf[wm2*16+8+g][cc];
                a[2]=Pf[wm2*16+g  ][cc+4];
                a[3]=Pf[wm2*16+8+g][cc+4];
                #pragma unroll
                for(int nt=0;nt<4;nt++){
                    int n = wn2*32 + nt*8 + g;
                    b[nt][0]=Vs[cc  ][n];
                    b[nt][1]=Vs[cc+4][n];
                }
                #pragma unroll
                for(int nt=0;nt<4;nt++)
                    mma8(acc2[nt], a, b[nt]);
            }
        }
    }
    #pragma unroll
    for(int i=0;i<2;i++){
        int row = wm2*16 + i*8 + g;
        float linv = 1.f/l_run[row];
        float* dst = Og + (long)(r0+row)*64;
        #pragma unroll
        for(int nt=0;nt<4;nt++){
            int col = wn2*32 + nt*8 + 2*tq;
            float2 v; v.x = acc2[nt][2*i]*linv; v.y = acc2[nt][2*i+1]*linv;
            *(float2*)(dst + col) = v;
        }
    }
}

// =====================================================================
// Fused attention output: ac[token] += softmax(alpha * q @ kl^T) @ tmp2
// =====================================================================
__global__ void __launch_bounds__(256,2) k_attnout(
    const float* __restrict__ Q, int ldq, long sQb, long sQh,
    const float* __restrict__ KL, long sKL,
    const float* __restrict__ T2, long sT2,
    float* __restrict__ AC, float alpha)
{
    int z = blockIdx.z; int hh = z & 7; int bb = z >> 3;
    const float* A = Q  + (long)bb*sQb + (long)hh*sQh;
    const float* B = KL + (long)z*sKL;
    const float* T = T2 + (long)z*sT2;
    __shared__ char smem_raw[35840];
    __shared__ float red[64][4];
    uint32_t (*As)[20] = (uint32_t(*)[20])smem_raw;
    uint32_t (*Bs)[20] = (uint32_t(*)[20])(smem_raw + 5120);
    uint32_t (*Pf)[68] = (uint32_t(*)[68])smem_raw;
    uint32_t (*Ts)[72] = (uint32_t(*)[72])(smem_raw + 17408);
    int t = threadIdx.x;
    int lane = t & 31, warp = t >> 5;
    int wm = warp >> 2, wn = warp & 3;
    int r0 = blockIdx.x*64;
    int lrow = t >> 2, lk = (t & 3)*4;
    int g = lane>>2, tq = lane&3;
    float acc[2][8][4];
    #pragma unroll
    for(int i=0;i<2;i++)
        #pragma unroll
        for(int j=0;j<8;j++)
            #pragma unroll
            for(int q=0;q<4;q++) acc[i][j][q]=0.f;
    for(int kt=0; kt<4; kt++){
        __syncthreads();
        *(uint4*)&As[lrow][lk] = cvt4(ldg4(A + (long)(r0+lrow)*ldq + kt*16 + lk));
        #pragma unroll
        for(int i=0;i<4;i++)
            *(uint4*)&Bs[i*64+lrow][lk] = cvt4(ldg4(B + (long)(i*64+lrow)*64 + kt*16 + lk));
        __syncthreads();
        #pragma unroll
        for(int ks=0;ks<2;ks++){
            int cc = ks*8 + tq;
            uint32_t a[2][4], b[8][2];
            int rA = wm*32 + g;
            #pragma unroll
            for(int mt=0;mt<2;mt++){
                a[mt][0]=As[rA+mt*16  ][cc];
                a[mt][1]=As[rA+mt*16+8][cc];
                a[mt][2]=As[rA+mt*16  ][cc+4];
                a[mt][3]=As[rA+mt*16+8][cc+4];
            }
            int rB = wn*64 + g;
            #pragma unroll
            for(int nt=0;nt<8;nt++){
                b[nt][0]=Bs[rB+nt*8][cc];
                b[nt][1]=Bs[rB+nt*8][cc+4];
            }
            #pragma unroll
            for(int mt=0;mt<2;mt++)
                #pragma unroll
                for(int nt=0;nt<8;nt++)
                    mma8(acc[mt][nt], a[mt], b[nt]);
        }
    }
    float pm[2][2];
    #pragma unroll
    for(int mt=0;mt<2;mt++)
        #pragma unroll
        for(int i=0;i<2;i++){
            float m = -1e30f;
            #pragma unroll
            for(int nt=0;nt<8;nt++){
                acc[mt][nt][2*i]   *= alpha;
                acc[mt][nt][2*i+1] *= alpha;
                m = fmaxf(m, fmaxf(acc[mt][nt][2*i], acc[mt][nt][2*i+1]));
            }
            m = fmaxf(m, __shfl_xor_sync(0xffffffffu, m, 1));
            m = fmaxf(m, __shfl_xor_sync(0xffffffffu, m, 2));
            pm[mt][i] = m;
        }
    if(tq==0){
        #pragma unroll
        for(int mt=0;mt<2;mt++)
            #pragma unroll
            for(int i=0;i<2;i++)
                red[wm*32+mt*16+i*8+g][wn] = pm[mt][i];
    }
    __syncthreads();
    float rmax[2][2];
    #pragma unroll
    for(int mt=0;mt<2;mt++)
        #pragma unroll
        for(int i=0;i<2;i++){
            int rid = wm*32+mt*16+i*8+g;
            rmax[mt][i] = fmaxf(fmaxf(red[rid][0],red[rid][1]), fmaxf(red[rid][2],red[rid][3]));
        }
    __syncthreads();
    float ps[2][2];
    #pragma unroll
    for(int mt=0;mt<2;mt++)
        #pragma unroll
        for(int i=0;i<2;i++){
            float s = 0.f;
            #pragma unroll
            for(int nt=0;nt<8;nt++){
                float e0 = __expf(acc[mt][nt][2*i]   - rmax[mt][i]);
                float e1 = __expf(acc[mt][nt][2*i+1] - rmax[mt][i]);
                acc[mt][nt][2*i]   = e0;
                acc[mt][nt][2*i+1] = e1;
                s += e0 + e1;
            }
            s += __shfl_xor_sync(0xffffffffu, s, 1);
            s += __shfl_xor_sync(0xffffffffu, s, 2);
            ps[mt][i] = s;
        }
    if(tq==0){
        #pragma unroll
        for(int mt=0;mt<2;mt++)
            #pragma unroll
            for(int i=0;i<2;i++)
                red[wm*32+mt*16+i*8+g][wn] = ps[mt][i];
    }
    __syncthreads();
    float inv2[2][2];
    #pragma unroll
    for(int mt=0;mt<2;mt++)
        #pragma unroll
        for(int i=0;i<2;i++){
            int rid = wm*32+mt*16+i*8+g;
            inv2[mt][i] = 1.f/(red[rid][0]+red[rid][1]+red[rid][2]+red[rid][3]);
            #pragma unroll
            for(int nt=0;nt<8;nt++){
                acc[mt][nt][2*i]   *= inv2[mt][i];
                acc[mt][nt][2*i+1] *= inv2[mt][i];
            }
        }
    int wm2 = warp >> 1, wn2 = warp & 1;
    float acc2[4][4];
    #pragma unroll
    for(int j=0;j<4;j++)
        #pragma unroll
        for(int q=0;q<4;q++) acc2[j][q]=0.f;
    for(int ch=0; ch<4; ch++){
        __syncthreads();
        if(wn == ch){
            #pragma unroll
            for(int mt=0;mt<2;mt++)
                #pragma unroll
                for(int i=0;i<2;i++){
                    int row_l = wm*32+mt*16+i*8+g;
                    #pragma unroll
                    for(int nt=0;nt<8;nt++){
                        int col_l = nt*8 + 2*tq;
                        Pf[row_l][col_l]   = f2tf(acc[mt][nt][2*i]);
                        Pf[row_l][col_l+1] = f2tf(acc[mt][nt][2*i+1]);
                    }
                }
        }
        {
            int kl_ = t >> 2, cb = (t & 3)*16;
            const float* Tp = T + (long)(64*ch + kl_)*64 + cb;
            #pragma unroll
            for(int j=0;j<4;j++){
                float4 v = ldg4(Tp + j*4);
                Ts[kl_][cb+j*4+0] = f2tf(v.x);
                Ts[kl_][cb+j*4+1] = f2tf(v.y);
                Ts[kl_][cb+j*4+2] = f2tf(v.z);
                Ts[kl_][cb+j*4+3] = f2tf(v.w);
            }
        }
        __syncthreads();
        #pragma unroll
        for(int kk=0;kk<8;kk++){
            int cc = kk*8 + tq;
            uint32_t a[4], b[4][2];
            a[0]=Pf[wm2*16+g  ][cc];
            a[1]=Pf[wm2*16+8+g][cc];
            a[2]=Pf[wm2*16+g  ][cc+4];
            a[3]=Pf[wm2*16+8+g][cc+4];
            #pragma unroll
            for(int nt=0;nt<4;nt++){
                int n = wn2*32 + nt*8 + g;
                b[nt][0]=Ts[cc  ][n];
                b[nt][1]=Ts[cc+4][n];
            }
            #pragma unroll
            for(int nt=0;nt<4;nt++)
                mma8(acc2[nt], a, b[nt]);
        }
    }
    #pragma unroll
    for(int i=0;i<2;i++){
        int gm = r0 + wm2*16 + i*8 + g;
        if(gm < 255) continue;
        float* dst = AC + ((long)bb*4097 + (gm-255))*512 + hh*64;
        #pragma unroll
        for(int nt=0;nt<4;nt++){
            int gn = wn2*32 + nt*8 + 2*tq;
            float2 o = *(float2*)(dst + gn);
            float2 v; v.x = acc2[nt][2*i] + o.x; v.y = acc2[nt][2*i+1] + o.y;
            *(float2*)(dst + gn) = v;
        }
    }
}

// C = alpha * A @ B  (NN), pinv epilogues, 2-stage double buffer.
__global__ void __launch_bounds__(256,2) k_mma_nn(
    const float* __restrict__ A, int lda, long sAb, long sAh,
    const float* __restrict__ B, int ldb, long sBb, long sBh,
    float* __restrict__ C, int ldc, long sCb, long sCh,
    float* __restrict__ D, long sDb, long sDh,
    int M, int N, int K, float alpha, float dconst, int cmode)
{
    int z = blockIdx.z; int hh = z & 7; int bb = z >> 3;
    A += (long)bb*sAb + (long)hh*sAh;
    B += (long)bb*sBb + (long)hh*sBh;
    C += (long)bb*sCb + (long)hh*sCh;
    if(D) D += (long)bb*sDb + (long)hh*sDh;
    __shared__ uint32_t As[2][128][20];
    __shared__ uint32_t Bs[2][16][136];
    int t = threadIdx.x;
    int lane = t & 31, warp = t >> 5;
    int wm = warp >> 2, wn = warp & 3;
    int r0 = blockIdx.x*128, c0 = blockIdx.y*128;
    int lrow = t >> 2, lk = (t & 3)*4;
    int bk = t >> 5, bn = (t & 31)*4;
    const float* Ap0 = A + (long)(r0+lrow)*lda + lk;
    const float* Ap1 = A + (long)(r0+lrow+64)*lda + lk;
    const float* Bq0 = B + (long)bk*ldb + c0 + bn;
    const float* Bq1 = B + (long)(bk+8)*ldb + c0 + bn;
    bool mA0 = (r0+lrow)<M, mA1 = (r0+lrow+64)<M;
    bool mBn = (c0+bn)<N;
    const float4 z4 = make_float4(0.f,0.f,0.f,0.f);
    float4 pa0 = mA0?ldg4(Ap0):z4, pa1 = mA1?ldg4(Ap1):z4;
    float4 pb0 = mBn?ldg4(Bq0):z4, pb1 = mBn?ldg4(Bq1):z4;
    *(uint4*)&As[0][lrow][lk]    = cvt4(pa0);
    *(uint4*)&As[0][lrow+64][lk] = cvt4(pa1);
    *(uint4*)&Bs[0][bk][bn]      = cvt4(pb0);
    *(uint4*)&Bs[0][bk+8][bn]    = cvt4(pb1);
    __syncthreads();
    float accr[4][4][4];
    #pragma unroll
    for(int i=0;i<4;i++)
        #pragma unroll
        for(int j=0;j<4;j++)
            #pragma unroll
            for(int q=0;q<4;q++) accr[i][j][q]=0.f;
    int nk = K >> 4;
    for(int kt=0; kt<nk; kt++){
        int buf = kt & 1;
        if(kt+1<nk){
            long o = (long)(kt+1)*16;
            pa0 = mA0?ldg4(Ap0+o):z4; pa1 = mA1?ldg4(Ap1+o):z4;
            pb0 = mBn?ldg4(Bq0+o*ldb):z4; pb1 = mBn?ldg4(Bq1+o*ldb):z4;
        }
        #pragma unroll
        for(int ks=0;ks<2;ks++){
            int cc = ks*8 + (lane&3);
            uint32_t a[4][4], b[4][2];
            int rA = wm*64 + (lane>>2);
            #pragma unroll
            for(int mt=0;mt<4;mt++){
                a[mt][0]=As[buf][rA+mt*16  ][cc];
                a[mt][1]=As[buf][rA+mt*16+8][cc];
                a[mt][2]=As[buf][rA+mt*16  ][cc+4];
                a[mt][3]=As[buf][rA+mt*16+8][cc+4];
            }
            int nB = wn*32 + (lane>>2);
            #pragma unroll
            for(int nt=0;nt<4;nt++){
                b[nt][0]=Bs[buf][cc  ][nB+nt*8];
                b[nt][1]=Bs[buf][cc+4][nB+nt*8];
            }
            #pragma unroll
            for(int mt=0;mt<4;mt++)
                #pragma unroll
                for(int nt=0;nt<4;nt++)
                    mma8(accr[mt][nt], a[mt], b[nt]);
        }
        if(kt+1<nk){
            int s = (kt+1) & 1;
            *(uint4*)&As[s][lrow][lk]    = cvt4(pa0);
            *(uint4*)&As[s][lrow+64][lk] = cvt4(pa1);
            *(uint4*)&Bs[s][bk][bn]      = cvt4(pb0);
            *(uint4*)&Bs[s][bk+8][bn]    = cvt4(pb1);
            __syncthreads();
        }
    }
    #pragma unroll
    for(int mt=0;mt<4;mt++)
    #pragma unroll
    for(int i=0;i<2;i++){
        int gm = r0 + wm*64 + mt*16 + i*8 + (lane>>2);
        if(gm>=M) continue;
        #pragma unroll
        for(int nt=0;nt<4;nt++){
            int gn = c0 + wn*32 + nt*8 + 2*(lane&3);
            float2 v;
            v.x = alpha*accr[mt][nt][2*i];
            v.y = alpha*accr[mt][nt][2*i+1];
            long o = (long)gm*ldc + gn;
            if(D){
                float2 dv;
                dv.x = ((gm==gn  )?dconst:0.f) - v.x;
                dv.y = ((gm==gn+1)?dconst:0.f) - v.y;
                *(float2*)(D+o) = dv;
            }
            if(cmode){
                v.x = ((gm==gn  )?dconst:0.f) - v.x;
                v.y = ((gm==gn+1)?dconst:0.f) - v.y;
            }
            *(float2*)(C+o) = v;
        }
    }
}

// C = alpha * A @ B (NN, TF32), N=64. 128x64 block, 8 warps of 32x32. (proven)
__global__ void __launch_bounds__(256,2) k_mma_nn64(
    const float* __restrict__ A, int lda, long sAb, long sAh,
    const float* __restrict__ B, int ldb, long sBb, long sBh,
    float* __restrict__ C, int ldc, long sCb, long sCh,
    int M, int K, float alpha, int rowLo)
{
    int z = blockIdx.z; int hh = z & 7; int bb = z >> 3;
    A += (long)bb*sAb + (long)hh*sAh;
    B += (long)bb*sBb + (long)hh*sBh;
    C += (long)bb*sCb + (long)hh*sCh;
    __shared__ uint32_t Af[2][2048];
    __shared__ uint32_t Bf[2][1024];
    int t = threadIdx.x, lane = t & 31, warp = t >> 5;
    int wm = warp >> 1, wn = warp & 1;
    int r0 = blockIdx.x*128;
    int alr = t >> 1, alk = (t & 1)*8;
    const float* Ap = A + (long)(r0+alr)*lda + alk;
    bool mA = (r0+alr) < M;
    int bk = t >> 4, bn = (t & 15)*4;
    const float* Bp = B + (long)bk*ldb + bn;
    const float4 z4 = make_float4(0.f,0.f,0.f,0.f);
    float4 a0,a1,b0;
    a0 = mA?ldg4(Ap):z4; a1 = mA?ldg4(Ap+4):z4;
    b0 = ldg4(Bp);
    {
        scatA(Af[0], alr, alk+0, f2tf(a0.x)); scatA(Af[0], alr, alk+1, f2tf(a0.y));
        scatA(Af[0], alr, alk+2, f2tf(a0.z)); scatA(Af[0], alr, alk+3, f2tf(a0.w));
        scatA(Af[0], alr, alk+4, f2tf(a1.x)); scatA(Af[0], alr, alk+5, f2tf(a1.y));
        scatA(Af[0], alr, alk+6, f2tf(a1.z)); scatA(Af[0], alr, alk+7, f2tf(a1.w));
        scatB8(Bf[0], bn+0, bk, f2tf(b0.x)); scatB8(Bf[0], bn+1, bk, f2tf(b0.y));
        scatB8(Bf[0], bn+2, bk, f2tf(b0.z)); scatB8(Bf[0], bn+3, bk, f2tf(b0.w));
    }
    __syncthreads();
    float acc[2][4][4];
    #pragma unroll
    for(int i=0;i<2;i++)
        #pragma unroll
        for(int j=0;j<4;j++)
            #pragma unroll
            for(int q=0;q<4;q++) acc[i][j][q]=0.f;
    int nk = K >> 4;
    for(int kt=0; kt<nk; kt++){
        if(kt+1<nk){
            long o = (long)(kt+1)*16;
            a0 = mA?ldg4(Ap+o):z4; a1 = mA?ldg4(Ap+o+4):z4;
            b0 = ldg4(Bp + o*ldb);
        }
        int buf = kt & 1;
        #pragma unroll
        for(int ks=0;ks<2;ks++){
            uint32_t af[2][4], bfr[4][2];
            #pragma unroll
            for(int mt=0;mt<2;mt++)
                *(uint4*)af[mt] = *(const uint4*)&Af[buf][(((ks<<3)+(wm<<1)+mt)<<7) + (lane<<2)];
            #pragma unroll
            for(int nt=0;nt<4;nt++)
                *(uint2*)bfr[nt] = *(const uint2*)&Bf[buf][(((ks<<3)+(wn<<2)+nt)<<6) + (lane<<1)];
            #pragma unroll
            for(int mt=0;mt<2;mt++)
                #pragma unroll
                for(int nt=0;nt<4;nt++)
                    mma8(acc[mt][nt], af[mt], bfr[nt]);
        }
        if(kt+1<nk){
            int s = (kt+1) & 1;
            scatA(Af[s], alr, alk+0, f2tf(a0.x)); scatA(Af[s], alr, alk+1, f2tf(a0.y));
            scatA(Af[s], alr, alk+2, f2tf(a0.z)); scatA(Af[s], alr, alk+3, f2tf(a0.w));
            scatA(Af[s], alr, alk+4, f2tf(a1.x)); scatA(Af[s], alr, alk+5, f2tf(a1.y));
            scatA(Af[s], alr, alk+6, f2tf(a1.z)); scatA(Af[s], alr, alk+7, f2tf(a1.w));
            scatB8(Bf[s], bn+0, bk, f2tf(b0.x)); scatB8(Bf[s], bn+1, bk, f2tf(b0.y));
            scatB8(Bf[s], bn+2, bk, f2tf(b0.z)); scatB8(Bf[s], bn+3, bk, f2tf(b0.w));
            __syncthreads();
        }
    }
    int g = lane >> 2, tq = lane & 3;
    #pragma unroll
    for(int mt=0;mt<2;mt++)
    #pragma unroll
    for(int i=0;i<2;i++){
        int gm = r0 + wm*32 + mt*16 + i*8 + g;
        if(gm >= M || gm < rowLo) continue;
        #pragma unroll
        for(int nt=0;nt<4;nt++){
            int gn = wn*32 + nt*8 + 2*tq;
            float2 v;
            v.x = alpha*acc[mt][nt][2*i];
            v.y = alpha*acc[mt][nt][2*i+1];
            *(float2*)(C + (long)gm*ldc + gn) = v;
        }
    }
}

// ---------------- landmarks (mean over 17 tokens), q scaled by 1/8 ----------------
__global__ void k_landmarks(const float* __restrict__ qkv, float* __restrict__ ql, float* __restrict__ kl){
    int idx = blockIdx.x;
    int mi = idx % 256; int hh = (idx/256) & 7; int b = idx / (256*8);
    int dh = threadIdx.x;
    float sq=0.f, sk=0.f;
    for(int j=0;j<LSUB;j++){
        long tok = (long)mi*LSUB + j;
        const float* base = qkv + ((long)b*4352 + tok)*1536 + hh*64 + dh;
        sq += base[0];
        sk += base[512];
    }
    long o = (long)idx*64 + dh;
    ql[o] = sq * (0.125f/LSUB);
    kl[o] = sk * (1.0f/LSUB);
}

// ---------------- pinv scalar reductions ----------------
__global__ void k_scal_init(){ if(threadIdx.x < 2) g_scal[threadIdx.x] = 0.f; }

__global__ void k_rowsum_max(const float* __restrict__ X){
    long row = blockIdx.x;
    const float* x = X + row*256;
    int t = threadIdx.x;
    __shared__ float red[256];
    red[t] = fabsf(x[t]); __syncthreads();
    for(int k=128;k;k>>=1){ if(t<k) red[t]+=red[t+k]; __syncthreads(); }
    if(t==0) atomicMax((int*)&g_scal[0], __float_as_int(red[0]));
}

__global__ void k_colsum_max(const float* __restrict__ X){
    int b = blockIdx.x; int j = threadIdx.x;
    const float* x = X + (long)b*65536;
    float s = 0.f;
    for(int i=0;i<256;i++) s += fabsf(x[i*256+j]);
    __shared__ float red[256];
    red[j]=s; __syncthreads();
    for(int k=128;k;k>>=1){ if(j<k) red[j]=fmaxf(red[j],red[j+k]); __syncthreads(); }
    if(j==0) atomicMax((int*)&g_scal[1], __float_as_int(red[0]));
}

__global__ void k_tr_scale(const float* __restrict__ X, float* __restrict__ Z){
    long idx = (long)blockIdx.x*256 + threadIdx.x;
    if(idx >= 64L*65536) return;
    float inv = 1.f/(g_scal[0]*g_scal[1]);
    int j = (int)(idx & 255); int i = (int)((idx>>8) & 255); long b = idx >> 16;
    Z[idx] = X[(b<<16) + ((long)j<<8) + i] * inv;
}

// ---------------- residual depthwise conv (k=33), WRITES token-major into ac ----------------
__global__ void k_resconv2(const float* __restrict__ qkv, const float* __restrict__ w,
                           float* __restrict__ ac){
    int bh = blockIdx.y; int hh = bh & 7; int b = bh >> 3;
    int t0 = blockIdx.x*64;
    __shared__ float sv[96][65];
    __shared__ float sw[33];
    int t = threadIdx.x;
    if(t < 33) sw[t] = w[hh*33 + t];
    const float* vb = qkv + ((long)b*4352)*1536 + 1024 + hh*64;
    for(int i=t;i<96*64;i+=256){
        int tok = t0 - 16 + (i>>6); int dh = i&63;
        sv[i>>6][dh] = (tok>=0 && tok<4352) ? vb[(long)tok*1536 + dh] : 0.f;
    }
    __syncthreads();
    for(int i=t;i<64*64;i+=256){
        int lt = i>>6, dh = i&63;
        int tok = t0 + lt;
        if(tok < 255) continue;
        float s = 0.f;
        #pragma unroll
        for(int j=0;j<33;j++) s = fmaf(sw[j], sv[lt+j][dh], s);
        ac[((long)b*4097 + (tok-255))*512 + hh*64 + dh] = s;
    }
}

// ---------------- transposes token<->planar ----------------
__global__ void k_h2planar(const float* __restrict__ h, float* __restrict__ cnn){
    __shared__ float tile[32][33];
    int b = blockIdx.z;
    int c0 = blockIdx.x*32, p0 = blockIdx.y*32;
    int tx = threadIdx.x, ty = threadIdx.y;
    for(int i=ty;i<32;i+=8)
        tile[i][tx] = h[((long)b*4097 + 1 + p0+i)*512 + c0+tx];
    __syncthreads();
    for(int i=ty;i<32;i+=8)
        cnn[((long)b*512 + c0+i)*4096 + p0+tx] = tile[tx][i];
}

__global__ void k_planar2h(const float* __restrict__ yp, float* __restrict__ h2){
    __shared__ float tile[32][33];
    int b = blockIdx.z;
    int c0 = blockIdx.x*32, p0 = blockIdx.y*32;
    int tx = threadIdx.x, ty = threadIdx.y;
    for(int i=ty;i<32;i+=8)
        tile[i][tx] = yp[((long)b*512 + c0+i)*4096 + p0+tx];
    __syncthreads();
    for(int i=ty;i<32;i+=8)
        h2[((long)b*4097 + 1 + p0+i)*512 + c0+tx] = tile[tx][i];
}

__global__ void k_cls_copy(const float* __restrict__ h, float* __restrict__ h2){
    int idx = blockIdx.x*256 + threadIdx.x;
    if(idx >= 8*512) return;
    int b = idx >> 9, c = idx & 511;
    h2[(long)b*4097*512 + c] = h[(long)b*4097*512 + c];
}

// ---------------- fused 7x7 + 5x5 + 3x3 depthwise conv, planar ----------------
__global__ void k_dwconv(const float* __restrict__ cnn,
                         const float* __restrict__ w7, const float* __restrict__ b7,
                         const float* __restrict__ w5, const float* __restrict__ b5,
                         const float* __restrict__ w3, const float* __restrict__ b3,
                         float* __restrict__ yp){
    int bc = blockIdx.x; int c = bc & 511;
    __shared__ float pl[64][65];
    __shared__ float ww[84];
    const float* in = cnn + (long)bc*4096;
    int t = threadIdx.x;
    for(int i=t;i<4096;i+=256) pl[i>>6][i&63] = in[i];
    if(t < 49)      ww[t]      = w7[c*49 + t];
    else if(t < 74) ww[t]      = w5[c*25 + t - 49];
    else if(t < 83) ww[t]      = w3[c*9  + t - 74];
    __syncthreads();
    float bias = b7[c] + b5[c] + b3[c];
    for(int i=t;i<4096;i+=256){
        int y = i >> 6, x = i & 63;
        float s = pl[y][x] + bias;
        #pragma unroll
        for(int ky=0;ky<7;ky++){ int yy=y+ky-3; if((unsigned)yy>=64u) continue;
            #pragma unroll
            for(int kx=0;kx<7;kx++){ int xx=x+kx-3; if((unsigned)xx>=64u) continue;
                s = fmaf(ww[ky*7+kx], pl[yy][xx], s); } }
        #pragma unroll
        for(int ky=0;ky<5;ky++){ int yy=y+ky-2; if((unsigned)yy>=64u) continue;
            #pragma unroll
            for(int kx=0;kx<5;kx++){ int xx=x+kx-2; if((unsigned)xx>=64u) continue;
                s = fmaf(ww[49+ky*5+kx], pl[yy][xx], s); } }
        #pragma unroll
        for(int ky=0;ky<3;ky++){ int yy=y+ky-1; if((unsigned)yy>=64u) continue;
            #pragma unroll
            for(int kx=0;kx<3;kx++){ int xx=x+kx-1; if((unsigned)xx>=64u) continue;
                s = fmaf(ww[74+ky*3+kx], pl[yy][xx], s); } }
        yp[(long)bc*4096 + i] = s;
    }
}

// ---------------- final output: (cls[8,512], feat[8,4096,512]) ----------------
__global__ void k_writeout(const float* __restrict__ h2, float* __restrict__ out){
    long idx = (long)blockIdx.x*256 + threadIdx.x;
    if(idx >= 8L*512 + 8L*4096*512) return;
    if(idx < 8*512){
        int b = (int)(idx >> 9), c = (int)(idx & 511);
        out[idx] = h2[((long)b*4097)*512 + c];
    } else {
        long r = idx - 4096;
        int c = (int)(r & 511); long q = r >> 9; int t = (int)(q % 4096); int b = (int)(q / 4096);
        out[idx] = h2[((long)b*4097 + 1 + t)*512 + c];
    }
}

// ================= host side =================
struct Ptrs {
    float *h,*h2,*stat,*qkv,*ql,*kl,*a2,*zA,*zB,*xz,*t1,*t2,*a3v,*tmp2,*ac,*cnn,*yp;
};

static void get_ptrs(Ptrs& p){
    cudaGetSymbolAddress((void**)&p.h,    g_h);
    cudaGetSymbolAddress((void**)&p.h2,   g_h2);
    cudaGetSymbolAddress((void**)&p.stat, g_stat);
    cudaGetSymbolAddress((void**)&p.qkv,  g_qkv);
    cudaGetSymbolAddress((void**)&p.ql,   g_ql);
    cudaGetSymbolAddress((void**)&p.kl,   g_kl);
    cudaGetSymbolAddress((void**)&p.a2,   g_a2);
    cudaGetSymbolAddress((void**)&p.zA,   g_zA);
    cudaGetSymbolAddress((void**)&p.zB,   g_zB);
    cudaGetSymbolAddress((void**)&p.xz,   g_xz);
    cudaGetSymbolAddress((void**)&p.t1,   g_t1);
    cudaGetSymbolAddress((void**)&p.t2,   g_t2);
    cudaGetSymbolAddress((void**)&p.a3v,  g_a3v);
    cudaGetSymbolAddress((void**)&p.tmp2, g_tmp2);
    cudaGetSymbolAddress((void**)&p.ac,   g_ac);
    cudaGetSymbolAddress((void**)&p.cnn,  g_cnn);
    cudaGetSymbolAddress((void**)&p.yp,   g_yp);
}

static void attention(Ptrs& p, float* hbuf,
                      const float* lng, const float* lnb,
                      const float* qkvw, const float* outw, const float* outb,
                      const float* resw,
                      cudaStream_t side, cudaEvent_t evFork, cudaEvent_t evA3v, cudaEvent_t evJoin)
{
    const long SQKV_B = 4352L*1536;
    const long SQL    = 256L*64;
    const long SA2    = 65536L;
    const long SV64   = 256L*64;

    // LN stats, then qkv = LN(h) @ qkv_w^T fused (34816 padded x 1536 x 512)
    k_lnstat<<<4097, 256>>>(hbuf, p.stat);
    k_mma_nt_ln<<<dim3(272,12,1), 256>>>(hbuf, p.stat, lng, lnb,
                                         qkvw, 512, p.qkv, 1536, 1536, 512);

    k_landmarks<<<64*256, 64>>>(p.qkv, p.ql, p.kl);

    // ---- fork: flash3 + resconv2 on side stream, overlapping the pinv chain ----
    cudaEventRecord(evFork, 0);
    cudaStreamWaitEvent(side, evFork, 0);
    k_flash3<<<dim3(4,1,64), 256, 55040, side>>>(p.ql, SQL, p.qkv, SQKV_B, p.a3v, SV64);
    cudaEventRecord(evA3v, side);
    k_resconv2<<<dim3(68,64), 256, 0, side>>>(p.qkv, resw, p.ac);
    cudaEventRecord(evJoin, side);

    // ---- legacy stream: a2 softmax + pinv chain ----
    k_simsm<<<dim3(4,1,64), 256>>>(p.ql, 64, 8*SQL, SQL,
                                   p.kl, 64, 8*SQL, SQL,
                                   p.a2, 256, 8*SA2, SA2, 1.f);
    k_scal_init<<<1, 32>>>();
    k_rowsum_max<<<64*256, 256>>>(p.a2);
    k_colsum_max<<<64, 256>>>(p.a2);
    k_tr_scale<<<16384, 256>>>(p.a2, p.zA);

    float* zc = p.zA; float* zn = p.zB;
    for(int it=0; it<6; it++){
        k_mma_nn<<<dim3(2,2,64), 256>>>(p.a2, 256, 8*SA2, SA2, zc, 256, 8*SA2, SA2,
                                        p.xz, 256, 8*SA2, SA2, p.t1, 8*SA2, SA2,
                                        256,256,256, 1.f, 7.f, 0);
        k_mma_nn<<<dim3(2,2,64), 256>>>(p.xz, 256, 8*SA2, SA2, p.t1, 256, 8*SA2, SA2,
                                        p.t2, 256, 8*SA2, SA2, nullptr, 0,0,
                                        256,256,256, 1.f, 15.f, 1);
        k_mma_nn<<<dim3(2,2,64), 256>>>(p.xz, 256, 8*SA2, SA2, p.t2, 256, 8*SA2, SA2,
                                        p.t1, 256, 8*SA2, SA2, nullptr, 0,0,
                                        256,256,256, 1.f, 13.f, 1);
        k_mma_nn<<<dim3(2,2,64), 256>>>(zc, 256, 8*SA2, SA2, p.t1, 256, 8*SA2, SA2,
                                        zn, 256, 8*SA2, SA2, nullptr, 0,0,
                                        256,256,256, 0.25f, 0.f, 0);
        float* tmp = zc; zc = zn; zn = tmp;
    }

    // join a3v before tmp2
    cudaStreamWaitEvent(0, evA3v, 0);
    k_mma_nn64<<<dim3(2,1,64), 256>>>(zc, 256, 8*SA2, SA2, p.a3v, 64, 8*SV64, SV64,
                                      p.tmp2, 64, 8*SV64, SV64, 256, 256, 1.f, 0);

    // join resconv2 before attnout (attnout adds into ac)
    cudaStreamWaitEvent(0, evJoin, 0);
    k_attnout<<<dim3(68,1,64), 256>>>(p.qkv, 1536, SQKV_B, 64,
                                      p.kl, SQL, p.tmp2, SV64,
                                      p.ac, 0.125f);

    // hbuf += ac @ out_w^T + out_b
    k_mma_nt<<<dim3(257,4,1), 256>>>(p.ac, 512, 0,0, outw, 512, 0,0,
                                     hbuf, 512, 0,0, 32776, 512, 512, 1.f, outb, 1);
}

extern "C" void kernel_launch(void* const* d_in, const int* in_sizes, int n_in,
                              void* d_out, int out_size)
{
    const float* features = (const float*)d_in[0];
    const float* cls_tok  = (const float*)d_in[1];
    const float* ln1_g    = (const float*)d_in[2];
    const float* ln1_b    = (const float*)d_in[3];
    const float* qkv1_w   = (const float*)d_in[4];
    const float* out1_w   = (const float*)d_in[5];
    const float* out1_b   = (const float*)d_in[6];
    const float* res1_w   = (const float*)d_in[7];
    const float* p7_w     = (const float*)d_in[8];
    const float* p7_b     = (const float*)d_in[9];
    const float* p5_w     = (const float*)d_in[10];
    const float* p5_b     = (const float*)d_in[11];
    const float* p3_w     = (const float*)d_in[12];
    const float* p3_b     = (const float*)d_in[13];
    const float* ln2_g    = (const float*)d_in[14];
    const float* ln2_b    = (const float*)d_in[15];
    const float* qkv2_w   = (const float*)d_in[16];
    const float* out2_w   = (const float*)d_in[17];
    const float* out2_b   = (const float*)d_in[18];
    const float* res2_w   = (const float*)d_in[19];
    float* out = (float*)d_out;

    cudaFuncSetAttribute(k_flash3, cudaFuncAttributeMaxDynamicSharedMemorySize, 55040);

    static cudaStream_t side = nullptr;
    static cudaEvent_t ev[6];
    if(side == nullptr){
        cudaStreamCreateWithFlags(&side, cudaStreamNonBlocking);
        for(int i=0;i<6;i++) cudaEventCreateWithFlags(&ev[i], cudaEventDisableTiming);
    }

    Ptrs p;
    get_ptrs(p);

    k_build_h<<<65552, 256>>>(features, cls_tok);

    attention(p, p.h, ln1_g, ln1_b, qkv1_w, out1_w, out1_b, res1_w,
              side, ev[0], ev[1], ev[2]);

    k_h2planar<<<dim3(16,128,8), dim3(32,8)>>>(p.h, p.cnn);
    k_dwconv<<<4096, 256>>>(p.cnn, p7_w, p7_b, p5_w, p5_b, p3_w, p3_b, p.yp);
    k_planar2h<<<dim3(16,128,8), dim3(32,8)>>>(p.yp, p.h2);
    k_cls_copy<<<16, 256>>>(p.h, p.h2);

    attention(p, p.h2, ln2_g, ln2_b, qkv2_w, out2_w, out2_b, res2_w,
              side, ev[3], ev[4], ev[5]);

    k_writeout<<<65552, 256>>>(p.h2, out);
}

// round 16
// speedup vs baseline: 1.6537x; 1.0346x over previous
#include <cuda_runtime.h>
#include <math.h>
#include <stdint.h>

// ---------------- problem constants ----------------
// B=8, C=512, HEADS=8, DH=64, tokens=4097 (cls+4096), pad=255 -> N=4352
// landmarks m=256, l=17, pinv iters=6, res kernel 33  (build r16: persistent pinv)
#define LSUB 17

// ---------------- device scratch ----------------
__device__ float g_h   [8L*4097*512];
__device__ float g_h2  [8L*4097*512];
__device__ float g_stat[8L*4097*2];
__device__ float g_qkv [8L*4352*1536];
__device__ float g_ql  [64L*256*64];
__device__ float g_kl  [64L*256*64];
__device__ float g_a2  [64L*256*256];
__device__ float g_zA  [64L*256*256];
__device__ float g_zB  [64L*256*256];
__device__ float g_xz  [64L*256*256];
__device__ float g_t1  [64L*256*256];
__device__ float g_t2  [64L*256*256];
__device__ float g_a3v [64L*256*64];
__device__ float g_tmp2[64L*256*64];
__device__ float g_ac  [8L*4097*512];
__device__ float g_cnn [8L*512*4096];
__device__ float g_yp  [8L*512*4096];
__device__ float g_scal[2];
__device__ unsigned g_cnt = 0;
__device__ volatile unsigned g_sense = 0;

__device__ __forceinline__ float4 ldg4(const float* p){ return *(const float4*)p; }
__device__ __forceinline__ float4 ldcg4(const float* p){
    float4 v;
    asm volatile("ld.global.cg.v4.f32 {%0,%1,%2,%3}, [%4];"
                 : "=f"(v.x),"=f"(v.y),"=f"(v.z),"=f"(v.w) : "l"(p));
    return v;
}

// ---------------- tf32 mma helpers ----------------
__device__ __forceinline__ uint32_t f2tf(float x){
    uint32_t u; asm("cvt.rna.tf32.f32 %0, %1;" : "=r"(u) : "f"(x)); return u;
}
__device__ __forceinline__ uint4 cvt4(float4 v){
    uint4 u; u.x=f2tf(v.x); u.y=f2tf(v.y); u.z=f2tf(v.z); u.w=f2tf(v.w); return u;
}
__device__ __forceinline__ void mma8(float* d, const uint32_t* a, const uint32_t* b){
    asm("mma.sync.aligned.m16n8k8.row.col.f32.tf32.tf32.f32 "
        "{%0,%1,%2,%3}, {%4,%5,%6,%7}, {%8,%9}, {%0,%1,%2,%3};"
        : "+f"(d[0]),"+f"(d[1]),"+f"(d[2]),"+f"(d[3])
        : "r"(a[0]),"r"(a[1]),"r"(a[2]),"r"(a[3]), "r"(b[0]),"r"(b[1]));
}

// Fragment-major scatter (for k_mma_nn64): element (row,k) of 128x16 A tile
__device__ __forceinline__ void scatA(uint32_t* Af, int row, int k, uint32_t v){
    int ks=k>>3, kc=k&7;
    Af[(((ks<<3)+(row>>4))<<7) + ((((row&7)<<2)+(kc&3))<<2) + ((row>>3)&1) + ((kc>>2)<<1)] = v;
}
// B tile with 8 n-tiles (64 cols)
__device__ __forceinline__ void scatB8(uint32_t* Bf, int n, int k, uint32_t v){
    int ks=k>>3, kc=k&7;
    Bf[(((ks<<3)+(n>>3))<<6) + ((((n&7)<<2)+(kc&3))<<1) + (kc>>2)] = v;
}

// ---------------- small kernels ----------------
__global__ void k_build_h(const float* __restrict__ feat, const float* __restrict__ cls){
    long idx = (long)blockIdx.x*256 + threadIdx.x;
    if(idx >= 8L*4097*512) return;
    int c = idx & 511; long r = idx >> 9; int t = (int)(r % 4097); int b = (int)(r / 4097);
    g_h[idx] = (t==0) ? cls[c] : feat[((long)b*4096 + (t-1))*512 + c];
}

// LN row stats: one warp per token row, one pass (mean, rstd)
__global__ void k_lnstat(const float* __restrict__ h, float* __restrict__ stat){
    long row = (long)blockIdx.x*8 + (threadIdx.x >> 5);
    if(row >= 8L*4097) return;
    int lane = threadIdx.x & 31;
    const float* x = h + row*512;
    float s = 0.f, s2 = 0.f;
    #pragma unroll
    for(int i=0;i<4;i++){
        float4 v = ldg4(x + lane*4 + i*128);
        s  += v.x + v.y + v.z + v.w;
        s2 += v.x*v.x + v.y*v.y + v.z*v.z + v.w*v.w;
    }
    #pragma unroll
    for(int o=16;o;o>>=1){
        s  += __shfl_xor_sync(0xffffffffu, s,  o);
        s2 += __shfl_xor_sync(0xffffffffu, s2, o);
    }
    if(lane == 0){
        float mean = s * (1.f/512.f);
        float var  = s2 * (1.f/512.f) - mean*mean;
        stat[2*row]   = mean;
        stat[2*row+1] = rsqrtf(var + 1e-5f);
    }
}

// =====================================================================
// TF32 tensor-core GEMMs: 128x128 block, 8 warps of 64x32, BK=16,
// 2-stage smem double buffer (one sync per ktile)
// =====================================================================

// qkv GEMM with LN fused on the A side (proven R15).
__global__ void __launch_bounds__(256,2) k_mma_nt_ln(
    const float* __restrict__ H, const float* __restrict__ stat,
    const float* __restrict__ gam, const float* __restrict__ bet,
    const float* __restrict__ B, int ldb,
    float* __restrict__ C, int ldc,
    int N, int K)
{
    __shared__ uint32_t As[2][128][20];
    __shared__ uint32_t Bs[2][128][20];
    int t = threadIdx.x;
    int lane = t & 31, warp = t >> 5;
    int wm = warp >> 2, wn = warp & 3;
    int r0 = blockIdx.x*128, c0 = blockIdx.y*128;
    int lrow = t >> 2, lk = (t & 3)*4;
    int gm0 = r0+lrow, gm1 = r0+lrow+64;
    int b0_ = gm0/4352, p0_ = gm0%4352;
    int b1_ = gm1/4352, p1_ = gm1%4352;
    bool v0 = p0_ >= 255, v1 = p1_ >= 255;
    long hr0 = (long)b0_*4097 + (p0_-255);
    long hr1 = (long)b1_*4097 + (p1_-255);
    float mu0=0.f, rs0=0.f, mu1=0.f, rs1=0.f;
    if(v0){ mu0 = stat[2*hr0]; rs0 = stat[2*hr0+1]; }
    if(v1){ mu1 = stat[2*hr1]; rs1 = stat[2*hr1+1]; }
    const float* Hp0 = H + hr0*512 + lk;
    const float* Hp1 = H + hr1*512 + lk;
    const float* Bp0 = B + (long)(c0+lrow)*ldb + lk;
    const float* Bp1 = B + (long)(c0+lrow+64)*ldb + lk;
    const float4 z4 = make_float4(0.f,0.f,0.f,0.f);
    float4 pa0 = v0?ldg4(Hp0):z4, pa1 = v1?ldg4(Hp1):z4;
    float4 pg = ldg4(gam + lk), pb = ldg4(bet + lk);
    float4 pb0 = ldg4(Bp0), pb1 = ldg4(Bp1);
    {
        float4 a0, a1;
        a0.x=(pa0.x-mu0)*rs0*pg.x+pb.x; a0.y=(pa0.y-mu0)*rs0*pg.y+pb.y;
        a0.z=(pa0.z-mu0)*rs0*pg.z+pb.z; a0.w=(pa0.w-mu0)*rs0*pg.w+pb.w;
        a1.x=(pa1.x-mu1)*rs1*pg.x+pb.x; a1.y=(pa1.y-mu1)*rs1*pg.y+pb.y;
        a1.z=(pa1.z-mu1)*rs1*pg.z+pb.z; a1.w=(pa1.w-mu1)*rs1*pg.w+pb.w;
        if(!v0) a0 = z4;
        if(!v1) a1 = z4;
        *(uint4*)&As[0][lrow][lk]    = cvt4(a0);
        *(uint4*)&As[0][lrow+64][lk] = cvt4(a1);
        *(uint4*)&Bs[0][lrow][lk]    = cvt4(pb0);
        *(uint4*)&Bs[0][lrow+64][lk] = cvt4(pb1);
    }
    __syncthreads();
    float accr[4][4][4];
    #pragma unroll
    for(int i=0;i<4;i++)
        #pragma unroll
        for(int j=0;j<4;j++)
            #pragma unroll
            for(int q=0;q<4;q++) accr[i][j][q]=0.f;
    int nk = K >> 4;
    for(int kt=0; kt<nk; kt++){
        int buf = kt & 1;
        if(kt+1<nk){
            int o = (kt+1)*16;
            pa0 = v0?ldg4(Hp0+o):z4; pa1 = v1?ldg4(Hp1+o):z4;
            pg = ldg4(gam + o + lk); pb = ldg4(bet + o + lk);
            pb0 = ldg4(Bp0+o); pb1 = ldg4(Bp1+o);
        }
        #pragma unroll
        for(int ks=0;ks<2;ks++){
            int cc = ks*8 + (lane&3);
            uint32_t a[4][4], b[4][2];
            int rA = wm*64 + (lane>>2);
            #pragma unroll
            for(int mt=0;mt<4;mt++){
                a[mt][0]=As[buf][rA+mt*16  ][cc];
                a[mt][1]=As[buf][rA+mt*16+8][cc];
                a[mt][2]=As[buf][rA+mt*16  ][cc+4];
                a[mt][3]=As[buf][rA+mt*16+8][cc+4];
            }
            int rB = wn*32 + (lane>>2);
            #pragma unroll
            for(int nt=0;nt<4;nt++){
                b[nt][0]=Bs[buf][rB+nt*8][cc];
                b[nt][1]=Bs[buf][rB+nt*8][cc+4];
            }
            #pragma unroll
            for(int mt=0;mt<4;mt++)
                #pragma unroll
                for(int nt=0;nt<4;nt++)
                    mma8(accr[mt][nt], a[mt], b[nt]);
        }
        if(kt+1<nk){
            int s = (kt+1) & 1;
            float4 a0, a1;
            a0.x=(pa0.x-mu0)*rs0*pg.x+pb.x; a0.y=(pa0.y-mu0)*rs0*pg.y+pb.y;
            a0.z=(pa0.z-mu0)*rs0*pg.z+pb.z; a0.w=(pa0.w-mu0)*rs0*pg.w+pb.w;
            a1.x=(pa1.x-mu1)*rs1*pg.x+pb.x; a1.y=(pa1.y-mu1)*rs1*pg.y+pb.y;
            a1.z=(pa1.z-mu1)*rs1*pg.z+pb.z; a1.w=(pa1.w-mu1)*rs1*pg.w+pb.w;
            if(!v0) a0 = z4;
            if(!v1) a1 = z4;
            *(uint4*)&As[s][lrow][lk]    = cvt4(a0);
            *(uint4*)&As[s][lrow+64][lk] = cvt4(a1);
            *(uint4*)&Bs[s][lrow][lk]    = cvt4(pb0);
            *(uint4*)&Bs[s][lrow+64][lk] = cvt4(pb1);
            __syncthreads();
        }
    }
    #pragma unroll
    for(int mt=0;mt<4;mt++)
    #pragma unroll
    for(int i=0;i<2;i++){
        int gm = r0 + wm*64 + mt*16 + i*8 + (lane>>2);
        #pragma unroll
        for(int nt=0;nt<4;nt++){
            int gn = c0 + wn*32 + nt*8 + 2*(lane&3);
            float2 v;
            v.x = accr[mt][nt][2*i];
            v.y = accr[mt][nt][2*i+1];
            *(float2*)(C + (long)gm*ldc + gn) = v;
        }
    }
}

// C = alpha * A @ B^T (+bias)(+C)   A:(M,K) lda, B:(N,K) ldb   batched (b,h)
__global__ void __launch_bounds__(256,2) k_mma_nt(
    const float* __restrict__ A, int lda, long sAb, long sAh,
    const float* __restrict__ B, int ldb, long sBb, long sBh,
    float* __restrict__ C, int ldc, long sCb, long sCh,
    int M, int N, int K, float alpha, const float* __restrict__ bias, int acc)
{
    int z = blockIdx.z; int hh = z & 7; int bb = z >> 3;
    A += (long)bb*sAb + (long)hh*sAh;
    B += (long)bb*sBb + (long)hh*sBh;
    C += (long)bb*sCb + (long)hh*sCh;
    __shared__ uint32_t As[2][128][20];
    __shared__ uint32_t Bs[2][128][20];
    int t = threadIdx.x;
    int lane = t & 31, warp = t >> 5;
    int wm = warp >> 2, wn = warp & 3;
    int r0 = blockIdx.x*128, c0 = blockIdx.y*128;
    int lrow = t >> 2, lk = (t & 3)*4;
    const float* Ap0 = A + (long)(r0+lrow)*lda + lk;
    const float* Ap1 = A + (long)(r0+lrow+64)*lda + lk;
    const float* Bp0 = B + (long)(c0+lrow)*ldb + lk;
    const float* Bp1 = B + (long)(c0+lrow+64)*ldb + lk;
    bool mA0 = (r0+lrow)<M, mA1 = (r0+lrow+64)<M;
    bool mB0 = (c0+lrow)<N, mB1 = (c0+lrow+64)<N;
    const float4 z4 = make_float4(0.f,0.f,0.f,0.f);
    float4 pa0 = mA0?ldg4(Ap0):z4, pa1 = mA1?ldg4(Ap1):z4;
    float4 pb0 = mB0?ldg4(Bp0):z4, pb1 = mB1?ldg4(Bp1):z4;
    *(uint4*)&As[0][lrow][lk]    = cvt4(pa0);
    *(uint4*)&As[0][lrow+64][lk] = cvt4(pa1);
    *(uint4*)&Bs[0][lrow][lk]    = cvt4(pb0);
    *(uint4*)&Bs[0][lrow+64][lk] = cvt4(pb1);
    __syncthreads();
    float accr[4][4][4];
    #pragma unroll
    for(int i=0;i<4;i++)
        #pragma unroll
        for(int j=0;j<4;j++)
            #pragma unroll
            for(int q=0;q<4;q++) accr[i][j][q]=0.f;
    int nk = K >> 4;
    for(int kt=0; kt<nk; kt++){
        int buf = kt & 1;
        if(kt+1<nk){
            int o = (kt+1)*16;
            pa0 = mA0?ldg4(Ap0+o):z4; pa1 = mA1?ldg4(Ap1+o):z4;
            pb0 = mB0?ldg4(Bp0+o):z4; pb1 = mB1?ldg4(Bp1+o):z4;
        }
        #pragma unroll
        for(int ks=0;ks<2;ks++){
            int cc = ks*8 + (lane&3);
            uint32_t a[4][4], b[4][2];
            int rA = wm*64 + (lane>>2);
            #pragma unroll
            for(int mt=0;mt<4;mt++){
                a[mt][0]=As[buf][rA+mt*16  ][cc];
                a[mt][1]=As[buf][rA+mt*16+8][cc];
                a[mt][2]=As[buf][rA+mt*16  ][cc+4];
                a[mt][3]=As[buf][rA+mt*16+8][cc+4];
            }
            int rB = wn*32 + (lane>>2);
            #pragma unroll
            for(int nt=0;nt<4;nt++){
                b[nt][0]=Bs[buf][rB+nt*8][cc];
                b[nt][1]=Bs[buf][rB+nt*8][cc+4];
            }
            #pragma unroll
            for(int mt=0;mt<4;mt++)
                #pragma unroll
                for(int nt=0;nt<4;nt++)
                    mma8(accr[mt][nt], a[mt], b[nt]);
        }
        if(kt+1<nk){
            int s = (kt+1) & 1;
            *(uint4*)&As[s][lrow][lk]    = cvt4(pa0);
            *(uint4*)&As[s][lrow+64][lk] = cvt4(pa1);
            *(uint4*)&Bs[s][lrow][lk]    = cvt4(pb0);
            *(uint4*)&Bs[s][lrow+64][lk] = cvt4(pb1);
            __syncthreads();
        }
    }
    #pragma unroll
    for(int mt=0;mt<4;mt++)
    #pragma unroll
    for(int i=0;i<2;i++){
        int gm = r0 + wm*64 + mt*16 + i*8 + (lane>>2);
        if(gm>=M) continue;
        #pragma unroll
        for(int nt=0;nt<4;nt++){
            int gn = c0 + wn*32 + nt*8 + 2*(lane&3);
            float2 v;
            v.x = alpha*accr[mt][nt][2*i];
            v.y = alpha*accr[mt][nt][2*i+1];
            if(bias){ v.x += bias[gn]; v.y += bias[gn+1]; }
            float* cp = C + (long)gm*ldc + gn;
            if(acc){ v.x += cp[0]; v.y += cp[1]; }
            *(float2*)cp = v;
        }
    }
}

// =====================================================================
// Persistent pinv: all 6 Newton-Schulz iterations (24 GEMMs) in ONE launch.
// Grid = 256 blocks (4 tiles x 64 bh), co-resident (<=296 slots), software
// sense-reversing grid barrier. All GEMM input loads via ld.global.cg
// (L2-only) to avoid stale-L1 reads across barriers.
// =====================================================================
__device__ __forceinline__ void gridbar(unsigned* lsense){
    __syncthreads();
    if(threadIdx.x == 0){
        unsigned target = *lsense ^ 1u;
        __threadfence();
        unsigned old = atomicAdd(&g_cnt, 1u);
        if(old == 255u){
            atomicExch(&g_cnt, 0u);
            __threadfence();
            g_sense = target;
        } else {
            while(g_sense != target){}
        }
        *lsense = target;
    }
    __syncthreads();
}

__device__ __forceinline__ void pinv_gemm(
    const float* __restrict__ A, const float* __restrict__ B,
    float* __restrict__ C, float* __restrict__ D,
    int r0, int c0, float alpha, float dconst, int cmode,
    uint32_t As[2][128][20], uint32_t Bs[2][16][136])
{
    int t = threadIdx.x;
    int lane = t & 31, warp = t >> 5;
    int wm = warp >> 2, wn = warp & 3;
    int lrow = t >> 2, lk = (t & 3)*4;
    int bk = t >> 5, bn = (t & 31)*4;
    const float* Ap0 = A + (long)(r0+lrow)*256 + lk;
    const float* Ap1 = A + (long)(r0+lrow+64)*256 + lk;
    const float* Bq0 = B + (long)bk*256 + c0 + bn;
    const float* Bq1 = B + (long)(bk+8)*256 + c0 + bn;
    float4 pa0 = ldcg4(Ap0), pa1 = ldcg4(Ap1);
    float4 pb0 = ldcg4(Bq0), pb1 = ldcg4(Bq1);
    *(uint4*)&As[0][lrow][lk]    = cvt4(pa0);
    *(uint4*)&As[0][lrow+64][lk] = cvt4(pa1);
    *(uint4*)&Bs[0][bk][bn]      = cvt4(pb0);
    *(uint4*)&Bs[0][bk+8][bn]    = cvt4(pb1);
    __syncthreads();
    float accr[4][4][4];
    #pragma unroll
    for(int i=0;i<4;i++)
        #pragma unroll
        for(int j=0;j<4;j++)
            #pragma unroll
            for(int q=0;q<4;q++) accr[i][j][q]=0.f;
    for(int kt=0; kt<16; kt++){
        int buf = kt & 1;
        if(kt+1<16){
            long o = (long)(kt+1)*16;
            pa0 = ldcg4(Ap0+o); pa1 = ldcg4(Ap1+o);
            pb0 = ldcg4(Bq0+o*256); pb1 = ldcg4(Bq1+o*256);
        }
        #pragma unroll
        for(int ks=0;ks<2;ks++){
            int cc = ks*8 + (lane&3);
            uint32_t a[4][4], b[4][2];
            int rA = wm*64 + (lane>>2);
            #pragma unroll
            for(int mt=0;mt<4;mt++){
                a[mt][0]=As[buf][rA+mt*16  ][cc];
                a[mt][1]=As[buf][rA+mt*16+8][cc];
                a[mt][2]=As[buf][rA+mt*16  ][cc+4];
                a[mt][3]=As[buf][rA+mt*16+8][cc+4];
            }
            int nB = wn*32 + (lane>>2);
            #pragma unroll
            for(int nt=0;nt<4;nt++){
                b[nt][0]=Bs[buf][cc  ][nB+nt*8];
                b[nt][1]=Bs[buf][cc+4][nB+nt*8];
            }
            #pragma unroll
            for(int mt=0;mt<4;mt++)
                #pragma unroll
                for(int nt=0;nt<4;nt++)
                    mma8(accr[mt][nt], a[mt], b[nt]);
        }
        if(kt+1<16){
            int s = (kt+1) & 1;
            *(uint4*)&As[s][lrow][lk]    = cvt4(pa0);
            *(uint4*)&As[s][lrow+64][lk] = cvt4(pa1);
            *(uint4*)&Bs[s][bk][bn]      = cvt4(pb0);
            *(uint4*)&Bs[s][bk+8][bn]    = cvt4(pb1);
            __syncthreads();
        }
    }
    #pragma unroll
    for(int mt=0;mt<4;mt++)
    #pragma unroll
    for(int i=0;i<2;i++){
        int gm = r0 + wm*64 + mt*16 + i*8 + (lane>>2);
        #pragma unroll
        for(int nt=0;nt<4;nt++){
            int gn = c0 + wn*32 + nt*8 + 2*(lane&3);
            float2 v;
            v.x = alpha*accr[mt][nt][2*i];
            v.y = alpha*accr[mt][nt][2*i+1];
            long o = (long)gm*256 + gn;
            if(D){
                float2 dv;
                dv.x = ((gm==gn  )?dconst:0.f) - v.x;
                dv.y = ((gm==gn+1)?dconst:0.f) - v.y;
                *(float2*)(D+o) = dv;
            }
            if(cmode){
                v.x = ((gm==gn  )?dconst:0.f) - v.x;
                v.y = ((gm==gn+1)?dconst:0.f) - v.y;
            }
            *(float2*)(C+o) = v;
        }
    }
}

__global__ void __launch_bounds__(256,2) k_pinv(
    const float* __restrict__ a2g, float* __restrict__ zAg, float* __restrict__ zBg,
    float* __restrict__ xzg, float* __restrict__ t1g, float* __restrict__ t2g)
{
    __shared__ uint32_t As[2][128][20];
    __shared__ uint32_t Bs[2][16][136];
    __shared__ unsigned lsense;
    int z = blockIdx.x >> 2;
    int tile = blockIdx.x & 3;
    int r0 = (tile >> 1)*128, c0 = (tile & 1)*128;
    long off = (long)z*65536;
    const float* a2 = a2g + off;
    float* zA = zAg + off; float* zB = zBg + off;
    float* xz = xzg + off; float* t1 = t1g + off; float* t2 = t2g + off;
    if(threadIdx.x == 0) lsense = g_sense;
    __syncthreads();
    float* zc = zA; float* zn = zB;
    #pragma unroll 1
    for(int it=0; it<6; it++){
        pinv_gemm(a2, zc, xz, t1, r0, c0, 1.f, 7.f, 0, As, Bs);
        gridbar(&lsense);
        pinv_gemm(xz, t1, t2, nullptr, r0, c0, 1.f, 15.f, 1, As, Bs);
        gridbar(&lsense);
        pinv_gemm(xz, t2, t1, nullptr, r0, c0, 1.f, 13.f, 1, As, Bs);
        gridbar(&lsense);
        pinv_gemm(zc, t1, zn, nullptr, r0, c0, 0.25f, 0.f, 0, As, Bs);
        if(it < 5) gridbar(&lsense);
        float* tmp = zc; zc = zn; zn = tmp;
    }
}

// Fused GEMM+softmax: C = softmax_row(alpha * A @ B^T), K=64, N=256.
__global__ void __launch_bounds__(256,2) k_simsm(
    const float* __restrict__ A, int lda, long sAb, long sAh,
    const float* __restrict__ B, int ldb, long sBb, long sBh,
    float* __restrict__ C, int ldc, long sCb, long sCh,
    float alpha)
{
    int z = blockIdx.z; int hh = z & 7; int bb = z >> 3;
    A += (long)bb*sAb + (long)hh*sAh;
    B += (long)bb*sBb + (long)hh*sBh;
    C += (long)bb*sCb + (long)hh*sCh;
    __shared__ uint32_t As[64][20];
    __shared__ uint32_t Bs[256][20];
    __shared__ float red[64][4];
    int t = threadIdx.x;
    int lane = t & 31, warp = t >> 5;
    int wm = warp >> 2, wn = warp & 3;
    int r0 = blockIdx.x*64;
    int lrow = t >> 2, lk = (t & 3)*4;
    float acc[2][8][4];
    #pragma unroll
    for(int i=0;i<2;i++)
        #pragma unroll
        for(int j=0;j<8;j++)
            #pragma unroll
            for(int q=0;q<4;q++) acc[i][j][q]=0.f;
    for(int kt=0; kt<4; kt++){
        __syncthreads();
        *(uint4*)&As[lrow][lk] = cvt4(ldg4(A + (long)(r0+lrow)*lda + kt*16 + lk));
        #pragma unroll
        for(int i=0;i<4;i++)
            *(uint4*)&Bs[i*64+lrow][lk] = cvt4(ldg4(B + (long)(i*64+lrow)*ldb + kt*16 + lk));
        __syncthreads();
        #pragma unroll
        for(int ks=0;ks<2;ks++){
            int cc = ks*8 + (lane&3);
            uint32_t a[2][4], b[8][2];
            int rA = wm*32 + (lane>>2);
            #pragma unroll
            for(int mt=0;mt<2;mt++){
                a[mt][0]=As[rA+mt*16  ][cc];
                a[mt][1]=As[rA+mt*16+8][cc];
                a[mt][2]=As[rA+mt*16  ][cc+4];
                a[mt][3]=As[rA+mt*16+8][cc+4];
            }
            int rB = wn*64 + (lane>>2);
            #pragma unroll
            for(int nt=0;nt<8;nt++){
                b[nt][0]=Bs[rB+nt*8][cc];
                b[nt][1]=Bs[rB+nt*8][cc+4];
            }
            #pragma unroll
            for(int mt=0;mt<2;mt++)
                #pragma unroll
                for(int nt=0;nt<8;nt++)
                    mma8(acc[mt][nt], a[mt], b[nt]);
        }
    }
    int g = lane>>2, tq = lane&3;
    float pm[2][2];
    #pragma unroll
    for(int mt=0;mt<2;mt++)
        #pragma unroll
        for(int i=0;i<2;i++){
            float m = -1e30f;
            #pragma unroll
            for(int nt=0;nt<8;nt++){
                acc[mt][nt][2*i]   *= alpha;
                acc[mt][nt][2*i+1] *= alpha;
                m = fmaxf(m, fmaxf(acc[mt][nt][2*i], acc[mt][nt][2*i+1]));
            }
            m = fmaxf(m, __shfl_xor_sync(0xffffffffu, m, 1));
            m = fmaxf(m, __shfl_xor_sync(0xffffffffu, m, 2));
            pm[mt][i] = m;
        }
    if(tq==0){
        #pragma unroll
        for(int mt=0;mt<2;mt++)
            #pragma unroll
            for(int i=0;i<2;i++)
                red[wm*32+mt*16+i*8+g][wn] = pm[mt][i];
    }
    __syncthreads();
    float rmax[2][2];
    #pragma unroll
    for(int mt=0;mt<2;mt++)
        #pragma unroll
        for(int i=0;i<2;i++){
            int rid = wm*32+mt*16+i*8+g;
            rmax[mt][i] = fmaxf(fmaxf(red[rid][0],red[rid][1]), fmaxf(red[rid][2],red[rid][3]));
        }
    __syncthreads();
    float ps[2][2];
    #pragma unroll
    for(int mt=0;mt<2;mt++)
        #pragma unroll
        for(int i=0;i<2;i++){
            float s = 0.f;
            #pragma unroll
            for(int nt=0;nt<8;nt++){
                float e0 = __expf(acc[mt][nt][2*i]   - rmax[mt][i]);
                float e1 = __expf(acc[mt][nt][2*i+1] - rmax[mt][i]);
                acc[mt][nt][2*i]   = e0;
                acc[mt][nt][2*i+1] = e1;
                s += e0 + e1;
            }
            s += __shfl_xor_sync(0xffffffffu, s, 1);
            s += __shfl_xor_sync(0xffffffffu, s, 2);
            ps[mt][i] = s;
        }
    if(tq==0){
        #pragma unroll
        for(int mt=0;mt<2;mt++)
            #pragma unroll
            for(int i=0;i<2;i++)
                red[wm*32+mt*16+i*8+g][wn] = ps[mt][i];
    }
    __syncthreads();
    #pragma unroll
    for(int mt=0;mt<2;mt++)
        #pragma unroll
        for(int i=0;i<2;i++){
            int rid = wm*32+mt*16+i*8+g;
            float inv = 1.f/(red[rid][0]+red[rid][1]+red[rid][2]+red[rid][3]);
            long gm = r0 + rid;
            #pragma unroll
            for(int nt=0;nt<8;nt++){
                int gn = wn*64 + nt*8 + 2*tq;
                float2 v; v.x = acc[mt][nt][2*i]*inv; v.y = acc[mt][nt][2*i+1]*inv;
                *(float2*)(C + gm*ldc + gn) = v;
            }
        }
}

// =====================================================================
// Flash-style fused sim3+softmax+a3v (proven R12)
// =====================================================================
__global__ void __launch_bounds__(256,2) k_flash3(
    const float* __restrict__ QL, long sQL,
    const float* __restrict__ QKV, long sQKVb,
    float* __restrict__ Ov, long sO)
{
    extern __shared__ char dyn[];
    uint32_t (*Qs)[68] = (uint32_t(*)[68])dyn;
    uint32_t (*Ks)[20] = (uint32_t(*)[20])(dyn + 17408);
    uint32_t (*Pf)[68] = (uint32_t(*)[68])(dyn + 17408);
    uint32_t (*Vs)[72] = (uint32_t(*)[72])(dyn + 17408 + 17408);
    float (*red)[4] = (float(*)[4])(dyn + 53248);
    float* m_run = (float*)(dyn + 54272);
    float* l_run = (float*)(dyn + 54528);
    float* sf    = (float*)(dyn + 54784);
    int z = blockIdx.z; int hh = z & 7; int bb = z >> 3;
    const float* Q  = QL  + (long)z*sQL;
    const float* Kg = QKV + (long)bb*sQKVb + 512  + hh*64;
    const float* Vg = QKV + (long)bb*sQKVb + 1024 + hh*64;
    float* Og = Ov + (long)z*sO;
    int t = threadIdx.x, lane = t & 31, warp = t >> 5;
    int wm = warp >> 2, wn = warp & 3;
    int wm2 = warp >> 1, wn2 = warp & 1;
    int g = lane >> 2, tq = lane & 3;
    int r0 = blockIdx.x*64;
    {
        int row = t >> 2, cb = (t & 3)*16;
        const float* qp = Q + (long)(r0+row)*64 + cb;
        #pragma unroll
        for(int j=0;j<4;j++){
            float4 v = ldg4(qp + j*4);
            Qs[row][cb+j*4+0]=f2tf(v.x); Qs[row][cb+j*4+1]=f2tf(v.y);
            Qs[row][cb+j*4+2]=f2tf(v.z); Qs[row][cb+j*4+3]=f2tf(v.w);
        }
    }
    if(t < 64){ m_run[t] = -1e30f; l_run[t] = 0.f; }
    float acc2[4][4];
    #pragma unroll
    for(int j=0;j<4;j++)
        #pragma unroll
        for(int q=0;q<4;q++) acc2[j][q]=0.f;
    for(int ch=0; ch<17; ch++){
        long kc0 = (long)ch*256;
        float acc[2][8][4];
        #pragma unroll
        for(int i=0;i<2;i++)
            #pragma unroll
            for(int j=0;j<8;j++)
                #pragma unroll
                for(int q=0;q<4;q++) acc[i][j][q]=0.f;
        for(int kt=0; kt<4; kt++){
            __syncthreads();
            int lrow = t >> 2, lk = (t & 3)*4;
            #pragma unroll
            for(int i=0;i<4;i++){
                int row = i*64 + lrow;
                *(uint4*)&Ks[row][lk] = cvt4(ldg4(Kg + (kc0+row)*1536 + kt*16 + lk));
            }
            __syncthreads();
            #pragma unroll
            for(int ks=0;ks<2;ks++){
                int cc = ks*8 + tq, qc = kt*16 + cc;
                uint32_t a[2][4], b[8][2];
                int rA = wm*32 + g;
                #pragma unroll
                for(int mt=0;mt<2;mt++){
                    a[mt][0]=Qs[rA+mt*16  ][qc];
                    a[mt][1]=Qs[rA+mt*16+8][qc];
                    a[mt][2]=Qs[rA+mt*16  ][qc+4];
                    a[mt][3]=Qs[rA+mt*16+8][qc+4];
                }
                int rB = wn*64 + g;
                #pragma unroll
                for(int nt=0;nt<8;nt++){
                    b[nt][0]=Ks[rB+nt*8][cc];
                    b[nt][1]=Ks[rB+nt*8][cc+4];
                }
                #pragma unroll
                for(int mt=0;mt<2;mt++)
                    #pragma unroll
                    for(int nt=0;nt<8;nt++)
                        mma8(acc[mt][nt], a[mt], b[nt]);
            }
        }
        float pm[2][2];
        #pragma unroll
        for(int mt=0;mt<2;mt++)
            #pragma unroll
            for(int i=0;i<2;i++){
                float m = -1e30f;
                #pragma unroll
                for(int nt=0;nt<8;nt++)
                    m = fmaxf(m, fmaxf(acc[mt][nt][2*i], acc[mt][nt][2*i+1]));
                m = fmaxf(m, __shfl_xor_sync(0xffffffffu, m, 1));
                m = fmaxf(m, __shfl_xor_sync(0xffffffffu, m, 2));
                pm[mt][i] = m;
            }
        if(tq==0){
            #pragma unroll
            for(int mt=0;mt<2;mt++)
                #pragma unroll
                for(int i=0;i<2;i++)
                    red[wm*32+mt*16+i*8+g][wn] = pm[mt][i];
        }
        __syncthreads();
        float mn_[2][2];
        #pragma unroll
        for(int mt=0;mt<2;mt++)
            #pragma unroll
            for(int i=0;i<2;i++){
                int rid = wm*32+mt*16+i*8+g;
                float cm = fmaxf(fmaxf(red[rid][0],red[rid][1]), fmaxf(red[rid][2],red[rid][3]));
                mn_[mt][i] = fmaxf(m_run[rid], cm);
            }
        __syncthreads();
        float ps[2][2];
        #pragma unroll
        for(int mt=0;mt<2;mt++)
            #pragma unroll
            for(int i=0;i<2;i++){
                float s = 0.f;
                #pragma unroll
                for(int nt=0;nt<8;nt++){
                    float e0 = __expf(acc[mt][nt][2*i]   - mn_[mt][i]);
                    float e1 = __expf(acc[mt][nt][2*i+1] - mn_[mt][i]);
                    acc[mt][nt][2*i]   = e0;
                    acc[mt][nt][2*i+1] = e1;
                    s += e0 + e1;
                }
                s += __shfl_xor_sync(0xffffffffu, s, 1);
                s += __shfl_xor_sync(0xffffffffu, s, 2);
                ps[mt][i] = s;
            }
        if(tq==0){
            #pragma unroll
            for(int mt=0;mt<2;mt++)
                #pragma unroll
                for(int i=0;i<2;i++)
                    red[wm*32+mt*16+i*8+g][wn] = ps[mt][i];
        }
        __syncthreads();
        if(wn==0 && tq==0){
            #pragma unroll
            for(int mt=0;mt<2;mt++)
                #pragma unroll
                for(int i=0;i<2;i++){
                    int rid = wm*32+mt*16+i*8+g;
                    float ct = red[rid][0]+red[rid][1]+red[rid][2]+red[rid][3];
                    float mn = mn_[mt][i];
                    float f  = __expf(m_run[rid] - mn);
                    l_run[rid] = l_run[rid]*f + ct;
                    m_run[rid] = mn;
                    sf[rid] = f;
                }
        }
        __syncthreads();
        #pragma unroll
        for(int i=0;i<2;i++){
            float f2 = sf[wm2*16 + i*8 + g];
            #pragma unroll
            for(int nt=0;nt<4;nt++){ acc2[nt][2*i]*=f2; acc2[nt][2*i+1]*=f2; }
        }
        for(int sub=0; sub<4; sub++){
            __syncthreads();
            if(wn == sub){
                #pragma unroll
                for(int mt=0;mt<2;mt++)
                    #pragma unroll
                    for(int i=0;i<2;i++){
                        int rl = wm*32+mt*16+i*8+g;
                        #pragma unroll
                        for(int nt=0;nt<8;nt++){
                            int cl = nt*8 + 2*tq;
                            Pf[rl][cl]   = f2tf(acc[mt][nt][2*i]);
                            Pf[rl][cl+1] = f2tf(acc[mt][nt][2*i+1]);
                        }
                    }
            }
            {
                int kl = t >> 2, cb = (t & 3)*16;
                const float* vp = Vg + (kc0 + sub*64 + kl)*1536 + cb;
                #pragma unroll
                for(int j=0;j<4;j++){
                    float4 v = ldg4(vp + j*4);
                    Vs[kl][cb+j*4+0]=f2tf(v.x); Vs[kl][cb+j*4+1]=f2tf(v.y);
                    Vs[kl][cb+j*4+2]=f2tf(v.z); Vs[kl][cb+j*4+3]=f2tf(v.w);
                }
            }
            __syncthreads();
            #pragma unroll
            for(int kk=0;kk<8;kk++){
                int cc = kk*8 + tq;
                uint32_t a[4], b[4][2];
                a[0]=Pf[wm2*16+g  ][cc];
                a[1]=Pf[wm2*16+8+g][cc];
                a[2]=Pf[wm2*16+g  ][cc+4];
                a[3]=Pf[wm2*16+8+g][cc+4];
                #pragma unroll
                for(int nt=0;nt<4;nt++){
                    int n = wn2*32 + nt*8 + g;
                    b[nt][0]=Vs[cc  ][n];
                    b[nt][1]=Vs[cc+4][n];
                }
                #pragma unroll
                for(int nt=0;nt<4;nt++)
                    mma8(acc2[nt], a, b[nt]);
            }
        }
    }
    #pragma unroll
    for(int i=0;i<2;i++){
        int row = wm2*16 + i*8 + g;
        float linv = 1.f/l_run[row];
        float* dst = Og + (long)(r0+row)*64;
        #pragma unroll
        for(int nt=0;nt<4;nt++){
            int col = wn2*32 + nt*8 + 2*tq;
            float2 v; v.x = acc2[nt][2*i]*linv; v.y = acc2[nt][2*i+1]*linv;
            *(float2*)(dst + col) = v;
        }
    }
}

// =====================================================================
// Fused attention output: ac[token] += softmax(alpha * q @ kl^T) @ tmp2
// =====================================================================
__global__ void __launch_bounds__(256,2) k_attnout(
    const float* __restrict__ Q, int ldq, long sQb, long sQh,
    const float* __restrict__ KL, long sKL,
    const float* __restrict__ T2, long sT2,
    float* __restrict__ AC, float alpha)
{
    int z = blockIdx.z; int hh = z & 7; int bb = z >> 3;
    const float* A = Q  + (long)bb*sQb + (long)hh*sQh;
    const float* B = KL + (long)z*sKL;
    const float* T = T2 + (long)z*sT2;
    __shared__ char smem_raw[35840];
    __shared__ float red[64][4];
    uint32_t (*As)[20] = (uint32_t(*)[20])smem_raw;
    uint32_t (*Bs)[20] = (uint32_t(*)[20])(smem_raw + 5120);
    uint32_t (*Pf)[68] = (uint32_t(*)[68])smem_raw;
    uint32_t (*Ts)[72] = (uint32_t(*)[72])(smem_raw + 17408);
    int t = threadIdx.x;
    int lane = t & 31, warp = t >> 5;
    int wm = warp >> 2, wn = warp & 3;
    int r0 = blockIdx.x*64;
    int lrow = t >> 2, lk = (t & 3)*4;
    int g = lane>>2, tq = lane&3;
    float acc[2][8][4];
    #pragma unroll
    for(int i=0;i<2;i++)
        #pragma unroll
        for(int j=0;j<8;j++)
            #pragma unroll
            for(int q=0;q<4;q++) acc[i][j][q]=0.f;
    for(int kt=0; kt<4; kt++){
        __syncthreads();
        *(uint4*)&As[lrow][lk] = cvt4(ldg4(A + (long)(r0+lrow)*ldq + kt*16 + lk));
        #pragma unroll
        for(int i=0;i<4;i++)
            *(uint4*)&Bs[i*64+lrow][lk] = cvt4(ldg4(B + (long)(i*64+lrow)*64 + kt*16 + lk));
        __syncthreads();
        #pragma unroll
        for(int ks=0;ks<2;ks++){
            int cc = ks*8 + tq;
            uint32_t a[2][4], b[8][2];
            int rA = wm*32 + g;
            #pragma unroll
            for(int mt=0;mt<2;mt++){
                a[mt][0]=As[rA+mt*16  ][cc];
                a[mt][1]=As[rA+mt*16+8][cc];
                a[mt][2]=As[rA+mt*16  ][cc+4];
                a[mt][3]=As[rA+mt*16+8][cc+4];
            }
            int rB = wn*64 + g;
            #pragma unroll
            for(int nt=0;nt<8;nt++){
                b[nt][0]=Bs[rB+nt*8][cc];
                b[nt][1]=Bs[rB+nt*8][cc+4];
            }
            #pragma unroll
            for(int mt=0;mt<2;mt++)
                #pragma unroll
                for(int nt=0;nt<8;nt++)
                    mma8(acc[mt][nt], a[mt], b[nt]);
        }
    }
    float pm[2][2];
    #pragma unroll
    for(int mt=0;mt<2;mt++)
        #pragma unroll
        for(int i=0;i<2;i++){
            float m = -1e30f;
            #pragma unroll
            for(int nt=0;nt<8;nt++){
                acc[mt][nt][2*i]   *= alpha;
                acc[mt][nt][2*i+1] *= alpha;
                m = fmaxf(m, fmaxf(acc[mt][nt][2*i], acc[mt][nt][2*i+1]));
            }
            m = fmaxf(m, __shfl_xor_sync(0xffffffffu, m, 1));
            m = fmaxf(m, __shfl_xor_sync(0xffffffffu, m, 2));
            pm[mt][i] = m;
        }
    if(tq==0){
        #pragma unroll
        for(int mt=0;mt<2;mt++)
            #pragma unroll
            for(int i=0;i<2;i++)
                red[wm*32+mt*16+i*8+g][wn] = pm[mt][i];
    }
    __syncthreads();
    float rmax[2][2];
    #pragma unroll
    for(int mt=0;mt<2;mt++)
        #pragma unroll
        for(int i=0;i<2;i++){
            int rid = wm*32+mt*16+i*8+g;
            rmax[mt][i] = fmaxf(fmaxf(red[rid][0],red[rid][1]), fmaxf(red[rid][2],red[rid][3]));
        }
    __syncthreads();
    float ps[2][2];
    #pragma unroll
    for(int mt=0;mt<2;mt++)
        #pragma unroll
        for(int i=0;i<2;i++){
            float s = 0.f;
            #pragma unroll
            for(int nt=0;nt<8;nt++){
                float e0 = __expf(acc[mt][nt][2*i]   - rmax[mt][i]);
                float e1 = __expf(acc[mt][nt][2*i+1] - rmax[mt][i]);
                acc[mt][nt][2*i]   = e0;
                acc[mt][nt][2*i+1] = e1;
                s += e0 + e1;
            }
            s += __shfl_xor_sync(0xffffffffu, s, 1);
            s += __shfl_xor_sync(0xffffffffu, s, 2);
            ps[mt][i] = s;
        }
    if(tq==0){
        #pragma unroll
        for(int mt=0;mt<2;mt++)
            #pragma unroll
            for(int i=0;i<2;i++)
                red[wm*32+mt*16+i*8+g][wn] = ps[mt][i];
    }
    __syncthreads();
    float inv2[2][2];
    #pragma unroll
    for(int mt=0;mt<2;mt++)
        #pragma unroll
        for(int i=0;i<2;i++){
            int rid = wm*32+mt*16+i*8+g;
            inv2[mt][i] = 1.f/(red[rid][0]+red[rid][1]+red[rid][2]+red[rid][3]);
            #pragma unroll
            for(int nt=0;nt<8;nt++){
                acc[mt][nt][2*i]   *= inv2[mt][i];
                acc[mt][nt][2*i+1] *= inv2[mt][i];
            }
        }
    int wm2 = warp >> 1, wn2 = warp & 1;
    float acc2[4][4];
    #pragma unroll
    for(int j=0;j<4;j++)
        #pragma unroll
        for(int q=0;q<4;q++) acc2[j][q]=0.f;
    for(int ch=0; ch<4; ch++){
        __syncthreads();
        if(wn == ch){
            #pragma unroll
            for(int mt=0;mt<2;mt++)
                #pragma unroll
                for(int i=0;i<2;i++){
                    int row_l = wm*32+mt*16+i*8+g;
                    #pragma unroll
                    for(int nt=0;nt<8;nt++){
                        int col_l = nt*8 + 2*tq;
                        Pf[row_l][col_l]   = f2tf(acc[mt][nt][2*i]);
                        Pf[row_l][col_l+1] = f2tf(acc[mt][nt][2*i+1]);
                    }
                }
        }
        {
            int kl_ = t >> 2, cb = (t & 3)*16;
            const float* Tp = T + (long)(64*ch + kl_)*64 + cb;
            #pragma unroll
            for(int j=0;j<4;j++){
                float4 v = ldg4(Tp + j*4);
                Ts[kl_][cb+j*4+0] = f2tf(v.x);
                Ts[kl_][cb+j*4+1] = f2tf(v.y);
                Ts[kl_][cb+j*4+2] = f2tf(v.z);
                Ts[kl_][cb+j*4+3] = f2tf(v.w);
            }
        }
        __syncthreads();
        #pragma unroll
        for(int kk=0;kk<8;kk++){
            int cc = kk*8 + tq;
            uint32_t a[4], b[4][2];
            a[0]=Pf[wm2*16+g  ][cc];
            a[1]=Pf[wm2*16+8+g][cc];
            a[2]=Pf[wm2*16+g  ][cc+4];
            a[3]=Pf[wm2*16+8+g][cc+4];
            #pragma unroll
            for(int nt=0;nt<4;nt++){
                int n = wn2*32 + nt*8 + g;
                b[nt][0]=Ts[cc  ][n];
                b[nt][1]=Ts[cc+4][n];
            }
            #pragma unroll
            for(int nt=0;nt<4;nt++)
                mma8(acc2[nt], a, b[nt]);
        }
    }
    #pragma unroll
    for(int i=0;i<2;i++){
        int gm = r0 + wm2*16 + i*8 + g;
        if(gm < 255) continue;
        float* dst = AC + ((long)bb*4097 + (gm-255))*512 + hh*64;
        #pragma unroll
        for(int nt=0;nt<4;nt++){
            int gn = wn2*32 + nt*8 + 2*tq;
            float2 o = *(float2*)(dst + gn);
            float2 v; v.x = acc2[nt][2*i] + o.x; v.y = acc2[nt][2*i+1] + o.y;
            *(float2*)(dst + gn) = v;
        }
    }
}

// C = alpha * A @ B (NN, TF32), N=64. 128x64 block, 8 warps of 32x32. (proven)
__global__ void __launch_bounds__(256,2) k_mma_nn64(
    const float* __restrict__ A, int lda, long sAb, long sAh,
    const float* __restrict__ B, int ldb, long sBb, long sBh,
    float* __restrict__ C, int ldc, long sCb, long sCh,
    int M, int K, float alpha, int rowLo)
{
    int z = blockIdx.z; int hh = z & 7; int bb = z >> 3;
    A += (long)bb*sAb + (long)hh*sAh;
    B += (long)bb*sBb + (long)hh*sBh;
    C += (long)bb*sCb + (long)hh*sCh;
    __shared__ uint32_t Af[2][2048];
    __shared__ uint32_t Bf[2][1024];
    int t = threadIdx.x, lane = t & 31, warp = t >> 5;
    int wm = warp >> 1, wn = warp & 1;
    int r0 = blockIdx.x*128;
    int alr = t >> 1, alk = (t & 1)*8;
    const float* Ap = A + (long)(r0+alr)*lda + alk;
    bool mA = (r0+alr) < M;
    int bk = t >> 4, bn = (t & 15)*4;
    const float* Bp = B + (long)bk*ldb + bn;
    const float4 z4 = make_float4(0.f,0.f,0.f,0.f);
    float4 a0,a1,b0;
    a0 = mA?ldg4(Ap):z4; a1 = mA?ldg4(Ap+4):z4;
    b0 = ldg4(Bp);
    {
        scatA(Af[0], alr, alk+0, f2tf(a0.x)); scatA(Af[0], alr, alk+1, f2tf(a0.y));
        scatA(Af[0], alr, alk+2, f2tf(a0.z)); scatA(Af[0], alr, alk+3, f2tf(a0.w));
        scatA(Af[0], alr, alk+4, f2tf(a1.x)); scatA(Af[0], alr, alk+5, f2tf(a1.y));
        scatA(Af[0], alr, alk+6, f2tf(a1.z)); scatA(Af[0], alr, alk+7, f2tf(a1.w));
        scatB8(Bf[0], bn+0, bk, f2tf(b0.x)); scatB8(Bf[0], bn+1, bk, f2tf(b0.y));
        scatB8(Bf[0], bn+2, bk, f2tf(b0.z)); scatB8(Bf[0], bn+3, bk, f2tf(b0.w));
    }
    __syncthreads();
    float acc[2][4][4];
    #pragma unroll
    for(int i=0;i<2;i++)
        #pragma unroll
        for(int j=0;j<4;j++)
            #pragma unroll
            for(int q=0;q<4;q++) acc[i][j][q]=0.f;
    int nk = K >> 4;
    for(int kt=0; kt<nk; kt++){
        if(kt+1<nk){
            long o = (long)(kt+1)*16;
            a0 = mA?ldg4(Ap+o):z4; a1 = mA?ldg4(Ap+o+4):z4;
            b0 = ldg4(Bp + o*ldb);
        }
        int buf = kt & 1;
        #pragma unroll
        for(int ks=0;ks<2;ks++){
            uint32_t af[2][4], bfr[4][2];
            #pragma unroll
            for(int mt=0;mt<2;mt++)
                *(uint4*)af[mt] = *(const uint4*)&Af[buf][(((ks<<3)+(wm<<1)+mt)<<7) + (lane<<2)];
            #pragma unroll
            for(int nt=0;nt<4;nt++)
                *(uint2*)bfr[nt] = *(const uint2*)&Bf[buf][(((ks<<3)+(wn<<2)+nt)<<6) + (lane<<1)];
            #pragma unroll
            for(int mt=0;mt<2;mt++)
                #pragma unroll
                for(int nt=0;nt<4;nt++)
                    mma8(acc[mt][nt], af[mt], bfr[nt]);
        }
        if(kt+1<nk){
            int s = (kt+1) & 1;
            scatA(Af[s], alr, alk+0, f2tf(a0.x)); scatA(Af[s], alr, alk+1, f2tf(a0.y));
            scatA(Af[s], alr, alk+2, f2tf(a0.z)); scatA(Af[s], alr, alk+3, f2tf(a0.w));
            scatA(Af[s], alr, alk+4, f2tf(a1.x)); scatA(Af[s], alr, alk+5, f2tf(a1.y));
            scatA(Af[s], alr, alk+6, f2tf(a1.z)); scatA(Af[s], alr, alk+7, f2tf(a1.w));
            scatB8(Bf[s], bn+0, bk, f2tf(b0.x)); scatB8(Bf[s], bn+1, bk, f2tf(b0.y));
            scatB8(Bf[s], bn+2, bk, f2tf(b0.z)); scatB8(Bf[s], bn+3, bk, f2tf(b0.w));
            __syncthreads();
        }
    }
    int g = lane >> 2, tq = lane & 3;
    #pragma unroll
    for(int mt=0;mt<2;mt++)
    #pragma unroll
    for(int i=0;i<2;i++){
        int gm = r0 + wm*32 + mt*16 + i*8 + g;
        if(gm >= M || gm < rowLo) continue;
        #pragma unroll
        for(int nt=0;nt<4;nt++){
            int gn = wn*32 + nt*8 + 2*tq;
            float2 v;
            v.x = alpha*acc[mt][nt][2*i];
            v.y = alpha*acc[mt][nt][2*i+1];
            *(float2*)(C + (long)gm*ldc + gn) = v;
        }
    }
}

// ---------------- landmarks (mean over 17 tokens), q scaled by 1/8 ----------------
__global__ void k_landmarks(const float* __restrict__ qkv, float* __restrict__ ql, float* __restrict__ kl){
    int idx = blockIdx.x;
    int mi = idx % 256; int hh = (idx/256) & 7; int b = idx / (256*8);
    int dh = threadIdx.x;
    float sq=0.f, sk=0.f;
    for(int j=0;j<LSUB;j++){
        long tok = (long)mi*LSUB + j;
        const float* base = qkv + ((long)b*4352 + tok)*1536 + hh*64 + dh;
        sq += base[0];
        sk += base[512];
    }
    long o = (long)idx*64 + dh;
    ql[o] = sq * (0.125f/LSUB);
    kl[o] = sk * (1.0f/LSUB);
}

// ---------------- pinv scalar reductions ----------------
__global__ void k_scal_init(){ if(threadIdx.x < 2) g_scal[threadIdx.x] = 0.f; }

__global__ void k_rowsum_max(const float* __restrict__ X){
    long row = blockIdx.x;
    const float* x = X + row*256;
    int t = threadIdx.x;
    __shared__ float red[256];
    red[t] = fabsf(x[t]); __syncthreads();
    for(int k=128;k;k>>=1){ if(t<k) red[t]+=red[t+k]; __syncthreads(); }
    if(t==0) atomicMax((int*)&g_scal[0], __float_as_int(red[0]));
}

__global__ void k_colsum_max(const float* __restrict__ X){
    int b = blockIdx.x; int j = threadIdx.x;
    const float* x = X + (long)b*65536;
    float s = 0.f;
    for(int i=0;i<256;i++) s += fabsf(x[i*256+j]);
    __shared__ float red[256];
    red[j]=s; __syncthreads();
    for(int k=128;k;k>>=1){ if(j<k) red[j]=fmaxf(red[j],red[j+k]); __syncthreads(); }
    if(j==0) atomicMax((int*)&g_scal[1], __float_as_int(red[0]));
}

__global__ void k_tr_scale(const float* __restrict__ X, float* __restrict__ Z){
    long idx = (long)blockIdx.x*256 + threadIdx.x;
    if(idx >= 64L*65536) return;
    float inv = 1.f/(g_scal[0]*g_scal[1]);
    int j = (int)(idx & 255); int i = (int)((idx>>8) & 255); long b = idx >> 16;
    Z[idx] = X[(b<<16) + ((long)j<<8) + i] * inv;
}

// ---------------- residual depthwise conv (k=33), WRITES token-major into ac ----------------
__global__ void k_resconv2(const float* __restrict__ qkv, const float* __restrict__ w,
                           float* __restrict__ ac){
    int bh = blockIdx.y; int hh = bh & 7; int b = bh >> 3;
    int t0 = blockIdx.x*64;
    __shared__ float sv[96][65];
    __shared__ float sw[33];
    int t = threadIdx.x;
    if(t < 33) sw[t] = w[hh*33 + t];
    const float* vb = qkv + ((long)b*4352)*1536 + 1024 + hh*64;
    for(int i=t;i<96*64;i+=256){
        int tok = t0 - 16 + (i>>6); int dh = i&63;
        sv[i>>6][dh] = (tok>=0 && tok<4352) ? vb[(long)tok*1536 + dh] : 0.f;
    }
    __syncthreads();
    for(int i=t;i<64*64;i+=256){
        int lt = i>>6, dh = i&63;
        int tok = t0 + lt;
        if(tok < 255) continue;
        float s = 0.f;
        #pragma unroll
        for(int j=0;j<33;j++) s = fmaf(sw[j], sv[lt+j][dh], s);
        ac[((long)b*4097 + (tok-255))*512 + hh*64 + dh] = s;
    }
}

// ---------------- transposes token<->planar ----------------
__global__ void k_h2planar(const float* __restrict__ h, float* __restrict__ cnn){
    __shared__ float tile[32][33];
    int b = blockIdx.z;
    int c0 = blockIdx.x*32, p0 = blockIdx.y*32;
    int tx = threadIdx.x, ty = threadIdx.y;
    for(int i=ty;i<32;i+=8)
        tile[i][tx] = h[((long)b*4097 + 1 + p0+i)*512 + c0+tx];
    __syncthreads();
    for(int i=ty;i<32;i+=8)
        cnn[((long)b*512 + c0+i)*4096 + p0+tx] = tile[tx][i];
}

__global__ void k_planar2h(const float* __restrict__ yp, float* __restrict__ h2){
    __shared__ float tile[32][33];
    int b = blockIdx.z;
    int c0 = blockIdx.x*32, p0 = blockIdx.y*32;
    int tx = threadIdx.x, ty = threadIdx.y;
    for(int i=ty;i<32;i+=8)
        tile[i][tx] = yp[((long)b*512 + c0+i)*4096 + p0+tx];
    __syncthreads();
    for(int i=ty;i<32;i+=8)
        h2[((long)b*4097 + 1 + p0+i)*512 + c0+tx] = tile[tx][i];
}

__global__ void k_cls_copy(const float* __restrict__ h, float* __restrict__ h2){
    int idx = blockIdx.x*256 + threadIdx.x;
    if(idx >= 8*512) return;
    int b = idx >> 9, c = idx & 511;
    h2[(long)b*4097*512 + c] = h[(long)b*4097*512 + c];
}

// ---------------- fused 7x7 + 5x5 + 3x3 depthwise conv, planar ----------------
__global__ void k_dwconv(const float* __restrict__ cnn,
                         const float* __restrict__ w7, const float* __restrict__ b7,
                         const float* __restrict__ w5, const float* __restrict__ b5,
                         const float* __restrict__ w3, const float* __restrict__ b3,
                         float* __restrict__ yp){
    int bc = blockIdx.x; int c = bc & 511;
    __shared__ float pl[64][65];
    __shared__ float ww[84];
    const float* in = cnn + (long)bc*4096;
    int t = threadIdx.x;
    for(int i=t;i<4096;i+=256) pl[i>>6][i&63] = in[i];
    if(t < 49)      ww[t]      = w7[c*49 + t];
    else if(t < 74) ww[t]      = w5[c*25 + t - 49];
    else if(t < 83) ww[t]      = w3[c*9  + t - 74];
    __syncthreads();
    float bias = b7[c] + b5[c] + b3[c];
    for(int i=t;i<4096;i+=256){
        int y = i >> 6, x = i & 63;
        float s = pl[y][x] + bias;
        #pragma unroll
        for(int ky=0;ky<7;ky++){ int yy=y+ky-3; if((unsigned)yy>=64u) continue;
            #pragma unroll
            for(int kx=0;kx<7;kx++){ int xx=x+kx-3; if((unsigned)xx>=64u) continue;
                s = fmaf(ww[ky*7+kx], pl[yy][xx], s); } }
        #pragma unroll
        for(int ky=0;ky<5;ky++){ int yy=y+ky-2; if((unsigned)yy>=64u) continue;
            #pragma unroll
            for(int kx=0;kx<5;kx++){ int xx=x+kx-2; if((unsigned)xx>=64u) continue;
                s = fmaf(ww[49+ky*5+kx], pl[yy][xx], s); } }
        #pragma unroll
        for(int ky=0;ky<3;ky++){ int yy=y+ky-1; if((unsigned)yy>=64u) continue;
            #pragma unroll
            for(int kx=0;kx<3;kx++){ int xx=x+kx-1; if((unsigned)xx>=64u) continue;
                s = fmaf(ww[74+ky*3+kx], pl[yy][xx], s); } }
        yp[(long)bc*4096 + i] = s;
    }
}

// ---------------- final output: (cls[8,512], feat[8,4096,512]) ----------------
__global__ void k_writeout(const float* __restrict__ h2, float* __restrict__ out){
    long idx = (long)blockIdx.x*256 + threadIdx.x;
    if(idx >= 8L*512 + 8L*4096*512) return;
    if(idx < 8*512){
        int b = (int)(idx >> 9), c = (int)(idx & 511);
        out[idx] = h2[((long)b*4097)*512 + c];
    } else {
        long r = idx - 4096;
        int c = (int)(r & 511); long q = r >> 9; int t = (int)(q % 4096); int b = (int)(q / 4096);
        out[idx] = h2[((long)b*4097 + 1 + t)*512 + c];
    }
}

// ================= host side =================
struct Ptrs {
    float *h,*h2,*stat,*qkv,*ql,*kl,*a2,*zA,*zB,*xz,*t1,*t2,*a3v,*tmp2,*ac,*cnn,*yp;
};

static void get_ptrs(Ptrs& p){
    cudaGetSymbolAddress((void**)&p.h,    g_h);
    cudaGetSymbolAddress((void**)&p.h2,   g_h2);
    cudaGetSymbolAddress((void**)&p.stat, g_stat);
    cudaGetSymbolAddress((void**)&p.qkv,  g_qkv);
    cudaGetSymbolAddress((void**)&p.ql,   g_ql);
    cudaGetSymbolAddress((void**)&p.kl,   g_kl);
    cudaGetSymbolAddress((void**)&p.a2,   g_a2);
    cudaGetSymbolAddress((void**)&p.zA,   g_zA);
    cudaGetSymbolAddress((void**)&p.zB,   g_zB);
    cudaGetSymbolAddress((void**)&p.xz,   g_xz);
    cudaGetSymbolAddress((void**)&p.t1,   g_t1);
    cudaGetSymbolAddress((void**)&p.t2,   g_t2);
    cudaGetSymbolAddress((void**)&p.a3v,  g_a3v);
    cudaGetSymbolAddress((void**)&p.tmp2, g_tmp2);
    cudaGetSymbolAddress((void**)&p.ac,   g_ac);
    cudaGetSymbolAddress((void**)&p.cnn,  g_cnn);
    cudaGetSymbolAddress((void**)&p.yp,   g_yp);
}

static void attention(Ptrs& p, float* hbuf,
                      const float* lng, const float* lnb,
                      const float* qkvw, const float* outw, const float* outb,
                      const float* resw,
                      cudaStream_t side, cudaEvent_t evFork, cudaEvent_t evA3v, cudaEvent_t evJoin)
{
    const long SQKV_B = 4352L*1536;
    const long SQL    = 256L*64;
    const long SA2    = 65536L;
    const long SV64   = 256L*64;

    // LN stats, then qkv = LN(h) @ qkv_w^T fused (34816 padded x 1536 x 512)
    k_lnstat<<<4097, 256>>>(hbuf, p.stat);
    k_mma_nt_ln<<<dim3(272,12,1), 256>>>(hbuf, p.stat, lng, lnb,
                                         qkvw, 512, p.qkv, 1536, 1536, 512);

    k_landmarks<<<64*256, 64>>>(p.qkv, p.ql, p.kl);

    // ---- fork: flash3 + resconv2 on side stream, overlapping the pinv chain ----
    cudaEventRecord(evFork, 0);
    cudaStreamWaitEvent(side, evFork, 0);
    k_flash3<<<dim3(4,1,64), 256, 55040, side>>>(p.ql, SQL, p.qkv, SQKV_B, p.a3v, SV64);
    cudaEventRecord(evA3v, side);
    k_resconv2<<<dim3(68,64), 256, 0, side>>>(p.qkv, resw, p.ac);
    cudaEventRecord(evJoin, side);

    // ---- legacy stream: a2 softmax + persistent pinv ----
    k_simsm<<<dim3(4,1,64), 256>>>(p.ql, 64, 8*SQL, SQL,
                                   p.kl, 64, 8*SQL, SQL,
                                   p.a2, 256, 8*SA2, SA2, 1.f);
    k_scal_init<<<1, 32>>>();
    k_rowsum_max<<<64*256, 256>>>(p.a2);
    k_colsum_max<<<64, 256>>>(p.a2);
    k_tr_scale<<<16384, 256>>>(p.a2, p.zA);

    // all 6 Newton-Schulz iterations in one persistent launch; final z in zA
    k_pinv<<<256, 256>>>(p.a2, p.zA, p.zB, p.xz, p.t1, p.t2);

    // join a3v before tmp2
    cudaStreamWaitEvent(0, evA3v, 0);
    k_mma_nn64<<<dim3(2,1,64), 256>>>(p.zA, 256, 8*SA2, SA2, p.a3v, 64, 8*SV64, SV64,
                                      p.tmp2, 64, 8*SV64, SV64, 256, 256, 1.f, 0);

    // join resconv2 before attnout (attnout adds into ac)
    cudaStreamWaitEvent(0, evJoin, 0);
    k_attnout<<<dim3(68,1,64), 256>>>(p.qkv, 1536, SQKV_B, 64,
                                      p.kl, SQL, p.tmp2, SV64,
                                      p.ac, 0.125f);

    // hbuf += ac @ out_w^T + out_b
    k_mma_nt<<<dim3(257,4,1), 256>>>(p.ac, 512, 0,0, outw, 512, 0,0,
                                     hbuf, 512, 0,0, 32776, 512, 512, 1.f, outb, 1);
}

extern "C" void kernel_launch(void* const* d_in, const int* in_sizes, int n_in,
                              void* d_out, int out_size)
{
    const float* features = (const float*)d_in[0];
    const float* cls_tok  = (const float*)d_in[1];
    const float* ln1_g    = (const float*)d_in[2];
    const float* ln1_b    = (const float*)d_in[3];
    const float* qkv1_w   = (const float*)d_in[4];
    const float* out1_w   = (const float*)d_in[5];
    const float* out1_b   = (const float*)d_in[6];
    const float* res1_w   = (const float*)d_in[7];
    const float* p7_w     = (const float*)d_in[8];
    const float* p7_b     = (const float*)d_in[9];
    const float* p5_w     = (const float*)d_in[10];
    const float* p5_b     = (const float*)d_in[11];
    const float* p3_w     = (const float*)d_in[12];
    const float* p3_b     = (const float*)d_in[13];
    const float* ln2_g    = (const float*)d_in[14];
    const float* ln2_b    = (const float*)d_in[15];
    const float* qkv2_w   = (const float*)d_in[16];
    const float* out2_w   = (const float*)d_in[17];
    const float* out2_b   = (const float*)d_in[18];
    const float* res2_w   = (const float*)d_in[19];
    float* out = (float*)d_out;

    cudaFuncSetAttribute(k_flash3, cudaFuncAttributeMaxDynamicSharedMemorySize, 55040);

    static cudaStream_t side = nullptr;
    static cudaEvent_t ev[6];
    if(side == nullptr){
        cudaStreamCreateWithFlags(&side, cudaStreamNonBlocking);
        for(int i=0;i<6;i++) cudaEventCreateWithFlags(&ev[i], cudaEventDisableTiming);
    }

    Ptrs p;
    get_ptrs(p);

    k_build_h<<<65552, 256>>>(features, cls_tok);

    attention(p, p.h, ln1_g, ln1_b, qkv1_w, out1_w, out1_b, res1_w,
              side, ev[0], ev[1], ev[2]);

    k_h2planar<<<dim3(16,128,8), dim3(32,8)>>>(p.h, p.cnn);
    k_dwconv<<<4096, 256>>>(p.cnn, p7_w, p7_b, p5_w, p5_b, p3_w, p3_b, p.yp);
    k_planar2h<<<dim3(16,128,8), dim3(32,8)>>>(p.yp, p.h2);
    k_cls_copy<<<16, 256>>>(p.h, p.h2);

    attention(p, p.h2, ln2_g, ln2_b, qkv2_w, out2_w, out2_b, res2_w,
              side, ev[3], ev[4], ev[5]);

    k_writeout<<<65552, 256>>>(p.h2, out);
}